// round 1
// baseline (speedup 1.0000x reference)
#include <cuda_runtime.h>
#include <math.h>

// Problem constants
#define BATCH 8
#define SEQ   4096
#define CH    768
#define NH    12
#define HD    64
#define RM    128              // random feature dim M
#define BH    (BATCH*NH)       // 96
#define LAMBDA 0.3f
#define NSTEP 5
#define SPLITS 16
#define NCHUNK (SEQ/SPLITS)    // 256

// ---------------- scratch (static device globals; no allocs) ----------------
__device__ float g_Q  [(size_t)BH*SEQ*HD];           // qs (pre-scaled), [b,h,n,d]
__device__ float g_V  [(size_t)BH*SEQ*HD];           // v,               [b,h,n,d]
__device__ float g_RF [(size_t)BH*SEQ*RM];           // unnormalized rf  [b,h,n,m]
__device__ float g_D  [BH*RM];                       // 1/colnorm
__device__ float g_PART[(size_t)SPLITS*BH*RM*(RM+HD)]; // split-K partials
__device__ float g_KK [(size_t)BH*RM*RM];            // scaled kk
__device__ float g_KV [(size_t)BH*RM*HD];            // scaled kv
__device__ float g_Lc [BH];                          // Lipschitz L
__device__ float g_S  [(size_t)BH*RM*HD];            // d_m * s
__device__ float g_OUTC[(size_t)BATCH*SEQ*CH];       // [b,n,c] pre-proj

// ---------------- generic 128x128x16 SGEMM, 8x8 per thread ------------------
// EPI==0: C=x@Wqkv, split epilogue -> g_Q (scaled) / g_V in head-major layout
// EPI==1: A=g_OUTC, C=A@Wproj + bias -> d_out
template<int EPI>
__global__ __launch_bounds__(256)
void sgemm_kernel(const float* __restrict__ A, const float* __restrict__ Bm,
                  const float* __restrict__ bias, float* __restrict__ Cout,
                  int Kdim, int Ncols)
{
    const float* Ap = (EPI == 1) ? (const float*)g_OUTC : A;
    __shared__ float As[16*132];   // transposed A tile: As[k*132+m]
    __shared__ float Bs[16*132];   // Bs[k*132+n]
    int tid  = threadIdx.x;
    int brow = blockIdx.y * 128;
    int bcol = blockIdx.x * 128;

    float acc[8][8];
#pragma unroll
    for (int i = 0; i < 8; i++)
#pragma unroll
        for (int j = 0; j < 8; j++) acc[i][j] = 0.f;

    int ty = tid >> 4, tx = tid & 15;
    int m0 = ty * 8, n0 = tx * 8;

    for (int k0 = 0; k0 < Kdim; k0 += 16) {
#pragma unroll
        for (int l = 0; l < 2; l++) {            // A: 512 float4
            int f = tid + l * 256;
            int row = f >> 2, kq = (f & 3) * 4;
            float4 v = *(const float4*)&Ap[(size_t)(brow + row) * Kdim + k0 + kq];
            As[(kq + 0) * 132 + row] = v.x;
            As[(kq + 1) * 132 + row] = v.y;
            As[(kq + 2) * 132 + row] = v.z;
            As[(kq + 3) * 132 + row] = v.w;
        }
#pragma unroll
        for (int l = 0; l < 2; l++) {            // B: 512 float4
            int f = tid + l * 256;
            int kr = f >> 5, cq = (f & 31) * 4;
            *(float4*)&Bs[kr * 132 + cq] =
                *(const float4*)&Bm[(size_t)(k0 + kr) * Ncols + bcol + cq];
        }
        __syncthreads();
#pragma unroll
        for (int k = 0; k < 16; k++) {
            float4 a0 = *(float4*)&As[k * 132 + m0];
            float4 a1 = *(float4*)&As[k * 132 + m0 + 4];
            float4 b0 = *(float4*)&Bs[k * 132 + n0];
            float4 b1 = *(float4*)&Bs[k * 132 + n0 + 4];
            float a[8] = {a0.x, a0.y, a0.z, a0.w, a1.x, a1.y, a1.z, a1.w};
            float b[8] = {b0.x, b0.y, b0.z, b0.w, b1.x, b1.y, b1.z, b1.w};
#pragma unroll
            for (int i = 0; i < 8; i++)
#pragma unroll
                for (int j = 0; j < 8; j++) acc[i][j] += a[i] * b[j];
        }
        __syncthreads();
    }

    if (EPI == 0) {
        (void)bias; (void)Cout;
#pragma unroll
        for (int i = 0; i < 8; i++) {
            int grow = brow + m0 + i;
            int bb = grow >> 12;       // /SEQ
            int nn = grow & 4095;
#pragma unroll
            for (int j = 0; j < 8; j++) {
                int col = bcol + n0 + j;
                float v = acc[i][j];
                if (col < CH) {
                    int h = col >> 6, dd = col & 63;
                    g_Q[(((size_t)(bb * NH + h)) * SEQ + nn) * HD + dd] =
                        v * 0.35355339059327373f;   // hd^(-1/4)
                } else {
                    int c2 = col - CH;
                    int h = c2 >> 6, dd = c2 & 63;
                    g_V[(((size_t)(bb * NH + h)) * SEQ + nn) * HD + dd] = v;
                }
            }
        }
    } else {
#pragma unroll
        for (int i = 0; i < 8; i++) {
            int grow = brow + m0 + i;
#pragma unroll
            for (int j = 0; j < 8; j += 4) {
                int col = bcol + n0 + j;
                float4 bv = *(const float4*)&bias[col];
                float4 o;
                o.x = acc[i][j + 0] + bv.x;
                o.y = acc[i][j + 1] + bv.y;
                o.z = acc[i][j + 2] + bv.z;
                o.w = acc[i][j + 3] + bv.w;
                *(float4*)&Cout[(size_t)grow * Ncols + col] = o;
            }
        }
    }
}

// ---------------- random feature map: rf = exp(qs@R - 0.5||qs||^2)/sqrt(M) --
__global__ __launch_bounds__(256)
void rf_kernel(const float* __restrict__ randm)
{
    __shared__ float Rs[64 * 132];   // [k][m], pitch 132
    __shared__ float Qs[32 * 68];    // [row][k], pitch 68
    int bh = blockIdx.y;
    int h  = bh % NH;
    int rowblk = blockIdx.x;         // 128 blocks of 32 rows

    for (int f = threadIdx.x; f < 64 * RM / 4; f += 256) {
        int k = f >> 5, mq = (f & 31) * 4;
        *(float4*)&Rs[k * 132 + mq] =
            *(const float4*)&randm[((size_t)h * HD + k) * RM + mq];
    }
    const float* Qbase = g_Q + ((size_t)bh * SEQ + (size_t)rowblk * 32) * HD;
    for (int f = threadIdx.x; f < 32 * HD / 4; f += 256) {
        int r = f >> 4, kq = (f & 15) * 4;
        *(float4*)&Qs[r * 68 + kq] = *(const float4*)&Qbase[(size_t)r * HD + kq];
    }
    __syncthreads();

    int r  = threadIdx.x >> 3;           // 0..31
    int mq = (threadIdx.x & 7) * 16;     // 16 m's per thread
    float acc[16];
#pragma unroll
    for (int i = 0; i < 16; i++) acc[i] = 0.f;
    float sq = 0.f;
    for (int k = 0; k < HD; k++) {
        float qv = Qs[r * 68 + k];
        sq += qv * qv;
        const float4* rp = (const float4*)&Rs[k * 132 + mq];
#pragma unroll
        for (int q = 0; q < 4; q++) {
            float4 v = rp[q];
            acc[q * 4 + 0] += qv * v.x;
            acc[q * 4 + 1] += qv * v.y;
            acc[q * 4 + 2] += qv * v.z;
            acc[q * 4 + 3] += qv * v.w;
        }
    }
    float* dst = g_RF + ((size_t)bh * SEQ + (size_t)rowblk * 32 + r) * RM + mq;
    float base = -0.5f * sq;
    const float sc = 0.08838834764831845f;  // 1/sqrt(128)
#pragma unroll
    for (int q = 0; q < 4; q++) {
        float4 o;
        o.x = expf(acc[q * 4 + 0] + base) * sc;
        o.y = expf(acc[q * 4 + 1] + base) * sc;
        o.z = expf(acc[q * 4 + 2] + base) * sc;
        o.w = expf(acc[q * 4 + 3] + base) * sc;
        *(float4*)&dst[q * 4] = o;
    }
}

// ---------------- column norms over sequence axis ---------------------------
__global__ __launch_bounds__(256)
void colnorm_kernel()
{
    __shared__ float red[8][32];
    int bh  = blockIdx.y;
    int lane = threadIdx.x & 31;
    int m   = blockIdx.x * 32 + lane;
    int grp = threadIdx.x >> 5;
    const float* base = g_RF + (size_t)bh * SEQ * RM;
    float sum = 0.f;
    for (int n = grp; n < SEQ; n += 8) {
        float v = base[(size_t)n * RM + m];
        sum += v * v;
    }
    red[grp][lane] = sum;
    __syncthreads();
    if (grp == 0) {
        float t = 0.f;
#pragma unroll
        for (int g = 0; g < 8; g++) t += red[g][lane];
        float nrm = sqrtf(t);
        g_D[bh * RM + m] = 1.0f / fmaxf(nrm, 1e-12f);
    }
}

// ---------------- kk/kv split-K partial GEMM: C = rf^T [rf|v] over 256 rows -
__global__ __launch_bounds__(256)
void kkkv_kernel()
{
    __shared__ float Xs[16 * 132];
    __shared__ float Ys[16 * 68];
    int bh    = blockIdx.y;
    int split = blockIdx.x / 3;
    int ct    = blockIdx.x % 3;   // 0: kk cols 0..63, 1: kk cols 64..127, 2: kv
    const float* rf = g_RF + ((size_t)bh * SEQ + (size_t)split * NCHUNK) * RM;
    const float* yp; int ystr;
    if (ct == 2) { yp = g_V + ((size_t)bh * SEQ + (size_t)split * NCHUNK) * HD; ystr = HD; }
    else         { yp = rf + ct * 64; ystr = RM; }

    float acc[4][8];
#pragma unroll
    for (int i = 0; i < 4; i++)
#pragma unroll
        for (int j = 0; j < 8; j++) acc[i][j] = 0.f;

    int tmI = threadIdx.x >> 3;   // m0 = tmI*4
    int tj  = threadIdx.x & 7;    // j0 = tj*8

    for (int n0 = 0; n0 < NCHUNK; n0 += 16) {
#pragma unroll
        for (int l = 0; l < 2; l++) {
            int f = threadIdx.x + l * 256;
            int nn = f >> 5, mq = (f & 31) * 4;
            *(float4*)&Xs[nn * 132 + mq] =
                *(const float4*)&rf[(size_t)(n0 + nn) * RM + mq];
        }
        {
            int f = threadIdx.x;
            int nn = f >> 4, jq = (f & 15) * 4;
            *(float4*)&Ys[nn * 68 + jq] =
                *(const float4*)&yp[(size_t)(n0 + nn) * ystr + jq];
        }
        __syncthreads();
#pragma unroll
        for (int nn = 0; nn < 16; nn++) {
            float4 a  = *(float4*)&Xs[nn * 132 + tmI * 4];
            float4 b0 = *(float4*)&Ys[nn * 68 + tj * 8];
            float4 b1 = *(float4*)&Ys[nn * 68 + tj * 8 + 4];
            float aa[4] = {a.x, a.y, a.z, a.w};
            float bb[8] = {b0.x, b0.y, b0.z, b0.w, b1.x, b1.y, b1.z, b1.w};
#pragma unroll
            for (int i = 0; i < 4; i++)
#pragma unroll
                for (int j = 0; j < 8; j++) acc[i][j] += aa[i] * bb[j];
        }
        __syncthreads();
    }
    float* dst = g_PART + ((size_t)split * BH + bh) * (RM * (RM + HD));
#pragma unroll
    for (int i = 0; i < 4; i++)
#pragma unroll
        for (int j = 0; j < 8; j++)
            dst[(tmI * 4 + i) * (RM + HD) + ct * HD + tj * 8 + j] = acc[i][j];
}

// ---------------- reduce splits, scale by d, compute L -----------------------
__global__ __launch_bounds__(256)
void reduce_kernel()
{
    extern __shared__ float kks[];    // 128*128 floats (64 KB dynamic)
    __shared__ float dsh[RM];
    __shared__ float rowsum[RM];
    int bh = blockIdx.x;
    if (threadIdx.x < RM) dsh[threadIdx.x] = g_D[bh * RM + threadIdx.x];
    __syncthreads();
    for (int idx = threadIdx.x; idx < RM * (RM + HD); idx += 256) {
        int m = idx / (RM + HD);
        int j = idx - m * (RM + HD);
        float s = 0.f;
#pragma unroll
        for (int sp = 0; sp < SPLITS; sp++)
            s += g_PART[((size_t)sp * BH + bh) * (RM * (RM + HD)) + idx];
        if (j < RM) {
            float v = s * dsh[m] * dsh[j];
            kks[m * RM + j] = v;
            g_KK[((size_t)bh * RM + m) * RM + j] = v;
        } else {
            g_KV[((size_t)bh * RM + m) * HD + (j - RM)] = s * dsh[m];
        }
    }
    __syncthreads();
    if (threadIdx.x < RM) {
        float rs = 0.f;
        for (int j = 0; j < RM; j++) rs += fabsf(kks[threadIdx.x * RM + j]);
        rowsum[threadIdx.x] = rs;
    }
    __syncthreads();
    if (threadIdx.x == 0) {
        float mx = 0.f;
        for (int i = 0; i < RM; i++) mx = fmaxf(mx, rowsum[i]);
        g_Lc[bh] = mx + 1.0f;
    }
}

// ---------------- ISTA soft-thresholding loop (per head) --------------------
__device__ __forceinline__ float softf(float z, float t)
{
    float a = fabsf(z) - t;
    return a > 0.f ? (z >= 0.f ? a : -a) : 0.f;
}

__global__ __launch_bounds__(256)
void ista_kernel()
{
    extern __shared__ float sm[];
    float* kks = sm;                 // [128][129]
    float* kvs = sm + RM * 129;      // [128][64]
    float* ss  = kvs + RM * HD;      // [128][68]
    int bh = blockIdx.x;
    float L    = g_Lc[bh];
    float invL = 1.0f / L;
    float thr  = LAMBDA * invL;

    for (int idx = threadIdx.x; idx < RM * RM; idx += 256) {
        int m = idx >> 7, j = idx & 127;
        kks[m * 129 + j] = g_KK[(size_t)bh * RM * RM + idx];
    }
    for (int idx = threadIdx.x; idx < RM * HD; idx += 256)
        kvs[idx] = g_KV[(size_t)bh * RM * HD + idx];
    __syncthreads();

    int m  = threadIdx.x >> 1;
    int ch = (threadIdx.x & 1) * 32;
#pragma unroll
    for (int i = 0; i < 32; i++)
        ss[m * 68 + ch + i] = softf(kvs[m * HD + ch + i], LAMBDA);
    __syncthreads();

    for (int it = 0; it < NSTEP; it++) {
        float acc[32];
#pragma unroll
        for (int i = 0; i < 32; i++) acc[i] = 0.f;
        for (int p = 0; p < RM; p++) {
            float kv_ = kks[m * 129 + p];
            const float4* sp = (const float4*)&ss[p * 68 + ch];
#pragma unroll
            for (int q = 0; q < 8; q++) {
                float4 v = sp[q];
                acc[q * 4 + 0] += kv_ * v.x;
                acc[q * 4 + 1] += kv_ * v.y;
                acc[q * 4 + 2] += kv_ * v.z;
                acc[q * 4 + 3] += kv_ * v.w;
            }
        }
        float r[32];
#pragma unroll
        for (int i = 0; i < 32; i++) {
            float z = ss[m * 68 + ch + i] - (acc[i] - kvs[m * HD + ch + i]) * invL;
            r[i] = softf(z, thr);
        }
        __syncthreads();
#pragma unroll
        for (int q = 0; q < 8; q++)
            *(float4*)&ss[m * 68 + ch + q * 4] =
                make_float4(r[q * 4], r[q * 4 + 1], r[q * 4 + 2], r[q * 4 + 3]);
        __syncthreads();
    }
    float dm = g_D[bh * RM + m];
#pragma unroll
    for (int q = 0; q < 8; q++) {
        float4 v = *(float4*)&ss[m * 68 + ch + q * 4];
        v.x *= dm; v.y *= dm; v.z *= dm; v.w *= dm;
        *(float4*)&g_S[((size_t)bh * RM + m) * HD + ch + q * 4] = v;
    }
}

// ---------------- out = rf @ (D s), written in [b,n,c] layout ----------------
__global__ __launch_bounds__(256)
void outgemm_kernel()
{
    __shared__ float ssm[RM * HD];       // [k][j]
    __shared__ float rfs[128 * 20];      // [row][k-chunk 16] pitch 20
    int bh = blockIdx.y;
    int rb = blockIdx.x;                 // 32 blocks of 128 rows
    int b = bh / NH, h = bh % NH;

    for (int idx = threadIdx.x; idx < RM * HD / 4; idx += 256)
        *(float4*)&ssm[idx * 4] =
            *(const float4*)&g_S[(size_t)bh * RM * HD + idx * 4];

    const float* rf = g_RF + ((size_t)bh * SEQ + (size_t)rb * 128) * RM;

    float acc[4][8];
#pragma unroll
    for (int i = 0; i < 4; i++)
#pragma unroll
        for (int j = 0; j < 8; j++) acc[i][j] = 0.f;

    int rw = threadIdx.x >> 3;           // rows rw*4
    int tc = threadIdx.x & 7;            // cols tc*8

    for (int k0 = 0; k0 < RM; k0 += 16) {
        __syncthreads();
#pragma unroll
        for (int l = 0; l < 2; l++) {
            int f = threadIdx.x + l * 256;
            int row = f >> 2, kq = (f & 3) * 4;
            *(float4*)&rfs[row * 20 + kq] =
                *(const float4*)&rf[(size_t)row * RM + k0 + kq];
        }
        __syncthreads();
#pragma unroll
        for (int k = 0; k < 16; k++) {
            float aa[4];
#pragma unroll
            for (int i = 0; i < 4; i++) aa[i] = rfs[(rw * 4 + i) * 20 + k];
            float4 b0 = *(float4*)&ssm[(k0 + k) * HD + tc * 8];
            float4 b1 = *(float4*)&ssm[(k0 + k) * HD + tc * 8 + 4];
            float bb[8] = {b0.x, b0.y, b0.z, b0.w, b1.x, b1.y, b1.z, b1.w};
#pragma unroll
            for (int i = 0; i < 4; i++)
#pragma unroll
                for (int j = 0; j < 8; j++) acc[i][j] += aa[i] * bb[j];
        }
    }
#pragma unroll
    for (int i = 0; i < 4; i++) {
        int row = rb * 128 + rw * 4 + i;
        float* dst = g_OUTC + ((size_t)b * SEQ + row) * CH + h * HD + tc * 8;
        *(float4*)&dst[0] = make_float4(acc[i][0], acc[i][1], acc[i][2], acc[i][3]);
        *(float4*)&dst[4] = make_float4(acc[i][4], acc[i][5], acc[i][6], acc[i][7]);
    }
}

// ---------------- launch ----------------------------------------------------
extern "C" void kernel_launch(void* const* d_in, const int* in_sizes, int n_in,
                              void* d_out, int out_size)
{
    const float *x = nullptr, *wqkv = nullptr, *wproj = nullptr,
                *bias = nullptr, *rm = nullptr;
    for (int i = 0; i < n_in; i++) {
        const float* p = (const float*)d_in[i];
        switch (in_sizes[i]) {
            case BATCH * SEQ * CH: x = p; break;          // 25165824
            case CH * 2 * CH:      wqkv = p; break;       // 1179648
            case CH * CH:          wproj = p; break;      // 589824
            case CH:               bias = p; break;       // 768
            case NH * HD * RM:     rm = p; break;         // 98304
        }
    }
    float* out = (float*)d_out;
    (void)out_size;

    cudaFuncSetAttribute(reduce_kernel,
                         cudaFuncAttributeMaxDynamicSharedMemorySize, RM * RM * 4);
    cudaFuncSetAttribute(ista_kernel,
                         cudaFuncAttributeMaxDynamicSharedMemorySize,
                         (RM * 129 + RM * HD + RM * 68) * 4);

    // 1. qkv = x @ Wqkv, split into head-major qs / v
    sgemm_kernel<0><<<dim3(12, 256), 256>>>(x, wqkv, nullptr, nullptr, CH, 2 * CH);
    // 2. random feature map
    rf_kernel<<<dim3(128, BH), 256>>>(rm);
    // 3. column norms (deterministic tree reduction)
    colnorm_kernel<<<dim3(4, BH), 256>>>();
    // 4. split-K kk/kv partials
    kkkv_kernel<<<dim3(48, BH), 256>>>();
    // 5. combine partials, apply norm scaling, Lipschitz L
    reduce_kernel<<<BH, 256, RM * RM * 4>>>();
    // 6. ISTA loop, writes d_m-scaled s
    ista_kernel<<<BH, 256, (RM * 129 + RM * HD + RM * 68) * 4>>>();
    // 7. out_head = rf @ s_scaled, written as [b,n,c]
    outgemm_kernel<<<dim3(32, BH), 256>>>();
    // 8. final projection + bias
    sgemm_kernel<1><<<dim3(6, 256), 256>>>(x, wproj, bias, out, CH, CH);
}

// round 3
// speedup vs baseline: 1.4155x; 1.4155x over previous
#include <cuda_runtime.h>
#include <cuda_bf16.h>
#include <math.h>
#include <cstdint>

// Problem constants
#define BATCH 8
#define SEQ   4096
#define CH    768
#define NH    12
#define HD    64
#define RM    128
#define BH    (BATCH*NH)
#define LAMBDA 0.3f
#define NSTEP 5
#define SPLITS 16
#define NCHUNK (SEQ/SPLITS)

// ---------------- scratch ----------------------------------------------------
__device__ float g_Q  [(size_t)BH*SEQ*HD];
__device__ float g_V  [(size_t)BH*SEQ*HD];
__device__ float g_RF [(size_t)BH*SEQ*RM];
__device__ float g_D  [BH*RM];
__device__ float g_PART[(size_t)SPLITS*BH*RM*(RM+HD)];
__device__ float g_KK [(size_t)BH*RM*RM];
__device__ float g_KV [(size_t)BH*RM*HD];
__device__ float g_Lc [BH];
__device__ float g_S  [(size_t)BH*RM*HD];
// bf16 split pairs
__device__ __nv_bfloat16 g_XA1[(size_t)BATCH*SEQ*CH];
__device__ __nv_bfloat16 g_XA2[(size_t)BATCH*SEQ*CH];
__device__ __nv_bfloat16 g_WQ1[(size_t)2*CH*CH];   // transposed [2C, C]
__device__ __nv_bfloat16 g_WQ2[(size_t)2*CH*CH];
__device__ __nv_bfloat16 g_WP1[(size_t)CH*CH];     // transposed [C, C]
__device__ __nv_bfloat16 g_WP2[(size_t)CH*CH];
__device__ __nv_bfloat16 g_OC1[(size_t)BATCH*SEQ*CH];
__device__ __nv_bfloat16 g_OC2[(size_t)BATCH*SEQ*CH];

// ---------------- warp-MMA helpers -------------------------------------------
__device__ __forceinline__ uint32_t smem_u32(const void* p) {
    uint32_t a;
    asm("{ .reg .u64 t; cvta.to.shared.u64 t, %1; cvt.u32.u64 %0, t; }"
        : "=r"(a) : "l"(p));
    return a;
}

__device__ __forceinline__ void ldmx4(uint32_t& r0, uint32_t& r1,
                                      uint32_t& r2, uint32_t& r3, uint32_t addr)
{
    asm volatile("ldmatrix.sync.aligned.m8n8.x4.shared.b16 {%0,%1,%2,%3}, [%4];"
                 : "=r"(r0), "=r"(r1), "=r"(r2), "=r"(r3) : "r"(addr));
}

__device__ __forceinline__ void mma16816(float* c, const uint32_t* a,
                                         const uint32_t* b)
{
    asm volatile(
        "mma.sync.aligned.m16n8k16.row.col.f32.bf16.bf16.f32 "
        "{%0,%1,%2,%3}, {%4,%5,%6,%7}, {%8,%9}, {%0,%1,%2,%3};"
        : "+f"(c[0]), "+f"(c[1]), "+f"(c[2]), "+f"(c[3])
        : "r"(a[0]), "r"(a[1]), "r"(a[2]), "r"(a[3]), "r"(b[0]), "r"(b[1]));
}

#define PITCH 40   // bf16 elements per smem row (80 B -> conflict-free ldmatrix)

// ---------------- HMMA GEMM: 128x128 tile, 3-term bf16 split ------------------
// EPI==0: A=x pair [32768,768], B=WqkvT pair [1536,768] -> g_Q (scaled) / g_V
// EPI==1: A=OC pair, B=WprojT pair [768,768], +bias -> Cout
template<int EPI>
__global__ __launch_bounds__(256, 2)
void hmma_gemm(const float* __restrict__ bias, float* __restrict__ Cout, int Kdim)
{
    __shared__ __nv_bfloat16 As1[128 * PITCH], As2[128 * PITCH];
    __shared__ __nv_bfloat16 Bs1[128 * PITCH], Bs2[128 * PITCH];

    const int tid  = threadIdx.x;
    const int wid  = tid >> 5;
    const int lane = tid & 31;
    const int wm   = wid & 1;         // warp row (2)
    const int wn   = wid >> 1;        // warp col (4)
    const int brow = blockIdx.y * 128;
    const int bcol = blockIdx.x * 128;

    const __nv_bfloat16* A1 = (EPI == 0) ? g_XA1 : g_OC1;
    const __nv_bfloat16* A2 = (EPI == 0) ? g_XA2 : g_OC2;
    const __nv_bfloat16* B1 = (EPI == 0) ? g_WQ1 : g_WP1;
    const __nv_bfloat16* B2 = (EPI == 0) ? g_WQ2 : g_WP2;

    float acc[4][4][4];
#pragma unroll
    for (int i = 0; i < 4; i++)
#pragma unroll
        for (int j = 0; j < 4; j++)
#pragma unroll
            for (int q = 0; q < 4; q++) acc[i][j][q] = 0.f;

    // ldmatrix source addresses (per thread)
    const uint32_t as1 = smem_u32(As1), as2 = smem_u32(As2);
    const uint32_t bs1 = smem_u32(Bs1), bs2 = smem_u32(Bs2);
    const int arow = wm * 64 + (lane & 15);
    const int acolL = (lane >> 4) * 8;
    const int bn   = wn * 32 + (lane & 7) + ((lane >> 4) & 1) * 8;
    const int bkL  = ((lane >> 3) & 1) * 8;

    const int nchunk = Kdim >> 5;
    for (int kc = 0; kc < nchunk; kc++) {
        const int k0 = kc << 5;
        // load 4 tiles, each 128 rows x 32 bf16
#pragma unroll
        for (int t = 0; t < 4; t++) {
            const __nv_bfloat16* src = (t == 0) ? A1 : (t == 1) ? A2 : (t == 2) ? B1 : B2;
            __nv_bfloat16* dst = (t == 0) ? As1 : (t == 1) ? As2 : (t == 2) ? Bs1 : Bs2;
            const int rbase = (t < 2) ? brow : bcol;
#pragma unroll
            for (int u = 0; u < 2; u++) {
                int c = u * 256 + tid;          // 0..511 (16B units)
                int row = c >> 2, ch = (c & 3) * 8;
                uint4 v = *(const uint4*)(src + (size_t)(rbase + row) * Kdim + k0 + ch);
                *(uint4*)(dst + row * PITCH + ch) = v;
            }
        }
        __syncthreads();

#pragma unroll
        for (int ks = 0; ks < 2; ks++) {
            const int acol = ks * 16 + acolL;
            const int bk   = ks * 16 + bkL;
            uint32_t a1[4][4], a2[4][4], b1[4][2], b2[4][2];
#pragma unroll
            for (int mt = 0; mt < 4; mt++) {
                uint32_t off = ((arow + mt * 16) * PITCH + acol) * 2;
                ldmx4(a1[mt][0], a1[mt][1], a1[mt][2], a1[mt][3], as1 + off);
                ldmx4(a2[mt][0], a2[mt][1], a2[mt][2], a2[mt][3], as2 + off);
            }
#pragma unroll
            for (int nt2 = 0; nt2 < 2; nt2++) {
                uint32_t off = ((bn + nt2 * 16) * PITCH + bk) * 2;
                ldmx4(b1[nt2 * 2][0], b1[nt2 * 2][1],
                      b1[nt2 * 2 + 1][0], b1[nt2 * 2 + 1][1], bs1 + off);
                ldmx4(b2[nt2 * 2][0], b2[nt2 * 2][1],
                      b2[nt2 * 2 + 1][0], b2[nt2 * 2 + 1][1], bs2 + off);
            }
#pragma unroll
            for (int mt = 0; mt < 4; mt++)
#pragma unroll
                for (int nt = 0; nt < 4; nt++) {
                    mma16816(acc[mt][nt], a1[mt], b1[nt]);
                    mma16816(acc[mt][nt], a1[mt], b2[nt]);
                    mma16816(acc[mt][nt], a2[mt], b1[nt]);
                }
        }
        __syncthreads();
    }

    // -------- epilogue --------
    const int g  = lane >> 2;     // group 0..7
    const int tg = lane & 3;      // 0..3
#pragma unroll
    for (int mt = 0; mt < 4; mt++)
#pragma unroll
        for (int nt = 0; nt < 4; nt++) {
#pragma unroll
            for (int half = 0; half < 2; half++) {
                int grow = brow + wm * 64 + mt * 16 + g + half * 8;
                int col  = bcol + wn * 32 + nt * 8 + tg * 2;
                float2 v = make_float2(acc[mt][nt][half * 2],
                                       acc[mt][nt][half * 2 + 1]);
                if (EPI == 0) {
                    int bb = grow >> 12, nn = grow & 4095;
                    if (col < CH) {
                        const float s = 0.35355339059327373f;  // hd^(-1/4)
                        v.x *= s; v.y *= s;
                        int h = col >> 6, dd = col & 63;
                        *(float2*)&g_Q[(((size_t)(bb * NH + h)) * SEQ + nn) * HD + dd] = v;
                    } else {
                        int c2 = col - CH;
                        int h = c2 >> 6, dd = c2 & 63;
                        *(float2*)&g_V[(((size_t)(bb * NH + h)) * SEQ + nn) * HD + dd] = v;
                    }
                } else {
                    v.x += bias[col];
                    v.y += bias[col + 1];
                    *(float2*)&Cout[(size_t)grow * CH + col] = v;
                }
            }
        }
}

// ---------------- conversion kernels -----------------------------------------
__global__ __launch_bounds__(256)
void conv_x_kernel(const float* __restrict__ x)
{
    size_t i = ((size_t)blockIdx.x * 256 + threadIdx.x) * 4;
    float4 v = *(const float4*)&x[i];
    __nv_bfloat16 h0 = __float2bfloat16(v.x), h1 = __float2bfloat16(v.y);
    __nv_bfloat16 h2 = __float2bfloat16(v.z), h3 = __float2bfloat16(v.w);
    *(__nv_bfloat162*)&g_XA1[i]     = __halves2bfloat162(h0, h1);
    *(__nv_bfloat162*)&g_XA1[i + 2] = __halves2bfloat162(h2, h3);
    *(__nv_bfloat162*)&g_XA2[i] = __halves2bfloat162(
        __float2bfloat16(v.x - __bfloat162float(h0)),
        __float2bfloat16(v.y - __bfloat162float(h1)));
    *(__nv_bfloat162*)&g_XA2[i + 2] = __halves2bfloat162(
        __float2bfloat16(v.z - __bfloat162float(h2)),
        __float2bfloat16(v.w - __bfloat162float(h3)));
}

template<int WHICH>   // 0: Wqkv -> WQ (N=1536), 1: Wproj -> WP (N=768)
__global__ __launch_bounds__(256)
void conv_w_kernel(const float* __restrict__ W, int N)
{
    __nv_bfloat16* o1 = (WHICH == 0) ? g_WQ1 : g_WP1;
    __nv_bfloat16* o2 = (WHICH == 0) ? g_WQ2 : g_WP2;
    int idx = blockIdx.x * 256 + threadIdx.x;   // over [N][K=768]
    int n = idx / CH, k = idx - n * CH;
    float v = W[(size_t)k * N + n];
    __nv_bfloat16 h = __float2bfloat16(v);
    o1[idx] = h;
    o2[idx] = __float2bfloat16(v - __bfloat162float(h));
}

// ---------------- random feature map ------------------------------------------
__global__ __launch_bounds__(256)
void rf_kernel(const float* __restrict__ randm)
{
    __shared__ float Rs[64 * 132];
    __shared__ float Qs[32 * 68];
    int bh = blockIdx.y;
    int h  = bh % NH;
    int rowblk = blockIdx.x;

    for (int f = threadIdx.x; f < 64 * RM / 4; f += 256) {
        int k = f >> 5, mq = (f & 31) * 4;
        *(float4*)&Rs[k * 132 + mq] =
            *(const float4*)&randm[((size_t)h * HD + k) * RM + mq];
    }
    const float* Qbase = g_Q + ((size_t)bh * SEQ + (size_t)rowblk * 32) * HD;
    for (int f = threadIdx.x; f < 32 * HD / 4; f += 256) {
        int r = f >> 4, kq = (f & 15) * 4;
        *(float4*)&Qs[r * 68 + kq] = *(const float4*)&Qbase[(size_t)r * HD + kq];
    }
    __syncthreads();

    int r  = threadIdx.x >> 3;
    int mq = (threadIdx.x & 7) * 16;
    float acc[16];
#pragma unroll
    for (int i = 0; i < 16; i++) acc[i] = 0.f;
    float sq = 0.f;
    for (int k = 0; k < HD; k++) {
        float qv = Qs[r * 68 + k];
        sq += qv * qv;
        const float4* rp = (const float4*)&Rs[k * 132 + mq];
#pragma unroll
        for (int q = 0; q < 4; q++) {
            float4 v = rp[q];
            acc[q * 4 + 0] += qv * v.x;
            acc[q * 4 + 1] += qv * v.y;
            acc[q * 4 + 2] += qv * v.z;
            acc[q * 4 + 3] += qv * v.w;
        }
    }
    float* dst = g_RF + ((size_t)bh * SEQ + (size_t)rowblk * 32 + r) * RM + mq;
    float base = -0.5f * sq;
    const float sc = 0.08838834764831845f;
#pragma unroll
    for (int q = 0; q < 4; q++) {
        float4 o;
        o.x = expf(acc[q * 4 + 0] + base) * sc;
        o.y = expf(acc[q * 4 + 1] + base) * sc;
        o.z = expf(acc[q * 4 + 2] + base) * sc;
        o.w = expf(acc[q * 4 + 3] + base) * sc;
        *(float4*)&dst[q * 4] = o;
    }
}

// ---------------- column norms --------------------------------------------------
__global__ __launch_bounds__(256)
void colnorm_kernel()
{
    __shared__ float red[8][32];
    int bh  = blockIdx.y;
    int lane = threadIdx.x & 31;
    int m   = blockIdx.x * 32 + lane;
    int grp = threadIdx.x >> 5;
    const float* base = g_RF + (size_t)bh * SEQ * RM;
    float sum = 0.f;
    for (int n = grp; n < SEQ; n += 8) {
        float v = base[(size_t)n * RM + m];
        sum += v * v;
    }
    red[grp][lane] = sum;
    __syncthreads();
    if (grp == 0) {
        float t = 0.f;
#pragma unroll
        for (int g = 0; g < 8; g++) t += red[g][lane];
        g_D[bh * RM + m] = 1.0f / fmaxf(sqrtf(t), 1e-12f);
    }
}

// ---------------- kk/kv split-K partials ----------------------------------------
__global__ __launch_bounds__(256)
void kkkv_kernel()
{
    __shared__ float Xs[16 * 132];
    __shared__ float Ys[16 * 68];
    int bh    = blockIdx.y;
    int split = blockIdx.x / 3;
    int ct    = blockIdx.x % 3;
    const float* rf = g_RF + ((size_t)bh * SEQ + (size_t)split * NCHUNK) * RM;
    const float* yp; int ystr;
    if (ct == 2) { yp = g_V + ((size_t)bh * SEQ + (size_t)split * NCHUNK) * HD; ystr = HD; }
    else         { yp = rf + ct * 64; ystr = RM; }

    float acc[4][8];
#pragma unroll
    for (int i = 0; i < 4; i++)
#pragma unroll
        for (int j = 0; j < 8; j++) acc[i][j] = 0.f;

    int tmI = threadIdx.x >> 3;
    int tj  = threadIdx.x & 7;

    for (int n0 = 0; n0 < NCHUNK; n0 += 16) {
#pragma unroll
        for (int l = 0; l < 2; l++) {
            int f = threadIdx.x + l * 256;
            int nn = f >> 5, mq = (f & 31) * 4;
            *(float4*)&Xs[nn * 132 + mq] =
                *(const float4*)&rf[(size_t)(n0 + nn) * RM + mq];
        }
        {
            int f = threadIdx.x;
            int nn = f >> 4, jq = (f & 15) * 4;
            *(float4*)&Ys[nn * 68 + jq] =
                *(const float4*)&yp[(size_t)(n0 + nn) * ystr + jq];
        }
        __syncthreads();
#pragma unroll
        for (int nn = 0; nn < 16; nn++) {
            float4 a  = *(float4*)&Xs[nn * 132 + tmI * 4];
            float4 b0 = *(float4*)&Ys[nn * 68 + tj * 8];
            float4 b1 = *(float4*)&Ys[nn * 68 + tj * 8 + 4];
            float aa[4] = {a.x, a.y, a.z, a.w};
            float bb[8] = {b0.x, b0.y, b0.z, b0.w, b1.x, b1.y, b1.z, b1.w};
#pragma unroll
            for (int i = 0; i < 4; i++)
#pragma unroll
                for (int j = 0; j < 8; j++) acc[i][j] += aa[i] * bb[j];
        }
        __syncthreads();
    }
    float* dst = g_PART + ((size_t)split * BH + bh) * (RM * (RM + HD));
#pragma unroll
    for (int i = 0; i < 4; i++)
#pragma unroll
        for (int j = 0; j < 8; j++)
            dst[(tmI * 4 + i) * (RM + HD) + ct * HD + tj * 8 + j] = acc[i][j];
}

// ---------------- reduce + scale + L --------------------------------------------
__global__ __launch_bounds__(256)
void reduce_kernel()
{
    extern __shared__ float kks[];
    __shared__ float dsh[RM];
    __shared__ float rowsum[RM];
    int bh = blockIdx.x;
    if (threadIdx.x < RM) dsh[threadIdx.x] = g_D[bh * RM + threadIdx.x];
    __syncthreads();
    for (int idx = threadIdx.x; idx < RM * (RM + HD); idx += 256) {
        int m = idx / (RM + HD);
        int j = idx - m * (RM + HD);
        float s = 0.f;
#pragma unroll
        for (int sp = 0; sp < SPLITS; sp++)
            s += g_PART[((size_t)sp * BH + bh) * (RM * (RM + HD)) + idx];
        if (j < RM) {
            float v = s * dsh[m] * dsh[j];
            kks[m * RM + j] = v;
            g_KK[((size_t)bh * RM + m) * RM + j] = v;
        } else {
            g_KV[((size_t)bh * RM + m) * HD + (j - RM)] = s * dsh[m];
        }
    }
    __syncthreads();
    if (threadIdx.x < RM) {
        float rs = 0.f;
        for (int j = 0; j < RM; j++) rs += fabsf(kks[threadIdx.x * RM + j]);
        rowsum[threadIdx.x] = rs;
    }
    __syncthreads();
    if (threadIdx.x == 0) {
        float mx = 0.f;
        for (int i = 0; i < RM; i++) mx = fmaxf(mx, rowsum[i]);
        g_Lc[bh] = mx + 1.0f;
    }
}

// ---------------- ISTA -----------------------------------------------------------
__device__ __forceinline__ float softf(float z, float t)
{
    float a = fabsf(z) - t;
    return a > 0.f ? (z >= 0.f ? a : -a) : 0.f;
}

__global__ __launch_bounds__(256)
void ista_kernel()
{
    extern __shared__ float sm[];
    float* kks = sm;
    float* kvs = sm + RM * 129;
    float* ss  = kvs + RM * HD;
    int bh = blockIdx.x;
    float L    = g_Lc[bh];
    float invL = 1.0f / L;
    float thr  = LAMBDA * invL;

    for (int idx = threadIdx.x; idx < RM * RM; idx += 256) {
        int m = idx >> 7, j = idx & 127;
        kks[m * 129 + j] = g_KK[(size_t)bh * RM * RM + idx];
    }
    for (int idx = threadIdx.x; idx < RM * HD; idx += 256)
        kvs[idx] = g_KV[(size_t)bh * RM * HD + idx];
    __syncthreads();

    int m  = threadIdx.x >> 1;
    int ch = (threadIdx.x & 1) * 32;
#pragma unroll
    for (int i = 0; i < 32; i++)
        ss[m * 68 + ch + i] = softf(kvs[m * HD + ch + i], LAMBDA);
    __syncthreads();

    for (int it = 0; it < NSTEP; it++) {
        float acc[32];
#pragma unroll
        for (int i = 0; i < 32; i++) acc[i] = 0.f;
        for (int p = 0; p < RM; p++) {
            float kv_ = kks[m * 129 + p];
            const float4* sp = (const float4*)&ss[p * 68 + ch];
#pragma unroll
            for (int q = 0; q < 8; q++) {
                float4 v = sp[q];
                acc[q * 4 + 0] += kv_ * v.x;
                acc[q * 4 + 1] += kv_ * v.y;
                acc[q * 4 + 2] += kv_ * v.z;
                acc[q * 4 + 3] += kv_ * v.w;
            }
        }
        float r[32];
#pragma unroll
        for (int i = 0; i < 32; i++) {
            float z = ss[m * 68 + ch + i] - (acc[i] - kvs[m * HD + ch + i]) * invL;
            r[i] = softf(z, thr);
        }
        __syncthreads();
#pragma unroll
        for (int q = 0; q < 8; q++)
            *(float4*)&ss[m * 68 + ch + q * 4] =
                make_float4(r[q * 4], r[q * 4 + 1], r[q * 4 + 2], r[q * 4 + 3]);
        __syncthreads();
    }
    float dm = g_D[bh * RM + m];
#pragma unroll
    for (int q = 0; q < 8; q++) {
        float4 v = *(float4*)&ss[m * 68 + ch + q * 4];
        v.x *= dm; v.y *= dm; v.z *= dm; v.w *= dm;
        *(float4*)&g_S[((size_t)bh * RM + m) * HD + ch + q * 4] = v;
    }
}

// ---------------- out = rf @ (D s), emitted as bf16 split pair -------------------
__global__ __launch_bounds__(256)
void outgemm_kernel()
{
    __shared__ float ssm[RM * HD];
    __shared__ float rfs[128 * 20];
    int bh = blockIdx.y;
    int rb = blockIdx.x;
    int b = bh / NH, h = bh % NH;

    for (int idx = threadIdx.x; idx < RM * HD / 4; idx += 256)
        *(float4*)&ssm[idx * 4] =
            *(const float4*)&g_S[(size_t)bh * RM * HD + idx * 4];

    const float* rf = g_RF + ((size_t)bh * SEQ + (size_t)rb * 128) * RM;

    float acc[4][8];
#pragma unroll
    for (int i = 0; i < 4; i++)
#pragma unroll
        for (int j = 0; j < 8; j++) acc[i][j] = 0.f;

    int rw = threadIdx.x >> 3;
    int tc = threadIdx.x & 7;

    for (int k0 = 0; k0 < RM; k0 += 16) {
        __syncthreads();
#pragma unroll
        for (int l = 0; l < 2; l++) {
            int f = threadIdx.x + l * 256;
            int row = f >> 2, kq = (f & 3) * 4;
            *(float4*)&rfs[row * 20 + kq] =
                *(const float4*)&rf[(size_t)row * RM + k0 + kq];
        }
        __syncthreads();
#pragma unroll
        for (int k = 0; k < 16; k++) {
            float aa[4];
#pragma unroll
            for (int i = 0; i < 4; i++) aa[i] = rfs[(rw * 4 + i) * 20 + k];
            float4 b0 = *(float4*)&ssm[(k0 + k) * HD + tc * 8];
            float4 b1 = *(float4*)&ssm[(k0 + k) * HD + tc * 8 + 4];
            float bb[8] = {b0.x, b0.y, b0.z, b0.w, b1.x, b1.y, b1.z, b1.w};
#pragma unroll
            for (int i = 0; i < 4; i++)
#pragma unroll
                for (int j = 0; j < 8; j++) acc[i][j] += aa[i] * bb[j];
        }
    }
#pragma unroll
    for (int i = 0; i < 4; i++) {
        int row = rb * 128 + rw * 4 + i;
        size_t base = ((size_t)b * SEQ + row) * CH + h * HD + tc * 8;
#pragma unroll
        for (int j = 0; j < 8; j += 2) {
            float v0 = acc[i][j], v1 = acc[i][j + 1];
            __nv_bfloat16 h0 = __float2bfloat16(v0), h1 = __float2bfloat16(v1);
            *(__nv_bfloat162*)&g_OC1[base + j] = __halves2bfloat162(h0, h1);
            *(__nv_bfloat162*)&g_OC2[base + j] = __halves2bfloat162(
                __float2bfloat16(v0 - __bfloat162float(h0)),
                __float2bfloat16(v1 - __bfloat162float(h1)));
        }
    }
}

// ---------------- launch -----------------------------------------------------------
extern "C" void kernel_launch(void* const* d_in, const int* in_sizes, int n_in,
                              void* d_out, int out_size)
{
    const float *x = nullptr, *wqkv = nullptr, *wproj = nullptr,
                *bias = nullptr, *rm = nullptr;
    for (int i = 0; i < n_in; i++) {
        const float* p = (const float*)d_in[i];
        switch (in_sizes[i]) {
            case BATCH * SEQ * CH: x = p; break;
            case CH * 2 * CH:      wqkv = p; break;
            case CH * CH:          wproj = p; break;
            case CH:               bias = p; break;
            case NH * HD * RM:     rm = p; break;
        }
    }
    float* out = (float*)d_out;
    (void)out_size;

    cudaFuncSetAttribute(reduce_kernel, cudaFuncAttributeMaxDynamicSharedMemorySize, RM * RM * 4);
    cudaFuncSetAttribute(ista_kernel, cudaFuncAttributeMaxDynamicSharedMemorySize,
                         (RM * 129 + RM * HD + RM * 68) * 4);

    // conversions to bf16 split pairs
    conv_x_kernel<<<BATCH * SEQ * CH / 1024, 256>>>(x);
    conv_w_kernel<0><<<2 * CH * CH / 256, 256>>>(wqkv, 2 * CH);
    conv_w_kernel<1><<<CH * CH / 256, 256>>>(wproj, CH);

    // 1. qkv = x @ Wqkv (HMMA split-bf16) -> g_Q scaled / g_V
    hmma_gemm<0><<<dim3(12, 256), 256>>>(nullptr, nullptr, CH);
    // 2. random feature map
    rf_kernel<<<dim3(128, BH), 256>>>(rm);
    // 3. column norms
    colnorm_kernel<<<dim3(4, BH), 256>>>();
    // 4. split-K kk/kv partials
    kkkv_kernel<<<dim3(48, BH), 256>>>();
    // 5. combine partials + L
    reduce_kernel<<<BH, 256, RM * RM * 4>>>();
    // 6. ISTA
    ista_kernel<<<BH, 256, (RM * 129 + RM * HD + RM * 68) * 4>>>();
    // 7. out_head = rf @ s (emits bf16 split pair)
    outgemm_kernel<<<dim3(32, BH), 256>>>();
    // 8. final projection + bias (HMMA split-bf16)
    hmma_gemm<1><<<dim3(6, 256), 256>>>(bias, out, CH);
}

// round 5
// speedup vs baseline: 1.6761x; 1.1842x over previous
#include <cuda_runtime.h>
#include <cuda_bf16.h>
#include <math.h>
#include <cstdint>

// Problem constants
#define BATCH 8
#define SEQ   4096
#define CH    768
#define NH    12
#define HD    64
#define RM    128
#define BH    (BATCH*NH)
#define LAMBDA 0.3f
#define NSTEP 5
#define SPLITS 4
#define NCHUNK (SEQ/SPLITS)    // 1024

// ---------------- scratch ----------------------------------------------------
__device__ float g_Q  [(size_t)BH*SEQ*HD];           // qs (pre-scaled) fp32
__device__ float g_D  [BH*RM];
__device__ float g_PART[(size_t)SPLITS*BH*RM*(RM+HD)];
__device__ float g_KK [(size_t)BH*RM*RM];
__device__ float g_KV [(size_t)BH*RM*HD];
__device__ float g_Lc [BH];
// bf16 split pairs
__device__ __nv_bfloat16 g_XA1[(size_t)BATCH*SEQ*CH];
__device__ __nv_bfloat16 g_XA2[(size_t)BATCH*SEQ*CH];
__device__ __nv_bfloat16 g_WQ1[(size_t)2*CH*CH];
__device__ __nv_bfloat16 g_WQ2[(size_t)2*CH*CH];
__device__ __nv_bfloat16 g_WP1[(size_t)CH*CH];
__device__ __nv_bfloat16 g_WP2[(size_t)CH*CH];
__device__ __nv_bfloat16 g_OC1[(size_t)BATCH*SEQ*CH];
__device__ __nv_bfloat16 g_OC2[(size_t)BATCH*SEQ*CH];
__device__ __nv_bfloat16 g_RF1[(size_t)BH*SEQ*RM];   // rf hi  [bh][n][m]
__device__ __nv_bfloat16 g_RF2[(size_t)BH*SEQ*RM];   // rf lo
__device__ __nv_bfloat16 g_VB1[(size_t)BH*SEQ*HD];   // v hi   [bh][n][d]
__device__ __nv_bfloat16 g_VB2[(size_t)BH*SEQ*HD];   // v lo
__device__ __nv_bfloat16 g_ST1[(size_t)BH*HD*RM];    // (d*s)^T hi [bh][d][m]
__device__ __nv_bfloat16 g_ST2[(size_t)BH*HD*RM];    // lo

// ---------------- warp-MMA helpers -------------------------------------------
__device__ __forceinline__ uint32_t smem_u32(const void* p) {
    uint32_t a;
    asm("{ .reg .u64 t; cvta.to.shared.u64 t, %1; cvt.u32.u64 %0, t; }"
        : "=r"(a) : "l"(p));
    return a;
}
__device__ __forceinline__ void ldmx4(uint32_t& r0, uint32_t& r1,
                                      uint32_t& r2, uint32_t& r3, uint32_t addr)
{
    asm volatile("ldmatrix.sync.aligned.m8n8.x4.shared.b16 {%0,%1,%2,%3}, [%4];"
                 : "=r"(r0), "=r"(r1), "=r"(r2), "=r"(r3) : "r"(addr));
}
__device__ __forceinline__ void ldmx4t(uint32_t* r, uint32_t addr)
{
    asm volatile("ldmatrix.sync.aligned.m8n8.x4.trans.shared.b16 {%0,%1,%2,%3}, [%4];"
                 : "=r"(r[0]), "=r"(r[1]), "=r"(r[2]), "=r"(r[3]) : "r"(addr));
}
__device__ __forceinline__ void mma16816(float* c, const uint32_t* a,
                                         const uint32_t* b)
{
    asm volatile(
        "mma.sync.aligned.m16n8k16.row.col.f32.bf16.bf16.f32 "
        "{%0,%1,%2,%3}, {%4,%5,%6,%7}, {%8,%9}, {%0,%1,%2,%3};"
        : "+f"(c[0]), "+f"(c[1]), "+f"(c[2]), "+f"(c[3])
        : "r"(a[0]), "r"(a[1]), "r"(a[2]), "r"(a[3]), "r"(b[0]), "r"(b[1]));
}
__device__ __forceinline__ void split2(float v, __nv_bfloat16& h, __nv_bfloat16& l)
{
    h = __float2bfloat16(v);
    l = __float2bfloat16(v - __bfloat162float(h));
}

#define PITCH 40   // smem pitch for dense gemm tiles

// ---------------- HMMA GEMM: 128x128 tile, 3-term bf16 split ------------------
template<int EPI>
__global__ __launch_bounds__(256, 2)
void hmma_gemm(const float* __restrict__ bias, float* __restrict__ Cout, int Kdim)
{
    __shared__ __nv_bfloat16 As1[128 * PITCH], As2[128 * PITCH];
    __shared__ __nv_bfloat16 Bs1[128 * PITCH], Bs2[128 * PITCH];

    const int tid  = threadIdx.x;
    const int wid  = tid >> 5;
    const int lane = tid & 31;
    const int wm   = wid & 1;
    const int wn   = wid >> 1;
    const int brow = blockIdx.y * 128;
    const int bcol = blockIdx.x * 128;

    const __nv_bfloat16* A1 = (EPI == 0) ? g_XA1 : g_OC1;
    const __nv_bfloat16* A2 = (EPI == 0) ? g_XA2 : g_OC2;
    const __nv_bfloat16* B1 = (EPI == 0) ? g_WQ1 : g_WP1;
    const __nv_bfloat16* B2 = (EPI == 0) ? g_WQ2 : g_WP2;

    float acc[4][4][4];
#pragma unroll
    for (int i = 0; i < 4; i++)
#pragma unroll
        for (int j = 0; j < 4; j++)
#pragma unroll
            for (int q = 0; q < 4; q++) acc[i][j][q] = 0.f;

    const uint32_t as1 = smem_u32(As1), as2 = smem_u32(As2);
    const uint32_t bs1 = smem_u32(Bs1), bs2 = smem_u32(Bs2);
    const int arow = wm * 64 + (lane & 15);
    const int acolL = (lane >> 4) * 8;
    const int bn   = wn * 32 + (lane & 7) + ((lane >> 4) & 1) * 8;
    const int bkL  = ((lane >> 3) & 1) * 8;

    const int nchunk = Kdim >> 5;
    for (int kc = 0; kc < nchunk; kc++) {
        const int k0 = kc << 5;
#pragma unroll
        for (int t = 0; t < 4; t++) {
            const __nv_bfloat16* src = (t == 0) ? A1 : (t == 1) ? A2 : (t == 2) ? B1 : B2;
            __nv_bfloat16* dst = (t == 0) ? As1 : (t == 1) ? As2 : (t == 2) ? Bs1 : Bs2;
            const int rbase = (t < 2) ? brow : bcol;
#pragma unroll
            for (int u = 0; u < 2; u++) {
                int c = u * 256 + tid;
                int row = c >> 2, ch = (c & 3) * 8;
                uint4 v = *(const uint4*)(src + (size_t)(rbase + row) * Kdim + k0 + ch);
                *(uint4*)(dst + row * PITCH + ch) = v;
            }
        }
        __syncthreads();

#pragma unroll
        for (int ks = 0; ks < 2; ks++) {
            const int acol = ks * 16 + acolL;
            const int bk   = ks * 16 + bkL;
            uint32_t a1[4][4], a2[4][4], b1[4][2], b2[4][2];
#pragma unroll
            for (int mt = 0; mt < 4; mt++) {
                uint32_t off = ((arow + mt * 16) * PITCH + acol) * 2;
                ldmx4(a1[mt][0], a1[mt][1], a1[mt][2], a1[mt][3], as1 + off);
                ldmx4(a2[mt][0], a2[mt][1], a2[mt][2], a2[mt][3], as2 + off);
            }
#pragma unroll
            for (int nt2 = 0; nt2 < 2; nt2++) {
                uint32_t off = ((bn + nt2 * 16) * PITCH + bk) * 2;
                ldmx4(b1[nt2 * 2][0], b1[nt2 * 2][1],
                      b1[nt2 * 2 + 1][0], b1[nt2 * 2 + 1][1], bs1 + off);
                ldmx4(b2[nt2 * 2][0], b2[nt2 * 2][1],
                      b2[nt2 * 2 + 1][0], b2[nt2 * 2 + 1][1], bs2 + off);
            }
#pragma unroll
            for (int mt = 0; mt < 4; mt++)
#pragma unroll
                for (int nt = 0; nt < 4; nt++) {
                    mma16816(acc[mt][nt], a1[mt], b1[nt]);
                    mma16816(acc[mt][nt], a1[mt], b2[nt]);
                    mma16816(acc[mt][nt], a2[mt], b1[nt]);
                }
        }
        __syncthreads();
    }

    const int g  = lane >> 2;
    const int tg = lane & 3;
#pragma unroll
    for (int mt = 0; mt < 4; mt++)
#pragma unroll
        for (int nt = 0; nt < 4; nt++) {
#pragma unroll
            for (int half = 0; half < 2; half++) {
                int grow = brow + wm * 64 + mt * 16 + g + half * 8;
                int col  = bcol + wn * 32 + nt * 8 + tg * 2;
                float2 v = make_float2(acc[mt][nt][half * 2],
                                       acc[mt][nt][half * 2 + 1]);
                if (EPI == 0) {
                    int bb = grow >> 12, nn = grow & 4095;
                    if (col < CH) {
                        const float s = 0.35355339059327373f;  // hd^(-1/4)
                        v.x *= s; v.y *= s;
                        int h = col >> 6, dd = col & 63;
                        *(float2*)&g_Q[(((size_t)(bb * NH + h)) * SEQ + nn) * HD + dd] = v;
                    } else {
                        int c2 = col - CH;
                        int h = c2 >> 6, dd = c2 & 63;
                        size_t adr = (((size_t)(bb * NH + h)) * SEQ + nn) * HD + dd;
                        __nv_bfloat16 h0, l0, h1, l1;
                        split2(v.x, h0, l0); split2(v.y, h1, l1);
                        *(__nv_bfloat162*)&g_VB1[adr] = __halves2bfloat162(h0, h1);
                        *(__nv_bfloat162*)&g_VB2[adr] = __halves2bfloat162(l0, l1);
                    }
                } else {
                    v.x += bias[col];
                    v.y += bias[col + 1];
                    *(float2*)&Cout[(size_t)grow * CH + col] = v;
                }
            }
        }
}

// ---------------- conversion kernels -----------------------------------------
__global__ __launch_bounds__(256)
void conv_x_kernel(const float* __restrict__ x)
{
    size_t i = ((size_t)blockIdx.x * 256 + threadIdx.x) * 4;
    float4 v = *(const float4*)&x[i];
    __nv_bfloat16 h0, l0, h1, l1, h2, l2, h3, l3;
    split2(v.x, h0, l0); split2(v.y, h1, l1);
    split2(v.z, h2, l2); split2(v.w, h3, l3);
    *(__nv_bfloat162*)&g_XA1[i]     = __halves2bfloat162(h0, h1);
    *(__nv_bfloat162*)&g_XA1[i + 2] = __halves2bfloat162(h2, h3);
    *(__nv_bfloat162*)&g_XA2[i]     = __halves2bfloat162(l0, l1);
    *(__nv_bfloat162*)&g_XA2[i + 2] = __halves2bfloat162(l2, l3);
}

template<int WHICH>
__global__ __launch_bounds__(256)
void conv_w_kernel(const float* __restrict__ W, int N)
{
    __nv_bfloat16* o1 = (WHICH == 0) ? g_WQ1 : g_WP1;
    __nv_bfloat16* o2 = (WHICH == 0) ? g_WQ2 : g_WP2;
    int idx = blockIdx.x * 256 + threadIdx.x;
    int n = idx / CH, k = idx - n * CH;
    float v = W[(size_t)k * N + n];
    __nv_bfloat16 h, l;
    split2(v, h, l);
    o1[idx] = h;
    o2[idx] = l;
}

// ---------------- random feature map -> bf16 split pair ------------------------
__global__ __launch_bounds__(256)
void rf_kernel(const float* __restrict__ randm)
{
    __shared__ float Rs[64 * 132];
    __shared__ float Qs[32 * 68];
    int bh = blockIdx.y;
    int h  = bh % NH;
    int rowblk = blockIdx.x;

    for (int f = threadIdx.x; f < 64 * RM / 4; f += 256) {
        int k = f >> 5, mq = (f & 31) * 4;
        *(float4*)&Rs[k * 132 + mq] =
            *(const float4*)&randm[((size_t)h * HD + k) * RM + mq];
    }
    const float* Qbase = g_Q + ((size_t)bh * SEQ + (size_t)rowblk * 32) * HD;
    for (int f = threadIdx.x; f < 32 * HD / 4; f += 256) {
        int r = f >> 4, kq = (f & 15) * 4;
        *(float4*)&Qs[r * 68 + kq] = *(const float4*)&Qbase[(size_t)r * HD + kq];
    }
    __syncthreads();

    int r  = threadIdx.x >> 3;
    int mq = (threadIdx.x & 7) * 16;
    float acc[16];
#pragma unroll
    for (int i = 0; i < 16; i++) acc[i] = 0.f;
    float sq = 0.f;
    for (int k = 0; k < HD; k++) {
        float qv = Qs[r * 68 + k];
        sq += qv * qv;
        const float4* rp = (const float4*)&Rs[k * 132 + mq];
#pragma unroll
        for (int q = 0; q < 4; q++) {
            float4 v = rp[q];
            acc[q * 4 + 0] += qv * v.x;
            acc[q * 4 + 1] += qv * v.y;
            acc[q * 4 + 2] += qv * v.z;
            acc[q * 4 + 3] += qv * v.w;
        }
    }
    size_t dst = ((size_t)bh * SEQ + (size_t)rowblk * 32 + r) * RM + mq;
    float base = -0.5f * sq;
    const float sc = 0.08838834764831845f;  // 1/sqrt(128)
#pragma unroll
    for (int q = 0; q < 4; q++) {
        float v0 = expf(acc[q * 4 + 0] + base) * sc;
        float v1 = expf(acc[q * 4 + 1] + base) * sc;
        float v2 = expf(acc[q * 4 + 2] + base) * sc;
        float v3 = expf(acc[q * 4 + 3] + base) * sc;
        __nv_bfloat16 h0, l0, h1, l1, h2, l2, h3, l3;
        split2(v0, h0, l0); split2(v1, h1, l1);
        split2(v2, h2, l2); split2(v3, h3, l3);
        *(__nv_bfloat162*)&g_RF1[dst + q * 4]     = __halves2bfloat162(h0, h1);
        *(__nv_bfloat162*)&g_RF1[dst + q * 4 + 2] = __halves2bfloat162(h2, h3);
        *(__nv_bfloat162*)&g_RF2[dst + q * 4]     = __halves2bfloat162(l0, l1);
        *(__nv_bfloat162*)&g_RF2[dst + q * 4 + 2] = __halves2bfloat162(l2, l3);
    }
}

// ---------------- column norms (reads rf pair) ---------------------------------
__global__ __launch_bounds__(256)
void colnorm_kernel()
{
    __shared__ float red[8][32];
    int bh  = blockIdx.y;
    int lane = threadIdx.x & 31;
    int m   = blockIdx.x * 32 + lane;
    int grp = threadIdx.x >> 5;
    const __nv_bfloat16* b1 = g_RF1 + (size_t)bh * SEQ * RM;
    const __nv_bfloat16* b2 = g_RF2 + (size_t)bh * SEQ * RM;
    float sum = 0.f;
    for (int n = grp; n < SEQ; n += 8) {
        float v = __bfloat162float(b1[(size_t)n * RM + m]) +
                  __bfloat162float(b2[(size_t)n * RM + m]);
        sum += v * v;
    }
    red[grp][lane] = sum;
    __syncthreads();
    if (grp == 0) {
        float t = 0.f;
#pragma unroll
        for (int g = 0; g < 8; g++) t += red[g][lane];
        g_D[bh * RM + m] = 1.0f / fmaxf(sqrtf(t), 1e-12f);
    }
}

// ---------------- kk/kv via HMMA with trans-ldmatrix ----------------------------
// C[m, j] = sum_n rf[n, m] * Y[n, j]  (Y = rf cols or v), per (bh, split, ct)
__global__ __launch_bounds__(256, 2)
void kkkv_hmma()
{
    __shared__ __nv_bfloat16 As1[32 * 136], As2[32 * 136];
    __shared__ __nv_bfloat16 Ys1[32 * 72],  Ys2[32 * 72];
    const int tid = threadIdx.x, wid = tid >> 5, lane = tid & 31;
    const int ct = blockIdx.x, bh = blockIdx.y, split = blockIdx.z;
    const int wm = wid >> 1, wn = wid & 1;     // 4 x 2 warps, tile 32x32

    size_t abase = ((size_t)bh * SEQ + (size_t)split * NCHUNK) * RM;
    const __nv_bfloat16 *a1 = g_RF1 + abase, *a2 = g_RF2 + abase;
    const __nv_bfloat16 *b1, *b2;
    int bstr;
    if (ct == 2) {
        size_t vb = ((size_t)bh * SEQ + (size_t)split * NCHUNK) * HD;
        b1 = g_VB1 + vb; b2 = g_VB2 + vb; bstr = HD;
    } else {
        b1 = a1 + ct * 64; b2 = a2 + ct * 64; bstr = RM;
    }

    float acc[2][4][4];
#pragma unroll
    for (int i = 0; i < 2; i++)
#pragma unroll
        for (int j = 0; j < 4; j++)
#pragma unroll
            for (int q = 0; q < 4; q++) acc[i][j][q] = 0.f;

    const uint32_t as1 = smem_u32(As1), as2 = smem_u32(As2);
    const uint32_t ys1 = smem_u32(Ys1), ys2 = smem_u32(Ys2);
    // trans-ldmatrix lane offsets:
    const int a_r = (lane & 7) + (lane >> 4) * 8;        // + ks*16
    const int a_c = ((lane >> 3) & 1) * 8;               // + m_base
    const int b_r = (lane & 7) + ((lane >> 3) & 1) * 8;  // + ks*16
    const int b_c = (lane >> 4) * 8;                     // + n_base

    for (int chunk = 0; chunk < NCHUNK / 32; chunk++) {
        const int n0 = chunk * 32;
#pragma unroll
        for (int l = 0; l < 2; l++) {
            int f = tid + l * 256;
            int r = f >> 4, c = (f & 15) * 8;
            *(uint4*)(As1 + r * 136 + c) = *(const uint4*)(a1 + (size_t)(n0 + r) * RM + c);
            *(uint4*)(As2 + r * 136 + c) = *(const uint4*)(a2 + (size_t)(n0 + r) * RM + c);
        }
        // Y: 32 rows x 64 cols per buffer = 256 uint4 each; 512 slots over 2 iters
#pragma unroll
        for (int l = 0; l < 2; l++) {
            int f = tid + l * 256;
            int which = f >> 8;                 // 0 -> Ys1, 1 -> Ys2
            int r = (f & 255) >> 3;             // 0..31
            int c = (f & 7) * 8;                // 0..56
            const __nv_bfloat16* bs = which ? b2 : b1;
            __nv_bfloat16* yd = which ? Ys2 : Ys1;
            *(uint4*)(yd + r * 72 + c) = *(const uint4*)(bs + (size_t)(n0 + r) * bstr + c);
        }
        __syncthreads();
#pragma unroll
        for (int ks = 0; ks < 2; ks++) {
            uint32_t A1f[2][4], A2f[2][4], B1f[4][2], B2f[4][2];
#pragma unroll
            for (int mt = 0; mt < 2; mt++) {
                uint32_t off = ((ks * 16 + a_r) * 136 + wm * 32 + mt * 16 + a_c) * 2;
                ldmx4t(A1f[mt], as1 + off);
                ldmx4t(A2f[mt], as2 + off);
            }
#pragma unroll
            for (int nb = 0; nb < 2; nb++) {
                uint32_t off = ((ks * 16 + b_r) * 72 + wn * 32 + nb * 16 + b_c) * 2;
                uint32_t t1[4], t2[4];
                ldmx4t(t1, ys1 + off);
                ldmx4t(t2, ys2 + off);
                B1f[nb * 2][0] = t1[0]; B1f[nb * 2][1] = t1[1];
                B1f[nb * 2 + 1][0] = t1[2]; B1f[nb * 2 + 1][1] = t1[3];
                B2f[nb * 2][0] = t2[0]; B2f[nb * 2][1] = t2[1];
                B2f[nb * 2 + 1][0] = t2[2]; B2f[nb * 2 + 1][1] = t2[3];
            }
#pragma unroll
            for (int mt = 0; mt < 2; mt++)
#pragma unroll
                for (int nt = 0; nt < 4; nt++) {
                    mma16816(acc[mt][nt], A1f[mt], B1f[nt]);
                    mma16816(acc[mt][nt], A1f[mt], B2f[nt]);
                    mma16816(acc[mt][nt], A2f[mt], B1f[nt]);
                }
        }
        __syncthreads();
    }

    float* dst = g_PART + ((size_t)split * BH + bh) * (RM * (RM + HD));
#pragma unroll
    for (int mt = 0; mt < 2; mt++)
#pragma unroll
        for (int nt = 0; nt < 4; nt++)
#pragma unroll
            for (int half = 0; half < 2; half++) {
                int m = wm * 32 + mt * 16 + (lane >> 2) + half * 8;
                int j = ct * 64 + wn * 32 + nt * 8 + (lane & 3) * 2;
                *(float2*)&dst[m * (RM + HD) + j] =
                    make_float2(acc[mt][nt][half * 2], acc[mt][nt][half * 2 + 1]);
            }
}

// ---------------- reduce + scale + L --------------------------------------------
__global__ __launch_bounds__(256)
void reduce_kernel()
{
    extern __shared__ float kks[];
    __shared__ float dsh[RM];
    __shared__ float rowsum[RM];
    int bh = blockIdx.x;
    if (threadIdx.x < RM) dsh[threadIdx.x] = g_D[bh * RM + threadIdx.x];
    __syncthreads();
    for (int idx = threadIdx.x; idx < RM * (RM + HD); idx += 256) {
        int m = idx / (RM + HD);
        int j = idx - m * (RM + HD);
        float s = 0.f;
#pragma unroll
        for (int sp = 0; sp < SPLITS; sp++)
            s += g_PART[((size_t)sp * BH + bh) * (RM * (RM + HD)) + idx];
        if (j < RM) {
            float v = s * dsh[m] * dsh[j];
            kks[m * RM + j] = v;
            g_KK[((size_t)bh * RM + m) * RM + j] = v;
        } else {
            g_KV[((size_t)bh * RM + m) * HD + (j - RM)] = s * dsh[m];
        }
    }
    __syncthreads();
    if (threadIdx.x < RM) {
        float rs = 0.f;
        for (int j = 0; j < RM; j++) rs += fabsf(kks[threadIdx.x * RM + j]);
        rowsum[threadIdx.x] = rs;
    }
    __syncthreads();
    if (threadIdx.x == 0) {
        float mx = 0.f;
        for (int i = 0; i < RM; i++) mx = fmaxf(mx, rowsum[i]);
        g_Lc[bh] = mx + 1.0f;
    }
}

// ---------------- ISTA (emits (d*s)^T bf16 split) --------------------------------
__device__ __forceinline__ float softf(float z, float t)
{
    float a = fabsf(z) - t;
    return a > 0.f ? (z >= 0.f ? a : -a) : 0.f;
}

__global__ __launch_bounds__(256)
void ista_kernel()
{
    extern __shared__ float sm[];
    float* kks = sm;
    float* kvs = sm + RM * 129;
    float* ss  = kvs + RM * HD;
    int bh = blockIdx.x;
    float L    = g_Lc[bh];
    float invL = 1.0f / L;
    float thr  = LAMBDA * invL;

    for (int idx = threadIdx.x; idx < RM * RM; idx += 256) {
        int m = idx >> 7, j = idx & 127;
        kks[m * 129 + j] = g_KK[(size_t)bh * RM * RM + idx];
    }
    for (int idx = threadIdx.x; idx < RM * HD; idx += 256)
        kvs[idx] = g_KV[(size_t)bh * RM * HD + idx];
    __syncthreads();

    int m  = threadIdx.x >> 1;
    int ch = (threadIdx.x & 1) * 32;
#pragma unroll
    for (int i = 0; i < 32; i++)
        ss[m * 68 + ch + i] = softf(kvs[m * HD + ch + i], LAMBDA);
    __syncthreads();

    for (int it = 0; it < NSTEP; it++) {
        float acc[32];
#pragma unroll
        for (int i = 0; i < 32; i++) acc[i] = 0.f;
        for (int p = 0; p < RM; p++) {
            float kv_ = kks[m * 129 + p];
            const float4* sp = (const float4*)&ss[p * 68 + ch];
#pragma unroll
            for (int q = 0; q < 8; q++) {
                float4 v = sp[q];
                acc[q * 4 + 0] += kv_ * v.x;
                acc[q * 4 + 1] += kv_ * v.y;
                acc[q * 4 + 2] += kv_ * v.z;
                acc[q * 4 + 3] += kv_ * v.w;
            }
        }
        float r[32];
#pragma unroll
        for (int i = 0; i < 32; i++) {
            float z = ss[m * 68 + ch + i] - (acc[i] - kvs[m * HD + ch + i]) * invL;
            r[i] = softf(z, thr);
        }
        __syncthreads();
#pragma unroll
        for (int q = 0; q < 8; q++)
            *(float4*)&ss[m * 68 + ch + q * 4] =
                make_float4(r[q * 4], r[q * 4 + 1], r[q * 4 + 2], r[q * 4 + 3]);
        __syncthreads();
    }
    // scale by d_m in place
    float dm = g_D[bh * RM + m];
#pragma unroll
    for (int q = 0; q < 8; q++) {
        float4 v = *(float4*)&ss[m * 68 + ch + q * 4];
        v.x *= dm; v.y *= dm; v.z *= dm; v.w *= dm;
        *(float4*)&ss[m * 68 + ch + q * 4] = v;
    }
    __syncthreads();
    // transposed bf16 split emit: sT[d][m]
    int d  = threadIdx.x >> 2;
    int ms = (threadIdx.x & 3) * 32;
    size_t ob = ((size_t)bh * HD + d) * RM + ms;
#pragma unroll
    for (int i = 0; i < 32; i += 2) {
        float v0 = ss[(ms + i) * 68 + d];
        float v1 = ss[(ms + i + 1) * 68 + d];
        __nv_bfloat16 h0, l0, h1, l1;
        split2(v0, h0, l0); split2(v1, h1, l1);
        *(__nv_bfloat162*)&g_ST1[ob + i] = __halves2bfloat162(h0, h1);
        *(__nv_bfloat162*)&g_ST2[ob + i] = __halves2bfloat162(l0, l1);
    }
}

// ---------------- out = rf @ sT^T via HMMA, emits OC bf16 pair --------------------
__global__ __launch_bounds__(256, 2)
void outgemm_hmma()
{
    __shared__ __nv_bfloat16 As1[128 * PITCH], As2[128 * PITCH];
    __shared__ __nv_bfloat16 Bs1[64 * PITCH],  Bs2[64 * PITCH];
    const int tid = threadIdx.x, wid = tid >> 5, lane = tid & 31;
    const int wm = wid & 3, wn = wid >> 2;     // 4 x 2, warp tile 32x32
    const int bh = blockIdx.y, nblk = blockIdx.x;
    const int b = bh / NH, h = bh % NH;

    size_t rfbase = ((size_t)bh * SEQ + (size_t)nblk * 128) * RM;
    size_t stbase = (size_t)bh * HD * RM;

    float acc[2][4][4];
#pragma unroll
    for (int i = 0; i < 2; i++)
#pragma unroll
        for (int j = 0; j < 4; j++)
#pragma unroll
            for (int q = 0; q < 4; q++) acc[i][j][q] = 0.f;

    const uint32_t as1 = smem_u32(As1), as2 = smem_u32(As2);
    const uint32_t bs1 = smem_u32(Bs1), bs2 = smem_u32(Bs2);
    const int arow = wm * 32 + (lane & 15);
    const int acolL = (lane >> 4) * 8;
    const int bn   = wn * 32 + (lane & 7) + ((lane >> 4) & 1) * 8;
    const int bkL  = ((lane >> 3) & 1) * 8;

    for (int kc = 0; kc < 4; kc++) {
        const int k0 = kc * 32;
#pragma unroll
        for (int l = 0; l < 2; l++) {
            int f = tid + l * 256;
            int r = f >> 2, c = (f & 3) * 8;
            *(uint4*)(As1 + r * PITCH + c) =
                *(const uint4*)(g_RF1 + rfbase + (size_t)r * RM + k0 + c);
            *(uint4*)(As2 + r * PITCH + c) =
                *(const uint4*)(g_RF2 + rfbase + (size_t)r * RM + k0 + c);
        }
        {
            int r = tid >> 2, c = (tid & 3) * 8;
            if (r < 64) {
                *(uint4*)(Bs1 + r * PITCH + c) =
                    *(const uint4*)(g_ST1 + stbase + (size_t)r * RM + k0 + c);
                *(uint4*)(Bs2 + r * PITCH + c) =
                    *(const uint4*)(g_ST2 + stbase + (size_t)r * RM + k0 + c);
            }
        }
        __syncthreads();
#pragma unroll
        for (int ks = 0; ks < 2; ks++) {
            const int acol = ks * 16 + acolL;
            const int bk   = ks * 16 + bkL;
            uint32_t a1[2][4], a2[2][4], b1[4][2], b2[4][2];
#pragma unroll
            for (int mt = 0; mt < 2; mt++) {
                uint32_t off = ((arow + mt * 16) * PITCH + acol) * 2;
                ldmx4(a1[mt][0], a1[mt][1], a1[mt][2], a1[mt][3], as1 + off);
                ldmx4(a2[mt][0], a2[mt][1], a2[mt][2], a2[mt][3], as2 + off);
            }
#pragma unroll
            for (int nt2 = 0; nt2 < 2; nt2++) {
                uint32_t off = ((bn + nt2 * 16) * PITCH + bk) * 2;
                ldmx4(b1[nt2 * 2][0], b1[nt2 * 2][1],
                      b1[nt2 * 2 + 1][0], b1[nt2 * 2 + 1][1], bs1 + off);
                ldmx4(b2[nt2 * 2][0], b2[nt2 * 2][1],
                      b2[nt2 * 2 + 1][0], b2[nt2 * 2 + 1][1], bs2 + off);
            }
#pragma unroll
            for (int mt = 0; mt < 2; mt++)
#pragma unroll
                for (int nt = 0; nt < 4; nt++) {
                    mma16816(acc[mt][nt], a1[mt], b1[nt]);
                    mma16816(acc[mt][nt], a1[mt], b2[nt]);
                    mma16816(acc[mt][nt], a2[mt], b1[nt]);
                }
        }
        __syncthreads();
    }

    const int g  = lane >> 2;
    const int tg = lane & 3;
#pragma unroll
    for (int mt = 0; mt < 2; mt++)
#pragma unroll
        for (int nt = 0; nt < 4; nt++)
#pragma unroll
            for (int half = 0; half < 2; half++) {
                int nrow = nblk * 128 + wm * 32 + mt * 16 + g + half * 8;
                int d    = wn * 32 + nt * 8 + tg * 2;
                float2 v = make_float2(acc[mt][nt][half * 2],
                                       acc[mt][nt][half * 2 + 1]);
                size_t adr = ((size_t)b * SEQ + nrow) * CH + h * HD + d;
                __nv_bfloat16 h0, l0, h1, l1;
                split2(v.x, h0, l0); split2(v.y, h1, l1);
                *(__nv_bfloat162*)&g_OC1[adr] = __halves2bfloat162(h0, h1);
                *(__nv_bfloat162*)&g_OC2[adr] = __halves2bfloat162(l0, l1);
            }
}

// ---------------- launch -----------------------------------------------------------
extern "C" void kernel_launch(void* const* d_in, const int* in_sizes, int n_in,
                              void* d_out, int out_size)
{
    const float *x = nullptr, *wqkv = nullptr, *wproj = nullptr,
                *bias = nullptr, *rm = nullptr;
    for (int i = 0; i < n_in; i++) {
        const float* p = (const float*)d_in[i];
        switch (in_sizes[i]) {
            case BATCH * SEQ * CH: x = p; break;
            case CH * 2 * CH:      wqkv = p; break;
            case CH * CH:          wproj = p; break;
            case CH:               bias = p; break;
            case NH * HD * RM:     rm = p; break;
        }
    }
    float* out = (float*)d_out;
    (void)out_size;

    cudaFuncSetAttribute(reduce_kernel, cudaFuncAttributeMaxDynamicSharedMemorySize, RM * RM * 4);
    cudaFuncSetAttribute(ista_kernel, cudaFuncAttributeMaxDynamicSharedMemorySize,
                         (RM * 129 + RM * HD + RM * 68) * 4);

    // conversions to bf16 split pairs
    conv_x_kernel<<<BATCH * SEQ * CH / 1024, 256>>>(x);
    conv_w_kernel<0><<<2 * CH * CH / 256, 256>>>(wqkv, 2 * CH);
    conv_w_kernel<1><<<CH * CH / 256, 256>>>(wproj, CH);

    // 1. qkv = x @ Wqkv (HMMA) -> g_Q fp32 scaled, v bf16 pair
    hmma_gemm<0><<<dim3(12, 256), 256>>>(nullptr, nullptr, CH);
    // 2. random feature map -> rf bf16 pair
    rf_kernel<<<dim3(128, BH), 256>>>(rm);
    // 3. column norms
    colnorm_kernel<<<dim3(4, BH), 256>>>();
    // 4. kk/kv partials (HMMA, trans-ldmatrix)
    kkkv_hmma<<<dim3(3, BH, SPLITS), 256>>>();
    // 5. combine partials + L
    reduce_kernel<<<BH, 256, RM * RM * 4>>>();
    // 6. ISTA -> (d*s)^T bf16 pair
    ista_kernel<<<BH, 256, (RM * 129 + RM * HD + RM * 68) * 4>>>();
    // 7. out_head = rf @ s (HMMA) -> OC bf16 pair
    outgemm_hmma<<<dim3(32, BH), 256>>>();
    // 8. final projection + bias (HMMA)
    hmma_gemm<1><<<dim3(6, 256), 256>>>(bias, out, CH);
}

// round 6
// speedup vs baseline: 1.7798x; 1.0619x over previous
#include <cuda_runtime.h>
#include <cuda_bf16.h>
#include <math.h>
#include <cstdint>

// Problem constants
#define BATCH 8
#define SEQ   4096
#define CH    768
#define NH    12
#define HD    64
#define RM    128
#define BH    (BATCH*NH)
#define LAMBDA 0.3f
#define NSTEP 5
#define SPLITS 4
#define NCHUNK (SEQ/SPLITS)    // 1024

// ---------------- scratch ----------------------------------------------------
__device__ float g_Q  [(size_t)BH*SEQ*HD];           // qs (pre-scaled) fp32
__device__ float g_D  [BH*RM];
__device__ float g_PART[(size_t)SPLITS*BH*RM*(RM+HD)];
__device__ float g_KK [(size_t)BH*RM*RM];
__device__ float g_KV [(size_t)BH*RM*HD];
__device__ float g_Lc [BH];
// bf16 split pairs
__device__ __nv_bfloat16 g_XA1[(size_t)BATCH*SEQ*CH];
__device__ __nv_bfloat16 g_XA2[(size_t)BATCH*SEQ*CH];
__device__ __nv_bfloat16 g_WQ1[(size_t)2*CH*CH];
__device__ __nv_bfloat16 g_WQ2[(size_t)2*CH*CH];
__device__ __nv_bfloat16 g_WP1[(size_t)CH*CH];
__device__ __nv_bfloat16 g_WP2[(size_t)CH*CH];
__device__ __nv_bfloat16 g_OC1[(size_t)BATCH*SEQ*CH];
__device__ __nv_bfloat16 g_OC2[(size_t)BATCH*SEQ*CH];
__device__ __nv_bfloat16 g_RF1[(size_t)BH*SEQ*RM];   // rf hi  [bh][n][m]
__device__ __nv_bfloat16 g_RF2[(size_t)BH*SEQ*RM];   // rf lo
__device__ __nv_bfloat16 g_VB1[(size_t)BH*SEQ*HD];   // v hi   [bh][n][d]
__device__ __nv_bfloat16 g_VB2[(size_t)BH*SEQ*HD];   // v lo
__device__ __nv_bfloat16 g_ST1[(size_t)BH*HD*RM];    // (d*s)^T hi [bh][d][m]
__device__ __nv_bfloat16 g_ST2[(size_t)BH*HD*RM];    // lo

// ---------------- warp-MMA / cp.async helpers ----------------------------------
__device__ __forceinline__ uint32_t smem_u32(const void* p) {
    uint32_t a;
    asm("{ .reg .u64 t; cvta.to.shared.u64 t, %1; cvt.u32.u64 %0, t; }"
        : "=r"(a) : "l"(p));
    return a;
}
__device__ __forceinline__ void ldmx4(uint32_t& r0, uint32_t& r1,
                                      uint32_t& r2, uint32_t& r3, uint32_t addr)
{
    asm volatile("ldmatrix.sync.aligned.m8n8.x4.shared.b16 {%0,%1,%2,%3}, [%4];"
                 : "=r"(r0), "=r"(r1), "=r"(r2), "=r"(r3) : "r"(addr));
}
__device__ __forceinline__ void ldmx4t(uint32_t* r, uint32_t addr)
{
    asm volatile("ldmatrix.sync.aligned.m8n8.x4.trans.shared.b16 {%0,%1,%2,%3}, [%4];"
                 : "=r"(r[0]), "=r"(r[1]), "=r"(r[2]), "=r"(r[3]) : "r"(addr));
}
__device__ __forceinline__ void mma16816(float* c, const uint32_t* a,
                                         const uint32_t* b)
{
    asm volatile(
        "mma.sync.aligned.m16n8k16.row.col.f32.bf16.bf16.f32 "
        "{%0,%1,%2,%3}, {%4,%5,%6,%7}, {%8,%9}, {%0,%1,%2,%3};"
        : "+f"(c[0]), "+f"(c[1]), "+f"(c[2]), "+f"(c[3])
        : "r"(a[0]), "r"(a[1]), "r"(a[2]), "r"(a[3]), "r"(b[0]), "r"(b[1]));
}
__device__ __forceinline__ void split2(float v, __nv_bfloat16& h, __nv_bfloat16& l)
{
    h = __float2bfloat16(v);
    l = __float2bfloat16(v - __bfloat162float(h));
}
__device__ __forceinline__ void cpa16(uint32_t saddr, const void* g)
{
    asm volatile("cp.async.cg.shared.global [%0], [%1], 16;"
                 :: "r"(saddr), "l"(g));
}
#define CP_COMMIT() asm volatile("cp.async.commit_group;")
#define CP_WAIT1()  asm volatile("cp.async.wait_group 1;")

#define PITCH 40               // smem pitch (bf16) for dense gemm tiles
#define DG_TILE (128*PITCH)    // 5120 elems per tile
#define DG_STAGE (4*DG_TILE)   // 20480 elems per stage
#define DG_SMEM (2*DG_STAGE*2) // 81920 bytes

// ---------------- HMMA GEMM: 128x128 tile, 3-term bf16 split, 2-stage cp.async --
template<int EPI>
__global__ __launch_bounds__(256, 2)
void hmma_gemm(const float* __restrict__ bias, float* __restrict__ Cout, int Kdim)
{
    extern __shared__ __nv_bfloat16 dsm[];

    const int tid  = threadIdx.x;
    const int wid  = tid >> 5;
    const int lane = tid & 31;
    const int wm   = wid & 1;
    const int wn   = wid >> 1;
    const int brow = blockIdx.y * 128;
    const int bcol = blockIdx.x * 128;

    const __nv_bfloat16* A1 = (EPI == 0) ? g_XA1 : g_OC1;
    const __nv_bfloat16* A2 = (EPI == 0) ? g_XA2 : g_OC2;
    const __nv_bfloat16* B1 = (EPI == 0) ? g_WQ1 : g_WP1;
    const __nv_bfloat16* B2 = (EPI == 0) ? g_WQ2 : g_WP2;

    float acc[4][4][4];
#pragma unroll
    for (int i = 0; i < 4; i++)
#pragma unroll
        for (int j = 0; j < 4; j++)
#pragma unroll
            for (int q = 0; q < 4; q++) acc[i][j][q] = 0.f;

    const uint32_t smbase = smem_u32(dsm);
    const int arow = wm * 64 + (lane & 15);
    const int acolL = (lane >> 4) * 8;
    const int bn   = wn * 32 + (lane & 7) + ((lane >> 4) & 1) * 8;
    const int bkL  = ((lane >> 3) & 1) * 8;

    // per-thread load slots (2 per tile)
    const int l_row0 = tid >> 2,        l_ch0 = (tid & 3) * 8;
    const int l_row1 = (tid + 256) >> 2, l_ch1 = ((tid + 256) & 3) * 8;

    auto load_stage = [&](int stage, int k0) {
        uint32_t sb = smbase + stage * DG_STAGE * 2;
#pragma unroll
        for (int t = 0; t < 4; t++) {
            const __nv_bfloat16* src = (t == 0) ? A1 : (t == 1) ? A2 : (t == 2) ? B1 : B2;
            const int rbase = (t < 2) ? brow : bcol;
            uint32_t tb = sb + t * DG_TILE * 2;
            cpa16(tb + (l_row0 * PITCH + l_ch0) * 2,
                  src + (size_t)(rbase + l_row0) * Kdim + k0 + l_ch0);
            cpa16(tb + (l_row1 * PITCH + l_ch1) * 2,
                  src + (size_t)(rbase + l_row1) * Kdim + k0 + l_ch1);
        }
    };

    const int nchunk = Kdim >> 5;
    load_stage(0, 0);
    CP_COMMIT();

    for (int kc = 0; kc < nchunk; kc++) {
        if (kc + 1 < nchunk) load_stage((kc + 1) & 1, (kc + 1) << 5);
        CP_COMMIT();
        CP_WAIT1();
        __syncthreads();

        const uint32_t sb = smbase + (kc & 1) * DG_STAGE * 2;
        const uint32_t as1 = sb, as2 = sb + DG_TILE * 2;
        const uint32_t bs1 = sb + 2 * DG_TILE * 2, bs2 = sb + 3 * DG_TILE * 2;
#pragma unroll
        for (int ks = 0; ks < 2; ks++) {
            const int acol = ks * 16 + acolL;
            const int bk   = ks * 16 + bkL;
            uint32_t a1[4][4], a2[4][4], b1[4][2], b2[4][2];
#pragma unroll
            for (int mt = 0; mt < 4; mt++) {
                uint32_t off = ((arow + mt * 16) * PITCH + acol) * 2;
                ldmx4(a1[mt][0], a1[mt][1], a1[mt][2], a1[mt][3], as1 + off);
                ldmx4(a2[mt][0], a2[mt][1], a2[mt][2], a2[mt][3], as2 + off);
            }
#pragma unroll
            for (int nt2 = 0; nt2 < 2; nt2++) {
                uint32_t off = ((bn + nt2 * 16) * PITCH + bk) * 2;
                ldmx4(b1[nt2 * 2][0], b1[nt2 * 2][1],
                      b1[nt2 * 2 + 1][0], b1[nt2 * 2 + 1][1], bs1 + off);
                ldmx4(b2[nt2 * 2][0], b2[nt2 * 2][1],
                      b2[nt2 * 2 + 1][0], b2[nt2 * 2 + 1][1], bs2 + off);
            }
#pragma unroll
            for (int mt = 0; mt < 4; mt++)
#pragma unroll
                for (int nt = 0; nt < 4; nt++) {
                    mma16816(acc[mt][nt], a1[mt], b1[nt]);
                    mma16816(acc[mt][nt], a1[mt], b2[nt]);
                    mma16816(acc[mt][nt], a2[mt], b1[nt]);
                }
        }
        __syncthreads();
    }

    const int g  = lane >> 2;
    const int tg = lane & 3;
#pragma unroll
    for (int mt = 0; mt < 4; mt++)
#pragma unroll
        for (int nt = 0; nt < 4; nt++) {
#pragma unroll
            for (int half = 0; half < 2; half++) {
                int grow = brow + wm * 64 + mt * 16 + g + half * 8;
                int col  = bcol + wn * 32 + nt * 8 + tg * 2;
                float2 v = make_float2(acc[mt][nt][half * 2],
                                       acc[mt][nt][half * 2 + 1]);
                if (EPI == 0) {
                    int bb = grow >> 12, nn = grow & 4095;
                    if (col < CH) {
                        const float s = 0.35355339059327373f;  // hd^(-1/4)
                        v.x *= s; v.y *= s;
                        int h = col >> 6, dd = col & 63;
                        *(float2*)&g_Q[(((size_t)(bb * NH + h)) * SEQ + nn) * HD + dd] = v;
                    } else {
                        int c2 = col - CH;
                        int h = c2 >> 6, dd = c2 & 63;
                        size_t adr = (((size_t)(bb * NH + h)) * SEQ + nn) * HD + dd;
                        __nv_bfloat16 h0, l0, h1, l1;
                        split2(v.x, h0, l0); split2(v.y, h1, l1);
                        *(__nv_bfloat162*)&g_VB1[adr] = __halves2bfloat162(h0, h1);
                        *(__nv_bfloat162*)&g_VB2[adr] = __halves2bfloat162(l0, l1);
                    }
                } else {
                    v.x += bias[col];
                    v.y += bias[col + 1];
                    *(float2*)&Cout[(size_t)grow * CH + col] = v;
                }
            }
        }
}

// ---------------- conversion kernels -----------------------------------------
__global__ __launch_bounds__(256)
void conv_x_kernel(const float* __restrict__ x)
{
    size_t i = ((size_t)blockIdx.x * 256 + threadIdx.x) * 4;
    float4 v = *(const float4*)&x[i];
    __nv_bfloat16 h0, l0, h1, l1, h2, l2, h3, l3;
    split2(v.x, h0, l0); split2(v.y, h1, l1);
    split2(v.z, h2, l2); split2(v.w, h3, l3);
    *(__nv_bfloat162*)&g_XA1[i]     = __halves2bfloat162(h0, h1);
    *(__nv_bfloat162*)&g_XA1[i + 2] = __halves2bfloat162(h2, h3);
    *(__nv_bfloat162*)&g_XA2[i]     = __halves2bfloat162(l0, l1);
    *(__nv_bfloat162*)&g_XA2[i + 2] = __halves2bfloat162(l2, l3);
}

template<int WHICH>
__global__ __launch_bounds__(256)
void conv_w_kernel(const float* __restrict__ W, int N)
{
    __nv_bfloat16* o1 = (WHICH == 0) ? g_WQ1 : g_WP1;
    __nv_bfloat16* o2 = (WHICH == 0) ? g_WQ2 : g_WP2;
    int idx = blockIdx.x * 256 + threadIdx.x;
    int n = idx / CH, k = idx - n * CH;
    float v = W[(size_t)k * N + n];
    __nv_bfloat16 h, l;
    split2(v, h, l);
    o1[idx] = h;
    o2[idx] = l;
}

// ---------------- random feature map -> bf16 split pair ------------------------
__global__ __launch_bounds__(256)
void rf_kernel(const float* __restrict__ randm)
{
    __shared__ float Rs[64 * 132];
    __shared__ float Qs[32 * 68];
    int bh = blockIdx.y;
    int h  = bh % NH;
    int rowblk = blockIdx.x;

    for (int f = threadIdx.x; f < 64 * RM / 4; f += 256) {
        int k = f >> 5, mq = (f & 31) * 4;
        *(float4*)&Rs[k * 132 + mq] =
            *(const float4*)&randm[((size_t)h * HD + k) * RM + mq];
    }
    const float* Qbase = g_Q + ((size_t)bh * SEQ + (size_t)rowblk * 32) * HD;
    for (int f = threadIdx.x; f < 32 * HD / 4; f += 256) {
        int r = f >> 4, kq = (f & 15) * 4;
        *(float4*)&Qs[r * 68 + kq] = *(const float4*)&Qbase[(size_t)r * HD + kq];
    }
    __syncthreads();

    int r  = threadIdx.x >> 3;
    int mq = (threadIdx.x & 7) * 16;
    float acc[16];
#pragma unroll
    for (int i = 0; i < 16; i++) acc[i] = 0.f;
    float sq = 0.f;
    for (int k = 0; k < HD; k++) {
        float qv = Qs[r * 68 + k];
        sq += qv * qv;
        const float4* rp = (const float4*)&Rs[k * 132 + mq];
#pragma unroll
        for (int q = 0; q < 4; q++) {
            float4 v = rp[q];
            acc[q * 4 + 0] += qv * v.x;
            acc[q * 4 + 1] += qv * v.y;
            acc[q * 4 + 2] += qv * v.z;
            acc[q * 4 + 3] += qv * v.w;
        }
    }
    size_t dst = ((size_t)bh * SEQ + (size_t)rowblk * 32 + r) * RM + mq;
    float base = -0.5f * sq;
    const float sc = 0.08838834764831845f;  // 1/sqrt(128)
#pragma unroll
    for (int q = 0; q < 4; q++) {
        float v0 = expf(acc[q * 4 + 0] + base) * sc;
        float v1 = expf(acc[q * 4 + 1] + base) * sc;
        float v2 = expf(acc[q * 4 + 2] + base) * sc;
        float v3 = expf(acc[q * 4 + 3] + base) * sc;
        __nv_bfloat16 h0, l0, h1, l1, h2, l2, h3, l3;
        split2(v0, h0, l0); split2(v1, h1, l1);
        split2(v2, h2, l2); split2(v3, h3, l3);
        *(__nv_bfloat162*)&g_RF1[dst + q * 4]     = __halves2bfloat162(h0, h1);
        *(__nv_bfloat162*)&g_RF1[dst + q * 4 + 2] = __halves2bfloat162(h2, h3);
        *(__nv_bfloat162*)&g_RF2[dst + q * 4]     = __halves2bfloat162(l0, l1);
        *(__nv_bfloat162*)&g_RF2[dst + q * 4 + 2] = __halves2bfloat162(l2, l3);
    }
}

// ---------------- kk/kv via HMMA, trans-ldmatrix, 2-stage cp.async --------------
#define KK_A_TILE (32*136)
#define KK_Y_TILE (32*72)
#define KK_STAGE (2*KK_A_TILE + 2*KK_Y_TILE)     // 13312 elems
#define KK_SMEM (2*KK_STAGE*2)                    // 53248 bytes

__global__ __launch_bounds__(256, 2)
void kkkv_hmma()
{
    extern __shared__ __nv_bfloat16 ksm[];
    const int tid = threadIdx.x, wid = tid >> 5, lane = tid & 31;
    const int ct = blockIdx.x, bh = blockIdx.y, split = blockIdx.z;
    const int wm = wid >> 1, wn = wid & 1;

    size_t abase = ((size_t)bh * SEQ + (size_t)split * NCHUNK) * RM;
    const __nv_bfloat16 *a1 = g_RF1 + abase, *a2 = g_RF2 + abase;
    const __nv_bfloat16 *b1, *b2;
    int bstr;
    if (ct == 2) {
        size_t vb = ((size_t)bh * SEQ + (size_t)split * NCHUNK) * HD;
        b1 = g_VB1 + vb; b2 = g_VB2 + vb; bstr = HD;
    } else {
        b1 = a1 + ct * 64; b2 = a2 + ct * 64; bstr = RM;
    }

    float acc[2][4][4];
#pragma unroll
    for (int i = 0; i < 2; i++)
#pragma unroll
        for (int j = 0; j < 4; j++)
#pragma unroll
            for (int q = 0; q < 4; q++) acc[i][j][q] = 0.f;

    const uint32_t smbase = smem_u32(ksm);
    const int a_r = (lane & 7) + (lane >> 4) * 8;
    const int a_c = ((lane >> 3) & 1) * 8;
    const int b_r = (lane & 7) + ((lane >> 3) & 1) * 8;
    const int b_c = (lane >> 4) * 8;

    // load slots: A1/A2: rows 0..31, 16 uint4 per row (2 per thread)
    const int ar0 = tid >> 4,        ac0 = (tid & 15) * 8;
    const int ar1 = (tid + 256) >> 4, ac1 = ((tid + 256) & 15) * 8;
    // Y: 2 buffers x 32 rows x 8 uint4 = 512 slots (2 per thread)
    auto load_stage = [&](int stage, int n0) {
        uint32_t sb = smbase + stage * KK_STAGE * 2;
        uint32_t sA1 = sb, sA2 = sb + KK_A_TILE * 2;
        uint32_t sY1 = sb + 2 * KK_A_TILE * 2, sY2 = sY1 + KK_Y_TILE * 2;
        cpa16(sA1 + (ar0 * 136 + ac0) * 2, a1 + (size_t)(n0 + ar0) * RM + ac0);
        cpa16(sA1 + (ar1 * 136 + ac1) * 2, a1 + (size_t)(n0 + ar1) * RM + ac1);
        cpa16(sA2 + (ar0 * 136 + ac0) * 2, a2 + (size_t)(n0 + ar0) * RM + ac0);
        cpa16(sA2 + (ar1 * 136 + ac1) * 2, a2 + (size_t)(n0 + ar1) * RM + ac1);
#pragma unroll
        for (int l = 0; l < 2; l++) {
            int f = tid + l * 256;
            int which = f >> 8;
            int r = (f & 255) >> 3;
            int c = (f & 7) * 8;
            const __nv_bfloat16* bs = which ? b2 : b1;
            uint32_t yd = which ? sY2 : sY1;
            cpa16(yd + (r * 72 + c) * 2, bs + (size_t)(n0 + r) * bstr + c);
        }
    };

    load_stage(0, 0);
    CP_COMMIT();

    for (int chunk = 0; chunk < NCHUNK / 32; chunk++) {
        if (chunk + 1 < NCHUNK / 32) load_stage((chunk + 1) & 1, (chunk + 1) * 32);
        CP_COMMIT();
        CP_WAIT1();
        __syncthreads();

        uint32_t sb = smbase + (chunk & 1) * KK_STAGE * 2;
        uint32_t as1 = sb, as2 = sb + KK_A_TILE * 2;
        uint32_t ys1 = sb + 2 * KK_A_TILE * 2, ys2 = ys1 + KK_Y_TILE * 2;
#pragma unroll
        for (int ks = 0; ks < 2; ks++) {
            uint32_t A1f[2][4], A2f[2][4], B1f[4][2], B2f[4][2];
#pragma unroll
            for (int mt = 0; mt < 2; mt++) {
                uint32_t off = ((ks * 16 + a_r) * 136 + wm * 32 + mt * 16 + a_c) * 2;
                ldmx4t(A1f[mt], as1 + off);
                ldmx4t(A2f[mt], as2 + off);
            }
#pragma unroll
            for (int nb = 0; nb < 2; nb++) {
                uint32_t off = ((ks * 16 + b_r) * 72 + wn * 32 + nb * 16 + b_c) * 2;
                uint32_t t1[4], t2[4];
                ldmx4t(t1, ys1 + off);
                ldmx4t(t2, ys2 + off);
                B1f[nb * 2][0] = t1[0]; B1f[nb * 2][1] = t1[1];
                B1f[nb * 2 + 1][0] = t1[2]; B1f[nb * 2 + 1][1] = t1[3];
                B2f[nb * 2][0] = t2[0]; B2f[nb * 2][1] = t2[1];
                B2f[nb * 2 + 1][0] = t2[2]; B2f[nb * 2 + 1][1] = t2[3];
            }
#pragma unroll
            for (int mt = 0; mt < 2; mt++)
#pragma unroll
                for (int nt = 0; nt < 4; nt++) {
                    mma16816(acc[mt][nt], A1f[mt], B1f[nt]);
                    mma16816(acc[mt][nt], A1f[mt], B2f[nt]);
                    mma16816(acc[mt][nt], A2f[mt], B1f[nt]);
                }
        }
        __syncthreads();
    }

    float* dst = g_PART + ((size_t)split * BH + bh) * (RM * (RM + HD));
#pragma unroll
    for (int mt = 0; mt < 2; mt++)
#pragma unroll
        for (int nt = 0; nt < 4; nt++)
#pragma unroll
            for (int half = 0; half < 2; half++) {
                int m = wm * 32 + mt * 16 + (lane >> 2) + half * 8;
                int j = ct * 64 + wn * 32 + nt * 8 + (lane & 3) * 2;
                *(float2*)&dst[m * (RM + HD) + j] =
                    make_float2(acc[mt][nt][half * 2], acc[mt][nt][half * 2 + 1]);
            }
}

// ---------------- reduce + d from kk diag + scale + L ----------------------------
__global__ __launch_bounds__(256)
void reduce_kernel()
{
    extern __shared__ float kks[];
    __shared__ float dsh[RM];
    __shared__ float rowsum[RM];
    int bh = blockIdx.x;
    // column norm^2 of unnormalized rf = diagonal of unnormalized kk
    if (threadIdx.x < RM) {
        float s = 0.f;
#pragma unroll
        for (int sp = 0; sp < SPLITS; sp++)
            s += g_PART[((size_t)sp * BH + bh) * (RM * (RM + HD))
                        + threadIdx.x * (RM + HD) + threadIdx.x];
        float nrm = sqrtf(s);
        float d = 1.0f / fmaxf(nrm, 1e-12f);
        dsh[threadIdx.x] = d;
        g_D[bh * RM + threadIdx.x] = d;
    }
    __syncthreads();
    for (int idx = threadIdx.x; idx < RM * (RM + HD); idx += 256) {
        int m = idx / (RM + HD);
        int j = idx - m * (RM + HD);
        float s = 0.f;
#pragma unroll
        for (int sp = 0; sp < SPLITS; sp++)
            s += g_PART[((size_t)sp * BH + bh) * (RM * (RM + HD)) + idx];
        if (j < RM) {
            float v = s * dsh[m] * dsh[j];
            kks[m * RM + j] = v;
            g_KK[((size_t)bh * RM + m) * RM + j] = v;
        } else {
            g_KV[((size_t)bh * RM + m) * HD + (j - RM)] = s * dsh[m];
        }
    }
    __syncthreads();
    if (threadIdx.x < RM) {
        float rs = 0.f;
        for (int j = 0; j < RM; j++) rs += fabsf(kks[threadIdx.x * RM + j]);
        rowsum[threadIdx.x] = rs;
    }
    __syncthreads();
    if (threadIdx.x == 0) {
        float mx = 0.f;
        for (int i = 0; i < RM; i++) mx = fmaxf(mx, rowsum[i]);
        g_Lc[bh] = mx + 1.0f;
    }
}

// ---------------- ISTA (emits (d*s)^T bf16 split) --------------------------------
__device__ __forceinline__ float softf(float z, float t)
{
    float a = fabsf(z) - t;
    return a > 0.f ? (z >= 0.f ? a : -a) : 0.f;
}

__global__ __launch_bounds__(256)
void ista_kernel()
{
    extern __shared__ float sm[];
    float* kks = sm;
    float* kvs = sm + RM * 129;
    float* ss  = kvs + RM * HD;
    int bh = blockIdx.x;
    float L    = g_Lc[bh];
    float invL = 1.0f / L;
    float thr  = LAMBDA * invL;

    for (int idx = threadIdx.x; idx < RM * RM; idx += 256) {
        int m = idx >> 7, j = idx & 127;
        kks[m * 129 + j] = g_KK[(size_t)bh * RM * RM + idx];
    }
    for (int idx = threadIdx.x; idx < RM * HD; idx += 256)
        kvs[idx] = g_KV[(size_t)bh * RM * HD + idx];
    __syncthreads();

    int m  = threadIdx.x >> 1;
    int ch = (threadIdx.x & 1) * 32;
#pragma unroll
    for (int i = 0; i < 32; i++)
        ss[m * 68 + ch + i] = softf(kvs[m * HD + ch + i], LAMBDA);
    __syncthreads();

    for (int it = 0; it < NSTEP; it++) {
        float acc[32];
#pragma unroll
        for (int i = 0; i < 32; i++) acc[i] = 0.f;
        for (int p = 0; p < RM; p++) {
            float kv_ = kks[m * 129 + p];
            const float4* sp = (const float4*)&ss[p * 68 + ch];
#pragma unroll
            for (int q = 0; q < 8; q++) {
                float4 v = sp[q];
                acc[q * 4 + 0] += kv_ * v.x;
                acc[q * 4 + 1] += kv_ * v.y;
                acc[q * 4 + 2] += kv_ * v.z;
                acc[q * 4 + 3] += kv_ * v.w;
            }
        }
        float r[32];
#pragma unroll
        for (int i = 0; i < 32; i++) {
            float z = ss[m * 68 + ch + i] - (acc[i] - kvs[m * HD + ch + i]) * invL;
            r[i] = softf(z, thr);
        }
        __syncthreads();
#pragma unroll
        for (int q = 0; q < 8; q++)
            *(float4*)&ss[m * 68 + ch + q * 4] =
                make_float4(r[q * 4], r[q * 4 + 1], r[q * 4 + 2], r[q * 4 + 3]);
        __syncthreads();
    }
    float dm = g_D[bh * RM + m];
#pragma unroll
    for (int q = 0; q < 8; q++) {
        float4 v = *(float4*)&ss[m * 68 + ch + q * 4];
        v.x *= dm; v.y *= dm; v.z *= dm; v.w *= dm;
        *(float4*)&ss[m * 68 + ch + q * 4] = v;
    }
    __syncthreads();
    int d  = threadIdx.x >> 2;
    int ms = (threadIdx.x & 3) * 32;
    size_t ob = ((size_t)bh * HD + d) * RM + ms;
#pragma unroll
    for (int i = 0; i < 32; i += 2) {
        float v0 = ss[(ms + i) * 68 + d];
        float v1 = ss[(ms + i + 1) * 68 + d];
        __nv_bfloat16 h0, l0, h1, l1;
        split2(v0, h0, l0); split2(v1, h1, l1);
        *(__nv_bfloat162*)&g_ST1[ob + i] = __halves2bfloat162(h0, h1);
        *(__nv_bfloat162*)&g_ST2[ob + i] = __halves2bfloat162(l0, l1);
    }
}

// ---------------- out = rf @ sT^T via HMMA, emits OC bf16 pair --------------------
__global__ __launch_bounds__(256, 2)
void outgemm_hmma()
{
    __shared__ __nv_bfloat16 As1[128 * PITCH], As2[128 * PITCH];
    __shared__ __nv_bfloat16 Bs1[64 * PITCH],  Bs2[64 * PITCH];
    const int tid = threadIdx.x, wid = tid >> 5, lane = tid & 31;
    const int wm = wid & 3, wn = wid >> 2;
    const int bh = blockIdx.y, nblk = blockIdx.x;
    const int b = bh / NH, h = bh % NH;

    size_t rfbase = ((size_t)bh * SEQ + (size_t)nblk * 128) * RM;
    size_t stbase = (size_t)bh * HD * RM;

    float acc[2][4][4];
#pragma unroll
    for (int i = 0; i < 2; i++)
#pragma unroll
        for (int j = 0; j < 4; j++)
#pragma unroll
            for (int q = 0; q < 4; q++) acc[i][j][q] = 0.f;

    const uint32_t as1 = smem_u32(As1), as2 = smem_u32(As2);
    const uint32_t bs1 = smem_u32(Bs1), bs2 = smem_u32(Bs2);
    const int arow = wm * 32 + (lane & 15);
    const int acolL = (lane >> 4) * 8;
    const int bn   = wn * 32 + (lane & 7) + ((lane >> 4) & 1) * 8;
    const int bkL  = ((lane >> 3) & 1) * 8;

    for (int kc = 0; kc < 4; kc++) {
        const int k0 = kc * 32;
#pragma unroll
        for (int l = 0; l < 2; l++) {
            int f = tid + l * 256;
            int r = f >> 2, c = (f & 3) * 8;
            *(uint4*)(As1 + r * PITCH + c) =
                *(const uint4*)(g_RF1 + rfbase + (size_t)r * RM + k0 + c);
            *(uint4*)(As2 + r * PITCH + c) =
                *(const uint4*)(g_RF2 + rfbase + (size_t)r * RM + k0 + c);
        }
        {
            int r = tid >> 2, c = (tid & 3) * 8;
            if (r < 64) {
                *(uint4*)(Bs1 + r * PITCH + c) =
                    *(const uint4*)(g_ST1 + stbase + (size_t)r * RM + k0 + c);
                *(uint4*)(Bs2 + r * PITCH + c) =
                    *(const uint4*)(g_ST2 + stbase + (size_t)r * RM + k0 + c);
            }
        }
        __syncthreads();
#pragma unroll
        for (int ks = 0; ks < 2; ks++) {
            const int acol = ks * 16 + acolL;
            const int bk   = ks * 16 + bkL;
            uint32_t a1[2][4], a2[2][4], b1[4][2], b2[4][2];
#pragma unroll
            for (int mt = 0; mt < 2; mt++) {
                uint32_t off = ((arow + mt * 16) * PITCH + acol) * 2;
                ldmx4(a1[mt][0], a1[mt][1], a1[mt][2], a1[mt][3], as1 + off);
                ldmx4(a2[mt][0], a2[mt][1], a2[mt][2], a2[mt][3], as2 + off);
            }
#pragma unroll
            for (int nt2 = 0; nt2 < 2; nt2++) {
                uint32_t off = ((bn + nt2 * 16) * PITCH + bk) * 2;
                ldmx4(b1[nt2 * 2][0], b1[nt2 * 2][1],
                      b1[nt2 * 2 + 1][0], b1[nt2 * 2 + 1][1], bs1 + off);
                ldmx4(b2[nt2 * 2][0], b2[nt2 * 2][1],
                      b2[nt2 * 2 + 1][0], b2[nt2 * 2 + 1][1], bs2 + off);
            }
#pragma unroll
            for (int mt = 0; mt < 2; mt++)
#pragma unroll
                for (int nt = 0; nt < 4; nt++) {
                    mma16816(acc[mt][nt], a1[mt], b1[nt]);
                    mma16816(acc[mt][nt], a1[mt], b2[nt]);
                    mma16816(acc[mt][nt], a2[mt], b1[nt]);
                }
        }
        __syncthreads();
    }

    const int g  = lane >> 2;
    const int tg = lane & 3;
#pragma unroll
    for (int mt = 0; mt < 2; mt++)
#pragma unroll
        for (int nt = 0; nt < 4; nt++)
#pragma unroll
            for (int half = 0; half < 2; half++) {
                int nrow = nblk * 128 + wm * 32 + mt * 16 + g + half * 8;
                int d    = wn * 32 + nt * 8 + tg * 2;
                float2 v = make_float2(acc[mt][nt][half * 2],
                                       acc[mt][nt][half * 2 + 1]);
                size_t adr = ((size_t)b * SEQ + nrow) * CH + h * HD + d;
                __nv_bfloat16 h0, l0, h1, l1;
                split2(v.x, h0, l0); split2(v.y, h1, l1);
                *(__nv_bfloat162*)&g_OC1[adr] = __halves2bfloat162(h0, h1);
                *(__nv_bfloat162*)&g_OC2[adr] = __halves2bfloat162(l0, l1);
            }
}

// ---------------- launch -----------------------------------------------------------
extern "C" void kernel_launch(void* const* d_in, const int* in_sizes, int n_in,
                              void* d_out, int out_size)
{
    const float *x = nullptr, *wqkv = nullptr, *wproj = nullptr,
                *bias = nullptr, *rm = nullptr;
    for (int i = 0; i < n_in; i++) {
        const float* p = (const float*)d_in[i];
        switch (in_sizes[i]) {
            case BATCH * SEQ * CH: x = p; break;
            case CH * 2 * CH:      wqkv = p; break;
            case CH * CH:          wproj = p; break;
            case CH:               bias = p; break;
            case NH * HD * RM:     rm = p; break;
        }
    }
    float* out = (float*)d_out;
    (void)out_size;

    cudaFuncSetAttribute(hmma_gemm<0>, cudaFuncAttributeMaxDynamicSharedMemorySize, DG_SMEM);
    cudaFuncSetAttribute(hmma_gemm<1>, cudaFuncAttributeMaxDynamicSharedMemorySize, DG_SMEM);
    cudaFuncSetAttribute(kkkv_hmma, cudaFuncAttributeMaxDynamicSharedMemorySize, KK_SMEM);
    cudaFuncSetAttribute(reduce_kernel, cudaFuncAttributeMaxDynamicSharedMemorySize, RM * RM * 4);
    cudaFuncSetAttribute(ista_kernel, cudaFuncAttributeMaxDynamicSharedMemorySize,
                         (RM * 129 + RM * HD + RM * 68) * 4);

    // conversions to bf16 split pairs
    conv_x_kernel<<<BATCH * SEQ * CH / 1024, 256>>>(x);
    conv_w_kernel<0><<<2 * CH * CH / 256, 256>>>(wqkv, 2 * CH);
    conv_w_kernel<1><<<CH * CH / 256, 256>>>(wproj, CH);

    // 1. qkv = x @ Wqkv (HMMA, cp.async pipelined)
    hmma_gemm<0><<<dim3(12, 256), 256, DG_SMEM>>>(nullptr, nullptr, CH);
    // 2. random feature map -> rf bf16 pair
    rf_kernel<<<dim3(128, BH), 256>>>(rm);
    // 3. kk/kv partials (HMMA, cp.async pipelined)
    kkkv_hmma<<<dim3(3, BH, SPLITS), 256, KK_SMEM>>>();
    // 4. combine partials + d from diag + L
    reduce_kernel<<<BH, 256, RM * RM * 4>>>();
    // 5. ISTA -> (d*s)^T bf16 pair
    ista_kernel<<<BH, 256, (RM * 129 + RM * HD + RM * 68) * 4>>>();
    // 6. out_head = rf @ s (HMMA) -> OC bf16 pair
    outgemm_hmma<<<dim3(32, BH), 256>>>();
    // 7. final projection + bias (HMMA, cp.async pipelined)
    hmma_gemm<1><<<dim3(6, 256), 256, DG_SMEM>>>(bias, out, CH);
}

// round 7
// speedup vs baseline: 3.2237x; 1.8113x over previous
#include <cuda_runtime.h>
#include <cuda_bf16.h>
#include <math.h>
#include <cstdint>

// Problem constants
#define BATCH 8
#define SEQ   4096
#define CH    768
#define NH    12
#define HD    64
#define RM    128
#define BH    (BATCH*NH)
#define LAMBDA 0.3f
#define NSTEP 5
#define SPLITS 4
#define NCHUNK (SEQ/SPLITS)    // 1024

// ---------------- scratch ----------------------------------------------------
__device__ float g_D  [BH*RM];
__device__ float g_PART[(size_t)SPLITS*BH*RM*(RM+HD)];
__device__ float g_KK [(size_t)BH*RM*RM];
__device__ float g_KV [(size_t)BH*RM*HD];
__device__ float g_Lc [BH];
// bf16 split pairs
__device__ __nv_bfloat16 g_XA1[(size_t)BATCH*SEQ*CH];
__device__ __nv_bfloat16 g_XA2[(size_t)BATCH*SEQ*CH];
__device__ __nv_bfloat16 g_WQ1[(size_t)2*CH*CH];
__device__ __nv_bfloat16 g_WQ2[(size_t)2*CH*CH];
__device__ __nv_bfloat16 g_WP1[(size_t)CH*CH];
__device__ __nv_bfloat16 g_WP2[(size_t)CH*CH];
__device__ __nv_bfloat16 g_OC1[(size_t)BATCH*SEQ*CH];
__device__ __nv_bfloat16 g_OC2[(size_t)BATCH*SEQ*CH];
__device__ __nv_bfloat16 g_QB1[(size_t)BH*SEQ*HD];   // qs hi  [bh][n][d]
__device__ __nv_bfloat16 g_QB2[(size_t)BH*SEQ*HD];   // qs lo
__device__ __nv_bfloat16 g_RT1[(size_t)NH*RM*HD];    // R^T hi [h][m][d]
__device__ __nv_bfloat16 g_RT2[(size_t)NH*RM*HD];    // lo
__device__ __nv_bfloat16 g_RF1[(size_t)BH*SEQ*RM];   // rf hi  [bh][n][m]
__device__ __nv_bfloat16 g_RF2[(size_t)BH*SEQ*RM];   // rf lo
__device__ __nv_bfloat16 g_VB1[(size_t)BH*SEQ*HD];   // v hi   [bh][n][d]
__device__ __nv_bfloat16 g_VB2[(size_t)BH*SEQ*HD];   // v lo
__device__ __nv_bfloat16 g_ST1[(size_t)BH*HD*RM];    // (d*s)^T hi [bh][d][m]
__device__ __nv_bfloat16 g_ST2[(size_t)BH*HD*RM];    // lo

// ---------------- warp-MMA / cp.async helpers ----------------------------------
__device__ __forceinline__ uint32_t smem_u32(const void* p) {
    uint32_t a;
    asm("{ .reg .u64 t; cvta.to.shared.u64 t, %1; cvt.u32.u64 %0, t; }"
        : "=r"(a) : "l"(p));
    return a;
}
__device__ __forceinline__ void ldmx4(uint32_t& r0, uint32_t& r1,
                                      uint32_t& r2, uint32_t& r3, uint32_t addr)
{
    asm volatile("ldmatrix.sync.aligned.m8n8.x4.shared.b16 {%0,%1,%2,%3}, [%4];"
                 : "=r"(r0), "=r"(r1), "=r"(r2), "=r"(r3) : "r"(addr));
}
__device__ __forceinline__ void ldmx4t(uint32_t* r, uint32_t addr)
{
    asm volatile("ldmatrix.sync.aligned.m8n8.x4.trans.shared.b16 {%0,%1,%2,%3}, [%4];"
                 : "=r"(r[0]), "=r"(r[1]), "=r"(r[2]), "=r"(r[3]) : "r"(addr));
}
__device__ __forceinline__ void mma16816(float* c, const uint32_t* a,
                                         const uint32_t* b)
{
    asm volatile(
        "mma.sync.aligned.m16n8k16.row.col.f32.bf16.bf16.f32 "
        "{%0,%1,%2,%3}, {%4,%5,%6,%7}, {%8,%9}, {%0,%1,%2,%3};"
        : "+f"(c[0]), "+f"(c[1]), "+f"(c[2]), "+f"(c[3])
        : "r"(a[0]), "r"(a[1]), "r"(a[2]), "r"(a[3]), "r"(b[0]), "r"(b[1]));
}
__device__ __forceinline__ void split2(float v, __nv_bfloat16& h, __nv_bfloat16& l)
{
    h = __float2bfloat16(v);
    l = __float2bfloat16(v - __bfloat162float(h));
}
__device__ __forceinline__ void cpa16(uint32_t saddr, const void* g)
{
    asm volatile("cp.async.cg.shared.global [%0], [%1], 16;"
                 :: "r"(saddr), "l"(g));
}
#define CP_COMMIT() asm volatile("cp.async.commit_group;")
#define CP_WAIT1()  asm volatile("cp.async.wait_group 1;")

#define PITCH 40               // smem pitch (bf16) for dense gemm tiles
#define DG_TILE (128*PITCH)
#define DG_STAGE (4*DG_TILE)
#define DG_SMEM (2*DG_STAGE*2) // 81920 bytes

// ---------------- HMMA GEMM: 128x128 tile, 3-term bf16 split, 2-stage cp.async --
template<int EPI>
__global__ __launch_bounds__(256, 2)
void hmma_gemm(const float* __restrict__ bias, float* __restrict__ Cout, int Kdim)
{
    extern __shared__ __nv_bfloat16 dsm[];

    const int tid  = threadIdx.x;
    const int wid  = tid >> 5;
    const int lane = tid & 31;
    const int wm   = wid & 1;
    const int wn   = wid >> 1;
    const int brow = blockIdx.y * 128;
    const int bcol = blockIdx.x * 128;

    const __nv_bfloat16* A1 = (EPI == 0) ? g_XA1 : g_OC1;
    const __nv_bfloat16* A2 = (EPI == 0) ? g_XA2 : g_OC2;
    const __nv_bfloat16* B1 = (EPI == 0) ? g_WQ1 : g_WP1;
    const __nv_bfloat16* B2 = (EPI == 0) ? g_WQ2 : g_WP2;

    float acc[4][4][4];
#pragma unroll
    for (int i = 0; i < 4; i++)
#pragma unroll
        for (int j = 0; j < 4; j++)
#pragma unroll
            for (int q = 0; q < 4; q++) acc[i][j][q] = 0.f;

    const uint32_t smbase = smem_u32(dsm);
    const int arow = wm * 64 + (lane & 15);
    const int acolL = (lane >> 4) * 8;
    const int bn   = wn * 32 + (lane & 7) + ((lane >> 4) & 1) * 8;
    const int bkL  = ((lane >> 3) & 1) * 8;

    const int l_row0 = tid >> 2,        l_ch0 = (tid & 3) * 8;
    const int l_row1 = (tid + 256) >> 2, l_ch1 = ((tid + 256) & 3) * 8;

    auto load_stage = [&](int stage, int k0) {
        uint32_t sb = smbase + stage * DG_STAGE * 2;
#pragma unroll
        for (int t = 0; t < 4; t++) {
            const __nv_bfloat16* src = (t == 0) ? A1 : (t == 1) ? A2 : (t == 2) ? B1 : B2;
            const int rbase = (t < 2) ? brow : bcol;
            uint32_t tb = sb + t * DG_TILE * 2;
            cpa16(tb + (l_row0 * PITCH + l_ch0) * 2,
                  src + (size_t)(rbase + l_row0) * Kdim + k0 + l_ch0);
            cpa16(tb + (l_row1 * PITCH + l_ch1) * 2,
                  src + (size_t)(rbase + l_row1) * Kdim + k0 + l_ch1);
        }
    };

    const int nchunk = Kdim >> 5;
    load_stage(0, 0);
    CP_COMMIT();

    for (int kc = 0; kc < nchunk; kc++) {
        if (kc + 1 < nchunk) load_stage((kc + 1) & 1, (kc + 1) << 5);
        CP_COMMIT();
        CP_WAIT1();
        __syncthreads();

        const uint32_t sb = smbase + (kc & 1) * DG_STAGE * 2;
        const uint32_t as1 = sb, as2 = sb + DG_TILE * 2;
        const uint32_t bs1 = sb + 2 * DG_TILE * 2, bs2 = sb + 3 * DG_TILE * 2;
#pragma unroll
        for (int ks = 0; ks < 2; ks++) {
            const int acol = ks * 16 + acolL;
            const int bk   = ks * 16 + bkL;
            uint32_t a1[4][4], a2[4][4], b1[4][2], b2[4][2];
#pragma unroll
            for (int mt = 0; mt < 4; mt++) {
                uint32_t off = ((arow + mt * 16) * PITCH + acol) * 2;
                ldmx4(a1[mt][0], a1[mt][1], a1[mt][2], a1[mt][3], as1 + off);
                ldmx4(a2[mt][0], a2[mt][1], a2[mt][2], a2[mt][3], as2 + off);
            }
#pragma unroll
            for (int nt2 = 0; nt2 < 2; nt2++) {
                uint32_t off = ((bn + nt2 * 16) * PITCH + bk) * 2;
                ldmx4(b1[nt2 * 2][0], b1[nt2 * 2][1],
                      b1[nt2 * 2 + 1][0], b1[nt2 * 2 + 1][1], bs1 + off);
                ldmx4(b2[nt2 * 2][0], b2[nt2 * 2][1],
                      b2[nt2 * 2 + 1][0], b2[nt2 * 2 + 1][1], bs2 + off);
            }
#pragma unroll
            for (int mt = 0; mt < 4; mt++)
#pragma unroll
                for (int nt = 0; nt < 4; nt++) {
                    mma16816(acc[mt][nt], a1[mt], b1[nt]);
                    mma16816(acc[mt][nt], a1[mt], b2[nt]);
                    mma16816(acc[mt][nt], a2[mt], b1[nt]);
                }
        }
        __syncthreads();
    }

    const int g  = lane >> 2;
    const int tg = lane & 3;
#pragma unroll
    for (int mt = 0; mt < 4; mt++)
#pragma unroll
        for (int nt = 0; nt < 4; nt++) {
#pragma unroll
            for (int half = 0; half < 2; half++) {
                int grow = brow + wm * 64 + mt * 16 + g + half * 8;
                int col  = bcol + wn * 32 + nt * 8 + tg * 2;
                float2 v = make_float2(acc[mt][nt][half * 2],
                                       acc[mt][nt][half * 2 + 1]);
                if (EPI == 0) {
                    int bb = grow >> 12, nn = grow & 4095;
                    __nv_bfloat16 h0, l0, h1, l1;
                    if (col < CH) {
                        const float s = 0.35355339059327373f;  // hd^(-1/4)
                        v.x *= s; v.y *= s;
                        int h = col >> 6, dd = col & 63;
                        size_t adr = (((size_t)(bb * NH + h)) * SEQ + nn) * HD + dd;
                        split2(v.x, h0, l0); split2(v.y, h1, l1);
                        *(__nv_bfloat162*)&g_QB1[adr] = __halves2bfloat162(h0, h1);
                        *(__nv_bfloat162*)&g_QB2[adr] = __halves2bfloat162(l0, l1);
                    } else {
                        int c2 = col - CH;
                        int h = c2 >> 6, dd = c2 & 63;
                        size_t adr = (((size_t)(bb * NH + h)) * SEQ + nn) * HD + dd;
                        split2(v.x, h0, l0); split2(v.y, h1, l1);
                        *(__nv_bfloat162*)&g_VB1[adr] = __halves2bfloat162(h0, h1);
                        *(__nv_bfloat162*)&g_VB2[adr] = __halves2bfloat162(l0, l1);
                    }
                } else {
                    v.x += bias[col];
                    v.y += bias[col + 1];
                    *(float2*)&Cout[(size_t)grow * CH + col] = v;
                }
            }
        }
}

// ---------------- conversion kernels -----------------------------------------
__global__ __launch_bounds__(256)
void conv_x_kernel(const float* __restrict__ x)
{
    size_t i = ((size_t)blockIdx.x * 256 + threadIdx.x) * 4;
    float4 v = *(const float4*)&x[i];
    __nv_bfloat16 h0, l0, h1, l1, h2, l2, h3, l3;
    split2(v.x, h0, l0); split2(v.y, h1, l1);
    split2(v.z, h2, l2); split2(v.w, h3, l3);
    *(__nv_bfloat162*)&g_XA1[i]     = __halves2bfloat162(h0, h1);
    *(__nv_bfloat162*)&g_XA1[i + 2] = __halves2bfloat162(h2, h3);
    *(__nv_bfloat162*)&g_XA2[i]     = __halves2bfloat162(l0, l1);
    *(__nv_bfloat162*)&g_XA2[i + 2] = __halves2bfloat162(l2, l3);
}

template<int WHICH>
__global__ __launch_bounds__(256)
void conv_w_kernel(const float* __restrict__ W, int N)
{
    __nv_bfloat16* o1 = (WHICH == 0) ? g_WQ1 : g_WP1;
    __nv_bfloat16* o2 = (WHICH == 0) ? g_WQ2 : g_WP2;
    int idx = blockIdx.x * 256 + threadIdx.x;
    int n = idx / CH, k = idx - n * CH;
    float v = W[(size_t)k * N + n];
    __nv_bfloat16 h, l;
    split2(v, h, l);
    o1[idx] = h;
    o2[idx] = l;
}

// R [h][d][m] -> R^T pair [h][m][d]
__global__ __launch_bounds__(256)
void conv_rt_kernel(const float* __restrict__ randm)
{
    int idx = blockIdx.x * 256 + threadIdx.x;    // over NH*RM*HD
    int h = idx / (RM * HD);
    int r = idx - h * (RM * HD);
    int m = r / HD, d = r - m * HD;
    float v = randm[((size_t)h * HD + d) * RM + m];
    __nv_bfloat16 hi, lo;
    split2(v, hi, lo);
    g_RT1[idx] = hi;
    g_RT2[idx] = lo;
}

// ---------------- rf via HMMA: rf = exp(q@R^T - 0.5||q||^2)/sqrt(M) -------------
#define RF_PITCH 72
#define RF_TILE (128*RF_PITCH)
#define RF_SMEM (4*RF_TILE*2)   // 73728 bytes

__global__ __launch_bounds__(256, 2)
void rf_hmma()
{
    extern __shared__ __nv_bfloat16 rsm[];
    __shared__ float rowq2[128];
    const int tid = threadIdx.x, wid = tid >> 5, lane = tid & 31;
    const int wm = wid & 1, wn = wid >> 1;
    const int bh = blockIdx.y, h = bh % NH;
    const int brow = blockIdx.x * 128;

    const __nv_bfloat16* A1 = g_QB1 + ((size_t)bh * SEQ + brow) * HD;
    const __nv_bfloat16* A2 = g_QB2 + ((size_t)bh * SEQ + brow) * HD;
    const __nv_bfloat16* B1 = g_RT1 + (size_t)h * RM * HD;
    const __nv_bfloat16* B2 = g_RT2 + (size_t)h * RM * HD;

    // load 4 tiles, 128 rows x 64 bf16 each (pitch 72)
#pragma unroll
    for (int t = 0; t < 4; t++) {
        const __nv_bfloat16* src = (t == 0) ? A1 : (t == 1) ? A2 : (t == 2) ? B1 : B2;
        __nv_bfloat16* dst = rsm + t * RF_TILE;
#pragma unroll
        for (int u = 0; u < 4; u++) {
            int f = u * 256 + tid;
            int r = f >> 3, c = (f & 7) * 8;
            *(uint4*)(dst + r * RF_PITCH + c) = *(const uint4*)(src + (size_t)r * HD + c);
        }
    }
    __syncthreads();

    // row sums of q^2 (hi+lo reconstruct)
    {
        int r = tid >> 1;
        int k0 = (tid & 1) * 32;
        const __nv_bfloat16* q1 = rsm + r * RF_PITCH + k0;
        const __nv_bfloat16* q2 = rsm + RF_TILE + r * RF_PITCH + k0;
        float s = 0.f;
#pragma unroll
        for (int k = 0; k < 32; k++) {
            float v = __bfloat162float(q1[k]) + __bfloat162float(q2[k]);
            s += v * v;
        }
        s += __shfl_xor_sync(0xffffffffu, s, 1);
        if (!(tid & 1)) rowq2[r] = s;
    }

    float acc[4][4][4];
#pragma unroll
    for (int i = 0; i < 4; i++)
#pragma unroll
        for (int j = 0; j < 4; j++)
#pragma unroll
            for (int q = 0; q < 4; q++) acc[i][j][q] = 0.f;

    const uint32_t smbase = smem_u32(rsm);
    const uint32_t as1 = smbase, as2 = smbase + RF_TILE * 2;
    const uint32_t bs1 = smbase + 2 * RF_TILE * 2, bs2 = smbase + 3 * RF_TILE * 2;
    const int arow = wm * 64 + (lane & 15);
    const int acolL = (lane >> 4) * 8;
    const int bn   = wn * 32 + (lane & 7) + ((lane >> 4) & 1) * 8;
    const int bkL  = ((lane >> 3) & 1) * 8;

#pragma unroll
    for (int ks = 0; ks < 4; ks++) {
        const int acol = ks * 16 + acolL;
        const int bk   = ks * 16 + bkL;
        uint32_t a1[4][4], a2[4][4], b1[4][2], b2[4][2];
#pragma unroll
        for (int mt = 0; mt < 4; mt++) {
            uint32_t off = ((arow + mt * 16) * RF_PITCH + acol) * 2;
            ldmx4(a1[mt][0], a1[mt][1], a1[mt][2], a1[mt][3], as1 + off);
            ldmx4(a2[mt][0], a2[mt][1], a2[mt][2], a2[mt][3], as2 + off);
        }
#pragma unroll
        for (int nt2 = 0; nt2 < 2; nt2++) {
            uint32_t off = ((bn + nt2 * 16) * RF_PITCH + bk) * 2;
            ldmx4(b1[nt2 * 2][0], b1[nt2 * 2][1],
                  b1[nt2 * 2 + 1][0], b1[nt2 * 2 + 1][1], bs1 + off);
            ldmx4(b2[nt2 * 2][0], b2[nt2 * 2][1],
                  b2[nt2 * 2 + 1][0], b2[nt2 * 2 + 1][1], bs2 + off);
        }
#pragma unroll
        for (int mt = 0; mt < 4; mt++)
#pragma unroll
            for (int nt = 0; nt < 4; nt++) {
                mma16816(acc[mt][nt], a1[mt], b1[nt]);
                mma16816(acc[mt][nt], a1[mt], b2[nt]);
                mma16816(acc[mt][nt], a2[mt], b1[nt]);
            }
    }
    __syncthreads();

    const int g  = lane >> 2;
    const int tg = lane & 3;
    const float sc = 0.08838834764831845f;  // 1/sqrt(128)
#pragma unroll
    for (int mt = 0; mt < 4; mt++)
#pragma unroll
        for (int nt = 0; nt < 4; nt++)
#pragma unroll
            for (int half = 0; half < 2; half++) {
                int row  = wm * 64 + mt * 16 + g + half * 8;
                int mcol = wn * 32 + nt * 8 + tg * 2;
                float base = -0.5f * rowq2[row];
                float v0 = expf(acc[mt][nt][half * 2]     + base) * sc;
                float v1 = expf(acc[mt][nt][half * 2 + 1] + base) * sc;
                __nv_bfloat16 h0, l0, h1, l1;
                split2(v0, h0, l0); split2(v1, h1, l1);
                size_t adr = ((size_t)bh * SEQ + brow + row) * RM + mcol;
                *(__nv_bfloat162*)&g_RF1[adr] = __halves2bfloat162(h0, h1);
                *(__nv_bfloat162*)&g_RF2[adr] = __halves2bfloat162(l0, l1);
            }
}

// ---------------- kk/kv via HMMA, trans-ldmatrix, 2-stage cp.async --------------
#define KK_A_TILE (32*136)
#define KK_Y_TILE (32*72)
#define KK_STAGE (2*KK_A_TILE + 2*KK_Y_TILE)
#define KK_SMEM (2*KK_STAGE*2)

__global__ __launch_bounds__(256, 2)
void kkkv_hmma()
{
    extern __shared__ __nv_bfloat16 ksm[];
    const int tid = threadIdx.x, wid = tid >> 5, lane = tid & 31;
    const int ct = blockIdx.x, bh = blockIdx.y, split = blockIdx.z;
    const int wm = wid >> 1, wn = wid & 1;

    size_t abase = ((size_t)bh * SEQ + (size_t)split * NCHUNK) * RM;
    const __nv_bfloat16 *a1 = g_RF1 + abase, *a2 = g_RF2 + abase;
    const __nv_bfloat16 *b1, *b2;
    int bstr;
    if (ct == 2) {
        size_t vb = ((size_t)bh * SEQ + (size_t)split * NCHUNK) * HD;
        b1 = g_VB1 + vb; b2 = g_VB2 + vb; bstr = HD;
    } else {
        b1 = a1 + ct * 64; b2 = a2 + ct * 64; bstr = RM;
    }

    float acc[2][4][4];
#pragma unroll
    for (int i = 0; i < 2; i++)
#pragma unroll
        for (int j = 0; j < 4; j++)
#pragma unroll
            for (int q = 0; q < 4; q++) acc[i][j][q] = 0.f;

    const uint32_t smbase = smem_u32(ksm);
    const int a_r = (lane & 7) + (lane >> 4) * 8;
    const int a_c = ((lane >> 3) & 1) * 8;
    const int b_r = (lane & 7) + ((lane >> 3) & 1) * 8;
    const int b_c = (lane >> 4) * 8;

    const int ar0 = tid >> 4,        ac0 = (tid & 15) * 8;
    const int ar1 = (tid + 256) >> 4, ac1 = ((tid + 256) & 15) * 8;
    auto load_stage = [&](int stage, int n0) {
        uint32_t sb = smbase + stage * KK_STAGE * 2;
        uint32_t sA1 = sb, sA2 = sb + KK_A_TILE * 2;
        uint32_t sY1 = sb + 2 * KK_A_TILE * 2, sY2 = sY1 + KK_Y_TILE * 2;
        cpa16(sA1 + (ar0 * 136 + ac0) * 2, a1 + (size_t)(n0 + ar0) * RM + ac0);
        cpa16(sA1 + (ar1 * 136 + ac1) * 2, a1 + (size_t)(n0 + ar1) * RM + ac1);
        cpa16(sA2 + (ar0 * 136 + ac0) * 2, a2 + (size_t)(n0 + ar0) * RM + ac0);
        cpa16(sA2 + (ar1 * 136 + ac1) * 2, a2 + (size_t)(n0 + ar1) * RM + ac1);
#pragma unroll
        for (int l = 0; l < 2; l++) {
            int f = tid + l * 256;
            int which = f >> 8;
            int r = (f & 255) >> 3;
            int c = (f & 7) * 8;
            const __nv_bfloat16* bs = which ? b2 : b1;
            uint32_t yd = which ? sY2 : sY1;
            cpa16(yd + (r * 72 + c) * 2, bs + (size_t)(n0 + r) * bstr + c);
        }
    };

    load_stage(0, 0);
    CP_COMMIT();

    for (int chunk = 0; chunk < NCHUNK / 32; chunk++) {
        if (chunk + 1 < NCHUNK / 32) load_stage((chunk + 1) & 1, (chunk + 1) * 32);
        CP_COMMIT();
        CP_WAIT1();
        __syncthreads();

        uint32_t sb = smbase + (chunk & 1) * KK_STAGE * 2;
        uint32_t as1 = sb, as2 = sb + KK_A_TILE * 2;
        uint32_t ys1 = sb + 2 * KK_A_TILE * 2, ys2 = ys1 + KK_Y_TILE * 2;
#pragma unroll
        for (int ks = 0; ks < 2; ks++) {
            uint32_t A1f[2][4], A2f[2][4], B1f[4][2], B2f[4][2];
#pragma unroll
            for (int mt = 0; mt < 2; mt++) {
                uint32_t off = ((ks * 16 + a_r) * 136 + wm * 32 + mt * 16 + a_c) * 2;
                ldmx4t(A1f[mt], as1 + off);
                ldmx4t(A2f[mt], as2 + off);
            }
#pragma unroll
            for (int nb = 0; nb < 2; nb++) {
                uint32_t off = ((ks * 16 + b_r) * 72 + wn * 32 + nb * 16 + b_c) * 2;
                uint32_t t1[4], t2[4];
                ldmx4t(t1, ys1 + off);
                ldmx4t(t2, ys2 + off);
                B1f[nb * 2][0] = t1[0]; B1f[nb * 2][1] = t1[1];
                B1f[nb * 2 + 1][0] = t1[2]; B1f[nb * 2 + 1][1] = t1[3];
                B2f[nb * 2][0] = t2[0]; B2f[nb * 2][1] = t2[1];
                B2f[nb * 2 + 1][0] = t2[2]; B2f[nb * 2 + 1][1] = t2[3];
            }
#pragma unroll
            for (int mt = 0; mt < 2; mt++)
#pragma unroll
                for (int nt = 0; nt < 4; nt++) {
                    mma16816(acc[mt][nt], A1f[mt], B1f[nt]);
                    mma16816(acc[mt][nt], A1f[mt], B2f[nt]);
                    mma16816(acc[mt][nt], A2f[mt], B1f[nt]);
                }
        }
        __syncthreads();
    }

    float* dst = g_PART + ((size_t)split * BH + bh) * (RM * (RM + HD));
#pragma unroll
    for (int mt = 0; mt < 2; mt++)
#pragma unroll
        for (int nt = 0; nt < 4; nt++)
#pragma unroll
            for (int half = 0; half < 2; half++) {
                int m = wm * 32 + mt * 16 + (lane >> 2) + half * 8;
                int j = ct * 64 + wn * 32 + nt * 8 + (lane & 3) * 2;
                *(float2*)&dst[m * (RM + HD) + j] =
                    make_float2(acc[mt][nt][half * 2], acc[mt][nt][half * 2 + 1]);
            }
}

// ---------------- reduce + d from kk diag + scale + L ----------------------------
__global__ __launch_bounds__(256)
void reduce_kernel()
{
    extern __shared__ float kks[];
    __shared__ float dsh[RM];
    __shared__ float rowsum[RM];
    int bh = blockIdx.x;
    if (threadIdx.x < RM) {
        float s = 0.f;
#pragma unroll
        for (int sp = 0; sp < SPLITS; sp++)
            s += g_PART[((size_t)sp * BH + bh) * (RM * (RM + HD))
                        + threadIdx.x * (RM + HD) + threadIdx.x];
        float d = 1.0f / fmaxf(sqrtf(s), 1e-12f);
        dsh[threadIdx.x] = d;
        g_D[bh * RM + threadIdx.x] = d;
    }
    __syncthreads();
    for (int idx = threadIdx.x; idx < RM * (RM + HD); idx += 256) {
        int m = idx / (RM + HD);
        int j = idx - m * (RM + HD);
        float s = 0.f;
#pragma unroll
        for (int sp = 0; sp < SPLITS; sp++)
            s += g_PART[((size_t)sp * BH + bh) * (RM * (RM + HD)) + idx];
        if (j < RM) {
            float v = s * dsh[m] * dsh[j];
            kks[m * RM + j] = v;
            g_KK[((size_t)bh * RM + m) * RM + j] = v;
        } else {
            g_KV[((size_t)bh * RM + m) * HD + (j - RM)] = s * dsh[m];
        }
    }
    __syncthreads();
    if (threadIdx.x < RM) {
        float rs = 0.f;
        for (int j = 0; j < RM; j++) rs += fabsf(kks[threadIdx.x * RM + j]);
        rowsum[threadIdx.x] = rs;
    }
    __syncthreads();
    if (threadIdx.x == 0) {
        float mx = 0.f;
        for (int i = 0; i < RM; i++) mx = fmaxf(mx, rowsum[i]);
        g_Lc[bh] = mx + 1.0f;
    }
}

// ---------------- ISTA (emits (d*s)^T bf16 split) --------------------------------
__device__ __forceinline__ float softf(float z, float t)
{
    float a = fabsf(z) - t;
    return a > 0.f ? (z >= 0.f ? a : -a) : 0.f;
}

__global__ __launch_bounds__(256)
void ista_kernel()
{
    extern __shared__ float sm[];
    float* kks = sm;
    float* kvs = sm + RM * 129;
    float* ss  = kvs + RM * HD;
    int bh = blockIdx.x;
    float L    = g_Lc[bh];
    float invL = 1.0f / L;
    float thr  = LAMBDA * invL;

    for (int idx = threadIdx.x; idx < RM * RM; idx += 256) {
        int m = idx >> 7, j = idx & 127;
        kks[m * 129 + j] = g_KK[(size_t)bh * RM * RM + idx];
    }
    for (int idx = threadIdx.x; idx < RM * HD; idx += 256)
        kvs[idx] = g_KV[(size_t)bh * RM * HD + idx];
    __syncthreads();

    int m  = threadIdx.x >> 1;
    int ch = (threadIdx.x & 1) * 32;
#pragma unroll
    for (int i = 0; i < 32; i++)
        ss[m * 68 + ch + i] = softf(kvs[m * HD + ch + i], LAMBDA);
    __syncthreads();

    for (int it = 0; it < NSTEP; it++) {
        float acc[32];
#pragma unroll
        for (int i = 0; i < 32; i++) acc[i] = 0.f;
        for (int p = 0; p < RM; p++) {
            float kv_ = kks[m * 129 + p];
            const float4* sp = (const float4*)&ss[p * 68 + ch];
#pragma unroll
            for (int q = 0; q < 8; q++) {
                float4 v = sp[q];
                acc[q * 4 + 0] += kv_ * v.x;
                acc[q * 4 + 1] += kv_ * v.y;
                acc[q * 4 + 2] += kv_ * v.z;
                acc[q * 4 + 3] += kv_ * v.w;
            }
        }
        float r[32];
#pragma unroll
        for (int i = 0; i < 32; i++) {
            float z = ss[m * 68 + ch + i] - (acc[i] - kvs[m * HD + ch + i]) * invL;
            r[i] = softf(z, thr);
        }
        __syncthreads();
#pragma unroll
        for (int q = 0; q < 8; q++)
            *(float4*)&ss[m * 68 + ch + q * 4] =
                make_float4(r[q * 4], r[q * 4 + 1], r[q * 4 + 2], r[q * 4 + 3]);
        __syncthreads();
    }
    float dm = g_D[bh * RM + m];
#pragma unroll
    for (int q = 0; q < 8; q++) {
        float4 v = *(float4*)&ss[m * 68 + ch + q * 4];
        v.x *= dm; v.y *= dm; v.z *= dm; v.w *= dm;
        *(float4*)&ss[m * 68 + ch + q * 4] = v;
    }
    __syncthreads();
    int d  = threadIdx.x >> 2;
    int ms = (threadIdx.x & 3) * 32;
    size_t ob = ((size_t)bh * HD + d) * RM + ms;
#pragma unroll
    for (int i = 0; i < 32; i += 2) {
        float v0 = ss[(ms + i) * 68 + d];
        float v1 = ss[(ms + i + 1) * 68 + d];
        __nv_bfloat16 h0, l0, h1, l1;
        split2(v0, h0, l0); split2(v1, h1, l1);
        *(__nv_bfloat162*)&g_ST1[ob + i] = __halves2bfloat162(h0, h1);
        *(__nv_bfloat162*)&g_ST2[ob + i] = __halves2bfloat162(l0, l1);
    }
}

// ---------------- out = rf @ sT^T via HMMA, emits OC bf16 pair --------------------
__global__ __launch_bounds__(256, 2)
void outgemm_hmma()
{
    __shared__ __nv_bfloat16 As1[128 * PITCH], As2[128 * PITCH];
    __shared__ __nv_bfloat16 Bs1[64 * PITCH],  Bs2[64 * PITCH];
    const int tid = threadIdx.x, wid = tid >> 5, lane = tid & 31;
    const int wm = wid & 3, wn = wid >> 2;
    const int bh = blockIdx.y, nblk = blockIdx.x;
    const int b = bh / NH, h = bh % NH;

    size_t rfbase = ((size_t)bh * SEQ + (size_t)nblk * 128) * RM;
    size_t stbase = (size_t)bh * HD * RM;

    float acc[2][4][4];
#pragma unroll
    for (int i = 0; i < 2; i++)
#pragma unroll
        for (int j = 0; j < 4; j++)
#pragma unroll
            for (int q = 0; q < 4; q++) acc[i][j][q] = 0.f;

    const uint32_t as1 = smem_u32(As1), as2 = smem_u32(As2);
    const uint32_t bs1 = smem_u32(Bs1), bs2 = smem_u32(Bs2);
    const int arow = wm * 32 + (lane & 15);
    const int acolL = (lane >> 4) * 8;
    const int bn   = wn * 32 + (lane & 7) + ((lane >> 4) & 1) * 8;
    const int bkL  = ((lane >> 3) & 1) * 8;

    for (int kc = 0; kc < 4; kc++) {
        const int k0 = kc * 32;
#pragma unroll
        for (int l = 0; l < 2; l++) {
            int f = tid + l * 256;
            int r = f >> 2, c = (f & 3) * 8;
            *(uint4*)(As1 + r * PITCH + c) =
                *(const uint4*)(g_RF1 + rfbase + (size_t)r * RM + k0 + c);
            *(uint4*)(As2 + r * PITCH + c) =
                *(const uint4*)(g_RF2 + rfbase + (size_t)r * RM + k0 + c);
        }
        {
            int r = tid >> 2, c = (tid & 3) * 8;
            if (r < 64) {
                *(uint4*)(Bs1 + r * PITCH + c) =
                    *(const uint4*)(g_ST1 + stbase + (size_t)r * RM + k0 + c);
                *(uint4*)(Bs2 + r * PITCH + c) =
                    *(const uint4*)(g_ST2 + stbase + (size_t)r * RM + k0 + c);
            }
        }
        __syncthreads();
#pragma unroll
        for (int ks = 0; ks < 2; ks++) {
            const int acol = ks * 16 + acolL;
            const int bk   = ks * 16 + bkL;
            uint32_t a1[2][4], a2[2][4], b1[4][2], b2[4][2];
#pragma unroll
            for (int mt = 0; mt < 2; mt++) {
                uint32_t off = ((arow + mt * 16) * PITCH + acol) * 2;
                ldmx4(a1[mt][0], a1[mt][1], a1[mt][2], a1[mt][3], as1 + off);
                ldmx4(a2[mt][0], a2[mt][1], a2[mt][2], a2[mt][3], as2 + off);
            }
#pragma unroll
            for (int nt2 = 0; nt2 < 2; nt2++) {
                uint32_t off = ((bn + nt2 * 16) * PITCH + bk) * 2;
                ldmx4(b1[nt2 * 2][0], b1[nt2 * 2][1],
                      b1[nt2 * 2 + 1][0], b1[nt2 * 2 + 1][1], bs1 + off);
                ldmx4(b2[nt2 * 2][0], b2[nt2 * 2][1],
                      b2[nt2 * 2 + 1][0], b2[nt2 * 2 + 1][1], bs2 + off);
            }
#pragma unroll
            for (int mt = 0; mt < 2; mt++)
#pragma unroll
                for (int nt = 0; nt < 4; nt++) {
                    mma16816(acc[mt][nt], a1[mt], b1[nt]);
                    mma16816(acc[mt][nt], a1[mt], b2[nt]);
                    mma16816(acc[mt][nt], a2[mt], b1[nt]);
                }
        }
        __syncthreads();
    }

    const int g  = lane >> 2;
    const int tg = lane & 3;
#pragma unroll
    for (int mt = 0; mt < 2; mt++)
#pragma unroll
        for (int nt = 0; nt < 4; nt++)
#pragma unroll
            for (int half = 0; half < 2; half++) {
                int nrow = nblk * 128 + wm * 32 + mt * 16 + g + half * 8;
                int d    = wn * 32 + nt * 8 + tg * 2;
                float2 v = make_float2(acc[mt][nt][half * 2],
                                       acc[mt][nt][half * 2 + 1]);
                size_t adr = ((size_t)b * SEQ + nrow) * CH + h * HD + d;
                __nv_bfloat16 h0, l0, h1, l1;
                split2(v.x, h0, l0); split2(v.y, h1, l1);
                *(__nv_bfloat162*)&g_OC1[adr] = __halves2bfloat162(h0, h1);
                *(__nv_bfloat162*)&g_OC2[adr] = __halves2bfloat162(l0, l1);
            }
}

// ---------------- launch -----------------------------------------------------------
extern "C" void kernel_launch(void* const* d_in, const int* in_sizes, int n_in,
                              void* d_out, int out_size)
{
    const float *x = nullptr, *wqkv = nullptr, *wproj = nullptr,
                *bias = nullptr, *rm = nullptr;
    for (int i = 0; i < n_in; i++) {
        const float* p = (const float*)d_in[i];
        switch (in_sizes[i]) {
            case BATCH * SEQ * CH: x = p; break;
            case CH * 2 * CH:      wqkv = p; break;
            case CH * CH:          wproj = p; break;
            case CH:               bias = p; break;
            case NH * HD * RM:     rm = p; break;
        }
    }
    float* out = (float*)d_out;
    (void)out_size;

    cudaFuncSetAttribute(hmma_gemm<0>, cudaFuncAttributeMaxDynamicSharedMemorySize, DG_SMEM);
    cudaFuncSetAttribute(hmma_gemm<1>, cudaFuncAttributeMaxDynamicSharedMemorySize, DG_SMEM);
    cudaFuncSetAttribute(rf_hmma, cudaFuncAttributeMaxDynamicSharedMemorySize, RF_SMEM);
    cudaFuncSetAttribute(kkkv_hmma, cudaFuncAttributeMaxDynamicSharedMemorySize, KK_SMEM);
    cudaFuncSetAttribute(reduce_kernel, cudaFuncAttributeMaxDynamicSharedMemorySize, RM * RM * 4);
    cudaFuncSetAttribute(ista_kernel, cudaFuncAttributeMaxDynamicSharedMemorySize,
                         (RM * 129 + RM * HD + RM * 68) * 4);

    // conversions to bf16 split pairs
    conv_x_kernel<<<BATCH * SEQ * CH / 1024, 256>>>(x);
    conv_w_kernel<0><<<2 * CH * CH / 256, 256>>>(wqkv, 2 * CH);
    conv_w_kernel<1><<<CH * CH / 256, 256>>>(wproj, CH);
    conv_rt_kernel<<<NH * RM * HD / 256, 256>>>(rm);

    // 1. qkv = x @ Wqkv (HMMA) -> q bf16 pair, v bf16 pair
    hmma_gemm<0><<<dim3(12, 256), 256, DG_SMEM>>>(nullptr, nullptr, CH);
    // 2. random feature map via HMMA -> rf bf16 pair
    rf_hmma<<<dim3(32, BH), 256, RF_SMEM>>>();
    // 3. kk/kv partials (HMMA, cp.async pipelined)
    kkkv_hmma<<<dim3(3, BH, SPLITS), 256, KK_SMEM>>>();
    // 4. combine partials + d from diag + L
    reduce_kernel<<<BH, 256, RM * RM * 4>>>();
    // 5. ISTA -> (d*s)^T bf16 pair
    ista_kernel<<<BH, 256, (RM * 129 + RM * HD + RM * 68) * 4>>>();
    // 6. out_head = rf @ s (HMMA) -> OC bf16 pair
    outgemm_hmma<<<dim3(32, BH), 256>>>();
    // 7. final projection + bias (HMMA, cp.async pipelined)
    hmma_gemm<1><<<dim3(6, 256), 256, DG_SMEM>>>(bias, out, CH);
}

// round 9
// speedup vs baseline: 3.2953x; 1.0222x over previous
#include <cuda_runtime.h>
#include <cuda_bf16.h>
#include <math.h>
#include <cstdint>

// Problem constants
#define BATCH 8
#define SEQ   4096
#define CH    768
#define NH    12
#define HD    64
#define RM    128
#define BH    (BATCH*NH)
#define LAMBDA 0.3f
#define NSTEP 5
#define SPLITS 4
#define NCHUNK (SEQ/SPLITS)    // 1024

// ---------------- scratch ----------------------------------------------------
__device__ float g_PART[(size_t)SPLITS*BH*RM*(RM+HD)];
// bf16 split pairs
__device__ __nv_bfloat16 g_XA1[(size_t)BATCH*SEQ*CH];
__device__ __nv_bfloat16 g_XA2[(size_t)BATCH*SEQ*CH];
__device__ __nv_bfloat16 g_WQ1[(size_t)2*CH*CH];
__device__ __nv_bfloat16 g_WQ2[(size_t)2*CH*CH];
__device__ __nv_bfloat16 g_WP1[(size_t)CH*CH];
__device__ __nv_bfloat16 g_WP2[(size_t)CH*CH];
__device__ __nv_bfloat16 g_OC1[(size_t)BATCH*SEQ*CH];
__device__ __nv_bfloat16 g_OC2[(size_t)BATCH*SEQ*CH];
__device__ __nv_bfloat16 g_QB1[(size_t)BH*SEQ*HD];   // qs hi  [bh][n][d]
__device__ __nv_bfloat16 g_QB2[(size_t)BH*SEQ*HD];   // qs lo
__device__ __nv_bfloat16 g_RT1[(size_t)NH*RM*HD];    // R^T hi [h][m][d]
__device__ __nv_bfloat16 g_RT2[(size_t)NH*RM*HD];    // lo
__device__ __nv_bfloat16 g_RF1[(size_t)BH*SEQ*RM];   // rf hi  [bh][n][m]
__device__ __nv_bfloat16 g_RF2[(size_t)BH*SEQ*RM];   // rf lo
__device__ __nv_bfloat16 g_VB1[(size_t)BH*SEQ*HD];   // v hi   [bh][n][d]
__device__ __nv_bfloat16 g_VB2[(size_t)BH*SEQ*HD];   // v lo
__device__ __nv_bfloat16 g_ST1[(size_t)BH*HD*RM];    // (d*s)^T hi [bh][d][m]
__device__ __nv_bfloat16 g_ST2[(size_t)BH*HD*RM];    // lo

// ---------------- warp-MMA / cp.async helpers ----------------------------------
__device__ __forceinline__ uint32_t smem_u32(const void* p) {
    uint32_t a;
    asm("{ .reg .u64 t; cvta.to.shared.u64 t, %1; cvt.u32.u64 %0, t; }"
        : "=r"(a) : "l"(p));
    return a;
}
__device__ __forceinline__ void ldmx4(uint32_t& r0, uint32_t& r1,
                                      uint32_t& r2, uint32_t& r3, uint32_t addr)
{
    asm volatile("ldmatrix.sync.aligned.m8n8.x4.shared.b16 {%0,%1,%2,%3}, [%4];"
                 : "=r"(r0), "=r"(r1), "=r"(r2), "=r"(r3) : "r"(addr));
}
__device__ __forceinline__ void ldmx4t(uint32_t* r, uint32_t addr)
{
    asm volatile("ldmatrix.sync.aligned.m8n8.x4.trans.shared.b16 {%0,%1,%2,%3}, [%4];"
                 : "=r"(r[0]), "=r"(r[1]), "=r"(r[2]), "=r"(r[3]) : "r"(addr));
}
__device__ __forceinline__ void mma16816(float* c, const uint32_t* a,
                                         const uint32_t* b)
{
    asm volatile(
        "mma.sync.aligned.m16n8k16.row.col.f32.bf16.bf16.f32 "
        "{%0,%1,%2,%3}, {%4,%5,%6,%7}, {%8,%9}, {%0,%1,%2,%3};"
        : "+f"(c[0]), "+f"(c[1]), "+f"(c[2]), "+f"(c[3])
        : "r"(a[0]), "r"(a[1]), "r"(a[2]), "r"(a[3]), "r"(b[0]), "r"(b[1]));
}
__device__ __forceinline__ void split2(float v, __nv_bfloat16& h, __nv_bfloat16& l)
{
    h = __float2bfloat16(v);
    l = __float2bfloat16(v - __bfloat162float(h));
}
__device__ __forceinline__ void cpa16(uint32_t saddr, const void* g)
{
    asm volatile("cp.async.cg.shared.global [%0], [%1], 16;"
                 :: "r"(saddr), "l"(g));
}
#define CP_COMMIT() asm volatile("cp.async.commit_group;")
#define CP_WAIT1()  asm volatile("cp.async.wait_group 1;")

#define PITCH 40               // smem pitch (bf16) for dense gemm tiles
#define DG_TILE (128*PITCH)
#define DG_STAGE (4*DG_TILE)
#define DG_SMEM (2*DG_STAGE*2) // 81920 bytes

// ---------------- HMMA GEMM: 128x128 tile, 3-term bf16 split --------------------
// 2-stage cp.async pipeline; wait BEFORE barrier (cross-thread visibility)
template<int EPI>
__global__ __launch_bounds__(256, 2)
void hmma_gemm(const float* __restrict__ bias, float* __restrict__ Cout, int Kdim)
{
    extern __shared__ __nv_bfloat16 dsm[];

    const int tid  = threadIdx.x;
    const int wid  = tid >> 5;
    const int lane = tid & 31;
    const int wm   = wid & 1;
    const int wn   = wid >> 1;
    const int brow = blockIdx.y * 128;
    const int bcol = blockIdx.x * 128;

    const __nv_bfloat16* A1 = (EPI == 0) ? g_XA1 : g_OC1;
    const __nv_bfloat16* A2 = (EPI == 0) ? g_XA2 : g_OC2;
    const __nv_bfloat16* B1 = (EPI == 0) ? g_WQ1 : g_WP1;
    const __nv_bfloat16* B2 = (EPI == 0) ? g_WQ2 : g_WP2;

    float acc[4][4][4];
#pragma unroll
    for (int i = 0; i < 4; i++)
#pragma unroll
        for (int j = 0; j < 4; j++)
#pragma unroll
            for (int q = 0; q < 4; q++) acc[i][j][q] = 0.f;

    const uint32_t smbase = smem_u32(dsm);
    const int arow = wm * 64 + (lane & 15);
    const int acolL = (lane >> 4) * 8;
    const int bn   = wn * 32 + (lane & 7) + ((lane >> 4) & 1) * 8;
    const int bkL  = ((lane >> 3) & 1) * 8;

    const int l_row0 = tid >> 2,        l_ch0 = (tid & 3) * 8;
    const int l_row1 = (tid + 256) >> 2, l_ch1 = ((tid + 256) & 3) * 8;

    auto load_stage = [&](int stage, int k0) {
        uint32_t sb = smbase + stage * DG_STAGE * 2;
#pragma unroll
        for (int t = 0; t < 4; t++) {
            const __nv_bfloat16* src = (t == 0) ? A1 : (t == 1) ? A2 : (t == 2) ? B1 : B2;
            const int rbase = (t < 2) ? brow : bcol;
            uint32_t tb = sb + t * DG_TILE * 2;
            cpa16(tb + (l_row0 * PITCH + l_ch0) * 2,
                  src + (size_t)(rbase + l_row0) * Kdim + k0 + l_ch0);
            cpa16(tb + (l_row1 * PITCH + l_ch1) * 2,
                  src + (size_t)(rbase + l_row1) * Kdim + k0 + l_ch1);
        }
    };

    const int nchunk = Kdim >> 5;
    load_stage(0, 0);
    CP_COMMIT();

    for (int kc = 0; kc < nchunk; kc++) {
        if (kc + 1 < nchunk) load_stage((kc + 1) & 1, (kc + 1) << 5);
        CP_COMMIT();
        CP_WAIT1();          // own stage-kc copies done
        __syncthreads();     // all threads' copies visible to all

        const uint32_t sb = smbase + (kc & 1) * DG_STAGE * 2;
        const uint32_t as1 = sb, as2 = sb + DG_TILE * 2;
        const uint32_t bs1 = sb + 2 * DG_TILE * 2, bs2 = sb + 3 * DG_TILE * 2;
#pragma unroll
        for (int ks = 0; ks < 2; ks++) {
            const int acol = ks * 16 + acolL;
            const int bk   = ks * 16 + bkL;
            uint32_t a1[4][4], a2[4][4], b1[4][2], b2[4][2];
#pragma unroll
            for (int mt = 0; mt < 4; mt++) {
                uint32_t off = ((arow + mt * 16) * PITCH + acol) * 2;
                ldmx4(a1[mt][0], a1[mt][1], a1[mt][2], a1[mt][3], as1 + off);
                ldmx4(a2[mt][0], a2[mt][1], a2[mt][2], a2[mt][3], as2 + off);
            }
#pragma unroll
            for (int nt2 = 0; nt2 < 2; nt2++) {
                uint32_t off = ((bn + nt2 * 16) * PITCH + bk) * 2;
                ldmx4(b1[nt2 * 2][0], b1[nt2 * 2][1],
                      b1[nt2 * 2 + 1][0], b1[nt2 * 2 + 1][1], bs1 + off);
                ldmx4(b2[nt2 * 2][0], b2[nt2 * 2][1],
                      b2[nt2 * 2 + 1][0], b2[nt2 * 2 + 1][1], bs2 + off);
            }
#pragma unroll
            for (int mt = 0; mt < 4; mt++)
#pragma unroll
                for (int nt = 0; nt < 4; nt++) {
                    mma16816(acc[mt][nt], a1[mt], b1[nt]);
                    mma16816(acc[mt][nt], a1[mt], b2[nt]);
                    mma16816(acc[mt][nt], a2[mt], b1[nt]);
                }
        }
        __syncthreads();     // all reads of stage kc done before it is overwritten
    }

    const int g  = lane >> 2;
    const int tg = lane & 3;
#pragma unroll
    for (int mt = 0; mt < 4; mt++)
#pragma unroll
        for (int nt = 0; nt < 4; nt++) {
#pragma unroll
            for (int half = 0; half < 2; half++) {
                int grow = brow + wm * 64 + mt * 16 + g + half * 8;
                int col  = bcol + wn * 32 + nt * 8 + tg * 2;
                float2 v = make_float2(acc[mt][nt][half * 2],
                                       acc[mt][nt][half * 2 + 1]);
                if (EPI == 0) {
                    int bb = grow >> 12, nn = grow & 4095;
                    __nv_bfloat16 h0, l0, h1, l1;
                    if (col < CH) {
                        const float s = 0.35355339059327373f;  // hd^(-1/4)
                        v.x *= s; v.y *= s;
                        int h = col >> 6, dd = col & 63;
                        size_t adr = (((size_t)(bb * NH + h)) * SEQ + nn) * HD + dd;
                        split2(v.x, h0, l0); split2(v.y, h1, l1);
                        *(__nv_bfloat162*)&g_QB1[adr] = __halves2bfloat162(h0, h1);
                        *(__nv_bfloat162*)&g_QB2[adr] = __halves2bfloat162(l0, l1);
                    } else {
                        int c2 = col - CH;
                        int h = c2 >> 6, dd = c2 & 63;
                        size_t adr = (((size_t)(bb * NH + h)) * SEQ + nn) * HD + dd;
                        split2(v.x, h0, l0); split2(v.y, h1, l1);
                        *(__nv_bfloat162*)&g_VB1[adr] = __halves2bfloat162(h0, h1);
                        *(__nv_bfloat162*)&g_VB2[adr] = __halves2bfloat162(l0, l1);
                    }
                } else {
                    v.x += bias[col];
                    v.y += bias[col + 1];
                    *(float2*)&Cout[(size_t)grow * CH + col] = v;
                }
            }
        }
}

// ---------------- conversion kernels -----------------------------------------
__global__ __launch_bounds__(256)
void conv_x_kernel(const float* __restrict__ x)
{
    size_t i = ((size_t)blockIdx.x * 256 + threadIdx.x) * 4;
    float4 v = *(const float4*)&x[i];
    __nv_bfloat16 h0, l0, h1, l1, h2, l2, h3, l3;
    split2(v.x, h0, l0); split2(v.y, h1, l1);
    split2(v.z, h2, l2); split2(v.w, h3, l3);
    *(__nv_bfloat162*)&g_XA1[i]     = __halves2bfloat162(h0, h1);
    *(__nv_bfloat162*)&g_XA1[i + 2] = __halves2bfloat162(h2, h3);
    *(__nv_bfloat162*)&g_XA2[i]     = __halves2bfloat162(l0, l1);
    *(__nv_bfloat162*)&g_XA2[i + 2] = __halves2bfloat162(l2, l3);
}

template<int WHICH>
__global__ __launch_bounds__(256)
void conv_w_kernel(const float* __restrict__ W, int N)
{
    __nv_bfloat16* o1 = (WHICH == 0) ? g_WQ1 : g_WP1;
    __nv_bfloat16* o2 = (WHICH == 0) ? g_WQ2 : g_WP2;
    int idx = blockIdx.x * 256 + threadIdx.x;
    int n = idx / CH, k = idx - n * CH;
    float v = W[(size_t)k * N + n];
    __nv_bfloat16 h, l;
    split2(v, h, l);
    o1[idx] = h;
    o2[idx] = l;
}

// R [h][d][m] -> R^T pair [h][m][d]
__global__ __launch_bounds__(256)
void conv_rt_kernel(const float* __restrict__ randm)
{
    int idx = blockIdx.x * 256 + threadIdx.x;
    int h = idx / (RM * HD);
    int r = idx - h * (RM * HD);
    int m = r / HD, d = r - m * HD;
    float v = randm[((size_t)h * HD + d) * RM + m];
    __nv_bfloat16 hi, lo;
    split2(v, hi, lo);
    g_RT1[idx] = hi;
    g_RT2[idx] = lo;
}

// ---------------- rf via HMMA: rf = exp(q@R^T - 0.5||q||^2)/sqrt(M) -------------
#define RF_PITCH 72
#define RF_TILE (128*RF_PITCH)
#define RF_SMEM (4*RF_TILE*2)

__global__ __launch_bounds__(256, 2)
void rf_hmma()
{
    extern __shared__ __nv_bfloat16 rsm[];
    __shared__ float rowq2[128];
    const int tid = threadIdx.x, wid = tid >> 5, lane = tid & 31;
    const int wm = wid & 1, wn = wid >> 1;
    const int bh = blockIdx.y, h = bh % NH;
    const int brow = blockIdx.x * 128;

    const __nv_bfloat16* A1 = g_QB1 + ((size_t)bh * SEQ + brow) * HD;
    const __nv_bfloat16* A2 = g_QB2 + ((size_t)bh * SEQ + brow) * HD;
    const __nv_bfloat16* B1 = g_RT1 + (size_t)h * RM * HD;
    const __nv_bfloat16* B2 = g_RT2 + (size_t)h * RM * HD;

#pragma unroll
    for (int t = 0; t < 4; t++) {
        const __nv_bfloat16* src = (t == 0) ? A1 : (t == 1) ? A2 : (t == 2) ? B1 : B2;
        __nv_bfloat16* dst = rsm + t * RF_TILE;
#pragma unroll
        for (int u = 0; u < 4; u++) {
            int f = u * 256 + tid;
            int r = f >> 3, c = (f & 7) * 8;
            *(uint4*)(dst + r * RF_PITCH + c) = *(const uint4*)(src + (size_t)r * HD + c);
        }
    }
    __syncthreads();

    {
        int r = tid >> 1;
        int k0 = (tid & 1) * 32;
        const __nv_bfloat16* q1 = rsm + r * RF_PITCH + k0;
        const __nv_bfloat16* q2 = rsm + RF_TILE + r * RF_PITCH + k0;
        float s = 0.f;
#pragma unroll
        for (int k = 0; k < 32; k++) {
            float v = __bfloat162float(q1[k]) + __bfloat162float(q2[k]);
            s += v * v;
        }
        s += __shfl_xor_sync(0xffffffffu, s, 1);
        if (!(tid & 1)) rowq2[r] = s;
    }

    float acc[4][4][4];
#pragma unroll
    for (int i = 0; i < 4; i++)
#pragma unroll
        for (int j = 0; j < 4; j++)
#pragma unroll
            for (int q = 0; q < 4; q++) acc[i][j][q] = 0.f;

    const uint32_t smbase = smem_u32(rsm);
    const uint32_t as1 = smbase, as2 = smbase + RF_TILE * 2;
    const uint32_t bs1 = smbase + 2 * RF_TILE * 2, bs2 = smbase + 3 * RF_TILE * 2;
    const int arow = wm * 64 + (lane & 15);
    const int acolL = (lane >> 4) * 8;
    const int bn   = wn * 32 + (lane & 7) + ((lane >> 4) & 1) * 8;
    const int bkL  = ((lane >> 3) & 1) * 8;

#pragma unroll
    for (int ks = 0; ks < 4; ks++) {
        const int acol = ks * 16 + acolL;
        const int bk   = ks * 16 + bkL;
        uint32_t a1[4][4], a2[4][4], b1[4][2], b2[4][2];
#pragma unroll
        for (int mt = 0; mt < 4; mt++) {
            uint32_t off = ((arow + mt * 16) * RF_PITCH + acol) * 2;
            ldmx4(a1[mt][0], a1[mt][1], a1[mt][2], a1[mt][3], as1 + off);
            ldmx4(a2[mt][0], a2[mt][1], a2[mt][2], a2[mt][3], as2 + off);
        }
#pragma unroll
        for (int nt2 = 0; nt2 < 2; nt2++) {
            uint32_t off = ((bn + nt2 * 16) * RF_PITCH + bk) * 2;
            ldmx4(b1[nt2 * 2][0], b1[nt2 * 2][1],
                  b1[nt2 * 2 + 1][0], b1[nt2 * 2 + 1][1], bs1 + off);
            ldmx4(b2[nt2 * 2][0], b2[nt2 * 2][1],
                  b2[nt2 * 2 + 1][0], b2[nt2 * 2 + 1][1], bs2 + off);
        }
#pragma unroll
        for (int mt = 0; mt < 4; mt++)
#pragma unroll
            for (int nt = 0; nt < 4; nt++) {
                mma16816(acc[mt][nt], a1[mt], b1[nt]);
                mma16816(acc[mt][nt], a1[mt], b2[nt]);
                mma16816(acc[mt][nt], a2[mt], b1[nt]);
            }
    }
    __syncthreads();

    const int g  = lane >> 2;
    const int tg = lane & 3;
    const float sc = 0.08838834764831845f;  // 1/sqrt(128)
#pragma unroll
    for (int mt = 0; mt < 4; mt++)
#pragma unroll
        for (int nt = 0; nt < 4; nt++)
#pragma unroll
            for (int half = 0; half < 2; half++) {
                int row  = wm * 64 + mt * 16 + g + half * 8;
                int mcol = wn * 32 + nt * 8 + tg * 2;
                float base = -0.5f * rowq2[row];
                float v0 = expf(acc[mt][nt][half * 2]     + base) * sc;
                float v1 = expf(acc[mt][nt][half * 2 + 1] + base) * sc;
                __nv_bfloat16 h0, l0, h1, l1;
                split2(v0, h0, l0); split2(v1, h1, l1);
                size_t adr = ((size_t)bh * SEQ + brow + row) * RM + mcol;
                *(__nv_bfloat162*)&g_RF1[adr] = __halves2bfloat162(h0, h1);
                *(__nv_bfloat162*)&g_RF2[adr] = __halves2bfloat162(l0, l1);
            }
}

// ---------------- kk/kv via HMMA, trans-ldmatrix, 2-stage cp.async --------------
#define KK_A_TILE (32*136)
#define KK_Y_TILE (32*72)
#define KK_STAGE (2*KK_A_TILE + 2*KK_Y_TILE)
#define KK_SMEM (2*KK_STAGE*2)

__global__ __launch_bounds__(256, 2)
void kkkv_hmma()
{
    extern __shared__ __nv_bfloat16 ksm[];
    const int tid = threadIdx.x, wid = tid >> 5, lane = tid & 31;
    const int ct = blockIdx.x, bh = blockIdx.y, split = blockIdx.z;
    const int wm = wid >> 1, wn = wid & 1;

    size_t abase = ((size_t)bh * SEQ + (size_t)split * NCHUNK) * RM;
    const __nv_bfloat16 *a1 = g_RF1 + abase, *a2 = g_RF2 + abase;
    const __nv_bfloat16 *b1, *b2;
    int bstr;
    if (ct == 2) {
        size_t vb = ((size_t)bh * SEQ + (size_t)split * NCHUNK) * HD;
        b1 = g_VB1 + vb; b2 = g_VB2 + vb; bstr = HD;
    } else {
        b1 = a1 + ct * 64; b2 = a2 + ct * 64; bstr = RM;
    }

    float acc[2][4][4];
#pragma unroll
    for (int i = 0; i < 2; i++)
#pragma unroll
        for (int j = 0; j < 4; j++)
#pragma unroll
            for (int q = 0; q < 4; q++) acc[i][j][q] = 0.f;

    const uint32_t smbase = smem_u32(ksm);
    const int a_r = (lane & 7) + (lane >> 4) * 8;
    const int a_c = ((lane >> 3) & 1) * 8;
    const int b_r = (lane & 7) + ((lane >> 3) & 1) * 8;
    const int b_c = (lane >> 4) * 8;

    const int ar0 = tid >> 4,        ac0 = (tid & 15) * 8;
    const int ar1 = (tid + 256) >> 4, ac1 = ((tid + 256) & 15) * 8;
    auto load_stage = [&](int stage, int n0) {
        uint32_t sb = smbase + stage * KK_STAGE * 2;
        uint32_t sA1 = sb, sA2 = sb + KK_A_TILE * 2;
        uint32_t sY1 = sb + 2 * KK_A_TILE * 2, sY2 = sY1 + KK_Y_TILE * 2;
        cpa16(sA1 + (ar0 * 136 + ac0) * 2, a1 + (size_t)(n0 + ar0) * RM + ac0);
        cpa16(sA1 + (ar1 * 136 + ac1) * 2, a1 + (size_t)(n0 + ar1) * RM + ac1);
        cpa16(sA2 + (ar0 * 136 + ac0) * 2, a2 + (size_t)(n0 + ar0) * RM + ac0);
        cpa16(sA2 + (ar1 * 136 + ac1) * 2, a2 + (size_t)(n0 + ar1) * RM + ac1);
#pragma unroll
        for (int l = 0; l < 2; l++) {
            int f = tid + l * 256;
            int which = f >> 8;
            int r = (f & 255) >> 3;
            int c = (f & 7) * 8;
            const __nv_bfloat16* bs = which ? b2 : b1;
            uint32_t yd = which ? sY2 : sY1;
            cpa16(yd + (r * 72 + c) * 2, bs + (size_t)(n0 + r) * bstr + c);
        }
    };

    load_stage(0, 0);
    CP_COMMIT();

    for (int chunk = 0; chunk < NCHUNK / 32; chunk++) {
        if (chunk + 1 < NCHUNK / 32) load_stage((chunk + 1) & 1, (chunk + 1) * 32);
        CP_COMMIT();
        CP_WAIT1();
        __syncthreads();

        uint32_t sb = smbase + (chunk & 1) * KK_STAGE * 2;
        uint32_t as1 = sb, as2 = sb + KK_A_TILE * 2;
        uint32_t ys1 = sb + 2 * KK_A_TILE * 2, ys2 = ys1 + KK_Y_TILE * 2;
#pragma unroll
        for (int ks = 0; ks < 2; ks++) {
            uint32_t A1f[2][4], A2f[2][4], B1f[4][2], B2f[4][2];
#pragma unroll
            for (int mt = 0; mt < 2; mt++) {
                uint32_t off = ((ks * 16 + a_r) * 136 + wm * 32 + mt * 16 + a_c) * 2;
                ldmx4t(A1f[mt], as1 + off);
                ldmx4t(A2f[mt], as2 + off);
            }
#pragma unroll
            for (int nb = 0; nb < 2; nb++) {
                uint32_t off = ((ks * 16 + b_r) * 72 + wn * 32 + nb * 16 + b_c) * 2;
                uint32_t t1[4], t2[4];
                ldmx4t(t1, ys1 + off);
                ldmx4t(t2, ys2 + off);
                B1f[nb * 2][0] = t1[0]; B1f[nb * 2][1] = t1[1];
                B1f[nb * 2 + 1][0] = t1[2]; B1f[nb * 2 + 1][1] = t1[3];
                B2f[nb * 2][0] = t2[0]; B2f[nb * 2][1] = t2[1];
                B2f[nb * 2 + 1][0] = t2[2]; B2f[nb * 2 + 1][1] = t2[3];
            }
#pragma unroll
            for (int mt = 0; mt < 2; mt++)
#pragma unroll
                for (int nt = 0; nt < 4; nt++) {
                    mma16816(acc[mt][nt], A1f[mt], B1f[nt]);
                    mma16816(acc[mt][nt], A1f[mt], B2f[nt]);
                    mma16816(acc[mt][nt], A2f[mt], B1f[nt]);
                }
        }
        __syncthreads();
    }

    float* dst = g_PART + ((size_t)split * BH + bh) * (RM * (RM + HD));
#pragma unroll
    for (int mt = 0; mt < 2; mt++)
#pragma unroll
        for (int nt = 0; nt < 4; nt++)
#pragma unroll
            for (int half = 0; half < 2; half++) {
                int m = wm * 32 + mt * 16 + (lane >> 2) + half * 8;
                int j = ct * 64 + wn * 32 + nt * 8 + (lane & 3) * 2;
                *(float2*)&dst[m * (RM + HD) + j] =
                    make_float2(acc[mt][nt][half * 2], acc[mt][nt][half * 2 + 1]);
            }
}

// ---------------- fused reduce + ISTA (emits (d*s)^T bf16 split) ------------------
__device__ __forceinline__ float softf(float z, float t)
{
    float a = fabsf(z) - t;
    return a > 0.f ? (z >= 0.f ? a : -a) : 0.f;
}

#define IST_SMEM ((RM*129 + RM*HD + RM*68) * 4)

__global__ __launch_bounds__(256)
void ista_fused()
{
    extern __shared__ float sm[];
    float* kks = sm;                 // [128][129]
    float* kvs = sm + RM * 129;      // [128][64]
    float* ss  = kvs + RM * HD;      // [128][68]
    __shared__ float dsh[RM];
    __shared__ float rowsum[RM];
    __shared__ float Lsh;
    int bh = blockIdx.x;
    const float* part = g_PART;

    // d from the diagonal of unnormalized kk
    if (threadIdx.x < RM) {
        float s = 0.f;
#pragma unroll
        for (int sp = 0; sp < SPLITS; sp++)
            s += part[((size_t)sp * BH + bh) * (RM * (RM + HD))
                      + threadIdx.x * (RM + HD) + threadIdx.x];
        dsh[threadIdx.x] = 1.0f / fmaxf(sqrtf(s), 1e-12f);
    }
    __syncthreads();

    // sum partials, scale into smem kks / kvs
    for (int idx = threadIdx.x; idx < RM * (RM + HD); idx += 256) {
        int m = idx / (RM + HD);
        int j = idx - m * (RM + HD);
        float s = 0.f;
#pragma unroll
        for (int sp = 0; sp < SPLITS; sp++)
            s += part[((size_t)sp * BH + bh) * (RM * (RM + HD)) + idx];
        if (j < RM) kks[m * 129 + j] = s * dsh[m] * dsh[j];
        else        kvs[m * HD + (j - RM)] = s * dsh[m];
    }
    __syncthreads();

    // Lipschitz bound
    if (threadIdx.x < RM) {
        float rs = 0.f;
        for (int j = 0; j < RM; j++) rs += fabsf(kks[threadIdx.x * 129 + j]);
        rowsum[threadIdx.x] = rs;
    }
    __syncthreads();
    if (threadIdx.x == 0) {
        float mx = 0.f;
        for (int i = 0; i < RM; i++) mx = fmaxf(mx, rowsum[i]);
        Lsh = mx + 1.0f;
    }
    __syncthreads();
    float invL = 1.0f / Lsh;
    float thr  = LAMBDA * invL;

    int m  = threadIdx.x >> 1;
    int ch = (threadIdx.x & 1) * 32;
#pragma unroll
    for (int i = 0; i < 32; i++)
        ss[m * 68 + ch + i] = softf(kvs[m * HD + ch + i], LAMBDA);
    __syncthreads();

    for (int it = 0; it < NSTEP; it++) {
        float acc[32];
#pragma unroll
        for (int i = 0; i < 32; i++) acc[i] = 0.f;
        for (int p = 0; p < RM; p++) {
            float kv_ = kks[m * 129 + p];
            const float4* sp = (const float4*)&ss[p * 68 + ch];
#pragma unroll
            for (int q = 0; q < 8; q++) {
                float4 v = sp[q];
                acc[q * 4 + 0] += kv_ * v.x;
                acc[q * 4 + 1] += kv_ * v.y;
                acc[q * 4 + 2] += kv_ * v.z;
                acc[q * 4 + 3] += kv_ * v.w;
            }
        }
        float r[32];
#pragma unroll
        for (int i = 0; i < 32; i++) {
            float z = ss[m * 68 + ch + i] - (acc[i] - kvs[m * HD + ch + i]) * invL;
            r[i] = softf(z, thr);
        }
        __syncthreads();
#pragma unroll
        for (int q = 0; q < 8; q++)
            *(float4*)&ss[m * 68 + ch + q * 4] =
                make_float4(r[q * 4], r[q * 4 + 1], r[q * 4 + 2], r[q * 4 + 3]);
        __syncthreads();
    }
    float dm = dsh[m];
#pragma unroll
    for (int q = 0; q < 8; q++) {
        float4 v = *(float4*)&ss[m * 68 + ch + q * 4];
        v.x *= dm; v.y *= dm; v.z *= dm; v.w *= dm;
        *(float4*)&ss[m * 68 + ch + q * 4] = v;
    }
    __syncthreads();
    int d  = threadIdx.x >> 2;
    int ms = (threadIdx.x & 3) * 32;
    size_t ob = ((size_t)bh * HD + d) * RM + ms;
#pragma unroll
    for (int i = 0; i < 32; i += 2) {
        float v0 = ss[(ms + i) * 68 + d];
        float v1 = ss[(ms + i + 1) * 68 + d];
        __nv_bfloat16 h0, l0, h1, l1;
        split2(v0, h0, l0); split2(v1, h1, l1);
        *(__nv_bfloat162*)&g_ST1[ob + i] = __halves2bfloat162(h0, h1);
        *(__nv_bfloat162*)&g_ST2[ob + i] = __halves2bfloat162(l0, l1);
    }
}

// ---------------- out = rf @ sT^T via HMMA, emits OC bf16 pair --------------------
__global__ __launch_bounds__(256, 2)
void outgemm_hmma()
{
    __shared__ __nv_bfloat16 As1[128 * PITCH], As2[128 * PITCH];
    __shared__ __nv_bfloat16 Bs1[64 * PITCH],  Bs2[64 * PITCH];
    const int tid = threadIdx.x, wid = tid >> 5, lane = tid & 31;
    const int wm = wid & 3, wn = wid >> 2;
    const int bh = blockIdx.y, nblk = blockIdx.x;
    const int b = bh / NH, h = bh % NH;

    size_t rfbase = ((size_t)bh * SEQ + (size_t)nblk * 128) * RM;
    size_t stbase = (size_t)bh * HD * RM;

    float acc[2][4][4];
#pragma unroll
    for (int i = 0; i < 2; i++)
#pragma unroll
        for (int j = 0; j < 4; j++)
#pragma unroll
            for (int q = 0; q < 4; q++) acc[i][j][q] = 0.f;

    const uint32_t as1 = smem_u32(As1), as2 = smem_u32(As2);
    const uint32_t bs1 = smem_u32(Bs1), bs2 = smem_u32(Bs2);
    const int arow = wm * 32 + (lane & 15);
    const int acolL = (lane >> 4) * 8;
    const int bn   = wn * 32 + (lane & 7) + ((lane >> 4) & 1) * 8;
    const int bkL  = ((lane >> 3) & 1) * 8;

    for (int kc = 0; kc < 4; kc++) {
        const int k0 = kc * 32;
#pragma unroll
        for (int l = 0; l < 2; l++) {
            int f = tid + l * 256;
            int r = f >> 2, c = (f & 3) * 8;
            *(uint4*)(As1 + r * PITCH + c) =
                *(const uint4*)(g_RF1 + rfbase + (size_t)r * RM + k0 + c);
            *(uint4*)(As2 + r * PITCH + c) =
                *(const uint4*)(g_RF2 + rfbase + (size_t)r * RM + k0 + c);
        }
        {
            int r = tid >> 2, c = (tid & 3) * 8;
            if (r < 64) {
                *(uint4*)(Bs1 + r * PITCH + c) =
                    *(const uint4*)(g_ST1 + stbase + (size_t)r * RM + k0 + c);
                *(uint4*)(Bs2 + r * PITCH + c) =
                    *(const uint4*)(g_ST2 + stbase + (size_t)r * RM + k0 + c);
            }
        }
        __syncthreads();
#pragma unroll
        for (int ks = 0; ks < 2; ks++) {
            const int acol = ks * 16 + acolL;
            const int bk   = ks * 16 + bkL;
            uint32_t a1[2][4], a2[2][4], b1[4][2], b2[4][2];
#pragma unroll
            for (int mt = 0; mt < 2; mt++) {
                uint32_t off = ((arow + mt * 16) * PITCH + acol) * 2;
                ldmx4(a1[mt][0], a1[mt][1], a1[mt][2], a1[mt][3], as1 + off);
                ldmx4(a2[mt][0], a2[mt][1], a2[mt][2], a2[mt][3], as2 + off);
            }
#pragma unroll
            for (int nt2 = 0; nt2 < 2; nt2++) {
                uint32_t off = ((bn + nt2 * 16) * PITCH + bk) * 2;
                ldmx4(b1[nt2 * 2][0], b1[nt2 * 2][1],
                      b1[nt2 * 2 + 1][0], b1[nt2 * 2 + 1][1], bs1 + off);
                ldmx4(b2[nt2 * 2][0], b2[nt2 * 2][1],
                      b2[nt2 * 2 + 1][0], b2[nt2 * 2 + 1][1], bs2 + off);
            }
#pragma unroll
            for (int mt = 0; mt < 2; mt++)
#pragma unroll
                for (int nt = 0; nt < 4; nt++) {
                    mma16816(acc[mt][nt], a1[mt], b1[nt]);
                    mma16816(acc[mt][nt], a1[mt], b2[nt]);
                    mma16816(acc[mt][nt], a2[mt], b1[nt]);
                }
        }
        __syncthreads();
    }

    const int g  = lane >> 2;
    const int tg = lane & 3;
#pragma unroll
    for (int mt = 0; mt < 2; mt++)
#pragma unroll
        for (int nt = 0; nt < 4; nt++)
#pragma unroll
            for (int half = 0; half < 2; half++) {
                int nrow = nblk * 128 + wm * 32 + mt * 16 + g + half * 8;
                int d    = wn * 32 + nt * 8 + tg * 2;
                float2 v = make_float2(acc[mt][nt][half * 2],
                                       acc[mt][nt][half * 2 + 1]);
                size_t adr = ((size_t)b * SEQ + nrow) * CH + h * HD + d;
                __nv_bfloat16 h0, l0, h1, l1;
                split2(v.x, h0, l0); split2(v.y, h1, l1);
                *(__nv_bfloat162*)&g_OC1[adr] = __halves2bfloat162(h0, h1);
                *(__nv_bfloat162*)&g_OC2[adr] = __halves2bfloat162(l0, l1);
            }
}

// ---------------- launch -----------------------------------------------------------
extern "C" void kernel_launch(void* const* d_in, const int* in_sizes, int n_in,
                              void* d_out, int out_size)
{
    const float *x = nullptr, *wqkv = nullptr, *wproj = nullptr,
                *bias = nullptr, *rm = nullptr;
    for (int i = 0; i < n_in; i++) {
        const float* p = (const float*)d_in[i];
        switch (in_sizes[i]) {
            case BATCH * SEQ * CH: x = p; break;
            case CH * 2 * CH:      wqkv = p; break;
            case CH * CH:          wproj = p; break;
            case CH:               bias = p; break;
            case NH * HD * RM:     rm = p; break;
        }
    }
    float* out = (float*)d_out;
    (void)out_size;

    cudaFuncSetAttribute(hmma_gemm<0>, cudaFuncAttributeMaxDynamicSharedMemorySize, DG_SMEM);
    cudaFuncSetAttribute(hmma_gemm<1>, cudaFuncAttributeMaxDynamicSharedMemorySize, DG_SMEM);
    cudaFuncSetAttribute(rf_hmma, cudaFuncAttributeMaxDynamicSharedMemorySize, RF_SMEM);
    cudaFuncSetAttribute(kkkv_hmma, cudaFuncAttributeMaxDynamicSharedMemorySize, KK_SMEM);
    cudaFuncSetAttribute(ista_fused, cudaFuncAttributeMaxDynamicSharedMemorySize, IST_SMEM);

    // conversions to bf16 split pairs
    conv_x_kernel<<<BATCH * SEQ * CH / 1024, 256>>>(x);
    conv_w_kernel<0><<<2 * CH * CH / 256, 256>>>(wqkv, 2 * CH);
    conv_w_kernel<1><<<CH * CH / 256, 256>>>(wproj, CH);
    conv_rt_kernel<<<NH * RM * HD / 256, 256>>>(rm);

    // 1. qkv = x @ Wqkv (HMMA) -> q bf16 pair, v bf16 pair
    hmma_gemm<0><<<dim3(12, 256), 256, DG_SMEM>>>(nullptr, nullptr, CH);
    // 2. random feature map via HMMA -> rf bf16 pair
    rf_hmma<<<dim3(32, BH), 256, RF_SMEM>>>();
    // 3. kk/kv partials (HMMA)
    kkkv_hmma<<<dim3(3, BH, SPLITS), 256, KK_SMEM>>>();
    // 4. fused reduce + d + L + ISTA -> (d*s)^T bf16 pair
    ista_fused<<<BH, 256, IST_SMEM>>>();
    // 5. out_head = rf @ s (HMMA) -> OC bf16 pair
    outgemm_hmma<<<dim3(32, BH), 256>>>();
    // 6. final projection + bias (HMMA)
    hmma_gemm<1><<<dim3(6, 256), 256, DG_SMEM>>>(bias, out, CH);
}

// round 10
// speedup vs baseline: 3.6806x; 1.1169x over previous
#include <cuda_runtime.h>
#include <cuda_bf16.h>
#include <cuda_fp16.h>
#include <math.h>
#include <cstdint>

// Problem constants
#define BATCH 8
#define SEQ   4096
#define CH    768
#define NH    12
#define HD    64
#define RM    128
#define BH    (BATCH*NH)
#define LAMBDA 0.3f
#define NSTEP 5
#define SPLITS 4
#define NCHUNK (SEQ/SPLITS)    // 1024

// ---------------- scratch ----------------------------------------------------
__device__ float g_PART[(size_t)SPLITS*BH*RM*(RM+HD)];
// bf16 split pairs (accuracy-critical path: x -> q -> rf logits)
__device__ __nv_bfloat16 g_XA1[(size_t)BATCH*SEQ*CH];
__device__ __nv_bfloat16 g_XA2[(size_t)BATCH*SEQ*CH];
__device__ __nv_bfloat16 g_WQ1[(size_t)2*CH*CH];
__device__ __nv_bfloat16 g_WQ2[(size_t)2*CH*CH];
__device__ __nv_bfloat16 g_QB1[(size_t)BH*SEQ*HD];
__device__ __nv_bfloat16 g_QB2[(size_t)BH*SEQ*HD];
__device__ __nv_bfloat16 g_RT1[(size_t)NH*RM*HD];
__device__ __nv_bfloat16 g_RT2[(size_t)NH*RM*HD];
// fp16 (2-term path)
__device__ __half g_RF1[(size_t)BH*SEQ*RM];   // rf hi  [bh][n][m]
__device__ __half g_RF2[(size_t)BH*SEQ*RM];   // rf lo
__device__ __half g_VB1[(size_t)BH*SEQ*HD];   // v single [bh][n][d]
__device__ __half g_ST1[(size_t)BH*HD*RM];    // (d*s)^T single [bh][d][m]
__device__ __half g_OC1[(size_t)BATCH*SEQ*CH];
__device__ __half g_OC2[(size_t)BATCH*SEQ*CH];
__device__ __half g_WP1[(size_t)CH*CH];       // WprojT single

// ---------------- helpers ------------------------------------------------------
__device__ __forceinline__ uint32_t smem_u32(const void* p) {
    uint32_t a;
    asm("{ .reg .u64 t; cvta.to.shared.u64 t, %1; cvt.u32.u64 %0, t; }"
        : "=r"(a) : "l"(p));
    return a;
}
__device__ __forceinline__ void ldmx4(uint32_t& r0, uint32_t& r1,
                                      uint32_t& r2, uint32_t& r3, uint32_t addr)
{
    asm volatile("ldmatrix.sync.aligned.m8n8.x4.shared.b16 {%0,%1,%2,%3}, [%4];"
                 : "=r"(r0), "=r"(r1), "=r"(r2), "=r"(r3) : "r"(addr));
}
__device__ __forceinline__ void ldmx4t(uint32_t* r, uint32_t addr)
{
    asm volatile("ldmatrix.sync.aligned.m8n8.x4.trans.shared.b16 {%0,%1,%2,%3}, [%4];"
                 : "=r"(r[0]), "=r"(r[1]), "=r"(r[2]), "=r"(r[3]) : "r"(addr));
}
__device__ __forceinline__ void mma_bf16(float* c, const uint32_t* a,
                                         const uint32_t* b)
{
    asm volatile(
        "mma.sync.aligned.m16n8k16.row.col.f32.bf16.bf16.f32 "
        "{%0,%1,%2,%3}, {%4,%5,%6,%7}, {%8,%9}, {%0,%1,%2,%3};"
        : "+f"(c[0]), "+f"(c[1]), "+f"(c[2]), "+f"(c[3])
        : "r"(a[0]), "r"(a[1]), "r"(a[2]), "r"(a[3]), "r"(b[0]), "r"(b[1]));
}
__device__ __forceinline__ void mma_f16(float* c, const uint32_t* a,
                                        const uint32_t* b)
{
    asm volatile(
        "mma.sync.aligned.m16n8k16.row.col.f32.f16.f16.f32 "
        "{%0,%1,%2,%3}, {%4,%5,%6,%7}, {%8,%9}, {%0,%1,%2,%3};"
        : "+f"(c[0]), "+f"(c[1]), "+f"(c[2]), "+f"(c[3])
        : "r"(a[0]), "r"(a[1]), "r"(a[2]), "r"(a[3]), "r"(b[0]), "r"(b[1]));
}
__device__ __forceinline__ void split2b(float v, __nv_bfloat16& h, __nv_bfloat16& l)
{
    h = __float2bfloat16(v);
    l = __float2bfloat16(v - __bfloat162float(h));
}
__device__ __forceinline__ void split2h(float v, __half& h, __half& l)
{
    h = __float2half(v);
    l = __float2half(v - __half2float(h));
}
__device__ __forceinline__ void cpa16(uint32_t saddr, const void* g)
{
    asm volatile("cp.async.cg.shared.global [%0], [%1], 16;"
                 :: "r"(saddr), "l"(g));
}
#define CP_COMMIT() asm volatile("cp.async.commit_group;")
#define CP_WAIT1()  asm volatile("cp.async.wait_group 1;")

#define PITCH 40
#define DG_TILE (128*PITCH)
#define DG_STAGE (4*DG_TILE)
#define DG_SMEM (2*DG_STAGE*2) // 81920 bytes

// ---------------- dense HMMA GEMM ------------------------------------------------
// EPI==0: bf16 3-term: [q|v] = x @ WqkvT; emits q bf16 pair (scaled), v fp16 single
// EPI==1: fp16 2-term: out = OC(pair) @ WP1(single) + bias -> fp32
template<int EPI>
__global__ __launch_bounds__(256, 2)
void hmma_gemm(const float* __restrict__ bias, float* __restrict__ Cout, int Kdim)
{
    extern __shared__ uint16_t dsm[];

    const int tid  = threadIdx.x;
    const int wid  = tid >> 5;
    const int lane = tid & 31;
    const int wm   = wid & 1;
    const int wn   = wid >> 1;
    const int brow = blockIdx.y * 128;
    const int bcol = blockIdx.x * 128;

    const uint16_t* A1 = (EPI == 0) ? (const uint16_t*)g_XA1 : (const uint16_t*)g_OC1;
    const uint16_t* A2 = (EPI == 0) ? (const uint16_t*)g_XA2 : (const uint16_t*)g_OC2;
    const uint16_t* B1 = (EPI == 0) ? (const uint16_t*)g_WQ1 : (const uint16_t*)g_WP1;
    const uint16_t* B2 = (EPI == 0) ? (const uint16_t*)g_WQ2 : nullptr;
    const int NT = (EPI == 0) ? 4 : 3;   // tiles per stage

    float acc[4][4][4];
#pragma unroll
    for (int i = 0; i < 4; i++)
#pragma unroll
        for (int j = 0; j < 4; j++)
#pragma unroll
            for (int q = 0; q < 4; q++) acc[i][j][q] = 0.f;

    const uint32_t smbase = smem_u32(dsm);
    const int arow = wm * 64 + (lane & 15);
    const int acolL = (lane >> 4) * 8;
    const int bn   = wn * 32 + (lane & 7) + ((lane >> 4) & 1) * 8;
    const int bkL  = ((lane >> 3) & 1) * 8;

    const int l_row0 = tid >> 2,        l_ch0 = (tid & 3) * 8;
    const int l_row1 = (tid + 256) >> 2, l_ch1 = ((tid + 256) & 3) * 8;

    auto load_stage = [&](int stage, int k0) {
        uint32_t sb = smbase + stage * DG_STAGE * 2;
#pragma unroll
        for (int t = 0; t < NT; t++) {
            const uint16_t* src = (t == 0) ? A1 : (t == 1) ? A2 : (t == 2) ? B1 : B2;
            const int rbase = (t < 2) ? brow : bcol;
            uint32_t tb = sb + t * DG_TILE * 2;
            cpa16(tb + (l_row0 * PITCH + l_ch0) * 2,
                  src + (size_t)(rbase + l_row0) * Kdim + k0 + l_ch0);
            cpa16(tb + (l_row1 * PITCH + l_ch1) * 2,
                  src + (size_t)(rbase + l_row1) * Kdim + k0 + l_ch1);
        }
    };

    const int nchunk = Kdim >> 5;
    load_stage(0, 0);
    CP_COMMIT();

    for (int kc = 0; kc < nchunk; kc++) {
        if (kc + 1 < nchunk) load_stage((kc + 1) & 1, (kc + 1) << 5);
        CP_COMMIT();
        CP_WAIT1();
        __syncthreads();

        const uint32_t sb = smbase + (kc & 1) * DG_STAGE * 2;
        const uint32_t as1 = sb, as2 = sb + DG_TILE * 2;
        const uint32_t bs1 = sb + 2 * DG_TILE * 2, bs2 = sb + 3 * DG_TILE * 2;
#pragma unroll
        for (int ks = 0; ks < 2; ks++) {
            const int acol = ks * 16 + acolL;
            const int bk   = ks * 16 + bkL;
            uint32_t a1[4][4], a2[4][4], b1[4][2], b2[4][2];
#pragma unroll
            for (int mt = 0; mt < 4; mt++) {
                uint32_t off = ((arow + mt * 16) * PITCH + acol) * 2;
                ldmx4(a1[mt][0], a1[mt][1], a1[mt][2], a1[mt][3], as1 + off);
                ldmx4(a2[mt][0], a2[mt][1], a2[mt][2], a2[mt][3], as2 + off);
            }
#pragma unroll
            for (int nt2 = 0; nt2 < 2; nt2++) {
                uint32_t off = ((bn + nt2 * 16) * PITCH + bk) * 2;
                ldmx4(b1[nt2 * 2][0], b1[nt2 * 2][1],
                      b1[nt2 * 2 + 1][0], b1[nt2 * 2 + 1][1], bs1 + off);
                if (EPI == 0)
                    ldmx4(b2[nt2 * 2][0], b2[nt2 * 2][1],
                          b2[nt2 * 2 + 1][0], b2[nt2 * 2 + 1][1], bs2 + off);
            }
#pragma unroll
            for (int mt = 0; mt < 4; mt++)
#pragma unroll
                for (int nt = 0; nt < 4; nt++) {
                    if (EPI == 0) {
                        mma_bf16(acc[mt][nt], a1[mt], b1[nt]);
                        mma_bf16(acc[mt][nt], a1[mt], b2[nt]);
                        mma_bf16(acc[mt][nt], a2[mt], b1[nt]);
                    } else {
                        mma_f16(acc[mt][nt], a1[mt], b1[nt]);
                        mma_f16(acc[mt][nt], a2[mt], b1[nt]);
                    }
                }
        }
        __syncthreads();
    }

    const int g  = lane >> 2;
    const int tg = lane & 3;
#pragma unroll
    for (int mt = 0; mt < 4; mt++)
#pragma unroll
        for (int nt = 0; nt < 4; nt++) {
#pragma unroll
            for (int half = 0; half < 2; half++) {
                int grow = brow + wm * 64 + mt * 16 + g + half * 8;
                int col  = bcol + wn * 32 + nt * 8 + tg * 2;
                float2 v = make_float2(acc[mt][nt][half * 2],
                                       acc[mt][nt][half * 2 + 1]);
                if (EPI == 0) {
                    int bb = grow >> 12, nn = grow & 4095;
                    if (col < CH) {
                        const float s = 0.35355339059327373f;  // hd^(-1/4)
                        v.x *= s; v.y *= s;
                        int h = col >> 6, dd = col & 63;
                        size_t adr = (((size_t)(bb * NH + h)) * SEQ + nn) * HD + dd;
                        __nv_bfloat16 h0, l0, h1, l1;
                        split2b(v.x, h0, l0); split2b(v.y, h1, l1);
                        *(__nv_bfloat162*)&g_QB1[adr] = __halves2bfloat162(h0, h1);
                        *(__nv_bfloat162*)&g_QB2[adr] = __halves2bfloat162(l0, l1);
                    } else {
                        int c2 = col - CH;
                        int h = c2 >> 6, dd = c2 & 63;
                        size_t adr = (((size_t)(bb * NH + h)) * SEQ + nn) * HD + dd;
                        *(__half2*)&g_VB1[adr] =
                            __halves2half2(__float2half(v.x), __float2half(v.y));
                    }
                } else {
                    v.x += bias[col];
                    v.y += bias[col + 1];
                    *(float2*)&Cout[(size_t)grow * CH + col] = v;
                }
            }
        }
}

// ---------------- conversion kernels -----------------------------------------
__global__ __launch_bounds__(256)
void conv_x_kernel(const float* __restrict__ x)
{
    size_t i = ((size_t)blockIdx.x * 256 + threadIdx.x) * 4;
    float4 v = *(const float4*)&x[i];
    __nv_bfloat16 h0, l0, h1, l1, h2, l2, h3, l3;
    split2b(v.x, h0, l0); split2b(v.y, h1, l1);
    split2b(v.z, h2, l2); split2b(v.w, h3, l3);
    *(__nv_bfloat162*)&g_XA1[i]     = __halves2bfloat162(h0, h1);
    *(__nv_bfloat162*)&g_XA1[i + 2] = __halves2bfloat162(h2, h3);
    *(__nv_bfloat162*)&g_XA2[i]     = __halves2bfloat162(l0, l1);
    *(__nv_bfloat162*)&g_XA2[i + 2] = __halves2bfloat162(l2, l3);
}

__global__ __launch_bounds__(256)
void conv_wq_kernel(const float* __restrict__ W)
{
    int idx = blockIdx.x * 256 + threadIdx.x;   // over [1536][768]
    int n = idx / CH, k = idx - n * CH;
    float v = W[(size_t)k * (2 * CH) + n];
    __nv_bfloat16 h, l;
    split2b(v, h, l);
    g_WQ1[idx] = h;
    g_WQ2[idx] = l;
}

__global__ __launch_bounds__(256)
void conv_wp_kernel(const float* __restrict__ W)
{
    int idx = blockIdx.x * 256 + threadIdx.x;   // over [768][768]
    int n = idx / CH, k = idx - n * CH;
    g_WP1[idx] = __float2half(W[(size_t)k * CH + n]);
}

// R [h][d][m] -> R^T pair [h][m][d]
__global__ __launch_bounds__(256)
void conv_rt_kernel(const float* __restrict__ randm)
{
    int idx = blockIdx.x * 256 + threadIdx.x;
    int h = idx / (RM * HD);
    int r = idx - h * (RM * HD);
    int m = r / HD, d = r - m * HD;
    float v = randm[((size_t)h * HD + d) * RM + m];
    __nv_bfloat16 hi, lo;
    split2b(v, hi, lo);
    g_RT1[idx] = hi;
    g_RT2[idx] = lo;
}

// ---------------- rf via HMMA (bf16 3-term), emits fp16 pair ---------------------
#define RF_PITCH 72
#define RF_TILE (128*RF_PITCH)
#define RF_SMEM (4*RF_TILE*2)

__global__ __launch_bounds__(256, 2)
void rf_hmma()
{
    extern __shared__ __nv_bfloat16 rsm[];
    __shared__ float rowq2[128];
    const int tid = threadIdx.x, wid = tid >> 5, lane = tid & 31;
    const int wm = wid & 1, wn = wid >> 1;
    const int bh = blockIdx.y, h = bh % NH;
    const int brow = blockIdx.x * 128;

    const __nv_bfloat16* A1 = g_QB1 + ((size_t)bh * SEQ + brow) * HD;
    const __nv_bfloat16* A2 = g_QB2 + ((size_t)bh * SEQ + brow) * HD;
    const __nv_bfloat16* B1 = g_RT1 + (size_t)h * RM * HD;
    const __nv_bfloat16* B2 = g_RT2 + (size_t)h * RM * HD;

#pragma unroll
    for (int t = 0; t < 4; t++) {
        const __nv_bfloat16* src = (t == 0) ? A1 : (t == 1) ? A2 : (t == 2) ? B1 : B2;
        __nv_bfloat16* dst = rsm + t * RF_TILE;
#pragma unroll
        for (int u = 0; u < 4; u++) {
            int f = u * 256 + tid;
            int r = f >> 3, c = (f & 7) * 8;
            *(uint4*)(dst + r * RF_PITCH + c) = *(const uint4*)(src + (size_t)r * HD + c);
        }
    }
    __syncthreads();

    {
        int r = tid >> 1;
        int k0 = (tid & 1) * 32;
        const __nv_bfloat16* q1 = rsm + r * RF_PITCH + k0;
        const __nv_bfloat16* q2 = rsm + RF_TILE + r * RF_PITCH + k0;
        float s = 0.f;
#pragma unroll
        for (int k = 0; k < 32; k++) {
            float v = __bfloat162float(q1[k]) + __bfloat162float(q2[k]);
            s += v * v;
        }
        s += __shfl_xor_sync(0xffffffffu, s, 1);
        if (!(tid & 1)) rowq2[r] = s;
    }

    float acc[4][4][4];
#pragma unroll
    for (int i = 0; i < 4; i++)
#pragma unroll
        for (int j = 0; j < 4; j++)
#pragma unroll
            for (int q = 0; q < 4; q++) acc[i][j][q] = 0.f;

    const uint32_t smbase = smem_u32(rsm);
    const uint32_t as1 = smbase, as2 = smbase + RF_TILE * 2;
    const uint32_t bs1 = smbase + 2 * RF_TILE * 2, bs2 = smbase + 3 * RF_TILE * 2;
    const int arow = wm * 64 + (lane & 15);
    const int acolL = (lane >> 4) * 8;
    const int bn   = wn * 32 + (lane & 7) + ((lane >> 4) & 1) * 8;
    const int bkL  = ((lane >> 3) & 1) * 8;

#pragma unroll
    for (int ks = 0; ks < 4; ks++) {
        const int acol = ks * 16 + acolL;
        const int bk   = ks * 16 + bkL;
        uint32_t a1[4][4], a2[4][4], b1[4][2], b2[4][2];
#pragma unroll
        for (int mt = 0; mt < 4; mt++) {
            uint32_t off = ((arow + mt * 16) * RF_PITCH + acol) * 2;
            ldmx4(a1[mt][0], a1[mt][1], a1[mt][2], a1[mt][3], as1 + off);
            ldmx4(a2[mt][0], a2[mt][1], a2[mt][2], a2[mt][3], as2 + off);
        }
#pragma unroll
        for (int nt2 = 0; nt2 < 2; nt2++) {
            uint32_t off = ((bn + nt2 * 16) * RF_PITCH + bk) * 2;
            ldmx4(b1[nt2 * 2][0], b1[nt2 * 2][1],
                  b1[nt2 * 2 + 1][0], b1[nt2 * 2 + 1][1], bs1 + off);
            ldmx4(b2[nt2 * 2][0], b2[nt2 * 2][1],
                  b2[nt2 * 2 + 1][0], b2[nt2 * 2 + 1][1], bs2 + off);
        }
#pragma unroll
        for (int mt = 0; mt < 4; mt++)
#pragma unroll
            for (int nt = 0; nt < 4; nt++) {
                mma_bf16(acc[mt][nt], a1[mt], b1[nt]);
                mma_bf16(acc[mt][nt], a1[mt], b2[nt]);
                mma_bf16(acc[mt][nt], a2[mt], b1[nt]);
            }
    }
    __syncthreads();

    const int g  = lane >> 2;
    const int tg = lane & 3;
    const float sc = 0.08838834764831845f;  // 1/sqrt(128)
#pragma unroll
    for (int mt = 0; mt < 4; mt++)
#pragma unroll
        for (int nt = 0; nt < 4; nt++)
#pragma unroll
            for (int half = 0; half < 2; half++) {
                int row  = wm * 64 + mt * 16 + g + half * 8;
                int mcol = wn * 32 + nt * 8 + tg * 2;
                float base = -0.5f * rowq2[row];
                float v0 = expf(acc[mt][nt][half * 2]     + base) * sc;
                float v1 = expf(acc[mt][nt][half * 2 + 1] + base) * sc;
                __half h0, l0, h1, l1;
                split2h(v0, h0, l0); split2h(v1, h1, l1);
                size_t adr = ((size_t)bh * SEQ + brow + row) * RM + mcol;
                *(__half2*)&g_RF1[adr] = __halves2half2(h0, h1);
                *(__half2*)&g_RF2[adr] = __halves2half2(l0, l1);
            }
}

// ---------------- kk/kv via fp16 2-term HMMA (A=rf pair, B single) ---------------
#define KK_A_TILE (32*136)
#define KK_Y_TILE (32*72)
#define KK_STAGE (2*KK_A_TILE + KK_Y_TILE)
#define KK_SMEM (2*KK_STAGE*2)

__global__ __launch_bounds__(256, 2)
void kkkv_hmma()
{
    extern __shared__ __half ksm[];
    const int tid = threadIdx.x, wid = tid >> 5, lane = tid & 31;
    const int ct = blockIdx.x, bh = blockIdx.y, split = blockIdx.z;
    const int wm = wid >> 1, wn = wid & 1;

    size_t abase = ((size_t)bh * SEQ + (size_t)split * NCHUNK) * RM;
    const __half *a1 = g_RF1 + abase, *a2 = g_RF2 + abase;
    const __half *b1;
    int bstr;
    if (ct == 2) {
        b1 = g_VB1 + ((size_t)bh * SEQ + (size_t)split * NCHUNK) * HD;
        bstr = HD;
    } else {
        b1 = a1 + ct * 64;     // B single = rf hi part
        bstr = RM;
    }

    float acc[2][4][4];
#pragma unroll
    for (int i = 0; i < 2; i++)
#pragma unroll
        for (int j = 0; j < 4; j++)
#pragma unroll
            for (int q = 0; q < 4; q++) acc[i][j][q] = 0.f;

    const uint32_t smbase = smem_u32(ksm);
    const int a_r = (lane & 7) + (lane >> 4) * 8;
    const int a_c = ((lane >> 3) & 1) * 8;
    const int b_r = (lane & 7) + ((lane >> 3) & 1) * 8;
    const int b_c = (lane >> 4) * 8;

    const int ar0 = tid >> 4,        ac0 = (tid & 15) * 8;
    const int ar1 = (tid + 256) >> 4, ac1 = ((tid + 256) & 15) * 8;
    const int yr = tid >> 3, yc = (tid & 7) * 8;
    auto load_stage = [&](int stage, int n0) {
        uint32_t sb = smbase + stage * KK_STAGE * 2;
        uint32_t sA1 = sb, sA2 = sb + KK_A_TILE * 2;
        uint32_t sY1 = sb + 2 * KK_A_TILE * 2;
        cpa16(sA1 + (ar0 * 136 + ac0) * 2, a1 + (size_t)(n0 + ar0) * RM + ac0);
        cpa16(sA1 + (ar1 * 136 + ac1) * 2, a1 + (size_t)(n0 + ar1) * RM + ac1);
        cpa16(sA2 + (ar0 * 136 + ac0) * 2, a2 + (size_t)(n0 + ar0) * RM + ac0);
        cpa16(sA2 + (ar1 * 136 + ac1) * 2, a2 + (size_t)(n0 + ar1) * RM + ac1);
        cpa16(sY1 + (yr * 72 + yc) * 2, b1 + (size_t)(n0 + yr) * bstr + yc);
    };

    load_stage(0, 0);
    CP_COMMIT();

    for (int chunk = 0; chunk < NCHUNK / 32; chunk++) {
        if (chunk + 1 < NCHUNK / 32) load_stage((chunk + 1) & 1, (chunk + 1) * 32);
        CP_COMMIT();
        CP_WAIT1();
        __syncthreads();

        uint32_t sb = smbase + (chunk & 1) * KK_STAGE * 2;
        uint32_t as1 = sb, as2 = sb + KK_A_TILE * 2;
        uint32_t ys1 = sb + 2 * KK_A_TILE * 2;
#pragma unroll
        for (int ks = 0; ks < 2; ks++) {
            uint32_t A1f[2][4], A2f[2][4], B1f[4][2];
#pragma unroll
            for (int mt = 0; mt < 2; mt++) {
                uint32_t off = ((ks * 16 + a_r) * 136 + wm * 32 + mt * 16 + a_c) * 2;
                ldmx4t(A1f[mt], as1 + off);
                ldmx4t(A2f[mt], as2 + off);
            }
#pragma unroll
            for (int nb = 0; nb < 2; nb++) {
                uint32_t off = ((ks * 16 + b_r) * 72 + wn * 32 + nb * 16 + b_c) * 2;
                uint32_t t1[4];
                ldmx4t(t1, ys1 + off);
                B1f[nb * 2][0] = t1[0]; B1f[nb * 2][1] = t1[1];
                B1f[nb * 2 + 1][0] = t1[2]; B1f[nb * 2 + 1][1] = t1[3];
            }
#pragma unroll
            for (int mt = 0; mt < 2; mt++)
#pragma unroll
                for (int nt = 0; nt < 4; nt++) {
                    mma_f16(acc[mt][nt], A1f[mt], B1f[nt]);
                    mma_f16(acc[mt][nt], A2f[mt], B1f[nt]);
                }
        }
        __syncthreads();
    }

    float* dst = g_PART + ((size_t)split * BH + bh) * (RM * (RM + HD));
#pragma unroll
    for (int mt = 0; mt < 2; mt++)
#pragma unroll
        for (int nt = 0; nt < 4; nt++)
#pragma unroll
            for (int half = 0; half < 2; half++) {
                int m = wm * 32 + mt * 16 + (lane >> 2) + half * 8;
                int j = ct * 64 + wn * 32 + nt * 8 + (lane & 3) * 2;
                *(float2*)&dst[m * (RM + HD) + j] =
                    make_float2(acc[mt][nt][half * 2], acc[mt][nt][half * 2 + 1]);
            }
}

// ---------------- fused reduce + ISTA (emits (d*s)^T fp16 single) ----------------
__device__ __forceinline__ float softf(float z, float t)
{
    float a = fabsf(z) - t;
    return a > 0.f ? (z >= 0.f ? a : -a) : 0.f;
}

#define IST_SMEM ((RM*129 + RM*HD + RM*68) * 4)

__global__ __launch_bounds__(256)
void ista_fused()
{
    extern __shared__ float sm[];
    float* kks = sm;
    float* kvs = sm + RM * 129;
    float* ss  = kvs + RM * HD;
    __shared__ float dsh[RM];
    __shared__ float rowsum[RM];
    __shared__ float Lsh;
    int bh = blockIdx.x;
    const float* part = g_PART;

    if (threadIdx.x < RM) {
        float s = 0.f;
#pragma unroll
        for (int sp = 0; sp < SPLITS; sp++)
            s += part[((size_t)sp * BH + bh) * (RM * (RM + HD))
                      + threadIdx.x * (RM + HD) + threadIdx.x];
        dsh[threadIdx.x] = 1.0f / fmaxf(sqrtf(s), 1e-12f);
    }
    __syncthreads();

    for (int idx = threadIdx.x; idx < RM * (RM + HD); idx += 256) {
        int m = idx / (RM + HD);
        int j = idx - m * (RM + HD);
        float s = 0.f;
#pragma unroll
        for (int sp = 0; sp < SPLITS; sp++)
            s += part[((size_t)sp * BH + bh) * (RM * (RM + HD)) + idx];
        if (j < RM) kks[m * 129 + j] = s * dsh[m] * dsh[j];
        else        kvs[m * HD + (j - RM)] = s * dsh[m];
    }
    __syncthreads();

    if (threadIdx.x < RM) {
        float rs = 0.f;
        for (int j = 0; j < RM; j++) rs += fabsf(kks[threadIdx.x * 129 + j]);
        rowsum[threadIdx.x] = rs;
    }
    __syncthreads();
    if (threadIdx.x == 0) {
        float mx = 0.f;
        for (int i = 0; i < RM; i++) mx = fmaxf(mx, rowsum[i]);
        Lsh = mx + 1.0f;
    }
    __syncthreads();
    float invL = 1.0f / Lsh;
    float thr  = LAMBDA * invL;

    int m  = threadIdx.x >> 1;
    int ch = (threadIdx.x & 1) * 32;
#pragma unroll
    for (int i = 0; i < 32; i++)
        ss[m * 68 + ch + i] = softf(kvs[m * HD + ch + i], LAMBDA);
    __syncthreads();

    for (int it = 0; it < NSTEP; it++) {
        float acc[32];
#pragma unroll
        for (int i = 0; i < 32; i++) acc[i] = 0.f;
        for (int p = 0; p < RM; p++) {
            float kv_ = kks[m * 129 + p];
            const float4* sp = (const float4*)&ss[p * 68 + ch];
#pragma unroll
            for (int q = 0; q < 8; q++) {
                float4 v = sp[q];
                acc[q * 4 + 0] += kv_ * v.x;
                acc[q * 4 + 1] += kv_ * v.y;
                acc[q * 4 + 2] += kv_ * v.z;
                acc[q * 4 + 3] += kv_ * v.w;
            }
        }
        float r[32];
#pragma unroll
        for (int i = 0; i < 32; i++) {
            float z = ss[m * 68 + ch + i] - (acc[i] - kvs[m * HD + ch + i]) * invL;
            r[i] = softf(z, thr);
        }
        __syncthreads();
#pragma unroll
        for (int q = 0; q < 8; q++)
            *(float4*)&ss[m * 68 + ch + q * 4] =
                make_float4(r[q * 4], r[q * 4 + 1], r[q * 4 + 2], r[q * 4 + 3]);
        __syncthreads();
    }
    float dm = dsh[m];
#pragma unroll
    for (int q = 0; q < 8; q++) {
        float4 v = *(float4*)&ss[m * 68 + ch + q * 4];
        v.x *= dm; v.y *= dm; v.z *= dm; v.w *= dm;
        *(float4*)&ss[m * 68 + ch + q * 4] = v;
    }
    __syncthreads();
    int d  = threadIdx.x >> 2;
    int ms = (threadIdx.x & 3) * 32;
    size_t ob = ((size_t)bh * HD + d) * RM + ms;
#pragma unroll
    for (int i = 0; i < 32; i += 2) {
        float v0 = ss[(ms + i) * 68 + d];
        float v1 = ss[(ms + i + 1) * 68 + d];
        *(__half2*)&g_ST1[ob + i] =
            __halves2half2(__float2half(v0), __float2half(v1));
    }
}

// ---------------- out = rf(pair) @ sT(single) fp16 2-term, emits OC pair ----------
__global__ __launch_bounds__(256, 2)
void outgemm_hmma()
{
    __shared__ __half As1[128 * PITCH], As2[128 * PITCH];
    __shared__ __half Bs1[64 * PITCH];
    const int tid = threadIdx.x, wid = tid >> 5, lane = tid & 31;
    const int wm = wid & 3, wn = wid >> 2;
    const int bh = blockIdx.y, nblk = blockIdx.x;
    const int b = bh / NH, h = bh % NH;

    size_t rfbase = ((size_t)bh * SEQ + (size_t)nblk * 128) * RM;
    size_t stbase = (size_t)bh * HD * RM;

    float acc[2][4][4];
#pragma unroll
    for (int i = 0; i < 2; i++)
#pragma unroll
        for (int j = 0; j < 4; j++)
#pragma unroll
            for (int q = 0; q < 4; q++) acc[i][j][q] = 0.f;

    const uint32_t as1 = smem_u32(As1), as2 = smem_u32(As2);
    const uint32_t bs1 = smem_u32(Bs1);
    const int arow = wm * 32 + (lane & 15);
    const int acolL = (lane >> 4) * 8;
    const int bn   = wn * 32 + (lane & 7) + ((lane >> 4) & 1) * 8;
    const int bkL  = ((lane >> 3) & 1) * 8;

    for (int kc = 0; kc < 4; kc++) {
        const int k0 = kc * 32;
#pragma unroll
        for (int l = 0; l < 2; l++) {
            int f = tid + l * 256;
            int r = f >> 2, c = (f & 3) * 8;
            *(uint4*)(As1 + r * PITCH + c) =
                *(const uint4*)(g_RF1 + rfbase + (size_t)r * RM + k0 + c);
            *(uint4*)(As2 + r * PITCH + c) =
                *(const uint4*)(g_RF2 + rfbase + (size_t)r * RM + k0 + c);
        }
        {
            int r = tid >> 2, c = (tid & 3) * 8;
            if (r < 64)
                *(uint4*)(Bs1 + r * PITCH + c) =
                    *(const uint4*)(g_ST1 + stbase + (size_t)r * RM + k0 + c);
        }
        __syncthreads();
#pragma unroll
        for (int ks = 0; ks < 2; ks++) {
            const int acol = ks * 16 + acolL;
            const int bk   = ks * 16 + bkL;
            uint32_t a1[2][4], a2[2][4], b1[4][2];
#pragma unroll
            for (int mt = 0; mt < 2; mt++) {
                uint32_t off = ((arow + mt * 16) * PITCH + acol) * 2;
                ldmx4(a1[mt][0], a1[mt][1], a1[mt][2], a1[mt][3], as1 + off);
                ldmx4(a2[mt][0], a2[mt][1], a2[mt][2], a2[mt][3], as2 + off);
            }
#pragma unroll
            for (int nt2 = 0; nt2 < 2; nt2++) {
                uint32_t off = ((bn + nt2 * 16) * PITCH + bk) * 2;
                ldmx4(b1[nt2 * 2][0], b1[nt2 * 2][1],
                      b1[nt2 * 2 + 1][0], b1[nt2 * 2 + 1][1], bs1 + off);
            }
#pragma unroll
            for (int mt = 0; mt < 2; mt++)
#pragma unroll
                for (int nt = 0; nt < 4; nt++) {
                    mma_f16(acc[mt][nt], a1[mt], b1[nt]);
                    mma_f16(acc[mt][nt], a2[mt], b1[nt]);
                }
        }
        __syncthreads();
    }

    const int g  = lane >> 2;
    const int tg = lane & 3;
#pragma unroll
    for (int mt = 0; mt < 2; mt++)
#pragma unroll
        for (int nt = 0; nt < 4; nt++)
#pragma unroll
            for (int half = 0; half < 2; half++) {
                int nrow = nblk * 128 + wm * 32 + mt * 16 + g + half * 8;
                int d    = wn * 32 + nt * 8 + tg * 2;
                float2 v = make_float2(acc[mt][nt][half * 2],
                                       acc[mt][nt][half * 2 + 1]);
                size_t adr = ((size_t)b * SEQ + nrow) * CH + h * HD + d;
                __half h0, l0, h1, l1;
                split2h(v.x, h0, l0); split2h(v.y, h1, l1);
                *(__half2*)&g_OC1[adr] = __halves2half2(h0, h1);
                *(__half2*)&g_OC2[adr] = __halves2half2(l0, l1);
            }
}

// ---------------- launch -----------------------------------------------------------
extern "C" void kernel_launch(void* const* d_in, const int* in_sizes, int n_in,
                              void* d_out, int out_size)
{
    const float *x = nullptr, *wqkv = nullptr, *wproj = nullptr,
                *bias = nullptr, *rm = nullptr;
    for (int i = 0; i < n_in; i++) {
        const float* p = (const float*)d_in[i];
        switch (in_sizes[i]) {
            case BATCH * SEQ * CH: x = p; break;
            case CH * 2 * CH:      wqkv = p; break;
            case CH * CH:          wproj = p; break;
            case CH:               bias = p; break;
            case NH * HD * RM:     rm = p; break;
        }
    }
    float* out = (float*)d_out;
    (void)out_size;

    cudaFuncSetAttribute(hmma_gemm<0>, cudaFuncAttributeMaxDynamicSharedMemorySize, DG_SMEM);
    cudaFuncSetAttribute(hmma_gemm<1>, cudaFuncAttributeMaxDynamicSharedMemorySize, DG_SMEM);
    cudaFuncSetAttribute(rf_hmma, cudaFuncAttributeMaxDynamicSharedMemorySize, RF_SMEM);
    cudaFuncSetAttribute(kkkv_hmma, cudaFuncAttributeMaxDynamicSharedMemorySize, KK_SMEM);
    cudaFuncSetAttribute(ista_fused, cudaFuncAttributeMaxDynamicSharedMemorySize, IST_SMEM);

    // conversions
    conv_x_kernel<<<BATCH * SEQ * CH / 1024, 256>>>(x);
    conv_wq_kernel<<<2 * CH * CH / 256, 256>>>(wqkv);
    conv_wp_kernel<<<CH * CH / 256, 256>>>(wproj);
    conv_rt_kernel<<<NH * RM * HD / 256, 256>>>(rm);

    // 1. qkv = x @ Wqkv (bf16 3-term) -> q bf16 pair, v fp16 single
    hmma_gemm<0><<<dim3(12, 256), 256, DG_SMEM>>>(nullptr, nullptr, CH);
    // 2. rf (bf16 3-term) -> rf fp16 pair
    rf_hmma<<<dim3(32, BH), 256, RF_SMEM>>>();
    // 3. kk/kv partials (fp16 2-term)
    kkkv_hmma<<<dim3(3, BH, SPLITS), 256, KK_SMEM>>>();
    // 4. fused reduce + d + L + ISTA -> sT fp16 single
    ista_fused<<<BH, 256, IST_SMEM>>>();
    // 5. out_head = rf @ s (fp16 2-term) -> OC fp16 pair
    outgemm_hmma<<<dim3(32, BH), 256>>>();
    // 6. final projection + bias (fp16 2-term)
    hmma_gemm<1><<<dim3(6, 256), 256, DG_SMEM>>>(bias, out, CH);
}

// round 11
// speedup vs baseline: 4.1001x; 1.1140x over previous
#include <cuda_runtime.h>
#include <cuda_fp16.h>
#include <math.h>
#include <cstdint>

// Problem constants
#define BATCH 8
#define SEQ   4096
#define CH    768
#define NH    12
#define HD    64
#define RM    128
#define BH    (BATCH*NH)
#define LAMBDA 0.3f
#define NSTEP 5
#define SPLITS 4
#define NCHUNK (SEQ/SPLITS)    // 1024

// ---------------- scratch ----------------------------------------------------
__device__ float g_PART[(size_t)SPLITS*BH*RM*(RM+HD)];
// fp16 split pairs / singles
__device__ __half g_XH1[(size_t)BATCH*SEQ*CH];       // x hi
__device__ __half g_XH2[(size_t)BATCH*SEQ*CH];       // x lo
__device__ __half g_WQ1[(size_t)CH*CH];              // WqT pair (q cols) [n][k]
__device__ __half g_WQ2[(size_t)CH*CH];
__device__ __half g_WV1[(size_t)CH*CH];              // WvT single (v cols)
__device__ __half g_WP1[(size_t)CH*CH];              // WprojT single
__device__ __half g_QB1[(size_t)BH*SEQ*HD];          // qs pair [bh][n][d]
__device__ __half g_QB2[(size_t)BH*SEQ*HD];
__device__ __half g_RT1[(size_t)NH*RM*HD];           // R^T pair [h][m][d]
__device__ __half g_RT2[(size_t)NH*RM*HD];
__device__ __half g_RF1[(size_t)BH*SEQ*RM];          // rf pair [bh][n][m]
__device__ __half g_RF2[(size_t)BH*SEQ*RM];
__device__ __half g_VB1[(size_t)BH*SEQ*HD];          // v single [bh][n][d]
__device__ __half g_ST1[(size_t)BH*HD*RM];           // (d*s)^T single [bh][d][m]
__device__ __half g_OC1[(size_t)BATCH*SEQ*CH];       // out-head pair
__device__ __half g_OC2[(size_t)BATCH*SEQ*CH];

// ---------------- helpers ------------------------------------------------------
__device__ __forceinline__ uint32_t smem_u32(const void* p) {
    uint32_t a;
    asm("{ .reg .u64 t; cvta.to.shared.u64 t, %1; cvt.u32.u64 %0, t; }"
        : "=r"(a) : "l"(p));
    return a;
}
__device__ __forceinline__ void ldmx4(uint32_t& r0, uint32_t& r1,
                                      uint32_t& r2, uint32_t& r3, uint32_t addr)
{
    asm volatile("ldmatrix.sync.aligned.m8n8.x4.shared.b16 {%0,%1,%2,%3}, [%4];"
                 : "=r"(r0), "=r"(r1), "=r"(r2), "=r"(r3) : "r"(addr));
}
__device__ __forceinline__ void ldmx4t(uint32_t* r, uint32_t addr)
{
    asm volatile("ldmatrix.sync.aligned.m8n8.x4.trans.shared.b16 {%0,%1,%2,%3}, [%4];"
                 : "=r"(r[0]), "=r"(r[1]), "=r"(r[2]), "=r"(r[3]) : "r"(addr));
}
__device__ __forceinline__ void mma_f16(float* c, const uint32_t* a,
                                        const uint32_t* b)
{
    asm volatile(
        "mma.sync.aligned.m16n8k16.row.col.f32.f16.f16.f32 "
        "{%0,%1,%2,%3}, {%4,%5,%6,%7}, {%8,%9}, {%0,%1,%2,%3};"
        : "+f"(c[0]), "+f"(c[1]), "+f"(c[2]), "+f"(c[3])
        : "r"(a[0]), "r"(a[1]), "r"(a[2]), "r"(a[3]), "r"(b[0]), "r"(b[1]));
}
__device__ __forceinline__ void split2h(float v, __half& h, __half& l)
{
    h = __float2half(v);
    l = __float2half(v - __half2float(h));
}
__device__ __forceinline__ void cpa16(uint32_t saddr, const void* g)
{
    asm volatile("cp.async.cg.shared.global [%0], [%1], 16;"
                 :: "r"(saddr), "l"(g));
}
#define CP_COMMIT() asm volatile("cp.async.commit_group;")
#define CP_WAIT1()  asm volatile("cp.async.wait_group 1;")

#define PITCH 40
#define DG_TILE (128*PITCH)
#define DG_STAGE (4*DG_TILE)
#define DG_SMEM (2*DG_STAGE*2) // 81920 bytes

// ---------------- dense HMMA GEMM (fp16) -------------------------------------------
// EPI==0: [q|v] = x @ WqkvT. q-col blocks: 3-term (A pair x B pair, 3 MMAs);
//         v-col blocks: 2-term (A pair x B single). Emits q fp16 pair / v fp16 single.
// EPI==1: out = OC(pair) @ WP(single) + bias -> fp32 (2-term)
template<int EPI>
__global__ __launch_bounds__(256, 2)
void hmma_gemm(const float* __restrict__ bias, float* __restrict__ Cout, int Kdim)
{
    extern __shared__ uint16_t dsm[];

    const int tid  = threadIdx.x;
    const int wid  = tid >> 5;
    const int lane = tid & 31;
    const int wm   = wid & 1;
    const int wn   = wid >> 1;
    const int brow = blockIdx.y * 128;
    const int bcol = blockIdx.x * 128;

    const uint16_t* A1 = (EPI == 0) ? (const uint16_t*)g_XH1 : (const uint16_t*)g_OC1;
    const uint16_t* A2 = (EPI == 0) ? (const uint16_t*)g_XH2 : (const uint16_t*)g_OC2;
    const bool qmode = (EPI == 0) && (bcol < CH);
    const uint16_t* B1;
    const uint16_t* B2 = nullptr;
    int bb0;
    if (EPI == 1)      { B1 = (const uint16_t*)g_WP1; bb0 = bcol; }
    else if (qmode)    { B1 = (const uint16_t*)g_WQ1;
                         B2 = (const uint16_t*)g_WQ2; bb0 = bcol; }
    else               { B1 = (const uint16_t*)g_WV1; bb0 = bcol - CH; }
    const int NT = qmode ? 4 : 3;

    float acc[4][4][4];
#pragma unroll
    for (int i = 0; i < 4; i++)
#pragma unroll
        for (int j = 0; j < 4; j++)
#pragma unroll
            for (int q = 0; q < 4; q++) acc[i][j][q] = 0.f;

    const uint32_t smbase = smem_u32(dsm);
    const int arow = wm * 64 + (lane & 15);
    const int acolL = (lane >> 4) * 8;
    const int bn   = wn * 32 + (lane & 7) + ((lane >> 4) & 1) * 8;
    const int bkL  = ((lane >> 3) & 1) * 8;

    const int l_row0 = tid >> 2,        l_ch0 = (tid & 3) * 8;
    const int l_row1 = (tid + 256) >> 2, l_ch1 = ((tid + 256) & 3) * 8;

    auto load_stage = [&](int stage, int k0) {
        uint32_t sb = smbase + stage * DG_STAGE * 2;
        for (int t = 0; t < NT; t++) {
            const uint16_t* src = (t == 0) ? A1 : (t == 1) ? A2 : (t == 2) ? B1 : B2;
            const int rbase = (t < 2) ? brow : bb0;
            uint32_t tb = sb + t * DG_TILE * 2;
            cpa16(tb + (l_row0 * PITCH + l_ch0) * 2,
                  src + (size_t)(rbase + l_row0) * Kdim + k0 + l_ch0);
            cpa16(tb + (l_row1 * PITCH + l_ch1) * 2,
                  src + (size_t)(rbase + l_row1) * Kdim + k0 + l_ch1);
        }
    };

    const int nchunk = Kdim >> 5;
    load_stage(0, 0);
    CP_COMMIT();

    for (int kc = 0; kc < nchunk; kc++) {
        if (kc + 1 < nchunk) load_stage((kc + 1) & 1, (kc + 1) << 5);
        CP_COMMIT();
        CP_WAIT1();
        __syncthreads();

        const uint32_t sb = smbase + (kc & 1) * DG_STAGE * 2;
        const uint32_t as1 = sb, as2 = sb + DG_TILE * 2;
        const uint32_t bs1 = sb + 2 * DG_TILE * 2, bs2 = sb + 3 * DG_TILE * 2;
#pragma unroll
        for (int ks = 0; ks < 2; ks++) {
            const int acol = ks * 16 + acolL;
            const int bk   = ks * 16 + bkL;
            uint32_t a1[4][4], a2[4][4], b1[4][2], b2[4][2];
#pragma unroll
            for (int mt = 0; mt < 4; mt++) {
                uint32_t off = ((arow + mt * 16) * PITCH + acol) * 2;
                ldmx4(a1[mt][0], a1[mt][1], a1[mt][2], a1[mt][3], as1 + off);
                ldmx4(a2[mt][0], a2[mt][1], a2[mt][2], a2[mt][3], as2 + off);
            }
#pragma unroll
            for (int nt2 = 0; nt2 < 2; nt2++) {
                uint32_t off = ((bn + nt2 * 16) * PITCH + bk) * 2;
                ldmx4(b1[nt2 * 2][0], b1[nt2 * 2][1],
                      b1[nt2 * 2 + 1][0], b1[nt2 * 2 + 1][1], bs1 + off);
                if (qmode)
                    ldmx4(b2[nt2 * 2][0], b2[nt2 * 2][1],
                          b2[nt2 * 2 + 1][0], b2[nt2 * 2 + 1][1], bs2 + off);
            }
            if (qmode) {
#pragma unroll
                for (int mt = 0; mt < 4; mt++)
#pragma unroll
                    for (int nt = 0; nt < 4; nt++) {
                        mma_f16(acc[mt][nt], a1[mt], b1[nt]);
                        mma_f16(acc[mt][nt], a1[mt], b2[nt]);
                        mma_f16(acc[mt][nt], a2[mt], b1[nt]);
                    }
            } else {
#pragma unroll
                for (int mt = 0; mt < 4; mt++)
#pragma unroll
                    for (int nt = 0; nt < 4; nt++) {
                        mma_f16(acc[mt][nt], a1[mt], b1[nt]);
                        mma_f16(acc[mt][nt], a2[mt], b1[nt]);
                    }
            }
        }
        __syncthreads();
    }

    const int g  = lane >> 2;
    const int tg = lane & 3;
#pragma unroll
    for (int mt = 0; mt < 4; mt++)
#pragma unroll
        for (int nt = 0; nt < 4; nt++) {
#pragma unroll
            for (int half = 0; half < 2; half++) {
                int grow = brow + wm * 64 + mt * 16 + g + half * 8;
                int col  = bcol + wn * 32 + nt * 8 + tg * 2;
                float2 v = make_float2(acc[mt][nt][half * 2],
                                       acc[mt][nt][half * 2 + 1]);
                if (EPI == 0) {
                    int bb = grow >> 12, nn = grow & 4095;
                    if (col < CH) {
                        const float s = 0.35355339059327373f;  // hd^(-1/4)
                        v.x *= s; v.y *= s;
                        int h = col >> 6, dd = col & 63;
                        size_t adr = (((size_t)(bb * NH + h)) * SEQ + nn) * HD + dd;
                        __half h0, l0, h1, l1;
                        split2h(v.x, h0, l0); split2h(v.y, h1, l1);
                        *(__half2*)&g_QB1[adr] = __halves2half2(h0, h1);
                        *(__half2*)&g_QB2[adr] = __halves2half2(l0, l1);
                    } else {
                        int c2 = col - CH;
                        int h = c2 >> 6, dd = c2 & 63;
                        size_t adr = (((size_t)(bb * NH + h)) * SEQ + nn) * HD + dd;
                        *(__half2*)&g_VB1[adr] =
                            __halves2half2(__float2half(v.x), __float2half(v.y));
                    }
                } else {
                    v.x += bias[col];
                    v.y += bias[col + 1];
                    *(float2*)&Cout[(size_t)grow * CH + col] = v;
                }
            }
        }
}

// ---------------- conversion kernels -----------------------------------------
__global__ __launch_bounds__(256)
void conv_x_kernel(const float* __restrict__ x)
{
    size_t i = ((size_t)blockIdx.x * 256 + threadIdx.x) * 4;
    float4 v = *(const float4*)&x[i];
    __half h0, l0, h1, l1, h2, l2, h3, l3;
    split2h(v.x, h0, l0); split2h(v.y, h1, l1);
    split2h(v.z, h2, l2); split2h(v.w, h3, l3);
    *(__half2*)&g_XH1[i]     = __halves2half2(h0, h1);
    *(__half2*)&g_XH1[i + 2] = __halves2half2(h2, h3);
    *(__half2*)&g_XH2[i]     = __halves2half2(l0, l1);
    *(__half2*)&g_XH2[i + 2] = __halves2half2(l2, l3);
}

__global__ __launch_bounds__(256)
void conv_wq_kernel(const float* __restrict__ W)
{
    int idx = blockIdx.x * 256 + threadIdx.x;   // over [1536][768], n outer
    int n = idx / CH, k = idx - n * CH;
    float v = W[(size_t)k * (2 * CH) + n];
    if (n < CH) {
        __half h, l;
        split2h(v, h, l);
        g_WQ1[(size_t)n * CH + k] = h;
        g_WQ2[(size_t)n * CH + k] = l;
    } else {
        g_WV1[(size_t)(n - CH) * CH + k] = __float2half(v);
    }
}

__global__ __launch_bounds__(256)
void conv_wp_kernel(const float* __restrict__ W)
{
    int idx = blockIdx.x * 256 + threadIdx.x;
    int n = idx / CH, k = idx - n * CH;
    g_WP1[idx] = __float2half(W[(size_t)k * CH + n]);
}

// R [h][d][m] -> R^T pair [h][m][d]
__global__ __launch_bounds__(256)
void conv_rt_kernel(const float* __restrict__ randm)
{
    int idx = blockIdx.x * 256 + threadIdx.x;
    int h = idx / (RM * HD);
    int r = idx - h * (RM * HD);
    int m = r / HD, d = r - m * HD;
    float v = randm[((size_t)h * HD + d) * RM + m];
    __half hi, lo;
    split2h(v, hi, lo);
    g_RT1[idx] = hi;
    g_RT2[idx] = lo;
}

// ---------------- rf via HMMA (fp16 3-term), emits fp16 pair ---------------------
#define RF_PITCH 72
#define RF_TILE (128*RF_PITCH)
#define RF_SMEM (4*RF_TILE*2)

__global__ __launch_bounds__(256, 2)
void rf_hmma()
{
    extern __shared__ __half rsm[];
    __shared__ float rowq2[128];
    const int tid = threadIdx.x, wid = tid >> 5, lane = tid & 31;
    const int wm = wid & 1, wn = wid >> 1;
    const int bh = blockIdx.y, h = bh % NH;
    const int brow = blockIdx.x * 128;

    const __half* A1 = g_QB1 + ((size_t)bh * SEQ + brow) * HD;
    const __half* A2 = g_QB2 + ((size_t)bh * SEQ + brow) * HD;
    const __half* B1 = g_RT1 + (size_t)h * RM * HD;
    const __half* B2 = g_RT2 + (size_t)h * RM * HD;

#pragma unroll
    for (int t = 0; t < 4; t++) {
        const __half* src = (t == 0) ? A1 : (t == 1) ? A2 : (t == 2) ? B1 : B2;
        __half* dst = rsm + t * RF_TILE;
#pragma unroll
        for (int u = 0; u < 4; u++) {
            int f = u * 256 + tid;
            int r = f >> 3, c = (f & 7) * 8;
            *(uint4*)(dst + r * RF_PITCH + c) = *(const uint4*)(src + (size_t)r * HD + c);
        }
    }
    __syncthreads();

    {
        int r = tid >> 1;
        int k0 = (tid & 1) * 32;
        const __half* q1 = rsm + r * RF_PITCH + k0;
        const __half* q2 = rsm + RF_TILE + r * RF_PITCH + k0;
        float s = 0.f;
#pragma unroll
        for (int k = 0; k < 32; k++) {
            float v = __half2float(q1[k]) + __half2float(q2[k]);
            s += v * v;
        }
        s += __shfl_xor_sync(0xffffffffu, s, 1);
        if (!(tid & 1)) rowq2[r] = s;
    }

    float acc[4][4][4];
#pragma unroll
    for (int i = 0; i < 4; i++)
#pragma unroll
        for (int j = 0; j < 4; j++)
#pragma unroll
            for (int q = 0; q < 4; q++) acc[i][j][q] = 0.f;

    const uint32_t smbase = smem_u32(rsm);
    const uint32_t as1 = smbase, as2 = smbase + RF_TILE * 2;
    const uint32_t bs1 = smbase + 2 * RF_TILE * 2, bs2 = smbase + 3 * RF_TILE * 2;
    const int arow = wm * 64 + (lane & 15);
    const int acolL = (lane >> 4) * 8;
    const int bn   = wn * 32 + (lane & 7) + ((lane >> 4) & 1) * 8;
    const int bkL  = ((lane >> 3) & 1) * 8;

#pragma unroll
    for (int ks = 0; ks < 4; ks++) {
        const int acol = ks * 16 + acolL;
        const int bk   = ks * 16 + bkL;
        uint32_t a1[4][4], a2[4][4], b1[4][2], b2[4][2];
#pragma unroll
        for (int mt = 0; mt < 4; mt++) {
            uint32_t off = ((arow + mt * 16) * RF_PITCH + acol) * 2;
            ldmx4(a1[mt][0], a1[mt][1], a1[mt][2], a1[mt][3], as1 + off);
            ldmx4(a2[mt][0], a2[mt][1], a2[mt][2], a2[mt][3], as2 + off);
        }
#pragma unroll
        for (int nt2 = 0; nt2 < 2; nt2++) {
            uint32_t off = ((bn + nt2 * 16) * RF_PITCH + bk) * 2;
            ldmx4(b1[nt2 * 2][0], b1[nt2 * 2][1],
                  b1[nt2 * 2 + 1][0], b1[nt2 * 2 + 1][1], bs1 + off);
            ldmx4(b2[nt2 * 2][0], b2[nt2 * 2][1],
                  b2[nt2 * 2 + 1][0], b2[nt2 * 2 + 1][1], bs2 + off);
        }
#pragma unroll
        for (int mt = 0; mt < 4; mt++)
#pragma unroll
            for (int nt = 0; nt < 4; nt++) {
                mma_f16(acc[mt][nt], a1[mt], b1[nt]);
                mma_f16(acc[mt][nt], a1[mt], b2[nt]);
                mma_f16(acc[mt][nt], a2[mt], b1[nt]);
            }
    }
    __syncthreads();

    const int g  = lane >> 2;
    const int tg = lane & 3;
    const float sc = 0.08838834764831845f;  // 1/sqrt(128)
#pragma unroll
    for (int mt = 0; mt < 4; mt++)
#pragma unroll
        for (int nt = 0; nt < 4; nt++)
#pragma unroll
            for (int half = 0; half < 2; half++) {
                int row  = wm * 64 + mt * 16 + g + half * 8;
                int mcol = wn * 32 + nt * 8 + tg * 2;
                float base = -0.5f * rowq2[row];
                float v0 = expf(acc[mt][nt][half * 2]     + base) * sc;
                float v1 = expf(acc[mt][nt][half * 2 + 1] + base) * sc;
                __half h0, l0, h1, l1;
                split2h(v0, h0, l0); split2h(v1, h1, l1);
                size_t adr = ((size_t)bh * SEQ + brow + row) * RM + mcol;
                *(__half2*)&g_RF1[adr] = __halves2half2(h0, h1);
                *(__half2*)&g_RF2[adr] = __halves2half2(l0, l1);
            }
}

// ---------------- kk/kv via fp16 2-term HMMA (A=rf pair, B single) ---------------
#define KK_A_TILE (32*136)
#define KK_Y_TILE (32*72)
#define KK_STAGE (2*KK_A_TILE + KK_Y_TILE)
#define KK_SMEM (2*KK_STAGE*2)

__global__ __launch_bounds__(256, 2)
void kkkv_hmma()
{
    extern __shared__ __half ksm[];
    const int tid = threadIdx.x, wid = tid >> 5, lane = tid & 31;
    const int ct = blockIdx.x, bh = blockIdx.y, split = blockIdx.z;
    const int wm = wid >> 1, wn = wid & 1;

    size_t abase = ((size_t)bh * SEQ + (size_t)split * NCHUNK) * RM;
    const __half *a1 = g_RF1 + abase, *a2 = g_RF2 + abase;
    const __half *b1;
    int bstr;
    if (ct == 2) {
        b1 = g_VB1 + ((size_t)bh * SEQ + (size_t)split * NCHUNK) * HD;
        bstr = HD;
    } else {
        b1 = a1 + ct * 64;
        bstr = RM;
    }

    float acc[2][4][4];
#pragma unroll
    for (int i = 0; i < 2; i++)
#pragma unroll
        for (int j = 0; j < 4; j++)
#pragma unroll
            for (int q = 0; q < 4; q++) acc[i][j][q] = 0.f;

    const uint32_t smbase = smem_u32(ksm);
    const int a_r = (lane & 7) + (lane >> 4) * 8;
    const int a_c = ((lane >> 3) & 1) * 8;
    const int b_r = (lane & 7) + ((lane >> 3) & 1) * 8;
    const int b_c = (lane >> 4) * 8;

    const int ar0 = tid >> 4,        ac0 = (tid & 15) * 8;
    const int ar1 = (tid + 256) >> 4, ac1 = ((tid + 256) & 15) * 8;
    const int yr = tid >> 3, yc = (tid & 7) * 8;
    auto load_stage = [&](int stage, int n0) {
        uint32_t sb = smbase + stage * KK_STAGE * 2;
        uint32_t sA1 = sb, sA2 = sb + KK_A_TILE * 2;
        uint32_t sY1 = sb + 2 * KK_A_TILE * 2;
        cpa16(sA1 + (ar0 * 136 + ac0) * 2, a1 + (size_t)(n0 + ar0) * RM + ac0);
        cpa16(sA1 + (ar1 * 136 + ac1) * 2, a1 + (size_t)(n0 + ar1) * RM + ac1);
        cpa16(sA2 + (ar0 * 136 + ac0) * 2, a2 + (size_t)(n0 + ar0) * RM + ac0);
        cpa16(sA2 + (ar1 * 136 + ac1) * 2, a2 + (size_t)(n0 + ar1) * RM + ac1);
        cpa16(sY1 + (yr * 72 + yc) * 2, b1 + (size_t)(n0 + yr) * bstr + yc);
    };

    load_stage(0, 0);
    CP_COMMIT();

    for (int chunk = 0; chunk < NCHUNK / 32; chunk++) {
        if (chunk + 1 < NCHUNK / 32) load_stage((chunk + 1) & 1, (chunk + 1) * 32);
        CP_COMMIT();
        CP_WAIT1();
        __syncthreads();

        uint32_t sb = smbase + (chunk & 1) * KK_STAGE * 2;
        uint32_t as1 = sb, as2 = sb + KK_A_TILE * 2;
        uint32_t ys1 = sb + 2 * KK_A_TILE * 2;
#pragma unroll
        for (int ks = 0; ks < 2; ks++) {
            uint32_t A1f[2][4], A2f[2][4], B1f[4][2];
#pragma unroll
            for (int mt = 0; mt < 2; mt++) {
                uint32_t off = ((ks * 16 + a_r) * 136 + wm * 32 + mt * 16 + a_c) * 2;
                ldmx4t(A1f[mt], as1 + off);
                ldmx4t(A2f[mt], as2 + off);
            }
#pragma unroll
            for (int nb = 0; nb < 2; nb++) {
                uint32_t off = ((ks * 16 + b_r) * 72 + wn * 32 + nb * 16 + b_c) * 2;
                uint32_t t1[4];
                ldmx4t(t1, ys1 + off);
                B1f[nb * 2][0] = t1[0]; B1f[nb * 2][1] = t1[1];
                B1f[nb * 2 + 1][0] = t1[2]; B1f[nb * 2 + 1][1] = t1[3];
            }
#pragma unroll
            for (int mt = 0; mt < 2; mt++)
#pragma unroll
                for (int nt = 0; nt < 4; nt++) {
                    mma_f16(acc[mt][nt], A1f[mt], B1f[nt]);
                    mma_f16(acc[mt][nt], A2f[mt], B1f[nt]);
                }
        }
        __syncthreads();
    }

    float* dst = g_PART + ((size_t)split * BH + bh) * (RM * (RM + HD));
#pragma unroll
    for (int mt = 0; mt < 2; mt++)
#pragma unroll
        for (int nt = 0; nt < 4; nt++)
#pragma unroll
            for (int half = 0; half < 2; half++) {
                int m = wm * 32 + mt * 16 + (lane >> 2) + half * 8;
                int j = ct * 64 + wn * 32 + nt * 8 + (lane & 3) * 2;
                *(float2*)&dst[m * (RM + HD) + j] =
                    make_float2(acc[mt][nt][half * 2], acc[mt][nt][half * 2 + 1]);
            }
}

// ---------------- fused reduce + ISTA (emits (d*s)^T fp16 single) ----------------
__device__ __forceinline__ float softf(float z, float t)
{
    float a = fabsf(z) - t;
    return a > 0.f ? (z >= 0.f ? a : -a) : 0.f;
}

#define IST_SMEM ((RM*129 + RM*HD + RM*68) * 4)

__global__ __launch_bounds__(256)
void ista_fused()
{
    extern __shared__ float sm[];
    float* kks = sm;
    float* kvs = sm + RM * 129;
    float* ss  = kvs + RM * HD;
    __shared__ float dsh[RM];
    __shared__ float rowsum[RM];
    __shared__ float Lsh;
    int bh = blockIdx.x;
    const float* part = g_PART;

    if (threadIdx.x < RM) {
        float s = 0.f;
#pragma unroll
        for (int sp = 0; sp < SPLITS; sp++)
            s += part[((size_t)sp * BH + bh) * (RM * (RM + HD))
                      + threadIdx.x * (RM + HD) + threadIdx.x];
        dsh[threadIdx.x] = 1.0f / fmaxf(sqrtf(s), 1e-12f);
    }
    __syncthreads();

    for (int idx = threadIdx.x; idx < RM * (RM + HD); idx += 256) {
        int m = idx / (RM + HD);
        int j = idx - m * (RM + HD);
        float s = 0.f;
#pragma unroll
        for (int sp = 0; sp < SPLITS; sp++)
            s += part[((size_t)sp * BH + bh) * (RM * (RM + HD)) + idx];
        if (j < RM) kks[m * 129 + j] = s * dsh[m] * dsh[j];
        else        kvs[m * HD + (j - RM)] = s * dsh[m];
    }
    __syncthreads();

    if (threadIdx.x < RM) {
        float rs = 0.f;
        for (int j = 0; j < RM; j++) rs += fabsf(kks[threadIdx.x * 129 + j]);
        rowsum[threadIdx.x] = rs;
    }
    __syncthreads();
    if (threadIdx.x == 0) {
        float mx = 0.f;
        for (int i = 0; i < RM; i++) mx = fmaxf(mx, rowsum[i]);
        Lsh = mx + 1.0f;
    }
    __syncthreads();
    float invL = 1.0f / Lsh;
    float thr  = LAMBDA * invL;

    int m  = threadIdx.x >> 1;
    int ch = (threadIdx.x & 1) * 32;
#pragma unroll
    for (int i = 0; i < 32; i++)
        ss[m * 68 + ch + i] = softf(kvs[m * HD + ch + i], LAMBDA);
    __syncthreads();

    for (int it = 0; it < NSTEP; it++) {
        float acc[32];
#pragma unroll
        for (int i = 0; i < 32; i++) acc[i] = 0.f;
        for (int p = 0; p < RM; p++) {
            float kv_ = kks[m * 129 + p];
            const float4* sp = (const float4*)&ss[p * 68 + ch];
#pragma unroll
            for (int q = 0; q < 8; q++) {
                float4 v = sp[q];
                acc[q * 4 + 0] += kv_ * v.x;
                acc[q * 4 + 1] += kv_ * v.y;
                acc[q * 4 + 2] += kv_ * v.z;
                acc[q * 4 + 3] += kv_ * v.w;
            }
        }
        float r[32];
#pragma unroll
        for (int i = 0; i < 32; i++) {
            float z = ss[m * 68 + ch + i] - (acc[i] - kvs[m * HD + ch + i]) * invL;
            r[i] = softf(z, thr);
        }
        __syncthreads();
#pragma unroll
        for (int q = 0; q < 8; q++)
            *(float4*)&ss[m * 68 + ch + q * 4] =
                make_float4(r[q * 4], r[q * 4 + 1], r[q * 4 + 2], r[q * 4 + 3]);
        __syncthreads();
    }
    float dm = dsh[m];
#pragma unroll
    for (int q = 0; q < 8; q++) {
        float4 v = *(float4*)&ss[m * 68 + ch + q * 4];
        v.x *= dm; v.y *= dm; v.z *= dm; v.w *= dm;
        *(float4*)&ss[m * 68 + ch + q * 4] = v;
    }
    __syncthreads();
    int d  = threadIdx.x >> 2;
    int ms = (threadIdx.x & 3) * 32;
    size_t ob = ((size_t)bh * HD + d) * RM + ms;
#pragma unroll
    for (int i = 0; i < 32; i += 2) {
        float v0 = ss[(ms + i) * 68 + d];
        float v1 = ss[(ms + i + 1) * 68 + d];
        *(__half2*)&g_ST1[ob + i] =
            __halves2half2(__float2half(v0), __float2half(v1));
    }
}

// ---------------- out = rf(pair) @ sT(single) fp16 2-term, emits OC pair ----------
__global__ __launch_bounds__(256, 2)
void outgemm_hmma()
{
    __shared__ __half As1[128 * PITCH], As2[128 * PITCH];
    __shared__ __half Bs1[64 * PITCH];
    const int tid = threadIdx.x, wid = tid >> 5, lane = tid & 31;
    const int wm = wid & 3, wn = wid >> 2;
    const int bh = blockIdx.y, nblk = blockIdx.x;
    const int b = bh / NH, h = bh % NH;

    size_t rfbase = ((size_t)bh * SEQ + (size_t)nblk * 128) * RM;
    size_t stbase = (size_t)bh * HD * RM;

    float acc[2][4][4];
#pragma unroll
    for (int i = 0; i < 2; i++)
#pragma unroll
        for (int j = 0; j < 4; j++)
#pragma unroll
            for (int q = 0; q < 4; q++) acc[i][j][q] = 0.f;

    const uint32_t as1 = smem_u32(As1), as2 = smem_u32(As2);
    const uint32_t bs1 = smem_u32(Bs1);
    const int arow = wm * 32 + (lane & 15);
    const int acolL = (lane >> 4) * 8;
    const int bn   = wn * 32 + (lane & 7) + ((lane >> 4) & 1) * 8;
    const int bkL  = ((lane >> 3) & 1) * 8;

    for (int kc = 0; kc < 4; kc++) {
        const int k0 = kc * 32;
#pragma unroll
        for (int l = 0; l < 2; l++) {
            int f = tid + l * 256;
            int r = f >> 2, c = (f & 3) * 8;
            *(uint4*)(As1 + r * PITCH + c) =
                *(const uint4*)(g_RF1 + rfbase + (size_t)r * RM + k0 + c);
            *(uint4*)(As2 + r * PITCH + c) =
                *(const uint4*)(g_RF2 + rfbase + (size_t)r * RM + k0 + c);
        }
        {
            int r = tid >> 2, c = (tid & 3) * 8;
            if (r < 64)
                *(uint4*)(Bs1 + r * PITCH + c) =
                    *(const uint4*)(g_ST1 + stbase + (size_t)r * RM + k0 + c);
        }
        __syncthreads();
#pragma unroll
        for (int ks = 0; ks < 2; ks++) {
            const int acol = ks * 16 + acolL;
            const int bk   = ks * 16 + bkL;
            uint32_t a1[2][4], a2[2][4], b1[4][2];
#pragma unroll
            for (int mt = 0; mt < 2; mt++) {
                uint32_t off = ((arow + mt * 16) * PITCH + acol) * 2;
                ldmx4(a1[mt][0], a1[mt][1], a1[mt][2], a1[mt][3], as1 + off);
                ldmx4(a2[mt][0], a2[mt][1], a2[mt][2], a2[mt][3], as2 + off);
            }
#pragma unroll
            for (int nt2 = 0; nt2 < 2; nt2++) {
                uint32_t off = ((bn + nt2 * 16) * PITCH + bk) * 2;
                ldmx4(b1[nt2 * 2][0], b1[nt2 * 2][1],
                      b1[nt2 * 2 + 1][0], b1[nt2 * 2 + 1][1], bs1 + off);
            }
#pragma unroll
            for (int mt = 0; mt < 2; mt++)
#pragma unroll
                for (int nt = 0; nt < 4; nt++) {
                    mma_f16(acc[mt][nt], a1[mt], b1[nt]);
                    mma_f16(acc[mt][nt], a2[mt], b1[nt]);
                }
        }
        __syncthreads();
    }

    const int g  = lane >> 2;
    const int tg = lane & 3;
#pragma unroll
    for (int mt = 0; mt < 2; mt++)
#pragma unroll
        for (int nt = 0; nt < 4; nt++)
#pragma unroll
            for (int half = 0; half < 2; half++) {
                int nrow = nblk * 128 + wm * 32 + mt * 16 + g + half * 8;
                int d    = wn * 32 + nt * 8 + tg * 2;
                float2 v = make_float2(acc[mt][nt][half * 2],
                                       acc[mt][nt][half * 2 + 1]);
                size_t adr = ((size_t)b * SEQ + nrow) * CH + h * HD + d;
                __half h0, l0, h1, l1;
                split2h(v.x, h0, l0); split2h(v.y, h1, l1);
                *(__half2*)&g_OC1[adr] = __halves2half2(h0, h1);
                *(__half2*)&g_OC2[adr] = __halves2half2(l0, l1);
            }
}

// ---------------- launch -----------------------------------------------------------
extern "C" void kernel_launch(void* const* d_in, const int* in_sizes, int n_in,
                              void* d_out, int out_size)
{
    const float *x = nullptr, *wqkv = nullptr, *wproj = nullptr,
                *bias = nullptr, *rm = nullptr;
    for (int i = 0; i < n_in; i++) {
        const float* p = (const float*)d_in[i];
        switch (in_sizes[i]) {
            case BATCH * SEQ * CH: x = p; break;
            case CH * 2 * CH:      wqkv = p; break;
            case CH * CH:          wproj = p; break;
            case CH:               bias = p; break;
            case NH * HD * RM:     rm = p; break;
        }
    }
    float* out = (float*)d_out;
    (void)out_size;

    cudaFuncSetAttribute(hmma_gemm<0>, cudaFuncAttributeMaxDynamicSharedMemorySize, DG_SMEM);
    cudaFuncSetAttribute(hmma_gemm<1>, cudaFuncAttributeMaxDynamicSharedMemorySize, DG_SMEM);
    cudaFuncSetAttribute(rf_hmma, cudaFuncAttributeMaxDynamicSharedMemorySize, RF_SMEM);
    cudaFuncSetAttribute(kkkv_hmma, cudaFuncAttributeMaxDynamicSharedMemorySize, KK_SMEM);
    cudaFuncSetAttribute(ista_fused, cudaFuncAttributeMaxDynamicSharedMemorySize, IST_SMEM);

    // conversions (all fp16)
    conv_x_kernel<<<BATCH * SEQ * CH / 1024, 256>>>(x);
    conv_wq_kernel<<<2 * CH * CH / 256, 256>>>(wqkv);
    conv_wp_kernel<<<CH * CH / 256, 256>>>(wproj);
    conv_rt_kernel<<<NH * RM * HD / 256, 256>>>(rm);

    // 1. qkv = x @ Wqkv (fp16; q cols 3-term, v cols 2-term)
    hmma_gemm<0><<<dim3(12, 256), 256, DG_SMEM>>>(nullptr, nullptr, CH);
    // 2. rf (fp16 3-term) -> rf fp16 pair
    rf_hmma<<<dim3(32, BH), 256, RF_SMEM>>>();
    // 3. kk/kv partials (fp16 2-term)
    kkkv_hmma<<<dim3(3, BH, SPLITS), 256, KK_SMEM>>>();
    // 4. fused reduce + d + L + ISTA -> sT fp16 single
    ista_fused<<<BH, 256, IST_SMEM>>>();
    // 5. out_head = rf @ s (fp16 2-term) -> OC fp16 pair
    outgemm_hmma<<<dim3(32, BH), 256>>>();
    // 6. final projection + bias (fp16 2-term)
    hmma_gemm<1><<<dim3(6, 256), 256, DG_SMEM>>>(bias, out, CH);
}

// round 12
// speedup vs baseline: 4.4975x; 1.0969x over previous
#include <cuda_runtime.h>
#include <cuda_fp16.h>
#include <math.h>
#include <cstdint>

// Problem constants
#define BATCH 8
#define SEQ   4096
#define CH    768
#define NH    12
#define HD    64
#define RM    128
#define BH    (BATCH*NH)
#define LAMBDA 0.3f
#define NSTEP 5
#define SPLITS 4
#define NCHUNK (SEQ/SPLITS)    // 1024

// ---------------- scratch ----------------------------------------------------
__device__ float g_PART[(size_t)SPLITS*BH*RM*(RM+HD)];
// fp16 split pairs / singles
__device__ __half g_XH1[(size_t)BATCH*SEQ*CH];       // x hi
__device__ __half g_XH2[(size_t)BATCH*SEQ*CH];       // x lo (q path only)
__device__ __half g_WQ1[(size_t)CH*CH];              // WqT pair [n][k]
__device__ __half g_WQ2[(size_t)CH*CH];
__device__ __half g_WV1[(size_t)CH*CH];              // WvT single
__device__ __half g_WP1[(size_t)CH*CH];              // WprojT single
__device__ __half g_QB1[(size_t)BH*SEQ*HD];          // qs pair [bh][n][d]
__device__ __half g_QB2[(size_t)BH*SEQ*HD];
__device__ __half g_RT1[(size_t)NH*RM*HD];           // R^T pair [h][m][d]
__device__ __half g_RT2[(size_t)NH*RM*HD];
__device__ __half g_RF1[(size_t)BH*SEQ*RM];          // rf pair [bh][n][m]
__device__ __half g_RF2[(size_t)BH*SEQ*RM];
__device__ __half g_VB1[(size_t)BH*SEQ*HD];          // v single [bh][n][d]
__device__ __half g_ST1[(size_t)BH*HD*RM];           // (d*s)^T single [bh][d][m]
__device__ __half g_OC1[(size_t)BATCH*SEQ*CH];       // out-head single

// ---------------- helpers ------------------------------------------------------
__device__ __forceinline__ uint32_t smem_u32(const void* p) {
    uint32_t a;
    asm("{ .reg .u64 t; cvta.to.shared.u64 t, %1; cvt.u32.u64 %0, t; }"
        : "=r"(a) : "l"(p));
    return a;
}
__device__ __forceinline__ void ldmx4(uint32_t& r0, uint32_t& r1,
                                      uint32_t& r2, uint32_t& r3, uint32_t addr)
{
    asm volatile("ldmatrix.sync.aligned.m8n8.x4.shared.b16 {%0,%1,%2,%3}, [%4];"
                 : "=r"(r0), "=r"(r1), "=r"(r2), "=r"(r3) : "r"(addr));
}
__device__ __forceinline__ void ldmx4t(uint32_t* r, uint32_t addr)
{
    asm volatile("ldmatrix.sync.aligned.m8n8.x4.trans.shared.b16 {%0,%1,%2,%3}, [%4];"
                 : "=r"(r[0]), "=r"(r[1]), "=r"(r[2]), "=r"(r[3]) : "r"(addr));
}
__device__ __forceinline__ void mma_f16(float* c, const uint32_t* a,
                                        const uint32_t* b)
{
    asm volatile(
        "mma.sync.aligned.m16n8k16.row.col.f32.f16.f16.f32 "
        "{%0,%1,%2,%3}, {%4,%5,%6,%7}, {%8,%9}, {%0,%1,%2,%3};"
        : "+f"(c[0]), "+f"(c[1]), "+f"(c[2]), "+f"(c[3])
        : "r"(a[0]), "r"(a[1]), "r"(a[2]), "r"(a[3]), "r"(b[0]), "r"(b[1]));
}
__device__ __forceinline__ void split2h(float v, __half& h, __half& l)
{
    h = __float2half(v);
    l = __float2half(v - __half2float(h));
}
__device__ __forceinline__ void cpa16(uint32_t saddr, const void* g)
{
    asm volatile("cp.async.cg.shared.global [%0], [%1], 16;"
                 :: "r"(saddr), "l"(g));
}
#define CP_COMMIT() asm volatile("cp.async.commit_group;")
#define CP_WAIT1()  asm volatile("cp.async.wait_group 1;")

#define PITCH 40
#define DG_TILE (128*PITCH)
#define DG_STAGE (4*DG_TILE)
#define DG_SMEM (2*DG_STAGE*2) // 81920 bytes

// ---------------- dense HMMA GEMM (fp16) -------------------------------------------
// EPI==0, q cols : 3-term (x pair x Wq pair)          -> q fp16 pair (scaled)
// EPI==0, v cols : 1-term (x hi   x Wv single)        -> v fp16 single
// EPI==1         : 1-term (OC single x WP single)+bias -> fp32 out
template<int EPI>
__global__ __launch_bounds__(256, 2)
void hmma_gemm(const float* __restrict__ bias, float* __restrict__ Cout, int Kdim)
{
    extern __shared__ uint16_t dsm[];

    const int tid  = threadIdx.x;
    const int wid  = tid >> 5;
    const int lane = tid & 31;
    const int wm   = wid & 1;
    const int wn   = wid >> 1;
    const int brow = blockIdx.y * 128;
    const int bcol = blockIdx.x * 128;

    const bool qmode = (EPI == 0) && (bcol < CH);
    const uint16_t* A1 = (EPI == 0) ? (const uint16_t*)g_XH1 : (const uint16_t*)g_OC1;
    const uint16_t* A2 = qmode ? (const uint16_t*)g_XH2 : nullptr;
    const uint16_t* B1;
    const uint16_t* B2 = nullptr;
    int bb0;
    if (EPI == 1)      { B1 = (const uint16_t*)g_WP1; bb0 = bcol; }
    else if (qmode)    { B1 = (const uint16_t*)g_WQ1;
                         B2 = (const uint16_t*)g_WQ2; bb0 = bcol; }
    else               { B1 = (const uint16_t*)g_WV1; bb0 = bcol - CH; }
    const int NT = qmode ? 4 : 2;   // tiles per stage: [A1,A2,B1,B2] or [A1,B1]

    float acc[4][4][4];
#pragma unroll
    for (int i = 0; i < 4; i++)
#pragma unroll
        for (int j = 0; j < 4; j++)
#pragma unroll
            for (int q = 0; q < 4; q++) acc[i][j][q] = 0.f;

    const uint32_t smbase = smem_u32(dsm);
    const int arow = wm * 64 + (lane & 15);
    const int acolL = (lane >> 4) * 8;
    const int bn   = wn * 32 + (lane & 7) + ((lane >> 4) & 1) * 8;
    const int bkL  = ((lane >> 3) & 1) * 8;

    const int l_row0 = tid >> 2,        l_ch0 = (tid & 3) * 8;
    const int l_row1 = (tid + 256) >> 2, l_ch1 = ((tid + 256) & 3) * 8;

    auto load_stage = [&](int stage, int k0) {
        uint32_t sb = smbase + stage * DG_STAGE * 2;
        for (int t = 0; t < NT; t++) {
            const uint16_t* src;
            int rbase;
            if (qmode) {
                src = (t == 0) ? A1 : (t == 1) ? A2 : (t == 2) ? B1 : B2;
                rbase = (t < 2) ? brow : bb0;
            } else {
                src = (t == 0) ? A1 : B1;
                rbase = (t == 0) ? brow : bb0;
            }
            uint32_t tb = sb + t * DG_TILE * 2;
            cpa16(tb + (l_row0 * PITCH + l_ch0) * 2,
                  src + (size_t)(rbase + l_row0) * Kdim + k0 + l_ch0);
            cpa16(tb + (l_row1 * PITCH + l_ch1) * 2,
                  src + (size_t)(rbase + l_row1) * Kdim + k0 + l_ch1);
        }
    };

    const int nchunk = Kdim >> 5;
    load_stage(0, 0);
    CP_COMMIT();

    for (int kc = 0; kc < nchunk; kc++) {
        if (kc + 1 < nchunk) load_stage((kc + 1) & 1, (kc + 1) << 5);
        CP_COMMIT();
        CP_WAIT1();
        __syncthreads();

        const uint32_t sb = smbase + (kc & 1) * DG_STAGE * 2;
        const uint32_t as1 = sb;
        const uint32_t as2 = sb + DG_TILE * 2;                     // qmode only
        const uint32_t bs1 = qmode ? sb + 2 * DG_TILE * 2 : sb + DG_TILE * 2;
        const uint32_t bs2 = sb + 3 * DG_TILE * 2;                 // qmode only
#pragma unroll
        for (int ks = 0; ks < 2; ks++) {
            const int acol = ks * 16 + acolL;
            const int bk   = ks * 16 + bkL;
            uint32_t a1[4][4], a2[4][4], b1[4][2], b2[4][2];
#pragma unroll
            for (int mt = 0; mt < 4; mt++) {
                uint32_t off = ((arow + mt * 16) * PITCH + acol) * 2;
                ldmx4(a1[mt][0], a1[mt][1], a1[mt][2], a1[mt][3], as1 + off);
                if (qmode)
                    ldmx4(a2[mt][0], a2[mt][1], a2[mt][2], a2[mt][3], as2 + off);
            }
#pragma unroll
            for (int nt2 = 0; nt2 < 2; nt2++) {
                uint32_t off = ((bn + nt2 * 16) * PITCH + bk) * 2;
                ldmx4(b1[nt2 * 2][0], b1[nt2 * 2][1],
                      b1[nt2 * 2 + 1][0], b1[nt2 * 2 + 1][1], bs1 + off);
                if (qmode)
                    ldmx4(b2[nt2 * 2][0], b2[nt2 * 2][1],
                          b2[nt2 * 2 + 1][0], b2[nt2 * 2 + 1][1], bs2 + off);
            }
            if (qmode) {
#pragma unroll
                for (int mt = 0; mt < 4; mt++)
#pragma unroll
                    for (int nt = 0; nt < 4; nt++) {
                        mma_f16(acc[mt][nt], a1[mt], b1[nt]);
                        mma_f16(acc[mt][nt], a1[mt], b2[nt]);
                        mma_f16(acc[mt][nt], a2[mt], b1[nt]);
                    }
            } else {
#pragma unroll
                for (int mt = 0; mt < 4; mt++)
#pragma unroll
                    for (int nt = 0; nt < 4; nt++)
                        mma_f16(acc[mt][nt], a1[mt], b1[nt]);
            }
        }
        __syncthreads();
    }

    const int g  = lane >> 2;
    const int tg = lane & 3;
#pragma unroll
    for (int mt = 0; mt < 4; mt++)
#pragma unroll
        for (int nt = 0; nt < 4; nt++) {
#pragma unroll
            for (int half = 0; half < 2; half++) {
                int grow = brow + wm * 64 + mt * 16 + g + half * 8;
                int col  = bcol + wn * 32 + nt * 8 + tg * 2;
                float2 v = make_float2(acc[mt][nt][half * 2],
                                       acc[mt][nt][half * 2 + 1]);
                if (EPI == 0) {
                    int bb = grow >> 12, nn = grow & 4095;
                    if (col < CH) {
                        const float s = 0.35355339059327373f;  // hd^(-1/4)
                        v.x *= s; v.y *= s;
                        int h = col >> 6, dd = col & 63;
                        size_t adr = (((size_t)(bb * NH + h)) * SEQ + nn) * HD + dd;
                        __half h0, l0, h1, l1;
                        split2h(v.x, h0, l0); split2h(v.y, h1, l1);
                        *(__half2*)&g_QB1[adr] = __halves2half2(h0, h1);
                        *(__half2*)&g_QB2[adr] = __halves2half2(l0, l1);
                    } else {
                        int c2 = col - CH;
                        int h = c2 >> 6, dd = c2 & 63;
                        size_t adr = (((size_t)(bb * NH + h)) * SEQ + nn) * HD + dd;
                        *(__half2*)&g_VB1[adr] =
                            __halves2half2(__float2half(v.x), __float2half(v.y));
                    }
                } else {
                    v.x += bias[col];
                    v.y += bias[col + 1];
                    *(float2*)&Cout[(size_t)grow * CH + col] = v;
                }
            }
        }
}

// ---------------- conversion kernels -----------------------------------------
__global__ __launch_bounds__(256)
void conv_x_kernel(const float* __restrict__ x)
{
    size_t i = ((size_t)blockIdx.x * 256 + threadIdx.x) * 4;
    float4 v = *(const float4*)&x[i];
    __half h0, l0, h1, l1, h2, l2, h3, l3;
    split2h(v.x, h0, l0); split2h(v.y, h1, l1);
    split2h(v.z, h2, l2); split2h(v.w, h3, l3);
    *(__half2*)&g_XH1[i]     = __halves2half2(h0, h1);
    *(__half2*)&g_XH1[i + 2] = __halves2half2(h2, h3);
    *(__half2*)&g_XH2[i]     = __halves2half2(l0, l1);
    *(__half2*)&g_XH2[i + 2] = __halves2half2(l2, l3);
}

__global__ __launch_bounds__(256)
void conv_wq_kernel(const float* __restrict__ W)
{
    int idx = blockIdx.x * 256 + threadIdx.x;   // over [1536][768], n outer
    int n = idx / CH, k = idx - n * CH;
    float v = W[(size_t)k * (2 * CH) + n];
    if (n < CH) {
        __half h, l;
        split2h(v, h, l);
        g_WQ1[(size_t)n * CH + k] = h;
        g_WQ2[(size_t)n * CH + k] = l;
    } else {
        g_WV1[(size_t)(n - CH) * CH + k] = __float2half(v);
    }
}

__global__ __launch_bounds__(256)
void conv_wp_kernel(const float* __restrict__ W)
{
    int idx = blockIdx.x * 256 + threadIdx.x;
    int n = idx / CH, k = idx - n * CH;
    g_WP1[idx] = __float2half(W[(size_t)k * CH + n]);
}

// R [h][d][m] -> R^T pair [h][m][d]
__global__ __launch_bounds__(256)
void conv_rt_kernel(const float* __restrict__ randm)
{
    int idx = blockIdx.x * 256 + threadIdx.x;
    int h = idx / (RM * HD);
    int r = idx - h * (RM * HD);
    int m = r / HD, d = r - m * HD;
    float v = randm[((size_t)h * HD + d) * RM + m];
    __half hi, lo;
    split2h(v, hi, lo);
    g_RT1[idx] = hi;
    g_RT2[idx] = lo;
}

// ---------------- rf via HMMA (fp16 3-term), emits fp16 pair ---------------------
#define RF_PITCH 72
#define RF_TILE (128*RF_PITCH)
#define RF_SMEM (4*RF_TILE*2)

__global__ __launch_bounds__(256, 2)
void rf_hmma()
{
    extern __shared__ __half rsm[];
    __shared__ float rowq2[128];
    const int tid = threadIdx.x, wid = tid >> 5, lane = tid & 31;
    const int wm = wid & 1, wn = wid >> 1;
    const int bh = blockIdx.y, h = bh % NH;
    const int brow = blockIdx.x * 128;

    const __half* A1 = g_QB1 + ((size_t)bh * SEQ + brow) * HD;
    const __half* A2 = g_QB2 + ((size_t)bh * SEQ + brow) * HD;
    const __half* B1 = g_RT1 + (size_t)h * RM * HD;
    const __half* B2 = g_RT2 + (size_t)h * RM * HD;

#pragma unroll
    for (int t = 0; t < 4; t++) {
        const __half* src = (t == 0) ? A1 : (t == 1) ? A2 : (t == 2) ? B1 : B2;
        __half* dst = rsm + t * RF_TILE;
#pragma unroll
        for (int u = 0; u < 4; u++) {
            int f = u * 256 + tid;
            int r = f >> 3, c = (f & 7) * 8;
            *(uint4*)(dst + r * RF_PITCH + c) = *(const uint4*)(src + (size_t)r * HD + c);
        }
    }
    __syncthreads();

    {
        int r = tid >> 1;
        int k0 = (tid & 1) * 32;
        const __half* q1 = rsm + r * RF_PITCH + k0;
        const __half* q2 = rsm + RF_TILE + r * RF_PITCH + k0;
        float s = 0.f;
#pragma unroll
        for (int k = 0; k < 32; k++) {
            float v = __half2float(q1[k]) + __half2float(q2[k]);
            s += v * v;
        }
        s += __shfl_xor_sync(0xffffffffu, s, 1);
        if (!(tid & 1)) rowq2[r] = s;
    }

    float acc[4][4][4];
#pragma unroll
    for (int i = 0; i < 4; i++)
#pragma unroll
        for (int j = 0; j < 4; j++)
#pragma unroll
            for (int q = 0; q < 4; q++) acc[i][j][q] = 0.f;

    const uint32_t smbase = smem_u32(rsm);
    const uint32_t as1 = smbase, as2 = smbase + RF_TILE * 2;
    const uint32_t bs1 = smbase + 2 * RF_TILE * 2, bs2 = smbase + 3 * RF_TILE * 2;
    const int arow = wm * 64 + (lane & 15);
    const int acolL = (lane >> 4) * 8;
    const int bn   = wn * 32 + (lane & 7) + ((lane >> 4) & 1) * 8;
    const int bkL  = ((lane >> 3) & 1) * 8;

#pragma unroll
    for (int ks = 0; ks < 4; ks++) {
        const int acol = ks * 16 + acolL;
        const int bk   = ks * 16 + bkL;
        uint32_t a1[4][4], a2[4][4], b1[4][2], b2[4][2];
#pragma unroll
        for (int mt = 0; mt < 4; mt++) {
            uint32_t off = ((arow + mt * 16) * RF_PITCH + acol) * 2;
            ldmx4(a1[mt][0], a1[mt][1], a1[mt][2], a1[mt][3], as1 + off);
            ldmx4(a2[mt][0], a2[mt][1], a2[mt][2], a2[mt][3], as2 + off);
        }
#pragma unroll
        for (int nt2 = 0; nt2 < 2; nt2++) {
            uint32_t off = ((bn + nt2 * 16) * RF_PITCH + bk) * 2;
            ldmx4(b1[nt2 * 2][0], b1[nt2 * 2][1],
                  b1[nt2 * 2 + 1][0], b1[nt2 * 2 + 1][1], bs1 + off);
            ldmx4(b2[nt2 * 2][0], b2[nt2 * 2][1],
                  b2[nt2 * 2 + 1][0], b2[nt2 * 2 + 1][1], bs2 + off);
        }
#pragma unroll
        for (int mt = 0; mt < 4; mt++)
#pragma unroll
            for (int nt = 0; nt < 4; nt++) {
                mma_f16(acc[mt][nt], a1[mt], b1[nt]);
                mma_f16(acc[mt][nt], a1[mt], b2[nt]);
                mma_f16(acc[mt][nt], a2[mt], b1[nt]);
            }
    }
    __syncthreads();

    const int g  = lane >> 2;
    const int tg = lane & 3;
    const float sc = 0.08838834764831845f;  // 1/sqrt(128)
#pragma unroll
    for (int mt = 0; mt < 4; mt++)
#pragma unroll
        for (int nt = 0; nt < 4; nt++)
#pragma unroll
            for (int half = 0; half < 2; half++) {
                int row  = wm * 64 + mt * 16 + g + half * 8;
                int mcol = wn * 32 + nt * 8 + tg * 2;
                float base = -0.5f * rowq2[row];
                float v0 = expf(acc[mt][nt][half * 2]     + base) * sc;
                float v1 = expf(acc[mt][nt][half * 2 + 1] + base) * sc;
                __half h0, l0, h1, l1;
                split2h(v0, h0, l0); split2h(v1, h1, l1);
                size_t adr = ((size_t)bh * SEQ + brow + row) * RM + mcol;
                *(__half2*)&g_RF1[adr] = __halves2half2(h0, h1);
                *(__half2*)&g_RF2[adr] = __halves2half2(l0, l1);
            }
}

// ---------------- kk/kv via fp16 2-term HMMA (A=rf pair, B single) ---------------
#define KK_A_TILE (32*136)
#define KK_Y_TILE (32*72)
#define KK_STAGE (2*KK_A_TILE + KK_Y_TILE)
#define KK_SMEM (2*KK_STAGE*2)

__global__ __launch_bounds__(256, 2)
void kkkv_hmma()
{
    extern __shared__ __half ksm[];
    const int tid = threadIdx.x, wid = tid >> 5, lane = tid & 31;
    const int ct = blockIdx.x, bh = blockIdx.y, split = blockIdx.z;
    const int wm = wid >> 1, wn = wid & 1;

    size_t abase = ((size_t)bh * SEQ + (size_t)split * NCHUNK) * RM;
    const __half *a1 = g_RF1 + abase, *a2 = g_RF2 + abase;
    const __half *b1;
    int bstr;
    if (ct == 2) {
        b1 = g_VB1 + ((size_t)bh * SEQ + (size_t)split * NCHUNK) * HD;
        bstr = HD;
    } else {
        b1 = a1 + ct * 64;
        bstr = RM;
    }

    float acc[2][4][4];
#pragma unroll
    for (int i = 0; i < 2; i++)
#pragma unroll
        for (int j = 0; j < 4; j++)
#pragma unroll
            for (int q = 0; q < 4; q++) acc[i][j][q] = 0.f;

    const uint32_t smbase = smem_u32(ksm);
    const int a_r = (lane & 7) + (lane >> 4) * 8;
    const int a_c = ((lane >> 3) & 1) * 8;
    const int b_r = (lane & 7) + ((lane >> 3) & 1) * 8;
    const int b_c = (lane >> 4) * 8;

    const int ar0 = tid >> 4,        ac0 = (tid & 15) * 8;
    const int ar1 = (tid + 256) >> 4, ac1 = ((tid + 256) & 15) * 8;
    const int yr = tid >> 3, yc = (tid & 7) * 8;
    auto load_stage = [&](int stage, int n0) {
        uint32_t sb = smbase + stage * KK_STAGE * 2;
        uint32_t sA1 = sb, sA2 = sb + KK_A_TILE * 2;
        uint32_t sY1 = sb + 2 * KK_A_TILE * 2;
        cpa16(sA1 + (ar0 * 136 + ac0) * 2, a1 + (size_t)(n0 + ar0) * RM + ac0);
        cpa16(sA1 + (ar1 * 136 + ac1) * 2, a1 + (size_t)(n0 + ar1) * RM + ac1);
        cpa16(sA2 + (ar0 * 136 + ac0) * 2, a2 + (size_t)(n0 + ar0) * RM + ac0);
        cpa16(sA2 + (ar1 * 136 + ac1) * 2, a2 + (size_t)(n0 + ar1) * RM + ac1);
        cpa16(sY1 + (yr * 72 + yc) * 2, b1 + (size_t)(n0 + yr) * bstr + yc);
    };

    load_stage(0, 0);
    CP_COMMIT();

    for (int chunk = 0; chunk < NCHUNK / 32; chunk++) {
        if (chunk + 1 < NCHUNK / 32) load_stage((chunk + 1) & 1, (chunk + 1) * 32);
        CP_COMMIT();
        CP_WAIT1();
        __syncthreads();

        uint32_t sb = smbase + (chunk & 1) * KK_STAGE * 2;
        uint32_t as1 = sb, as2 = sb + KK_A_TILE * 2;
        uint32_t ys1 = sb + 2 * KK_A_TILE * 2;
#pragma unroll
        for (int ks = 0; ks < 2; ks++) {
            uint32_t A1f[2][4], A2f[2][4], B1f[4][2];
#pragma unroll
            for (int mt = 0; mt < 2; mt++) {
                uint32_t off = ((ks * 16 + a_r) * 136 + wm * 32 + mt * 16 + a_c) * 2;
                ldmx4t(A1f[mt], as1 + off);
                ldmx4t(A2f[mt], as2 + off);
            }
#pragma unroll
            for (int nb = 0; nb < 2; nb++) {
                uint32_t off = ((ks * 16 + b_r) * 72 + wn * 32 + nb * 16 + b_c) * 2;
                uint32_t t1[4];
                ldmx4t(t1, ys1 + off);
                B1f[nb * 2][0] = t1[0]; B1f[nb * 2][1] = t1[1];
                B1f[nb * 2 + 1][0] = t1[2]; B1f[nb * 2 + 1][1] = t1[3];
            }
#pragma unroll
            for (int mt = 0; mt < 2; mt++)
#pragma unroll
                for (int nt = 0; nt < 4; nt++) {
                    mma_f16(acc[mt][nt], A1f[mt], B1f[nt]);
                    mma_f16(acc[mt][nt], A2f[mt], B1f[nt]);
                }
        }
        __syncthreads();
    }

    float* dst = g_PART + ((size_t)split * BH + bh) * (RM * (RM + HD));
#pragma unroll
    for (int mt = 0; mt < 2; mt++)
#pragma unroll
        for (int nt = 0; nt < 4; nt++)
#pragma unroll
            for (int half = 0; half < 2; half++) {
                int m = wm * 32 + mt * 16 + (lane >> 2) + half * 8;
                int j = ct * 64 + wn * 32 + nt * 8 + (lane & 3) * 2;
                *(float2*)&dst[m * (RM + HD) + j] =
                    make_float2(acc[mt][nt][half * 2], acc[mt][nt][half * 2 + 1]);
            }
}

// ---------------- fused reduce + ISTA (emits (d*s)^T fp16 single) ----------------
__device__ __forceinline__ float softf(float z, float t)
{
    float a = fabsf(z) - t;
    return a > 0.f ? (z >= 0.f ? a : -a) : 0.f;
}

#define IST_SMEM ((RM*129 + RM*HD + RM*68) * 4)

__global__ __launch_bounds__(256)
void ista_fused()
{
    extern __shared__ float sm[];
    float* kks = sm;
    float* kvs = sm + RM * 129;
    float* ss  = kvs + RM * HD;
    __shared__ float dsh[RM];
    __shared__ float rowsum[RM];
    __shared__ float Lsh;
    int bh = blockIdx.x;
    const float* part = g_PART;

    if (threadIdx.x < RM) {
        float s = 0.f;
#pragma unroll
        for (int sp = 0; sp < SPLITS; sp++)
            s += part[((size_t)sp * BH + bh) * (RM * (RM + HD))
                      + threadIdx.x * (RM + HD) + threadIdx.x];
        dsh[threadIdx.x] = 1.0f / fmaxf(sqrtf(s), 1e-12f);
    }
    __syncthreads();

    for (int idx = threadIdx.x; idx < RM * (RM + HD); idx += 256) {
        int m = idx / (RM + HD);
        int j = idx - m * (RM + HD);
        float s = 0.f;
#pragma unroll
        for (int sp = 0; sp < SPLITS; sp++)
            s += part[((size_t)sp * BH + bh) * (RM * (RM + HD)) + idx];
        if (j < RM) kks[m * 129 + j] = s * dsh[m] * dsh[j];
        else        kvs[m * HD + (j - RM)] = s * dsh[m];
    }
    __syncthreads();

    if (threadIdx.x < RM) {
        float rs = 0.f;
        for (int j = 0; j < RM; j++) rs += fabsf(kks[threadIdx.x * 129 + j]);
        rowsum[threadIdx.x] = rs;
    }
    __syncthreads();
    if (threadIdx.x == 0) {
        float mx = 0.f;
        for (int i = 0; i < RM; i++) mx = fmaxf(mx, rowsum[i]);
        Lsh = mx + 1.0f;
    }
    __syncthreads();
    float invL = 1.0f / Lsh;
    float thr  = LAMBDA * invL;

    int m  = threadIdx.x >> 1;
    int ch = (threadIdx.x & 1) * 32;
#pragma unroll
    for (int i = 0; i < 32; i++)
        ss[m * 68 + ch + i] = softf(kvs[m * HD + ch + i], LAMBDA);
    __syncthreads();

    for (int it = 0; it < NSTEP; it++) {
        float acc[32];
#pragma unroll
        for (int i = 0; i < 32; i++) acc[i] = 0.f;
        for (int p = 0; p < RM; p++) {
            float kv_ = kks[m * 129 + p];
            const float4* sp = (const float4*)&ss[p * 68 + ch];
#pragma unroll
            for (int q = 0; q < 8; q++) {
                float4 v = sp[q];
                acc[q * 4 + 0] += kv_ * v.x;
                acc[q * 4 + 1] += kv_ * v.y;
                acc[q * 4 + 2] += kv_ * v.z;
                acc[q * 4 + 3] += kv_ * v.w;
            }
        }
        float r[32];
#pragma unroll
        for (int i = 0; i < 32; i++) {
            float z = ss[m * 68 + ch + i] - (acc[i] - kvs[m * HD + ch + i]) * invL;
            r[i] = softf(z, thr);
        }
        __syncthreads();
#pragma unroll
        for (int q = 0; q < 8; q++)
            *(float4*)&ss[m * 68 + ch + q * 4] =
                make_float4(r[q * 4], r[q * 4 + 1], r[q * 4 + 2], r[q * 4 + 3]);
        __syncthreads();
    }
    float dm = dsh[m];
#pragma unroll
    for (int q = 0; q < 8; q++) {
        float4 v = *(float4*)&ss[m * 68 + ch + q * 4];
        v.x *= dm; v.y *= dm; v.z *= dm; v.w *= dm;
        *(float4*)&ss[m * 68 + ch + q * 4] = v;
    }
    __syncthreads();
    int d  = threadIdx.x >> 2;
    int ms = (threadIdx.x & 3) * 32;
    size_t ob = ((size_t)bh * HD + d) * RM + ms;
#pragma unroll
    for (int i = 0; i < 32; i += 2) {
        float v0 = ss[(ms + i) * 68 + d];
        float v1 = ss[(ms + i + 1) * 68 + d];
        *(__half2*)&g_ST1[ob + i] =
            __halves2half2(__float2half(v0), __float2half(v1));
    }
}

// ---------------- out = rf(pair) @ sT(single) fp16 2-term, emits OC single --------
__global__ __launch_bounds__(256, 2)
void outgemm_hmma()
{
    __shared__ __half As1[128 * PITCH], As2[128 * PITCH];
    __shared__ __half Bs1[64 * PITCH];
    const int tid = threadIdx.x, wid = tid >> 5, lane = tid & 31;
    const int wm = wid & 3, wn = wid >> 2;
    const int bh = blockIdx.y, nblk = blockIdx.x;
    const int b = bh / NH, h = bh % NH;

    size_t rfbase = ((size_t)bh * SEQ + (size_t)nblk * 128) * RM;
    size_t stbase = (size_t)bh * HD * RM;

    float acc[2][4][4];
#pragma unroll
    for (int i = 0; i < 2; i++)
#pragma unroll
        for (int j = 0; j < 4; j++)
#pragma unroll
            for (int q = 0; q < 4; q++) acc[i][j][q] = 0.f;

    const uint32_t as1 = smem_u32(As1), as2 = smem_u32(As2);
    const uint32_t bs1 = smem_u32(Bs1);
    const int arow = wm * 32 + (lane & 15);
    const int acolL = (lane >> 4) * 8;
    const int bn   = wn * 32 + (lane & 7) + ((lane >> 4) & 1) * 8;
    const int bkL  = ((lane >> 3) & 1) * 8;

    for (int kc = 0; kc < 4; kc++) {
        const int k0 = kc * 32;
#pragma unroll
        for (int l = 0; l < 2; l++) {
            int f = tid + l * 256;
            int r = f >> 2, c = (f & 3) * 8;
            *(uint4*)(As1 + r * PITCH + c) =
                *(const uint4*)(g_RF1 + rfbase + (size_t)r * RM + k0 + c);
            *(uint4*)(As2 + r * PITCH + c) =
                *(const uint4*)(g_RF2 + rfbase + (size_t)r * RM + k0 + c);
        }
        {
            int r = tid >> 2, c = (tid & 3) * 8;
            if (r < 64)
                *(uint4*)(Bs1 + r * PITCH + c) =
                    *(const uint4*)(g_ST1 + stbase + (size_t)r * RM + k0 + c);
        }
        __syncthreads();
#pragma unroll
        for (int ks = 0; ks < 2; ks++) {
            const int acol = ks * 16 + acolL;
            const int bk   = ks * 16 + bkL;
            uint32_t a1[2][4], a2[2][4], b1[4][2];
#pragma unroll
            for (int mt = 0; mt < 2; mt++) {
                uint32_t off = ((arow + mt * 16) * PITCH + acol) * 2;
                ldmx4(a1[mt][0], a1[mt][1], a1[mt][2], a1[mt][3], as1 + off);
                ldmx4(a2[mt][0], a2[mt][1], a2[mt][2], a2[mt][3], as2 + off);
            }
#pragma unroll
            for (int nt2 = 0; nt2 < 2; nt2++) {
                uint32_t off = ((bn + nt2 * 16) * PITCH + bk) * 2;
                ldmx4(b1[nt2 * 2][0], b1[nt2 * 2][1],
                      b1[nt2 * 2 + 1][0], b1[nt2 * 2 + 1][1], bs1 + off);
            }
#pragma unroll
            for (int mt = 0; mt < 2; mt++)
#pragma unroll
                for (int nt = 0; nt < 4; nt++) {
                    mma_f16(acc[mt][nt], a1[mt], b1[nt]);
                    mma_f16(acc[mt][nt], a2[mt], b1[nt]);
                }
        }
        __syncthreads();
    }

    const int g  = lane >> 2;
    const int tg = lane & 3;
#pragma unroll
    for (int mt = 0; mt < 2; mt++)
#pragma unroll
        for (int nt = 0; nt < 4; nt++)
#pragma unroll
            for (int half = 0; half < 2; half++) {
                int nrow = nblk * 128 + wm * 32 + mt * 16 + g + half * 8;
                int d    = wn * 32 + nt * 8 + tg * 2;
                float2 v = make_float2(acc[mt][nt][half * 2],
                                       acc[mt][nt][half * 2 + 1]);
                size_t adr = ((size_t)b * SEQ + nrow) * CH + h * HD + d;
                *(__half2*)&g_OC1[adr] =
                    __halves2half2(__float2half(v.x), __float2half(v.y));
            }
}

// ---------------- launch -----------------------------------------------------------
extern "C" void kernel_launch(void* const* d_in, const int* in_sizes, int n_in,
                              void* d_out, int out_size)
{
    const float *x = nullptr, *wqkv = nullptr, *wproj = nullptr,
                *bias = nullptr, *rm = nullptr;
    for (int i = 0; i < n_in; i++) {
        const float* p = (const float*)d_in[i];
        switch (in_sizes[i]) {
            case BATCH * SEQ * CH: x = p; break;
            case CH * 2 * CH:      wqkv = p; break;
            case CH * CH:          wproj = p; break;
            case CH:               bias = p; break;
            case NH * HD * RM:     rm = p; break;
        }
    }
    float* out = (float*)d_out;
    (void)out_size;

    cudaFuncSetAttribute(hmma_gemm<0>, cudaFuncAttributeMaxDynamicSharedMemorySize, DG_SMEM);
    cudaFuncSetAttribute(hmma_gemm<1>, cudaFuncAttributeMaxDynamicSharedMemorySize, DG_SMEM);
    cudaFuncSetAttribute(rf_hmma, cudaFuncAttributeMaxDynamicSharedMemorySize, RF_SMEM);
    cudaFuncSetAttribute(kkkv_hmma, cudaFuncAttributeMaxDynamicSharedMemorySize, KK_SMEM);
    cudaFuncSetAttribute(ista_fused, cudaFuncAttributeMaxDynamicSharedMemorySize, IST_SMEM);

    // conversions (all fp16)
    conv_x_kernel<<<BATCH * SEQ * CH / 1024, 256>>>(x);
    conv_wq_kernel<<<2 * CH * CH / 256, 256>>>(wqkv);
    conv_wp_kernel<<<CH * CH / 256, 256>>>(wproj);
    conv_rt_kernel<<<NH * RM * HD / 256, 256>>>(rm);

    // 1. qkv = x @ Wqkv (q cols 3-term, v cols 1-term)
    hmma_gemm<0><<<dim3(12, 256), 256, DG_SMEM>>>(nullptr, nullptr, CH);
    // 2. rf (fp16 3-term) -> rf fp16 pair
    rf_hmma<<<dim3(32, BH), 256, RF_SMEM>>>();
    // 3. kk/kv partials (fp16 2-term)
    kkkv_hmma<<<dim3(3, BH, SPLITS), 256, KK_SMEM>>>();
    // 4. fused reduce + d + L + ISTA -> sT fp16 single
    ista_fused<<<BH, 256, IST_SMEM>>>();
    // 5. out_head = rf @ s (fp16 2-term) -> OC fp16 single
    outgemm_hmma<<<dim3(32, BH), 256>>>();
    // 6. final projection + bias (fp16 1-term)
    hmma_gemm<1><<<dim3(6, 256), 256, DG_SMEM>>>(bias, out, CH);
}

// round 13
// speedup vs baseline: 4.6236x; 1.0280x over previous
#include <cuda_runtime.h>
#include <cuda_fp16.h>
#include <math.h>
#include <cstdint>

// Problem constants
#define BATCH 8
#define SEQ   4096
#define CH    768
#define NH    12
#define HD    64
#define RM    128
#define BH    (BATCH*NH)
#define LAMBDA 0.3f
#define NSTEP 5
#define SPLITS 4
#define NCHUNK (SEQ/SPLITS)    // 1024

// ---------------- scratch ----------------------------------------------------
__device__ float g_PART[(size_t)SPLITS*BH*RM*(RM+HD)];
// fp16 split pairs / singles
__device__ __half g_XH1[(size_t)BATCH*SEQ*CH];       // x hi
__device__ __half g_XH2[(size_t)BATCH*SEQ*CH];       // x lo (q path only)
__device__ __half g_WQ1[(size_t)CH*CH];              // WqT single [n][k]
__device__ __half g_WV1[(size_t)CH*CH];              // WvT single
__device__ __half g_WP1[(size_t)CH*CH];              // WprojT single
__device__ __half g_QB1[(size_t)BH*SEQ*HD];          // qs pair [bh][n][d]
__device__ __half g_QB2[(size_t)BH*SEQ*HD];
__device__ __half g_RT1[(size_t)NH*RM*HD];           // R^T pair [h][m][d]
__device__ __half g_RT2[(size_t)NH*RM*HD];
__device__ __half g_RF1[(size_t)BH*SEQ*RM];          // rf pair [bh][n][m]
__device__ __half g_RF2[(size_t)BH*SEQ*RM];
__device__ __half g_VB1[(size_t)BH*SEQ*HD];          // v single [bh][n][d]
__device__ __half g_ST1[(size_t)BH*HD*RM];           // (d*s)^T single [bh][d][m]
__device__ __half g_OC1[(size_t)BATCH*SEQ*CH];       // out-head single

// ---------------- helpers ------------------------------------------------------
__device__ __forceinline__ uint32_t smem_u32(const void* p) {
    uint32_t a;
    asm("{ .reg .u64 t; cvta.to.shared.u64 t, %1; cvt.u32.u64 %0, t; }"
        : "=r"(a) : "l"(p));
    return a;
}
__device__ __forceinline__ void ldmx4(uint32_t& r0, uint32_t& r1,
                                      uint32_t& r2, uint32_t& r3, uint32_t addr)
{
    asm volatile("ldmatrix.sync.aligned.m8n8.x4.shared.b16 {%0,%1,%2,%3}, [%4];"
                 : "=r"(r0), "=r"(r1), "=r"(r2), "=r"(r3) : "r"(addr));
}
__device__ __forceinline__ void ldmx4t(uint32_t* r, uint32_t addr)
{
    asm volatile("ldmatrix.sync.aligned.m8n8.x4.trans.shared.b16 {%0,%1,%2,%3}, [%4];"
                 : "=r"(r[0]), "=r"(r[1]), "=r"(r[2]), "=r"(r[3]) : "r"(addr));
}
__device__ __forceinline__ void mma_f16(float* c, const uint32_t* a,
                                        const uint32_t* b)
{
    asm volatile(
        "mma.sync.aligned.m16n8k16.row.col.f32.f16.f16.f32 "
        "{%0,%1,%2,%3}, {%4,%5,%6,%7}, {%8,%9}, {%0,%1,%2,%3};"
        : "+f"(c[0]), "+f"(c[1]), "+f"(c[2]), "+f"(c[3])
        : "r"(a[0]), "r"(a[1]), "r"(a[2]), "r"(a[3]), "r"(b[0]), "r"(b[1]));
}
__device__ __forceinline__ void split2h(float v, __half& h, __half& l)
{
    h = __float2half(v);
    l = __float2half(v - __half2float(h));
}
__device__ __forceinline__ void cpa16(uint32_t saddr, const void* g)
{
    asm volatile("cp.async.cg.shared.global [%0], [%1], 16;"
                 :: "r"(saddr), "l"(g));
}
#define CP_COMMIT() asm volatile("cp.async.commit_group;")
#define CP_WAIT1()  asm volatile("cp.async.wait_group 1;")

#define PITCH 40
#define DG_TILE (128*PITCH)
#define DG_STAGE (3*DG_TILE)
#define DG_SMEM (2*DG_STAGE*2) // 61440 bytes

// ---------------- dense HMMA GEMM (fp16) -------------------------------------------
// EPI==0, q cols : 2-term (x pair x Wq single)         -> q fp16 pair (scaled)
// EPI==0, v cols : 1-term (x hi   x Wv single)         -> v fp16 single
// EPI==1         : 1-term (OC single x WP single)+bias -> fp32 out
template<int EPI>
__global__ __launch_bounds__(256, 2)
void hmma_gemm(const float* __restrict__ bias, float* __restrict__ Cout, int Kdim)
{
    extern __shared__ uint16_t dsm[];

    const int tid  = threadIdx.x;
    const int wid  = tid >> 5;
    const int lane = tid & 31;
    const int wm   = wid & 1;
    const int wn   = wid >> 1;
    const int brow = blockIdx.y * 128;
    const int bcol = blockIdx.x * 128;

    const bool qmode = (EPI == 0) && (bcol < CH);
    const uint16_t* A1 = (EPI == 0) ? (const uint16_t*)g_XH1 : (const uint16_t*)g_OC1;
    const uint16_t* A2 = qmode ? (const uint16_t*)g_XH2 : nullptr;
    const uint16_t* B1;
    int bb0;
    if (EPI == 1)      { B1 = (const uint16_t*)g_WP1; bb0 = bcol; }
    else if (qmode)    { B1 = (const uint16_t*)g_WQ1; bb0 = bcol; }
    else               { B1 = (const uint16_t*)g_WV1; bb0 = bcol - CH; }
    const int NT = qmode ? 3 : 2;   // tiles per stage: [A1,A2,B1] or [A1,B1]

    float acc[4][4][4];
#pragma unroll
    for (int i = 0; i < 4; i++)
#pragma unroll
        for (int j = 0; j < 4; j++)
#pragma unroll
            for (int q = 0; q < 4; q++) acc[i][j][q] = 0.f;

    const uint32_t smbase = smem_u32(dsm);
    const int arow = wm * 64 + (lane & 15);
    const int acolL = (lane >> 4) * 8;
    const int bn   = wn * 32 + (lane & 7) + ((lane >> 4) & 1) * 8;
    const int bkL  = ((lane >> 3) & 1) * 8;

    const int l_row0 = tid >> 2,        l_ch0 = (tid & 3) * 8;
    const int l_row1 = (tid + 256) >> 2, l_ch1 = ((tid + 256) & 3) * 8;

    auto load_stage = [&](int stage, int k0) {
        uint32_t sb = smbase + stage * DG_STAGE * 2;
        for (int t = 0; t < NT; t++) {
            const uint16_t* src;
            int rbase;
            if (qmode) {
                src = (t == 0) ? A1 : (t == 1) ? A2 : B1;
                rbase = (t < 2) ? brow : bb0;
            } else {
                src = (t == 0) ? A1 : B1;
                rbase = (t == 0) ? brow : bb0;
            }
            uint32_t tb = sb + t * DG_TILE * 2;
            cpa16(tb + (l_row0 * PITCH + l_ch0) * 2,
                  src + (size_t)(rbase + l_row0) * Kdim + k0 + l_ch0);
            cpa16(tb + (l_row1 * PITCH + l_ch1) * 2,
                  src + (size_t)(rbase + l_row1) * Kdim + k0 + l_ch1);
        }
    };

    const int nchunk = Kdim >> 5;
    load_stage(0, 0);
    CP_COMMIT();

    for (int kc = 0; kc < nchunk; kc++) {
        if (kc + 1 < nchunk) load_stage((kc + 1) & 1, (kc + 1) << 5);
        CP_COMMIT();
        CP_WAIT1();
        __syncthreads();

        const uint32_t sb = smbase + (kc & 1) * DG_STAGE * 2;
        const uint32_t as1 = sb;
        const uint32_t as2 = sb + DG_TILE * 2;                     // qmode only
        const uint32_t bs1 = qmode ? sb + 2 * DG_TILE * 2 : sb + DG_TILE * 2;
#pragma unroll
        for (int ks = 0; ks < 2; ks++) {
            const int acol = ks * 16 + acolL;
            const int bk   = ks * 16 + bkL;
            uint32_t a1[4][4], a2[4][4], b1[4][2];
#pragma unroll
            for (int mt = 0; mt < 4; mt++) {
                uint32_t off = ((arow + mt * 16) * PITCH + acol) * 2;
                ldmx4(a1[mt][0], a1[mt][1], a1[mt][2], a1[mt][3], as1 + off);
                if (qmode)
                    ldmx4(a2[mt][0], a2[mt][1], a2[mt][2], a2[mt][3], as2 + off);
            }
#pragma unroll
            for (int nt2 = 0; nt2 < 2; nt2++) {
                uint32_t off = ((bn + nt2 * 16) * PITCH + bk) * 2;
                ldmx4(b1[nt2 * 2][0], b1[nt2 * 2][1],
                      b1[nt2 * 2 + 1][0], b1[nt2 * 2 + 1][1], bs1 + off);
            }
#pragma unroll
            for (int mt = 0; mt < 4; mt++)
#pragma unroll
                for (int nt = 0; nt < 4; nt++) {
                    mma_f16(acc[mt][nt], a1[mt], b1[nt]);
                    if (qmode)
                        mma_f16(acc[mt][nt], a2[mt], b1[nt]);
                }
        }
        __syncthreads();
    }

    const int g  = lane >> 2;
    const int tg = lane & 3;
#pragma unroll
    for (int mt = 0; mt < 4; mt++)
#pragma unroll
        for (int nt = 0; nt < 4; nt++) {
#pragma unroll
            for (int half = 0; half < 2; half++) {
                int grow = brow + wm * 64 + mt * 16 + g + half * 8;
                int col  = bcol + wn * 32 + nt * 8 + tg * 2;
                float2 v = make_float2(acc[mt][nt][half * 2],
                                       acc[mt][nt][half * 2 + 1]);
                if (EPI == 0) {
                    int bb = grow >> 12, nn = grow & 4095;
                    if (col < CH) {
                        const float s = 0.35355339059327373f;  // hd^(-1/4)
                        v.x *= s; v.y *= s;
                        int h = col >> 6, dd = col & 63;
                        size_t adr = (((size_t)(bb * NH + h)) * SEQ + nn) * HD + dd;
                        __half h0, l0, h1, l1;
                        split2h(v.x, h0, l0); split2h(v.y, h1, l1);
                        *(__half2*)&g_QB1[adr] = __halves2half2(h0, h1);
                        *(__half2*)&g_QB2[adr] = __halves2half2(l0, l1);
                    } else {
                        int c2 = col - CH;
                        int h = c2 >> 6, dd = c2 & 63;
                        size_t adr = (((size_t)(bb * NH + h)) * SEQ + nn) * HD + dd;
                        *(__half2*)&g_VB1[adr] =
                            __halves2half2(__float2half(v.x), __float2half(v.y));
                    }
                } else {
                    v.x += bias[col];
                    v.y += bias[col + 1];
                    *(float2*)&Cout[(size_t)grow * CH + col] = v;
                }
            }
        }
}

// ---------------- conversion kernels -----------------------------------------
__global__ __launch_bounds__(256)
void conv_x_kernel(const float* __restrict__ x)
{
    size_t i = ((size_t)blockIdx.x * 256 + threadIdx.x) * 4;
    float4 v = *(const float4*)&x[i];
    __half h0, l0, h1, l1, h2, l2, h3, l3;
    split2h(v.x, h0, l0); split2h(v.y, h1, l1);
    split2h(v.z, h2, l2); split2h(v.w, h3, l3);
    *(__half2*)&g_XH1[i]     = __halves2half2(h0, h1);
    *(__half2*)&g_XH1[i + 2] = __halves2half2(h2, h3);
    *(__half2*)&g_XH2[i]     = __halves2half2(l0, l1);
    *(__half2*)&g_XH2[i + 2] = __halves2half2(l2, l3);
}

__global__ __launch_bounds__(256)
void conv_wq_kernel(const float* __restrict__ W)
{
    int idx = blockIdx.x * 256 + threadIdx.x;   // over [1536][768], n outer
    int n = idx / CH, k = idx - n * CH;
    float v = W[(size_t)k * (2 * CH) + n];
    if (n < CH) g_WQ1[(size_t)n * CH + k] = __float2half(v);
    else        g_WV1[(size_t)(n - CH) * CH + k] = __float2half(v);
}

__global__ __launch_bounds__(256)
void conv_wp_kernel(const float* __restrict__ W)
{
    int idx = blockIdx.x * 256 + threadIdx.x;
    int n = idx / CH, k = idx - n * CH;
    g_WP1[idx] = __float2half(W[(size_t)k * CH + n]);
}

// R [h][d][m] -> R^T pair [h][m][d]
__global__ __launch_bounds__(256)
void conv_rt_kernel(const float* __restrict__ randm)
{
    int idx = blockIdx.x * 256 + threadIdx.x;
    int h = idx / (RM * HD);
    int r = idx - h * (RM * HD);
    int m = r / HD, d = r - m * HD;
    float v = randm[((size_t)h * HD + d) * RM + m];
    __half hi, lo;
    split2h(v, hi, lo);
    g_RT1[idx] = hi;
    g_RT2[idx] = lo;
}

// ---------------- rf via HMMA (fp16 3-term), emits fp16 pair ---------------------
#define RF_PITCH 72
#define RF_TILE (128*RF_PITCH)
#define RF_SMEM (4*RF_TILE*2)

__global__ __launch_bounds__(256, 2)
void rf_hmma()
{
    extern __shared__ __half rsm[];
    __shared__ float rowq2[128];
    const int tid = threadIdx.x, wid = tid >> 5, lane = tid & 31;
    const int wm = wid & 1, wn = wid >> 1;
    const int bh = blockIdx.y, h = bh % NH;
    const int brow = blockIdx.x * 128;

    const __half* A1 = g_QB1 + ((size_t)bh * SEQ + brow) * HD;
    const __half* A2 = g_QB2 + ((size_t)bh * SEQ + brow) * HD;
    const __half* B1 = g_RT1 + (size_t)h * RM * HD;
    const __half* B2 = g_RT2 + (size_t)h * RM * HD;

#pragma unroll
    for (int t = 0; t < 4; t++) {
        const __half* src = (t == 0) ? A1 : (t == 1) ? A2 : (t == 2) ? B1 : B2;
        __half* dst = rsm + t * RF_TILE;
#pragma unroll
        for (int u = 0; u < 4; u++) {
            int f = u * 256 + tid;
            int r = f >> 3, c = (f & 7) * 8;
            *(uint4*)(dst + r * RF_PITCH + c) = *(const uint4*)(src + (size_t)r * HD + c);
        }
    }
    __syncthreads();

    {
        int r = tid >> 1;
        int k0 = (tid & 1) * 32;
        const __half* q1 = rsm + r * RF_PITCH + k0;
        const __half* q2 = rsm + RF_TILE + r * RF_PITCH + k0;
        float s = 0.f;
#pragma unroll
        for (int k = 0; k < 32; k++) {
            float v = __half2float(q1[k]) + __half2float(q2[k]);
            s += v * v;
        }
        s += __shfl_xor_sync(0xffffffffu, s, 1);
        if (!(tid & 1)) rowq2[r] = s;
    }

    float acc[4][4][4];
#pragma unroll
    for (int i = 0; i < 4; i++)
#pragma unroll
        for (int j = 0; j < 4; j++)
#pragma unroll
            for (int q = 0; q < 4; q++) acc[i][j][q] = 0.f;

    const uint32_t smbase = smem_u32(rsm);
    const uint32_t as1 = smbase, as2 = smbase + RF_TILE * 2;
    const uint32_t bs1 = smbase + 2 * RF_TILE * 2, bs2 = smbase + 3 * RF_TILE * 2;
    const int arow = wm * 64 + (lane & 15);
    const int acolL = (lane >> 4) * 8;
    const int bn   = wn * 32 + (lane & 7) + ((lane >> 4) & 1) * 8;
    const int bkL  = ((lane >> 3) & 1) * 8;

#pragma unroll
    for (int ks = 0; ks < 4; ks++) {
        const int acol = ks * 16 + acolL;
        const int bk   = ks * 16 + bkL;
        uint32_t a1[4][4], a2[4][4], b1[4][2], b2[4][2];
#pragma unroll
        for (int mt = 0; mt < 4; mt++) {
            uint32_t off = ((arow + mt * 16) * RF_PITCH + acol) * 2;
            ldmx4(a1[mt][0], a1[mt][1], a1[mt][2], a1[mt][3], as1 + off);
            ldmx4(a2[mt][0], a2[mt][1], a2[mt][2], a2[mt][3], as2 + off);
        }
#pragma unroll
        for (int nt2 = 0; nt2 < 2; nt2++) {
            uint32_t off = ((bn + nt2 * 16) * RF_PITCH + bk) * 2;
            ldmx4(b1[nt2 * 2][0], b1[nt2 * 2][1],
                  b1[nt2 * 2 + 1][0], b1[nt2 * 2 + 1][1], bs1 + off);
            ldmx4(b2[nt2 * 2][0], b2[nt2 * 2][1],
                  b2[nt2 * 2 + 1][0], b2[nt2 * 2 + 1][1], bs2 + off);
        }
#pragma unroll
        for (int mt = 0; mt < 4; mt++)
#pragma unroll
            for (int nt = 0; nt < 4; nt++) {
                mma_f16(acc[mt][nt], a1[mt], b1[nt]);
                mma_f16(acc[mt][nt], a1[mt], b2[nt]);
                mma_f16(acc[mt][nt], a2[mt], b1[nt]);
            }
    }
    __syncthreads();

    const int g  = lane >> 2;
    const int tg = lane & 3;
    const float sc = 0.08838834764831845f;  // 1/sqrt(128)
#pragma unroll
    for (int mt = 0; mt < 4; mt++)
#pragma unroll
        for (int nt = 0; nt < 4; nt++)
#pragma unroll
            for (int half = 0; half < 2; half++) {
                int row  = wm * 64 + mt * 16 + g + half * 8;
                int mcol = wn * 32 + nt * 8 + tg * 2;
                float base = -0.5f * rowq2[row];
                float v0 = expf(acc[mt][nt][half * 2]     + base) * sc;
                float v1 = expf(acc[mt][nt][half * 2 + 1] + base) * sc;
                __half h0, l0, h1, l1;
                split2h(v0, h0, l0); split2h(v1, h1, l1);
                size_t adr = ((size_t)bh * SEQ + brow + row) * RM + mcol;
                *(__half2*)&g_RF1[adr] = __halves2half2(h0, h1);
                *(__half2*)&g_RF2[adr] = __halves2half2(l0, l1);
            }
}

// ---------------- kk/kv via fp16 2-term HMMA (A=rf pair, B single) ---------------
#define KK_A_TILE (32*136)
#define KK_Y_TILE (32*72)
#define KK_STAGE (2*KK_A_TILE + KK_Y_TILE)
#define KK_SMEM (2*KK_STAGE*2)

__global__ __launch_bounds__(256, 2)
void kkkv_hmma()
{
    extern __shared__ __half ksm[];
    const int tid = threadIdx.x, wid = tid >> 5, lane = tid & 31;
    const int ct = blockIdx.x, bh = blockIdx.y, split = blockIdx.z;
    const int wm = wid >> 1, wn = wid & 1;

    size_t abase = ((size_t)bh * SEQ + (size_t)split * NCHUNK) * RM;
    const __half *a1 = g_RF1 + abase, *a2 = g_RF2 + abase;
    const __half *b1;
    int bstr;
    if (ct == 2) {
        b1 = g_VB1 + ((size_t)bh * SEQ + (size_t)split * NCHUNK) * HD;
        bstr = HD;
    } else {
        b1 = a1 + ct * 64;
        bstr = RM;
    }

    float acc[2][4][4];
#pragma unroll
    for (int i = 0; i < 2; i++)
#pragma unroll
        for (int j = 0; j < 4; j++)
#pragma unroll
            for (int q = 0; q < 4; q++) acc[i][j][q] = 0.f;

    const uint32_t smbase = smem_u32(ksm);
    const int a_r = (lane & 7) + (lane >> 4) * 8;
    const int a_c = ((lane >> 3) & 1) * 8;
    const int b_r = (lane & 7) + ((lane >> 3) & 1) * 8;
    const int b_c = (lane >> 4) * 8;

    const int ar0 = tid >> 4,        ac0 = (tid & 15) * 8;
    const int ar1 = (tid + 256) >> 4, ac1 = ((tid + 256) & 15) * 8;
    const int yr = tid >> 3, yc = (tid & 7) * 8;
    auto load_stage = [&](int stage, int n0) {
        uint32_t sb = smbase + stage * KK_STAGE * 2;
        uint32_t sA1 = sb, sA2 = sb + KK_A_TILE * 2;
        uint32_t sY1 = sb + 2 * KK_A_TILE * 2;
        cpa16(sA1 + (ar0 * 136 + ac0) * 2, a1 + (size_t)(n0 + ar0) * RM + ac0);
        cpa16(sA1 + (ar1 * 136 + ac1) * 2, a1 + (size_t)(n0 + ar1) * RM + ac1);
        cpa16(sA2 + (ar0 * 136 + ac0) * 2, a2 + (size_t)(n0 + ar0) * RM + ac0);
        cpa16(sA2 + (ar1 * 136 + ac1) * 2, a2 + (size_t)(n0 + ar1) * RM + ac1);
        cpa16(sY1 + (yr * 72 + yc) * 2, b1 + (size_t)(n0 + yr) * bstr + yc);
    };

    load_stage(0, 0);
    CP_COMMIT();

    for (int chunk = 0; chunk < NCHUNK / 32; chunk++) {
        if (chunk + 1 < NCHUNK / 32) load_stage((chunk + 1) & 1, (chunk + 1) * 32);
        CP_COMMIT();
        CP_WAIT1();
        __syncthreads();

        uint32_t sb = smbase + (chunk & 1) * KK_STAGE * 2;
        uint32_t as1 = sb, as2 = sb + KK_A_TILE * 2;
        uint32_t ys1 = sb + 2 * KK_A_TILE * 2;
#pragma unroll
        for (int ks = 0; ks < 2; ks++) {
            uint32_t A1f[2][4], A2f[2][4], B1f[4][2];
#pragma unroll
            for (int mt = 0; mt < 2; mt++) {
                uint32_t off = ((ks * 16 + a_r) * 136 + wm * 32 + mt * 16 + a_c) * 2;
                ldmx4t(A1f[mt], as1 + off);
                ldmx4t(A2f[mt], as2 + off);
            }
#pragma unroll
            for (int nb = 0; nb < 2; nb++) {
                uint32_t off = ((ks * 16 + b_r) * 72 + wn * 32 + nb * 16 + b_c) * 2;
                uint32_t t1[4];
                ldmx4t(t1, ys1 + off);
                B1f[nb * 2][0] = t1[0]; B1f[nb * 2][1] = t1[1];
                B1f[nb * 2 + 1][0] = t1[2]; B1f[nb * 2 + 1][1] = t1[3];
            }
#pragma unroll
            for (int mt = 0; mt < 2; mt++)
#pragma unroll
                for (int nt = 0; nt < 4; nt++) {
                    mma_f16(acc[mt][nt], A1f[mt], B1f[nt]);
                    mma_f16(acc[mt][nt], A2f[mt], B1f[nt]);
                }
        }
        __syncthreads();
    }

    float* dst = g_PART + ((size_t)split * BH + bh) * (RM * (RM + HD));
#pragma unroll
    for (int mt = 0; mt < 2; mt++)
#pragma unroll
        for (int nt = 0; nt < 4; nt++)
#pragma unroll
            for (int half = 0; half < 2; half++) {
                int m = wm * 32 + mt * 16 + (lane >> 2) + half * 8;
                int j = ct * 64 + wn * 32 + nt * 8 + (lane & 3) * 2;
                *(float2*)&dst[m * (RM + HD) + j] =
                    make_float2(acc[mt][nt][half * 2], acc[mt][nt][half * 2 + 1]);
            }
}

// ---------------- fused reduce + ISTA (emits (d*s)^T fp16 single) ----------------
__device__ __forceinline__ float softf(float z, float t)
{
    float a = fabsf(z) - t;
    return a > 0.f ? (z >= 0.f ? a : -a) : 0.f;
}

#define IST_SMEM ((RM*129 + RM*HD + RM*68) * 4)

__global__ __launch_bounds__(256)
void ista_fused()
{
    extern __shared__ float sm[];
    float* kks = sm;
    float* kvs = sm + RM * 129;
    float* ss  = kvs + RM * HD;
    __shared__ float dsh[RM];
    __shared__ float rowsum[RM];
    __shared__ float Lsh;
    int bh = blockIdx.x;
    const float* part = g_PART;

    if (threadIdx.x < RM) {
        float s = 0.f;
#pragma unroll
        for (int sp = 0; sp < SPLITS; sp++)
            s += part[((size_t)sp * BH + bh) * (RM * (RM + HD))
                      + threadIdx.x * (RM + HD) + threadIdx.x];
        dsh[threadIdx.x] = 1.0f / fmaxf(sqrtf(s), 1e-12f);
    }
    __syncthreads();

    for (int idx = threadIdx.x; idx < RM * (RM + HD); idx += 256) {
        int m = idx / (RM + HD);
        int j = idx - m * (RM + HD);
        float s = 0.f;
#pragma unroll
        for (int sp = 0; sp < SPLITS; sp++)
            s += part[((size_t)sp * BH + bh) * (RM * (RM + HD)) + idx];
        if (j < RM) kks[m * 129 + j] = s * dsh[m] * dsh[j];
        else        kvs[m * HD + (j - RM)] = s * dsh[m];
    }
    __syncthreads();

    if (threadIdx.x < RM) {
        float rs = 0.f;
        for (int j = 0; j < RM; j++) rs += fabsf(kks[threadIdx.x * 129 + j]);
        rowsum[threadIdx.x] = rs;
    }
    __syncthreads();
    if (threadIdx.x == 0) {
        float mx = 0.f;
        for (int i = 0; i < RM; i++) mx = fmaxf(mx, rowsum[i]);
        Lsh = mx + 1.0f;
    }
    __syncthreads();
    float invL = 1.0f / Lsh;
    float thr  = LAMBDA * invL;

    int m  = threadIdx.x >> 1;
    int ch = (threadIdx.x & 1) * 32;
#pragma unroll
    for (int i = 0; i < 32; i++)
        ss[m * 68 + ch + i] = softf(kvs[m * HD + ch + i], LAMBDA);
    __syncthreads();

    for (int it = 0; it < NSTEP; it++) {
        float acc[32];
#pragma unroll
        for (int i = 0; i < 32; i++) acc[i] = 0.f;
        for (int p = 0; p < RM; p++) {
            float kv_ = kks[m * 129 + p];
            const float4* sp = (const float4*)&ss[p * 68 + ch];
#pragma unroll
            for (int q = 0; q < 8; q++) {
                float4 v = sp[q];
                acc[q * 4 + 0] += kv_ * v.x;
                acc[q * 4 + 1] += kv_ * v.y;
                acc[q * 4 + 2] += kv_ * v.z;
                acc[q * 4 + 3] += kv_ * v.w;
            }
        }
        float r[32];
#pragma unroll
        for (int i = 0; i < 32; i++) {
            float z = ss[m * 68 + ch + i] - (acc[i] - kvs[m * HD + ch + i]) * invL;
            r[i] = softf(z, thr);
        }
        __syncthreads();
#pragma unroll
        for (int q = 0; q < 8; q++)
            *(float4*)&ss[m * 68 + ch + q * 4] =
                make_float4(r[q * 4], r[q * 4 + 1], r[q * 4 + 2], r[q * 4 + 3]);
        __syncthreads();
    }
    float dm = dsh[m];
#pragma unroll
    for (int q = 0; q < 8; q++) {
        float4 v = *(float4*)&ss[m * 68 + ch + q * 4];
        v.x *= dm; v.y *= dm; v.z *= dm; v.w *= dm;
        *(float4*)&ss[m * 68 + ch + q * 4] = v;
    }
    __syncthreads();
    int d  = threadIdx.x >> 2;
    int ms = (threadIdx.x & 3) * 32;
    size_t ob = ((size_t)bh * HD + d) * RM + ms;
#pragma unroll
    for (int i = 0; i < 32; i += 2) {
        float v0 = ss[(ms + i) * 68 + d];
        float v1 = ss[(ms + i + 1) * 68 + d];
        *(__half2*)&g_ST1[ob + i] =
            __halves2half2(__float2half(v0), __float2half(v1));
    }
}

// ---------------- out = rf(pair) @ sT(single) fp16 2-term, emits OC single --------
__global__ __launch_bounds__(256, 2)
void outgemm_hmma()
{
    __shared__ __half As1[128 * PITCH], As2[128 * PITCH];
    __shared__ __half Bs1[64 * PITCH];
    const int tid = threadIdx.x, wid = tid >> 5, lane = tid & 31;
    const int wm = wid & 3, wn = wid >> 2;
    const int bh = blockIdx.y, nblk = blockIdx.x;
    const int b = bh / NH, h = bh % NH;

    size_t rfbase = ((size_t)bh * SEQ + (size_t)nblk * 128) * RM;
    size_t stbase = (size_t)bh * HD * RM;

    float acc[2][4][4];
#pragma unroll
    for (int i = 0; i < 2; i++)
#pragma unroll
        for (int j = 0; j < 4; j++)
#pragma unroll
            for (int q = 0; q < 4; q++) acc[i][j][q] = 0.f;

    const uint32_t as1 = smem_u32(As1), as2 = smem_u32(As2);
    const uint32_t bs1 = smem_u32(Bs1);
    const int arow = wm * 32 + (lane & 15);
    const int acolL = (lane >> 4) * 8;
    const int bn   = wn * 32 + (lane & 7) + ((lane >> 4) & 1) * 8;
    const int bkL  = ((lane >> 3) & 1) * 8;

    for (int kc = 0; kc < 4; kc++) {
        const int k0 = kc * 32;
#pragma unroll
        for (int l = 0; l < 2; l++) {
            int f = tid + l * 256;
            int r = f >> 2, c = (f & 3) * 8;
            *(uint4*)(As1 + r * PITCH + c) =
                *(const uint4*)(g_RF1 + rfbase + (size_t)r * RM + k0 + c);
            *(uint4*)(As2 + r * PITCH + c) =
                *(const uint4*)(g_RF2 + rfbase + (size_t)r * RM + k0 + c);
        }
        {
            int r = tid >> 2, c = (tid & 3) * 8;
            if (r < 64)
                *(uint4*)(Bs1 + r * PITCH + c) =
                    *(const uint4*)(g_ST1 + stbase + (size_t)r * RM + k0 + c);
        }
        __syncthreads();
#pragma unroll
        for (int ks = 0; ks < 2; ks++) {
            const int acol = ks * 16 + acolL;
            const int bk   = ks * 16 + bkL;
            uint32_t a1[2][4], a2[2][4], b1[4][2];
#pragma unroll
            for (int mt = 0; mt < 2; mt++) {
                uint32_t off = ((arow + mt * 16) * PITCH + acol) * 2;
                ldmx4(a1[mt][0], a1[mt][1], a1[mt][2], a1[mt][3], as1 + off);
                ldmx4(a2[mt][0], a2[mt][1], a2[mt][2], a2[mt][3], as2 + off);
            }
#pragma unroll
            for (int nt2 = 0; nt2 < 2; nt2++) {
                uint32_t off = ((bn + nt2 * 16) * PITCH + bk) * 2;
                ldmx4(b1[nt2 * 2][0], b1[nt2 * 2][1],
                      b1[nt2 * 2 + 1][0], b1[nt2 * 2 + 1][1], bs1 + off);
            }
#pragma unroll
            for (int mt = 0; mt < 2; mt++)
#pragma unroll
                for (int nt = 0; nt < 4; nt++) {
                    mma_f16(acc[mt][nt], a1[mt], b1[nt]);
                    mma_f16(acc[mt][nt], a2[mt], b1[nt]);
                }
        }
        __syncthreads();
    }

    const int g  = lane >> 2;
    const int tg = lane & 3;
#pragma unroll
    for (int mt = 0; mt < 2; mt++)
#pragma unroll
        for (int nt = 0; nt < 4; nt++)
#pragma unroll
            for (int half = 0; half < 2; half++) {
                int nrow = nblk * 128 + wm * 32 + mt * 16 + g + half * 8;
                int d    = wn * 32 + nt * 8 + tg * 2;
                float2 v = make_float2(acc[mt][nt][half * 2],
                                       acc[mt][nt][half * 2 + 1]);
                size_t adr = ((size_t)b * SEQ + nrow) * CH + h * HD + d;
                *(__half2*)&g_OC1[adr] =
                    __halves2half2(__float2half(v.x), __float2half(v.y));
            }
}

// ---------------- launch -----------------------------------------------------------
extern "C" void kernel_launch(void* const* d_in, const int* in_sizes, int n_in,
                              void* d_out, int out_size)
{
    const float *x = nullptr, *wqkv = nullptr, *wproj = nullptr,
                *bias = nullptr, *rm = nullptr;
    for (int i = 0; i < n_in; i++) {
        const float* p = (const float*)d_in[i];
        switch (in_sizes[i]) {
            case BATCH * SEQ * CH: x = p; break;
            case CH * 2 * CH:      wqkv = p; break;
            case CH * CH:          wproj = p; break;
            case CH:               bias = p; break;
            case NH * HD * RM:     rm = p; break;
        }
    }
    float* out = (float*)d_out;
    (void)out_size;

    cudaFuncSetAttribute(hmma_gemm<0>, cudaFuncAttributeMaxDynamicSharedMemorySize, DG_SMEM);
    cudaFuncSetAttribute(hmma_gemm<1>, cudaFuncAttributeMaxDynamicSharedMemorySize, DG_SMEM);
    cudaFuncSetAttribute(rf_hmma, cudaFuncAttributeMaxDynamicSharedMemorySize, RF_SMEM);
    cudaFuncSetAttribute(kkkv_hmma, cudaFuncAttributeMaxDynamicSharedMemorySize, KK_SMEM);
    cudaFuncSetAttribute(ista_fused, cudaFuncAttributeMaxDynamicSharedMemorySize, IST_SMEM);

    // conversions (all fp16)
    conv_x_kernel<<<BATCH * SEQ * CH / 1024, 256>>>(x);
    conv_wq_kernel<<<2 * CH * CH / 256, 256>>>(wqkv);
    conv_wp_kernel<<<CH * CH / 256, 256>>>(wproj);
    conv_rt_kernel<<<NH * RM * HD / 256, 256>>>(rm);

    // 1. qkv = x @ Wqkv (q cols 2-term, v cols 1-term)
    hmma_gemm<0><<<dim3(12, 256), 256, DG_SMEM>>>(nullptr, nullptr, CH);
    // 2. rf (fp16 3-term) -> rf fp16 pair
    rf_hmma<<<dim3(32, BH), 256, RF_SMEM>>>();
    // 3. kk/kv partials (fp16 2-term)
    kkkv_hmma<<<dim3(3, BH, SPLITS), 256, KK_SMEM>>>();
    // 4. fused reduce + d + L + ISTA -> sT fp16 single
    ista_fused<<<BH, 256, IST_SMEM>>>();
    // 5. out_head = rf @ s (fp16 2-term) -> OC fp16 single
    outgemm_hmma<<<dim3(32, BH), 256>>>();
    // 6. final projection + bias (fp16 1-term)
    hmma_gemm<1><<<dim3(6, 256), 256, DG_SMEM>>>(bias, out, CH);
}

// round 14
// speedup vs baseline: 4.8548x; 1.0500x over previous
#include <cuda_runtime.h>
#include <cuda_fp16.h>
#include <math.h>
#include <cstdint>

// Problem constants
#define BATCH 8
#define SEQ   4096
#define CH    768
#define NH    12
#define HD    64
#define RM    128
#define BH    (BATCH*NH)
#define LAMBDA 0.3f
#define NSTEP 5
#define SPLITS 4
#define NCHUNK (SEQ/SPLITS)    // 1024

// ---------------- scratch ----------------------------------------------------
__device__ float g_PART[(size_t)SPLITS*BH*RM*(RM+HD)];
// fp16 split pairs / singles
__device__ __half g_XH1[(size_t)BATCH*SEQ*CH];       // x hi
__device__ __half g_XH2[(size_t)BATCH*SEQ*CH];       // x lo (q path only)
__device__ __half g_WQ1[(size_t)CH*CH];              // WqT single [n][k]
__device__ __half g_WV1[(size_t)CH*CH];              // WvT single
__device__ __half g_WP1[(size_t)CH*CH];              // WprojT single
__device__ __half g_QB1[(size_t)BH*SEQ*HD];          // qs pair [bh][n][d]
__device__ __half g_QB2[(size_t)BH*SEQ*HD];
__device__ __half g_RT1[(size_t)NH*RM*HD];           // R^T pair [h][m][d]
__device__ __half g_RT2[(size_t)NH*RM*HD];
__device__ __half g_RF1[(size_t)BH*SEQ*RM];          // rf pair [bh][n][m]
__device__ __half g_RF2[(size_t)BH*SEQ*RM];
__device__ __half g_VB1[(size_t)BH*SEQ*HD];          // v single [bh][n][d]
__device__ __half g_ST1[(size_t)BH*HD*RM];           // (d*s)^T single [bh][d][m]
__device__ __half g_OC1[(size_t)BATCH*SEQ*CH];       // out-head single

// ---------------- helpers ------------------------------------------------------
__device__ __forceinline__ uint32_t smem_u32(const void* p) {
    uint32_t a;
    asm("{ .reg .u64 t; cvta.to.shared.u64 t, %1; cvt.u32.u64 %0, t; }"
        : "=r"(a) : "l"(p));
    return a;
}
__device__ __forceinline__ void ldmx4(uint32_t& r0, uint32_t& r1,
                                      uint32_t& r2, uint32_t& r3, uint32_t addr)
{
    asm volatile("ldmatrix.sync.aligned.m8n8.x4.shared.b16 {%0,%1,%2,%3}, [%4];"
                 : "=r"(r0), "=r"(r1), "=r"(r2), "=r"(r3) : "r"(addr));
}
__device__ __forceinline__ void ldmx4t(uint32_t* r, uint32_t addr)
{
    asm volatile("ldmatrix.sync.aligned.m8n8.x4.trans.shared.b16 {%0,%1,%2,%3}, [%4];"
                 : "=r"(r[0]), "=r"(r[1]), "=r"(r[2]), "=r"(r[3]) : "r"(addr));
}
__device__ __forceinline__ void mma_f16(float* c, const uint32_t* a,
                                        const uint32_t* b)
{
    asm volatile(
        "mma.sync.aligned.m16n8k16.row.col.f32.f16.f16.f32 "
        "{%0,%1,%2,%3}, {%4,%5,%6,%7}, {%8,%9}, {%0,%1,%2,%3};"
        : "+f"(c[0]), "+f"(c[1]), "+f"(c[2]), "+f"(c[3])
        : "r"(a[0]), "r"(a[1]), "r"(a[2]), "r"(a[3]), "r"(b[0]), "r"(b[1]));
}
__device__ __forceinline__ void split2h(float v, __half& h, __half& l)
{
    h = __float2half(v);
    l = __float2half(v - __half2float(h));
}
__device__ __forceinline__ void cpa16(uint32_t saddr, const void* g)
{
    asm volatile("cp.async.cg.shared.global [%0], [%1], 16;"
                 :: "r"(saddr), "l"(g));
}
#define CP_COMMIT() asm volatile("cp.async.commit_group;")
#define CP_WAIT1()  asm volatile("cp.async.wait_group 1;")

#define PITCH 40
#define DG_TILE (128*PITCH)
#define DG_STAGE (3*DG_TILE)
#define DG_SMEM (2*DG_STAGE*2) // 61440 bytes

// ---------------- dense HMMA GEMM (fp16) -------------------------------------------
// EPI==0, q cols : 2-term (x pair x Wq single)         -> q fp16 pair (scaled)
// EPI==0, v cols : 1-term (x hi   x Wv single)         -> v fp16 single
// EPI==1         : 1-term (OC single x WP single)+bias -> fp32 out
template<int EPI>
__global__ __launch_bounds__(256, 2)
void hmma_gemm(const float* __restrict__ bias, float* __restrict__ Cout, int Kdim)
{
    extern __shared__ uint16_t dsm[];

    const int tid  = threadIdx.x;
    const int wid  = tid >> 5;
    const int lane = tid & 31;
    const int wm   = wid & 1;
    const int wn   = wid >> 1;
    const int brow = blockIdx.y * 128;
    const int bcol = blockIdx.x * 128;

    const bool qmode = (EPI == 0) && (bcol < CH);
    const uint16_t* A1 = (EPI == 0) ? (const uint16_t*)g_XH1 : (const uint16_t*)g_OC1;
    const uint16_t* A2 = qmode ? (const uint16_t*)g_XH2 : nullptr;
    const uint16_t* B1;
    int bb0;
    if (EPI == 1)      { B1 = (const uint16_t*)g_WP1; bb0 = bcol; }
    else if (qmode)    { B1 = (const uint16_t*)g_WQ1; bb0 = bcol; }
    else               { B1 = (const uint16_t*)g_WV1; bb0 = bcol - CH; }
    const int NT = qmode ? 3 : 2;

    float acc[4][4][4];
#pragma unroll
    for (int i = 0; i < 4; i++)
#pragma unroll
        for (int j = 0; j < 4; j++)
#pragma unroll
            for (int q = 0; q < 4; q++) acc[i][j][q] = 0.f;

    const uint32_t smbase = smem_u32(dsm);
    const int arow = wm * 64 + (lane & 15);
    const int acolL = (lane >> 4) * 8;
    const int bn   = wn * 32 + (lane & 7) + ((lane >> 4) & 1) * 8;
    const int bkL  = ((lane >> 3) & 1) * 8;

    const int l_row0 = tid >> 2,        l_ch0 = (tid & 3) * 8;
    const int l_row1 = (tid + 256) >> 2, l_ch1 = ((tid + 256) & 3) * 8;

    auto load_stage = [&](int stage, int k0) {
        uint32_t sb = smbase + stage * DG_STAGE * 2;
        for (int t = 0; t < NT; t++) {
            const uint16_t* src;
            int rbase;
            if (qmode) {
                src = (t == 0) ? A1 : (t == 1) ? A2 : B1;
                rbase = (t < 2) ? brow : bb0;
            } else {
                src = (t == 0) ? A1 : B1;
                rbase = (t == 0) ? brow : bb0;
            }
            uint32_t tb = sb + t * DG_TILE * 2;
            cpa16(tb + (l_row0 * PITCH + l_ch0) * 2,
                  src + (size_t)(rbase + l_row0) * Kdim + k0 + l_ch0);
            cpa16(tb + (l_row1 * PITCH + l_ch1) * 2,
                  src + (size_t)(rbase + l_row1) * Kdim + k0 + l_ch1);
        }
    };

    const int nchunk = Kdim >> 5;
    load_stage(0, 0);
    CP_COMMIT();

    for (int kc = 0; kc < nchunk; kc++) {
        if (kc + 1 < nchunk) load_stage((kc + 1) & 1, (kc + 1) << 5);
        CP_COMMIT();
        CP_WAIT1();
        __syncthreads();

        const uint32_t sb = smbase + (kc & 1) * DG_STAGE * 2;
        const uint32_t as1 = sb;
        const uint32_t as2 = sb + DG_TILE * 2;
        const uint32_t bs1 = qmode ? sb + 2 * DG_TILE * 2 : sb + DG_TILE * 2;
#pragma unroll
        for (int ks = 0; ks < 2; ks++) {
            const int acol = ks * 16 + acolL;
            const int bk   = ks * 16 + bkL;
            uint32_t a1[4][4], a2[4][4], b1[4][2];
#pragma unroll
            for (int mt = 0; mt < 4; mt++) {
                uint32_t off = ((arow + mt * 16) * PITCH + acol) * 2;
                ldmx4(a1[mt][0], a1[mt][1], a1[mt][2], a1[mt][3], as1 + off);
                if (qmode)
                    ldmx4(a2[mt][0], a2[mt][1], a2[mt][2], a2[mt][3], as2 + off);
            }
#pragma unroll
            for (int nt2 = 0; nt2 < 2; nt2++) {
                uint32_t off = ((bn + nt2 * 16) * PITCH + bk) * 2;
                ldmx4(b1[nt2 * 2][0], b1[nt2 * 2][1],
                      b1[nt2 * 2 + 1][0], b1[nt2 * 2 + 1][1], bs1 + off);
            }
#pragma unroll
            for (int mt = 0; mt < 4; mt++)
#pragma unroll
                for (int nt = 0; nt < 4; nt++) {
                    mma_f16(acc[mt][nt], a1[mt], b1[nt]);
                    if (qmode)
                        mma_f16(acc[mt][nt], a2[mt], b1[nt]);
                }
        }
        __syncthreads();
    }

    const int g  = lane >> 2;
    const int tg = lane & 3;
#pragma unroll
    for (int mt = 0; mt < 4; mt++)
#pragma unroll
        for (int nt = 0; nt < 4; nt++) {
#pragma unroll
            for (int half = 0; half < 2; half++) {
                int grow = brow + wm * 64 + mt * 16 + g + half * 8;
                int col  = bcol + wn * 32 + nt * 8 + tg * 2;
                float2 v = make_float2(acc[mt][nt][half * 2],
                                       acc[mt][nt][half * 2 + 1]);
                if (EPI == 0) {
                    int bb = grow >> 12, nn = grow & 4095;
                    if (col < CH) {
                        const float s = 0.35355339059327373f;  // hd^(-1/4)
                        v.x *= s; v.y *= s;
                        int h = col >> 6, dd = col & 63;
                        size_t adr = (((size_t)(bb * NH + h)) * SEQ + nn) * HD + dd;
                        __half h0, l0, h1, l1;
                        split2h(v.x, h0, l0); split2h(v.y, h1, l1);
                        *(__half2*)&g_QB1[adr] = __halves2half2(h0, h1);
                        *(__half2*)&g_QB2[adr] = __halves2half2(l0, l1);
                    } else {
                        int c2 = col - CH;
                        int h = c2 >> 6, dd = c2 & 63;
                        size_t adr = (((size_t)(bb * NH + h)) * SEQ + nn) * HD + dd;
                        *(__half2*)&g_VB1[adr] =
                            __halves2half2(__float2half(v.x), __float2half(v.y));
                    }
                } else {
                    v.x += bias[col];
                    v.y += bias[col + 1];
                    *(float2*)&Cout[(size_t)grow * CH + col] = v;
                }
            }
        }
}

// ---------------- conversion kernels -----------------------------------------
__global__ __launch_bounds__(256)
void conv_x_kernel(const float* __restrict__ x)
{
    size_t i = ((size_t)blockIdx.x * 256 + threadIdx.x) * 4;
    float4 v = *(const float4*)&x[i];
    __half h0, l0, h1, l1, h2, l2, h3, l3;
    split2h(v.x, h0, l0); split2h(v.y, h1, l1);
    split2h(v.z, h2, l2); split2h(v.w, h3, l3);
    *(__half2*)&g_XH1[i]     = __halves2half2(h0, h1);
    *(__half2*)&g_XH1[i + 2] = __halves2half2(h2, h3);
    *(__half2*)&g_XH2[i]     = __halves2half2(l0, l1);
    *(__half2*)&g_XH2[i + 2] = __halves2half2(l2, l3);
}

// merged Wq/Wv + Wp + R^T conversion (range-branched)
__global__ __launch_bounds__(256)
void conv_small(const float* __restrict__ wqkv, const float* __restrict__ wproj,
                const float* __restrict__ randm)
{
    int idx = blockIdx.x * 256 + threadIdx.x;
    if (idx < 2 * CH * CH) {
        int n = idx / CH, k = idx - n * CH;
        float v = wqkv[(size_t)k * (2 * CH) + n];
        if (n < CH) g_WQ1[(size_t)n * CH + k] = __float2half(v);
        else        g_WV1[(size_t)(n - CH) * CH + k] = __float2half(v);
    } else if (idx < 3 * CH * CH) {
        int i2 = idx - 2 * CH * CH;
        int n = i2 / CH, k = i2 - n * CH;
        g_WP1[i2] = __float2half(wproj[(size_t)k * CH + n]);
    } else {
        int i2 = idx - 3 * CH * CH;
        int h = i2 / (RM * HD);
        int r = i2 - h * (RM * HD);
        int m = r / HD, d = r - m * HD;
        float v = randm[((size_t)h * HD + d) * RM + m];
        __half hi, lo;
        split2h(v, hi, lo);
        g_RT1[i2] = hi;
        g_RT2[i2] = lo;
    }
}

// ---------------- rf via HMMA (fp16 3-term), emits fp16 pair ---------------------
#define RF_PITCH 72
#define RF_TILE (128*RF_PITCH)
#define RF_SMEM (4*RF_TILE*2)

__global__ __launch_bounds__(256, 2)
void rf_hmma()
{
    extern __shared__ __half rsm[];
    __shared__ float rowq2[128];
    const int tid = threadIdx.x, wid = tid >> 5, lane = tid & 31;
    const int wm = wid & 1, wn = wid >> 1;
    const int bh = blockIdx.y, h = bh % NH;
    const int brow = blockIdx.x * 128;

    const __half* A1 = g_QB1 + ((size_t)bh * SEQ + brow) * HD;
    const __half* A2 = g_QB2 + ((size_t)bh * SEQ + brow) * HD;
    const __half* B1 = g_RT1 + (size_t)h * RM * HD;
    const __half* B2 = g_RT2 + (size_t)h * RM * HD;

#pragma unroll
    for (int t = 0; t < 4; t++) {
        const __half* src = (t == 0) ? A1 : (t == 1) ? A2 : (t == 2) ? B1 : B2;
        __half* dst = rsm + t * RF_TILE;
#pragma unroll
        for (int u = 0; u < 4; u++) {
            int f = u * 256 + tid;
            int r = f >> 3, c = (f & 7) * 8;
            *(uint4*)(dst + r * RF_PITCH + c) = *(const uint4*)(src + (size_t)r * HD + c);
        }
    }
    __syncthreads();

    {
        int r = tid >> 1;
        int k0 = (tid & 1) * 32;
        const __half* q1 = rsm + r * RF_PITCH + k0;
        const __half* q2 = rsm + RF_TILE + r * RF_PITCH + k0;
        float s = 0.f;
#pragma unroll
        for (int k = 0; k < 32; k++) {
            float v = __half2float(q1[k]) + __half2float(q2[k]);
            s += v * v;
        }
        s += __shfl_xor_sync(0xffffffffu, s, 1);
        if (!(tid & 1)) rowq2[r] = s;
    }

    float acc[4][4][4];
#pragma unroll
    for (int i = 0; i < 4; i++)
#pragma unroll
        for (int j = 0; j < 4; j++)
#pragma unroll
            for (int q = 0; q < 4; q++) acc[i][j][q] = 0.f;

    const uint32_t smbase = smem_u32(rsm);
    const uint32_t as1 = smbase, as2 = smbase + RF_TILE * 2;
    const uint32_t bs1 = smbase + 2 * RF_TILE * 2, bs2 = smbase + 3 * RF_TILE * 2;
    const int arow = wm * 64 + (lane & 15);
    const int acolL = (lane >> 4) * 8;
    const int bn   = wn * 32 + (lane & 7) + ((lane >> 4) & 1) * 8;
    const int bkL  = ((lane >> 3) & 1) * 8;

#pragma unroll
    for (int ks = 0; ks < 4; ks++) {
        const int acol = ks * 16 + acolL;
        const int bk   = ks * 16 + bkL;
        uint32_t a1[4][4], a2[4][4], b1[4][2], b2[4][2];
#pragma unroll
        for (int mt = 0; mt < 4; mt++) {
            uint32_t off = ((arow + mt * 16) * RF_PITCH + acol) * 2;
            ldmx4(a1[mt][0], a1[mt][1], a1[mt][2], a1[mt][3], as1 + off);
            ldmx4(a2[mt][0], a2[mt][1], a2[mt][2], a2[mt][3], as2 + off);
        }
#pragma unroll
        for (int nt2 = 0; nt2 < 2; nt2++) {
            uint32_t off = ((bn + nt2 * 16) * RF_PITCH + bk) * 2;
            ldmx4(b1[nt2 * 2][0], b1[nt2 * 2][1],
                  b1[nt2 * 2 + 1][0], b1[nt2 * 2 + 1][1], bs1 + off);
            ldmx4(b2[nt2 * 2][0], b2[nt2 * 2][1],
                  b2[nt2 * 2 + 1][0], b2[nt2 * 2 + 1][1], bs2 + off);
        }
#pragma unroll
        for (int mt = 0; mt < 4; mt++)
#pragma unroll
            for (int nt = 0; nt < 4; nt++) {
                mma_f16(acc[mt][nt], a1[mt], b1[nt]);
                mma_f16(acc[mt][nt], a1[mt], b2[nt]);
                mma_f16(acc[mt][nt], a2[mt], b1[nt]);
            }
    }
    __syncthreads();

    const int g  = lane >> 2;
    const int tg = lane & 3;
    const float sc = 0.08838834764831845f;  // 1/sqrt(128)
#pragma unroll
    for (int mt = 0; mt < 4; mt++)
#pragma unroll
        for (int nt = 0; nt < 4; nt++)
#pragma unroll
            for (int half = 0; half < 2; half++) {
                int row  = wm * 64 + mt * 16 + g + half * 8;
                int mcol = wn * 32 + nt * 8 + tg * 2;
                float base = -0.5f * rowq2[row];
                float v0 = expf(acc[mt][nt][half * 2]     + base) * sc;
                float v1 = expf(acc[mt][nt][half * 2 + 1] + base) * sc;
                __half h0, l0, h1, l1;
                split2h(v0, h0, l0); split2h(v1, h1, l1);
                size_t adr = ((size_t)bh * SEQ + brow + row) * RM + mcol;
                *(__half2*)&g_RF1[adr] = __halves2half2(h0, h1);
                *(__half2*)&g_RF2[adr] = __halves2half2(l0, l1);
            }
}

// ---------------- kk/kv via fp16 2-term HMMA (A=rf pair, B single) ---------------
#define KK_A_TILE (32*136)
#define KK_Y_TILE (32*72)
#define KK_STAGE (2*KK_A_TILE + KK_Y_TILE)
#define KK_SMEM (2*KK_STAGE*2)

__global__ __launch_bounds__(256, 2)
void kkkv_hmma()
{
    extern __shared__ __half ksm[];
    const int tid = threadIdx.x, wid = tid >> 5, lane = tid & 31;
    const int ct = blockIdx.x, bh = blockIdx.y, split = blockIdx.z;
    const int wm = wid >> 1, wn = wid & 1;

    size_t abase = ((size_t)bh * SEQ + (size_t)split * NCHUNK) * RM;
    const __half *a1 = g_RF1 + abase, *a2 = g_RF2 + abase;
    const __half *b1;
    int bstr;
    if (ct == 2) {
        b1 = g_VB1 + ((size_t)bh * SEQ + (size_t)split * NCHUNK) * HD;
        bstr = HD;
    } else {
        b1 = a1 + ct * 64;
        bstr = RM;
    }

    float acc[2][4][4];
#pragma unroll
    for (int i = 0; i < 2; i++)
#pragma unroll
        for (int j = 0; j < 4; j++)
#pragma unroll
            for (int q = 0; q < 4; q++) acc[i][j][q] = 0.f;

    const uint32_t smbase = smem_u32(ksm);
    const int a_r = (lane & 7) + (lane >> 4) * 8;
    const int a_c = ((lane >> 3) & 1) * 8;
    const int b_r = (lane & 7) + ((lane >> 3) & 1) * 8;
    const int b_c = (lane >> 4) * 8;

    const int ar0 = tid >> 4,        ac0 = (tid & 15) * 8;
    const int ar1 = (tid + 256) >> 4, ac1 = ((tid + 256) & 15) * 8;
    const int yr = tid >> 3, yc = (tid & 7) * 8;
    auto load_stage = [&](int stage, int n0) {
        uint32_t sb = smbase + stage * KK_STAGE * 2;
        uint32_t sA1 = sb, sA2 = sb + KK_A_TILE * 2;
        uint32_t sY1 = sb + 2 * KK_A_TILE * 2;
        cpa16(sA1 + (ar0 * 136 + ac0) * 2, a1 + (size_t)(n0 + ar0) * RM + ac0);
        cpa16(sA1 + (ar1 * 136 + ac1) * 2, a1 + (size_t)(n0 + ar1) * RM + ac1);
        cpa16(sA2 + (ar0 * 136 + ac0) * 2, a2 + (size_t)(n0 + ar0) * RM + ac0);
        cpa16(sA2 + (ar1 * 136 + ac1) * 2, a2 + (size_t)(n0 + ar1) * RM + ac1);
        cpa16(sY1 + (yr * 72 + yc) * 2, b1 + (size_t)(n0 + yr) * bstr + yc);
    };

    load_stage(0, 0);
    CP_COMMIT();

    for (int chunk = 0; chunk < NCHUNK / 32; chunk++) {
        if (chunk + 1 < NCHUNK / 32) load_stage((chunk + 1) & 1, (chunk + 1) * 32);
        CP_COMMIT();
        CP_WAIT1();
        __syncthreads();

        uint32_t sb = smbase + (chunk & 1) * KK_STAGE * 2;
        uint32_t as1 = sb, as2 = sb + KK_A_TILE * 2;
        uint32_t ys1 = sb + 2 * KK_A_TILE * 2;
#pragma unroll
        for (int ks = 0; ks < 2; ks++) {
            uint32_t A1f[2][4], A2f[2][4], B1f[4][2];
#pragma unroll
            for (int mt = 0; mt < 2; mt++) {
                uint32_t off = ((ks * 16 + a_r) * 136 + wm * 32 + mt * 16 + a_c) * 2;
                ldmx4t(A1f[mt], as1 + off);
                ldmx4t(A2f[mt], as2 + off);
            }
#pragma unroll
            for (int nb = 0; nb < 2; nb++) {
                uint32_t off = ((ks * 16 + b_r) * 72 + wn * 32 + nb * 16 + b_c) * 2;
                uint32_t t1[4];
                ldmx4t(t1, ys1 + off);
                B1f[nb * 2][0] = t1[0]; B1f[nb * 2][1] = t1[1];
                B1f[nb * 2 + 1][0] = t1[2]; B1f[nb * 2 + 1][1] = t1[3];
            }
#pragma unroll
            for (int mt = 0; mt < 2; mt++)
#pragma unroll
                for (int nt = 0; nt < 4; nt++) {
                    mma_f16(acc[mt][nt], A1f[mt], B1f[nt]);
                    mma_f16(acc[mt][nt], A2f[mt], B1f[nt]);
                }
        }
        __syncthreads();
    }

    float* dst = g_PART + ((size_t)split * BH + bh) * (RM * (RM + HD));
#pragma unroll
    for (int mt = 0; mt < 2; mt++)
#pragma unroll
        for (int nt = 0; nt < 4; nt++)
#pragma unroll
            for (int half = 0; half < 2; half++) {
                int m = wm * 32 + mt * 16 + (lane >> 2) + half * 8;
                int j = ct * 64 + wn * 32 + nt * 8 + (lane & 3) * 2;
                *(float2*)&dst[m * (RM + HD) + j] =
                    make_float2(acc[mt][nt][half * 2], acc[mt][nt][half * 2 + 1]);
            }
}

// ---------------- fused reduce + ISTA, split over d-halves -----------------------
// grid (BH, 2): block handles 32 of the 64 d-columns (independent ISTA columns)
__device__ __forceinline__ float softf(float z, float t)
{
    float a = fabsf(z) - t;
    return a > 0.f ? (z >= 0.f ? a : -a) : 0.f;
}

#define IST_SMEM ((RM*129 + RM*32 + RM*36) * 4)    // 100864 B

__global__ __launch_bounds__(256)
void ista_fused()
{
    extern __shared__ float sm[];
    float* kks = sm;                 // [128][129]
    float* kvs = sm + RM * 129;      // [128][32]
    float* ss  = kvs + RM * 32;      // [128][36]
    __shared__ float dsh[RM];
    __shared__ float rowsum[RM];
    __shared__ float Lsh;
    const int bh = blockIdx.x;
    const int dhalf = blockIdx.y;    // 0/1: d columns [dhalf*32, dhalf*32+32)
    const float* part = g_PART;

    if (threadIdx.x < RM) {
        float s = 0.f;
#pragma unroll
        for (int sp = 0; sp < SPLITS; sp++)
            s += part[((size_t)sp * BH + bh) * (RM * (RM + HD))
                      + threadIdx.x * (RM + HD) + threadIdx.x];
        dsh[threadIdx.x] = 1.0f / fmaxf(sqrtf(s), 1e-12f);
    }
    __syncthreads();

    // kk (full) into smem
    for (int idx = threadIdx.x; idx < RM * RM; idx += 256) {
        int m = idx >> 7, j = idx & 127;
        float s = 0.f;
#pragma unroll
        for (int sp = 0; sp < SPLITS; sp++)
            s += part[((size_t)sp * BH + bh) * (RM * (RM + HD)) + m * (RM + HD) + j];
        kks[m * 129 + j] = s * dsh[m] * dsh[j];
    }
    // kv (this block's 32-column half)
    for (int idx = threadIdx.x; idx < RM * 32; idx += 256) {
        int m = idx >> 5, c = idx & 31;
        float s = 0.f;
#pragma unroll
        for (int sp = 0; sp < SPLITS; sp++)
            s += part[((size_t)sp * BH + bh) * (RM * (RM + HD))
                      + m * (RM + HD) + RM + dhalf * 32 + c];
        kvs[m * 32 + c] = s * dsh[m];
    }
    __syncthreads();

    if (threadIdx.x < RM) {
        float rs = 0.f;
        for (int j = 0; j < RM; j++) rs += fabsf(kks[threadIdx.x * 129 + j]);
        rowsum[threadIdx.x] = rs;
    }
    __syncthreads();
    if (threadIdx.x == 0) {
        float mx = 0.f;
        for (int i = 0; i < RM; i++) mx = fmaxf(mx, rowsum[i]);
        Lsh = mx + 1.0f;
    }
    __syncthreads();
    float invL = 1.0f / Lsh;
    float thr  = LAMBDA * invL;

    int m  = threadIdx.x >> 1;
    int cl = (threadIdx.x & 1) * 16;
#pragma unroll
    for (int i = 0; i < 16; i++)
        ss[m * 36 + cl + i] = softf(kvs[m * 32 + cl + i], LAMBDA);
    __syncthreads();

    for (int it = 0; it < NSTEP; it++) {
        float acc[16];
#pragma unroll
        for (int i = 0; i < 16; i++) acc[i] = 0.f;
        for (int p = 0; p < RM; p++) {
            float kv_ = kks[m * 129 + p];
            const float4* sp = (const float4*)&ss[p * 36 + cl];
#pragma unroll
            for (int q = 0; q < 4; q++) {
                float4 v = sp[q];
                acc[q * 4 + 0] += kv_ * v.x;
                acc[q * 4 + 1] += kv_ * v.y;
                acc[q * 4 + 2] += kv_ * v.z;
                acc[q * 4 + 3] += kv_ * v.w;
            }
        }
        float r[16];
#pragma unroll
        for (int i = 0; i < 16; i++) {
            float z = ss[m * 36 + cl + i] - (acc[i] - kvs[m * 32 + cl + i]) * invL;
            r[i] = softf(z, thr);
        }
        __syncthreads();
#pragma unroll
        for (int q = 0; q < 4; q++)
            *(float4*)&ss[m * 36 + cl + q * 4] =
                make_float4(r[q * 4], r[q * 4 + 1], r[q * 4 + 2], r[q * 4 + 3]);
        __syncthreads();
    }
    float dm = dsh[m];
#pragma unroll
    for (int q = 0; q < 4; q++) {
        float4 v = *(float4*)&ss[m * 36 + cl + q * 4];
        v.x *= dm; v.y *= dm; v.z *= dm; v.w *= dm;
        *(float4*)&ss[m * 36 + cl + q * 4] = v;
    }
    __syncthreads();
    // transposed fp16 emit: sT[d][m] for d in this half
    int dl = threadIdx.x >> 3;           // 0..31 local d
    int ms = (threadIdx.x & 7) * 16;     // 16 m per thread
    size_t ob = ((size_t)bh * HD + dhalf * 32 + dl) * RM + ms;
#pragma unroll
    for (int i = 0; i < 16; i += 2) {
        float v0 = ss[(ms + i) * 36 + dl];
        float v1 = ss[(ms + i + 1) * 36 + dl];
        *(__half2*)&g_ST1[ob + i] =
            __halves2half2(__float2half(v0), __float2half(v1));
    }
}

// ---------------- out = rf(pair) @ sT(single) fp16 2-term, emits OC single --------
__global__ __launch_bounds__(256, 2)
void outgemm_hmma()
{
    __shared__ __half As1[128 * PITCH], As2[128 * PITCH];
    __shared__ __half Bs1[64 * PITCH];
    const int tid = threadIdx.x, wid = tid >> 5, lane = tid & 31;
    const int wm = wid & 3, wn = wid >> 2;
    const int bh = blockIdx.y, nblk = blockIdx.x;
    const int b = bh / NH, h = bh % NH;

    size_t rfbase = ((size_t)bh * SEQ + (size_t)nblk * 128) * RM;
    size_t stbase = (size_t)bh * HD * RM;

    float acc[2][4][4];
#pragma unroll
    for (int i = 0; i < 2; i++)
#pragma unroll
        for (int j = 0; j < 4; j++)
#pragma unroll
            for (int q = 0; q < 4; q++) acc[i][j][q] = 0.f;

    const uint32_t as1 = smem_u32(As1), as2 = smem_u32(As2);
    const uint32_t bs1 = smem_u32(Bs1);
    const int arow = wm * 32 + (lane & 15);
    const int acolL = (lane >> 4) * 8;
    const int bn   = wn * 32 + (lane & 7) + ((lane >> 4) & 1) * 8;
    const int bkL  = ((lane >> 3) & 1) * 8;

    for (int kc = 0; kc < 4; kc++) {
        const int k0 = kc * 32;
#pragma unroll
        for (int l = 0; l < 2; l++) {
            int f = tid + l * 256;
            int r = f >> 2, c = (f & 3) * 8;
            *(uint4*)(As1 + r * PITCH + c) =
                *(const uint4*)(g_RF1 + rfbase + (size_t)r * RM + k0 + c);
            *(uint4*)(As2 + r * PITCH + c) =
                *(const uint4*)(g_RF2 + rfbase + (size_t)r * RM + k0 + c);
        }
        {
            int r = tid >> 2, c = (tid & 3) * 8;
            if (r < 64)
                *(uint4*)(Bs1 + r * PITCH + c) =
                    *(const uint4*)(g_ST1 + stbase + (size_t)r * RM + k0 + c);
        }
        __syncthreads();
#pragma unroll
        for (int ks = 0; ks < 2; ks++) {
            const int acol = ks * 16 + acolL;
            const int bk   = ks * 16 + bkL;
            uint32_t a1[2][4], a2[2][4], b1[4][2];
#pragma unroll
            for (int mt = 0; mt < 2; mt++) {
                uint32_t off = ((arow + mt * 16) * PITCH + acol) * 2;
                ldmx4(a1[mt][0], a1[mt][1], a1[mt][2], a1[mt][3], as1 + off);
                ldmx4(a2[mt][0], a2[mt][1], a2[mt][2], a2[mt][3], as2 + off);
            }
#pragma unroll
            for (int nt2 = 0; nt2 < 2; nt2++) {
                uint32_t off = ((bn + nt2 * 16) * PITCH + bk) * 2;
                ldmx4(b1[nt2 * 2][0], b1[nt2 * 2][1],
                      b1[nt2 * 2 + 1][0], b1[nt2 * 2 + 1][1], bs1 + off);
            }
#pragma unroll
            for (int mt = 0; mt < 2; mt++)
#pragma unroll
                for (int nt = 0; nt < 4; nt++) {
                    mma_f16(acc[mt][nt], a1[mt], b1[nt]);
                    mma_f16(acc[mt][nt], a2[mt], b1[nt]);
                }
        }
        __syncthreads();
    }

    const int g  = lane >> 2;
    const int tg = lane & 3;
#pragma unroll
    for (int mt = 0; mt < 2; mt++)
#pragma unroll
        for (int nt = 0; nt < 4; nt++)
#pragma unroll
            for (int half = 0; half < 2; half++) {
                int nrow = nblk * 128 + wm * 32 + mt * 16 + g + half * 8;
                int d    = wn * 32 + nt * 8 + tg * 2;
                float2 v = make_float2(acc[mt][nt][half * 2],
                                       acc[mt][nt][half * 2 + 1]);
                size_t adr = ((size_t)b * SEQ + nrow) * CH + h * HD + d;
                *(__half2*)&g_OC1[adr] =
                    __halves2half2(__float2half(v.x), __float2half(v.y));
            }
}

// ---------------- launch -----------------------------------------------------------
extern "C" void kernel_launch(void* const* d_in, const int* in_sizes, int n_in,
                              void* d_out, int out_size)
{
    const float *x = nullptr, *wqkv = nullptr, *wproj = nullptr,
                *bias = nullptr, *rm = nullptr;
    for (int i = 0; i < n_in; i++) {
        const float* p = (const float*)d_in[i];
        switch (in_sizes[i]) {
            case BATCH * SEQ * CH: x = p; break;
            case CH * 2 * CH:      wqkv = p; break;
            case CH * CH:          wproj = p; break;
            case CH:               bias = p; break;
            case NH * HD * RM:     rm = p; break;
        }
    }
    float* out = (float*)d_out;
    (void)out_size;

    cudaFuncSetAttribute(hmma_gemm<0>, cudaFuncAttributeMaxDynamicSharedMemorySize, DG_SMEM);
    cudaFuncSetAttribute(hmma_gemm<1>, cudaFuncAttributeMaxDynamicSharedMemorySize, DG_SMEM);
    cudaFuncSetAttribute(rf_hmma, cudaFuncAttributeMaxDynamicSharedMemorySize, RF_SMEM);
    cudaFuncSetAttribute(kkkv_hmma, cudaFuncAttributeMaxDynamicSharedMemorySize, KK_SMEM);
    cudaFuncSetAttribute(ista_fused, cudaFuncAttributeMaxDynamicSharedMemorySize, IST_SMEM);

    // conversions (all fp16)
    conv_x_kernel<<<BATCH * SEQ * CH / 1024, 256>>>(x);
    conv_small<<<(3 * CH * CH + NH * RM * HD) / 256, 256>>>(wqkv, wproj, rm);

    // 1. qkv = x @ Wqkv (q cols 2-term, v cols 1-term)
    hmma_gemm<0><<<dim3(12, 256), 256, DG_SMEM>>>(nullptr, nullptr, CH);
    // 2. rf (fp16 3-term) -> rf fp16 pair
    rf_hmma<<<dim3(32, BH), 256, RF_SMEM>>>();
    // 3. kk/kv partials (fp16 2-term)
    kkkv_hmma<<<dim3(3, BH, SPLITS), 256, KK_SMEM>>>();
    // 4. fused reduce + d + L + ISTA (split over d-halves) -> sT fp16 single
    ista_fused<<<dim3(BH, 2), 256, IST_SMEM>>>();
    // 5. out_head = rf @ s (fp16 2-term) -> OC fp16 single
    outgemm_hmma<<<dim3(32, BH), 256>>>();
    // 6. final projection + bias (fp16 1-term)
    hmma_gemm<1><<<dim3(6, 256), 256, DG_SMEM>>>(bias, out, CH);
}

// round 15
// speedup vs baseline: 4.8858x; 1.0064x over previous
#include <cuda_runtime.h>
#include <cuda_fp16.h>
#include <math.h>
#include <cstdint>

// Problem constants
#define BATCH 8
#define SEQ   4096
#define CH    768
#define NH    12
#define HD    64
#define RM    128
#define BH    (BATCH*NH)
#define LAMBDA 0.3f
#define NSTEP 5
#define SPLITS 4
#define NCHUNK (SEQ/SPLITS)    // 1024

// ---------------- scratch ----------------------------------------------------
__device__ float g_PART[(size_t)SPLITS*BH*RM*(RM+HD)];
// fp16 split pairs / singles
__device__ __half g_XH1[(size_t)BATCH*SEQ*CH];       // x hi
__device__ __half g_XH2[(size_t)BATCH*SEQ*CH];       // x lo (q path only)
__device__ __half g_WQ1[(size_t)CH*CH];              // WqT single [n][k]
__device__ __half g_WV1[(size_t)CH*CH];              // WvT single
__device__ __half g_WP1[(size_t)CH*CH];              // WprojT single
__device__ __half g_QB1[(size_t)BH*SEQ*HD];          // qs pair [bh][n][d]
__device__ __half g_QB2[(size_t)BH*SEQ*HD];
__device__ __half g_RT1[(size_t)NH*RM*HD];           // R^T pair [h][m][d]
__device__ __half g_RT2[(size_t)NH*RM*HD];
__device__ __half g_RF1[(size_t)BH*SEQ*RM];          // rf pair [bh][n][m]
__device__ __half g_RF2[(size_t)BH*SEQ*RM];
__device__ __half g_VB1[(size_t)BH*SEQ*HD];          // v single [bh][n][d]
__device__ __half g_ST1[(size_t)BH*HD*RM];           // (d*s)^T single [bh][d][m]
__device__ __half g_OC1[(size_t)BATCH*SEQ*CH];       // out-head single

// ---------------- helpers ------------------------------------------------------
__device__ __forceinline__ uint32_t smem_u32(const void* p) {
    uint32_t a;
    asm("{ .reg .u64 t; cvta.to.shared.u64 t, %1; cvt.u32.u64 %0, t; }"
        : "=r"(a) : "l"(p));
    return a;
}
__device__ __forceinline__ void ldmx4(uint32_t& r0, uint32_t& r1,
                                      uint32_t& r2, uint32_t& r3, uint32_t addr)
{
    asm volatile("ldmatrix.sync.aligned.m8n8.x4.shared.b16 {%0,%1,%2,%3}, [%4];"
                 : "=r"(r0), "=r"(r1), "=r"(r2), "=r"(r3) : "r"(addr));
}
__device__ __forceinline__ void ldmx4t(uint32_t* r, uint32_t addr)
{
    asm volatile("ldmatrix.sync.aligned.m8n8.x4.trans.shared.b16 {%0,%1,%2,%3}, [%4];"
                 : "=r"(r[0]), "=r"(r[1]), "=r"(r[2]), "=r"(r[3]) : "r"(addr));
}
__device__ __forceinline__ void mma_f16(float* c, const uint32_t* a,
                                        const uint32_t* b)
{
    asm volatile(
        "mma.sync.aligned.m16n8k16.row.col.f32.f16.f16.f32 "
        "{%0,%1,%2,%3}, {%4,%5,%6,%7}, {%8,%9}, {%0,%1,%2,%3};"
        : "+f"(c[0]), "+f"(c[1]), "+f"(c[2]), "+f"(c[3])
        : "r"(a[0]), "r"(a[1]), "r"(a[2]), "r"(a[3]), "r"(b[0]), "r"(b[1]));
}
__device__ __forceinline__ void split2h(float v, __half& h, __half& l)
{
    h = __float2half(v);
    l = __float2half(v - __half2float(h));
}
__device__ __forceinline__ void cpa16(uint32_t saddr, const void* g)
{
    asm volatile("cp.async.cg.shared.global [%0], [%1], 16;"
                 :: "r"(saddr), "l"(g));
}
#define CP_COMMIT() asm volatile("cp.async.commit_group;")
#define CP_WAIT1()  asm volatile("cp.async.wait_group 1;")

#define PITCH 40
#define DG_TILE (128*PITCH)
#define DG_STAGE (3*DG_TILE)
#define DG_SMEM (2*DG_STAGE*2) // 61440 bytes

// ---------------- dense HMMA GEMM (fp16) -------------------------------------------
// EPI==0, q cols : 2-term (x pair x Wq single)         -> q fp16 pair (scaled)
// EPI==0, v cols : 1-term (x hi   x Wv single)         -> v fp16 single
// EPI==1         : 1-term (OC single x WP single)+bias -> fp32 out
template<int EPI>
__global__ __launch_bounds__(256, 2)
void hmma_gemm(const float* __restrict__ bias, float* __restrict__ Cout, int Kdim)
{
    extern __shared__ uint16_t dsm[];

    const int tid  = threadIdx.x;
    const int wid  = tid >> 5;
    const int lane = tid & 31;
    const int wm   = wid & 1;
    const int wn   = wid >> 1;
    const int brow = blockIdx.y * 128;
    const int bcol = blockIdx.x * 128;

    const bool qmode = (EPI == 0) && (bcol < CH);
    const uint16_t* A1 = (EPI == 0) ? (const uint16_t*)g_XH1 : (const uint16_t*)g_OC1;
    const uint16_t* A2 = qmode ? (const uint16_t*)g_XH2 : nullptr;
    const uint16_t* B1;
    int bb0;
    if (EPI == 1)      { B1 = (const uint16_t*)g_WP1; bb0 = bcol; }
    else if (qmode)    { B1 = (const uint16_t*)g_WQ1; bb0 = bcol; }
    else               { B1 = (const uint16_t*)g_WV1; bb0 = bcol - CH; }
    const int NT = qmode ? 3 : 2;

    float acc[4][4][4];
#pragma unroll
    for (int i = 0; i < 4; i++)
#pragma unroll
        for (int j = 0; j < 4; j++)
#pragma unroll
            for (int q = 0; q < 4; q++) acc[i][j][q] = 0.f;

    const uint32_t smbase = smem_u32(dsm);
    const int arow = wm * 64 + (lane & 15);
    const int acolL = (lane >> 4) * 8;
    const int bn   = wn * 32 + (lane & 7) + ((lane >> 4) & 1) * 8;
    const int bkL  = ((lane >> 3) & 1) * 8;

    const int l_row0 = tid >> 2,        l_ch0 = (tid & 3) * 8;
    const int l_row1 = (tid + 256) >> 2, l_ch1 = ((tid + 256) & 3) * 8;

    auto load_stage = [&](int stage, int k0) {
        uint32_t sb = smbase + stage * DG_STAGE * 2;
        for (int t = 0; t < NT; t++) {
            const uint16_t* src;
            int rbase;
            if (qmode) {
                src = (t == 0) ? A1 : (t == 1) ? A2 : B1;
                rbase = (t < 2) ? brow : bb0;
            } else {
                src = (t == 0) ? A1 : B1;
                rbase = (t == 0) ? brow : bb0;
            }
            uint32_t tb = sb + t * DG_TILE * 2;
            cpa16(tb + (l_row0 * PITCH + l_ch0) * 2,
                  src + (size_t)(rbase + l_row0) * Kdim + k0 + l_ch0);
            cpa16(tb + (l_row1 * PITCH + l_ch1) * 2,
                  src + (size_t)(rbase + l_row1) * Kdim + k0 + l_ch1);
        }
    };

    const int nchunk = Kdim >> 5;
    load_stage(0, 0);
    CP_COMMIT();

    for (int kc = 0; kc < nchunk; kc++) {
        if (kc + 1 < nchunk) load_stage((kc + 1) & 1, (kc + 1) << 5);
        CP_COMMIT();
        CP_WAIT1();
        __syncthreads();

        const uint32_t sb = smbase + (kc & 1) * DG_STAGE * 2;
        const uint32_t as1 = sb;
        const uint32_t as2 = sb + DG_TILE * 2;
        const uint32_t bs1 = qmode ? sb + 2 * DG_TILE * 2 : sb + DG_TILE * 2;
#pragma unroll
        for (int ks = 0; ks < 2; ks++) {
            const int acol = ks * 16 + acolL;
            const int bk   = ks * 16 + bkL;
            uint32_t a1[4][4], a2[4][4], b1[4][2];
#pragma unroll
            for (int mt = 0; mt < 4; mt++) {
                uint32_t off = ((arow + mt * 16) * PITCH + acol) * 2;
                ldmx4(a1[mt][0], a1[mt][1], a1[mt][2], a1[mt][3], as1 + off);
                if (qmode)
                    ldmx4(a2[mt][0], a2[mt][1], a2[mt][2], a2[mt][3], as2 + off);
            }
#pragma unroll
            for (int nt2 = 0; nt2 < 2; nt2++) {
                uint32_t off = ((bn + nt2 * 16) * PITCH + bk) * 2;
                ldmx4(b1[nt2 * 2][0], b1[nt2 * 2][1],
                      b1[nt2 * 2 + 1][0], b1[nt2 * 2 + 1][1], bs1 + off);
            }
#pragma unroll
            for (int mt = 0; mt < 4; mt++)
#pragma unroll
                for (int nt = 0; nt < 4; nt++) {
                    mma_f16(acc[mt][nt], a1[mt], b1[nt]);
                    if (qmode)
                        mma_f16(acc[mt][nt], a2[mt], b1[nt]);
                }
        }
        __syncthreads();
    }

    const int g  = lane >> 2;
    const int tg = lane & 3;
#pragma unroll
    for (int mt = 0; mt < 4; mt++)
#pragma unroll
        for (int nt = 0; nt < 4; nt++) {
#pragma unroll
            for (int half = 0; half < 2; half++) {
                int grow = brow + wm * 64 + mt * 16 + g + half * 8;
                int col  = bcol + wn * 32 + nt * 8 + tg * 2;
                float2 v = make_float2(acc[mt][nt][half * 2],
                                       acc[mt][nt][half * 2 + 1]);
                if (EPI == 0) {
                    int bb = grow >> 12, nn = grow & 4095;
                    if (col < CH) {
                        const float s = 0.35355339059327373f;  // hd^(-1/4)
                        v.x *= s; v.y *= s;
                        int h = col >> 6, dd = col & 63;
                        size_t adr = (((size_t)(bb * NH + h)) * SEQ + nn) * HD + dd;
                        __half h0, l0, h1, l1;
                        split2h(v.x, h0, l0); split2h(v.y, h1, l1);
                        *(__half2*)&g_QB1[adr] = __halves2half2(h0, h1);
                        *(__half2*)&g_QB2[adr] = __halves2half2(l0, l1);
                    } else {
                        int c2 = col - CH;
                        int h = c2 >> 6, dd = c2 & 63;
                        size_t adr = (((size_t)(bb * NH + h)) * SEQ + nn) * HD + dd;
                        *(__half2*)&g_VB1[adr] =
                            __halves2half2(__float2half(v.x), __float2half(v.y));
                    }
                } else {
                    v.x += bias[col];
                    v.y += bias[col + 1];
                    *(float2*)&Cout[(size_t)grow * CH + col] = v;
                }
            }
        }
}

// ---------------- conversion kernels -----------------------------------------
__global__ __launch_bounds__(256)
void conv_x_kernel(const float* __restrict__ x)
{
    size_t i = ((size_t)blockIdx.x * 256 + threadIdx.x) * 4;
    float4 v = *(const float4*)&x[i];
    __half h0, l0, h1, l1, h2, l2, h3, l3;
    split2h(v.x, h0, l0); split2h(v.y, h1, l1);
    split2h(v.z, h2, l2); split2h(v.w, h3, l3);
    *(__half2*)&g_XH1[i]     = __halves2half2(h0, h1);
    *(__half2*)&g_XH1[i + 2] = __halves2half2(h2, h3);
    *(__half2*)&g_XH2[i]     = __halves2half2(l0, l1);
    *(__half2*)&g_XH2[i + 2] = __halves2half2(l2, l3);
}

// merged Wq/Wv + Wp + R^T conversion (range-branched)
__global__ __launch_bounds__(256)
void conv_small(const float* __restrict__ wqkv, const float* __restrict__ wproj,
                const float* __restrict__ randm)
{
    int idx = blockIdx.x * 256 + threadIdx.x;
    if (idx < 2 * CH * CH) {
        int n = idx / CH, k = idx - n * CH;
        float v = wqkv[(size_t)k * (2 * CH) + n];
        if (n < CH) g_WQ1[(size_t)n * CH + k] = __float2half(v);
        else        g_WV1[(size_t)(n - CH) * CH + k] = __float2half(v);
    } else if (idx < 3 * CH * CH) {
        int i2 = idx - 2 * CH * CH;
        int n = i2 / CH, k = i2 - n * CH;
        g_WP1[i2] = __float2half(wproj[(size_t)k * CH + n]);
    } else {
        int i2 = idx - 3 * CH * CH;
        int h = i2 / (RM * HD);
        int r = i2 - h * (RM * HD);
        int m = r / HD, d = r - m * HD;
        float v = randm[((size_t)h * HD + d) * RM + m];
        __half hi, lo;
        split2h(v, hi, lo);
        g_RT1[i2] = hi;
        g_RT2[i2] = lo;
    }
}

// ---------------- rf via HMMA (fp16 3-term), emits fp16 pair ---------------------
#define RF_PITCH 72
#define RF_TILE (128*RF_PITCH)
#define RF_SMEM (4*RF_TILE*2)

__global__ __launch_bounds__(256, 2)
void rf_hmma()
{
    extern __shared__ __half rsm[];
    __shared__ float rowq2[128];
    const int tid = threadIdx.x, wid = tid >> 5, lane = tid & 31;
    const int wm = wid & 1, wn = wid >> 1;
    const int bh = blockIdx.y, h = bh % NH;
    const int brow = blockIdx.x * 128;

    const __half* A1 = g_QB1 + ((size_t)bh * SEQ + brow) * HD;
    const __half* A2 = g_QB2 + ((size_t)bh * SEQ + brow) * HD;
    const __half* B1 = g_RT1 + (size_t)h * RM * HD;
    const __half* B2 = g_RT2 + (size_t)h * RM * HD;

#pragma unroll
    for (int t = 0; t < 4; t++) {
        const __half* src = (t == 0) ? A1 : (t == 1) ? A2 : (t == 2) ? B1 : B2;
        __half* dst = rsm + t * RF_TILE;
#pragma unroll
        for (int u = 0; u < 4; u++) {
            int f = u * 256 + tid;
            int r = f >> 3, c = (f & 7) * 8;
            *(uint4*)(dst + r * RF_PITCH + c) = *(const uint4*)(src + (size_t)r * HD + c);
        }
    }
    __syncthreads();

    {
        int r = tid >> 1;
        int k0 = (tid & 1) * 32;
        const __half* q1 = rsm + r * RF_PITCH + k0;
        const __half* q2 = rsm + RF_TILE + r * RF_PITCH + k0;
        float s = 0.f;
#pragma unroll
        for (int k = 0; k < 32; k++) {
            float v = __half2float(q1[k]) + __half2float(q2[k]);
            s += v * v;
        }
        s += __shfl_xor_sync(0xffffffffu, s, 1);
        if (!(tid & 1)) rowq2[r] = s;
    }

    float acc[4][4][4];
#pragma unroll
    for (int i = 0; i < 4; i++)
#pragma unroll
        for (int j = 0; j < 4; j++)
#pragma unroll
            for (int q = 0; q < 4; q++) acc[i][j][q] = 0.f;

    const uint32_t smbase = smem_u32(rsm);
    const uint32_t as1 = smbase, as2 = smbase + RF_TILE * 2;
    const uint32_t bs1 = smbase + 2 * RF_TILE * 2, bs2 = smbase + 3 * RF_TILE * 2;
    const int arow = wm * 64 + (lane & 15);
    const int acolL = (lane >> 4) * 8;
    const int bn   = wn * 32 + (lane & 7) + ((lane >> 4) & 1) * 8;
    const int bkL  = ((lane >> 3) & 1) * 8;

#pragma unroll
    for (int ks = 0; ks < 4; ks++) {
        const int acol = ks * 16 + acolL;
        const int bk   = ks * 16 + bkL;
        uint32_t a1[4][4], a2[4][4], b1[4][2], b2[4][2];
#pragma unroll
        for (int mt = 0; mt < 4; mt++) {
            uint32_t off = ((arow + mt * 16) * RF_PITCH + acol) * 2;
            ldmx4(a1[mt][0], a1[mt][1], a1[mt][2], a1[mt][3], as1 + off);
            ldmx4(a2[mt][0], a2[mt][1], a2[mt][2], a2[mt][3], as2 + off);
        }
#pragma unroll
        for (int nt2 = 0; nt2 < 2; nt2++) {
            uint32_t off = ((bn + nt2 * 16) * RF_PITCH + bk) * 2;
            ldmx4(b1[nt2 * 2][0], b1[nt2 * 2][1],
                  b1[nt2 * 2 + 1][0], b1[nt2 * 2 + 1][1], bs1 + off);
            ldmx4(b2[nt2 * 2][0], b2[nt2 * 2][1],
                  b2[nt2 * 2 + 1][0], b2[nt2 * 2 + 1][1], bs2 + off);
        }
#pragma unroll
        for (int mt = 0; mt < 4; mt++)
#pragma unroll
            for (int nt = 0; nt < 4; nt++) {
                mma_f16(acc[mt][nt], a1[mt], b1[nt]);
                mma_f16(acc[mt][nt], a1[mt], b2[nt]);
                mma_f16(acc[mt][nt], a2[mt], b1[nt]);
            }
    }
    __syncthreads();

    const int g  = lane >> 2;
    const int tg = lane & 3;
    const float sc = 0.08838834764831845f;  // 1/sqrt(128)
#pragma unroll
    for (int mt = 0; mt < 4; mt++)
#pragma unroll
        for (int nt = 0; nt < 4; nt++)
#pragma unroll
            for (int half = 0; half < 2; half++) {
                int row  = wm * 64 + mt * 16 + g + half * 8;
                int mcol = wn * 32 + nt * 8 + tg * 2;
                float base = -0.5f * rowq2[row];
                float v0 = __expf(acc[mt][nt][half * 2]     + base) * sc;
                float v1 = __expf(acc[mt][nt][half * 2 + 1] + base) * sc;
                __half h0, l0, h1, l1;
                split2h(v0, h0, l0); split2h(v1, h1, l1);
                size_t adr = ((size_t)bh * SEQ + brow + row) * RM + mcol;
                *(__half2*)&g_RF1[adr] = __halves2half2(h0, h1);
                *(__half2*)&g_RF2[adr] = __halves2half2(l0, l1);
            }
}

// ---------------- kk/kv via fp16 2-term HMMA (A=rf pair, B single) ---------------
// 64-row chunks, 2-stage cp.async
#define KK_ROWS 64
#define KK_A_TILE (KK_ROWS*136)
#define KK_Y_TILE (KK_ROWS*72)
#define KK_STAGE (2*KK_A_TILE + KK_Y_TILE)
#define KK_SMEM (2*KK_STAGE*2)   // 88064 bytes

__global__ __launch_bounds__(256, 2)
void kkkv_hmma()
{
    extern __shared__ __half ksm[];
    const int tid = threadIdx.x, wid = tid >> 5, lane = tid & 31;
    const int ct = blockIdx.x, bh = blockIdx.y, split = blockIdx.z;
    const int wm = wid >> 1, wn = wid & 1;

    size_t abase = ((size_t)bh * SEQ + (size_t)split * NCHUNK) * RM;
    const __half *a1 = g_RF1 + abase, *a2 = g_RF2 + abase;
    const __half *b1;
    int bstr;
    if (ct == 2) {
        b1 = g_VB1 + ((size_t)bh * SEQ + (size_t)split * NCHUNK) * HD;
        bstr = HD;
    } else {
        b1 = a1 + ct * 64;
        bstr = RM;
    }

    float acc[2][4][4];
#pragma unroll
    for (int i = 0; i < 2; i++)
#pragma unroll
        for (int j = 0; j < 4; j++)
#pragma unroll
            for (int q = 0; q < 4; q++) acc[i][j][q] = 0.f;

    const uint32_t smbase = smem_u32(ksm);
    const int a_r = (lane & 7) + (lane >> 4) * 8;
    const int a_c = ((lane >> 3) & 1) * 8;
    const int b_r = (lane & 7) + ((lane >> 3) & 1) * 8;
    const int b_c = (lane >> 4) * 8;

    auto load_stage = [&](int stage, int n0) {
        uint32_t sb = smbase + stage * KK_STAGE * 2;
        uint32_t sA1 = sb, sA2 = sb + KK_A_TILE * 2;
        uint32_t sY1 = sb + 2 * KK_A_TILE * 2;
#pragma unroll
        for (int l = 0; l < 4; l++) {       // A: 64 rows x 16 uint4 = 1024 slots
            int f = tid + l * 256;
            int r = f >> 4, c = (f & 15) * 8;
            cpa16(sA1 + (r * 136 + c) * 2, a1 + (size_t)(n0 + r) * RM + c);
            cpa16(sA2 + (r * 136 + c) * 2, a2 + (size_t)(n0 + r) * RM + c);
        }
#pragma unroll
        for (int l = 0; l < 2; l++) {       // Y: 64 rows x 8 uint4 = 512 slots
            int f = tid + l * 256;
            int r = f >> 3, c = (f & 7) * 8;
            cpa16(sY1 + (r * 72 + c) * 2, b1 + (size_t)(n0 + r) * bstr + c);
        }
    };

    load_stage(0, 0);
    CP_COMMIT();

    for (int chunk = 0; chunk < NCHUNK / KK_ROWS; chunk++) {
        if (chunk + 1 < NCHUNK / KK_ROWS) load_stage((chunk + 1) & 1, (chunk + 1) * KK_ROWS);
        CP_COMMIT();
        CP_WAIT1();
        __syncthreads();

        uint32_t sb = smbase + (chunk & 1) * KK_STAGE * 2;
        uint32_t as1 = sb, as2 = sb + KK_A_TILE * 2;
        uint32_t ys1 = sb + 2 * KK_A_TILE * 2;
#pragma unroll
        for (int ks = 0; ks < 4; ks++) {
            uint32_t A1f[2][4], A2f[2][4], B1f[4][2];
#pragma unroll
            for (int mt = 0; mt < 2; mt++) {
                uint32_t off = ((ks * 16 + a_r) * 136 + wm * 32 + mt * 16 + a_c) * 2;
                ldmx4t(A1f[mt], as1 + off);
                ldmx4t(A2f[mt], as2 + off);
            }
#pragma unroll
            for (int nb = 0; nb < 2; nb++) {
                uint32_t off = ((ks * 16 + b_r) * 72 + wn * 32 + nb * 16 + b_c) * 2;
                uint32_t t1[4];
                ldmx4t(t1, ys1 + off);
                B1f[nb * 2][0] = t1[0]; B1f[nb * 2][1] = t1[1];
                B1f[nb * 2 + 1][0] = t1[2]; B1f[nb * 2 + 1][1] = t1[3];
            }
#pragma unroll
            for (int mt = 0; mt < 2; mt++)
#pragma unroll
                for (int nt = 0; nt < 4; nt++) {
                    mma_f16(acc[mt][nt], A1f[mt], B1f[nt]);
                    mma_f16(acc[mt][nt], A2f[mt], B1f[nt]);
                }
        }
        __syncthreads();
    }

    float* dst = g_PART + ((size_t)split * BH + bh) * (RM * (RM + HD));
#pragma unroll
    for (int mt = 0; mt < 2; mt++)
#pragma unroll
        for (int nt = 0; nt < 4; nt++)
#pragma unroll
            for (int half = 0; half < 2; half++) {
                int m = wm * 32 + mt * 16 + (lane >> 2) + half * 8;
                int j = ct * 64 + wn * 32 + nt * 8 + (lane & 3) * 2;
                *(float2*)&dst[m * (RM + HD) + j] =
                    make_float2(acc[mt][nt][half * 2], acc[mt][nt][half * 2 + 1]);
            }
}

// ---------------- fused reduce + ISTA, split over d-halves -----------------------
__device__ __forceinline__ float softf(float z, float t)
{
    float a = fabsf(z) - t;
    return a > 0.f ? (z >= 0.f ? a : -a) : 0.f;
}

#define IST_SMEM ((RM*129 + RM*32 + RM*36) * 4)    // 100864 B

__global__ __launch_bounds__(256)
void ista_fused()
{
    extern __shared__ float sm[];
    float* kks = sm;                 // [128][129]
    float* kvs = sm + RM * 129;      // [128][32]
    float* ss  = kvs + RM * 32;      // [128][36]
    __shared__ float dsh[RM];
    __shared__ float rowsum[RM];
    __shared__ float Lsh;
    const int bh = blockIdx.x;
    const int dhalf = blockIdx.y;
    const float* part = g_PART;

    if (threadIdx.x < RM) {
        float s = 0.f;
#pragma unroll
        for (int sp = 0; sp < SPLITS; sp++)
            s += part[((size_t)sp * BH + bh) * (RM * (RM + HD))
                      + threadIdx.x * (RM + HD) + threadIdx.x];
        dsh[threadIdx.x] = 1.0f / fmaxf(sqrtf(s), 1e-12f);
    }
    __syncthreads();

    for (int idx = threadIdx.x; idx < RM * RM; idx += 256) {
        int m = idx >> 7, j = idx & 127;
        float s = 0.f;
#pragma unroll
        for (int sp = 0; sp < SPLITS; sp++)
            s += part[((size_t)sp * BH + bh) * (RM * (RM + HD)) + m * (RM + HD) + j];
        kks[m * 129 + j] = s * dsh[m] * dsh[j];
    }
    for (int idx = threadIdx.x; idx < RM * 32; idx += 256) {
        int m = idx >> 5, c = idx & 31;
        float s = 0.f;
#pragma unroll
        for (int sp = 0; sp < SPLITS; sp++)
            s += part[((size_t)sp * BH + bh) * (RM * (RM + HD))
                      + m * (RM + HD) + RM + dhalf * 32 + c];
        kvs[m * 32 + c] = s * dsh[m];
    }
    __syncthreads();

    if (threadIdx.x < RM) {
        float rs = 0.f;
        for (int j = 0; j < RM; j++) rs += fabsf(kks[threadIdx.x * 129 + j]);
        rowsum[threadIdx.x] = rs;
    }
    __syncthreads();
    if (threadIdx.x == 0) {
        float mx = 0.f;
        for (int i = 0; i < RM; i++) mx = fmaxf(mx, rowsum[i]);
        Lsh = mx + 1.0f;
    }
    __syncthreads();
    float invL = 1.0f / Lsh;
    float thr  = LAMBDA * invL;

    int m  = threadIdx.x >> 1;
    int cl = (threadIdx.x & 1) * 16;
#pragma unroll
    for (int i = 0; i < 16; i++)
        ss[m * 36 + cl + i] = softf(kvs[m * 32 + cl + i], LAMBDA);
    __syncthreads();

    for (int it = 0; it < NSTEP; it++) {
        float acc[16];
#pragma unroll
        for (int i = 0; i < 16; i++) acc[i] = 0.f;
        for (int p = 0; p < RM; p++) {
            float kv_ = kks[m * 129 + p];
            const float4* sp = (const float4*)&ss[p * 36 + cl];
#pragma unroll
            for (int q = 0; q < 4; q++) {
                float4 v = sp[q];
                acc[q * 4 + 0] += kv_ * v.x;
                acc[q * 4 + 1] += kv_ * v.y;
                acc[q * 4 + 2] += kv_ * v.z;
                acc[q * 4 + 3] += kv_ * v.w;
            }
        }
        float r[16];
#pragma unroll
        for (int i = 0; i < 16; i++) {
            float z = ss[m * 36 + cl + i] - (acc[i] - kvs[m * 32 + cl + i]) * invL;
            r[i] = softf(z, thr);
        }
        __syncthreads();
#pragma unroll
        for (int q = 0; q < 4; q++)
            *(float4*)&ss[m * 36 + cl + q * 4] =
                make_float4(r[q * 4], r[q * 4 + 1], r[q * 4 + 2], r[q * 4 + 3]);
        __syncthreads();
    }
    float dm = dsh[m];
#pragma unroll
    for (int q = 0; q < 4; q++) {
        float4 v = *(float4*)&ss[m * 36 + cl + q * 4];
        v.x *= dm; v.y *= dm; v.z *= dm; v.w *= dm;
        *(float4*)&ss[m * 36 + cl + q * 4] = v;
    }
    __syncthreads();
    int dl = threadIdx.x >> 3;
    int ms = (threadIdx.x & 7) * 16;
    size_t ob = ((size_t)bh * HD + dhalf * 32 + dl) * RM + ms;
#pragma unroll
    for (int i = 0; i < 16; i += 2) {
        float v0 = ss[(ms + i) * 36 + dl];
        float v1 = ss[(ms + i + 1) * 36 + dl];
        *(__half2*)&g_ST1[ob + i] =
            __halves2half2(__float2half(v0), __float2half(v1));
    }
}

// ---------------- out = rf(pair) @ sT(single) fp16 2-term, emits OC single --------
__global__ __launch_bounds__(256, 2)
void outgemm_hmma()
{
    __shared__ __half As1[128 * PITCH], As2[128 * PITCH];
    __shared__ __half Bs1[64 * PITCH];
    const int tid = threadIdx.x, wid = tid >> 5, lane = tid & 31;
    const int wm = wid & 3, wn = wid >> 2;
    const int bh = blockIdx.y, nblk = blockIdx.x;
    const int b = bh / NH, h = bh % NH;

    size_t rfbase = ((size_t)bh * SEQ + (size_t)nblk * 128) * RM;
    size_t stbase = (size_t)bh * HD * RM;

    float acc[2][4][4];
#pragma unroll
    for (int i = 0; i < 2; i++)
#pragma unroll
        for (int j = 0; j < 4; j++)
#pragma unroll
            for (int q = 0; q < 4; q++) acc[i][j][q] = 0.f;

    const uint32_t as1 = smem_u32(As1), as2 = smem_u32(As2);
    const uint32_t bs1 = smem_u32(Bs1);
    const int arow = wm * 32 + (lane & 15);
    const int acolL = (lane >> 4) * 8;
    const int bn   = wn * 32 + (lane & 7) + ((lane >> 4) & 1) * 8;
    const int bkL  = ((lane >> 3) & 1) * 8;

    for (int kc = 0; kc < 4; kc++) {
        const int k0 = kc * 32;
#pragma unroll
        for (int l = 0; l < 2; l++) {
            int f = tid + l * 256;
            int r = f >> 2, c = (f & 3) * 8;
            *(uint4*)(As1 + r * PITCH + c) =
                *(const uint4*)(g_RF1 + rfbase + (size_t)r * RM + k0 + c);
            *(uint4*)(As2 + r * PITCH + c) =
                *(const uint4*)(g_RF2 + rfbase + (size_t)r * RM + k0 + c);
        }
        {
            int r = tid >> 2, c = (tid & 3) * 8;
            if (r < 64)
                *(uint4*)(Bs1 + r * PITCH + c) =
                    *(const uint4*)(g_ST1 + stbase + (size_t)r * RM + k0 + c);
        }
        __syncthreads();
#pragma unroll
        for (int ks = 0; ks < 2; ks++) {
            const int acol = ks * 16 + acolL;
            const int bk   = ks * 16 + bkL;
            uint32_t a1[2][4], a2[2][4], b1[4][2];
#pragma unroll
            for (int mt = 0; mt < 2; mt++) {
                uint32_t off = ((arow + mt * 16) * PITCH + acol) * 2;
                ldmx4(a1[mt][0], a1[mt][1], a1[mt][2], a1[mt][3], as1 + off);
                ldmx4(a2[mt][0], a2[mt][1], a2[mt][2], a2[mt][3], as2 + off);
            }
#pragma unroll
            for (int nt2 = 0; nt2 < 2; nt2++) {
                uint32_t off = ((bn + nt2 * 16) * PITCH + bk) * 2;
                ldmx4(b1[nt2 * 2][0], b1[nt2 * 2][1],
                      b1[nt2 * 2 + 1][0], b1[nt2 * 2 + 1][1], bs1 + off);
            }
#pragma unroll
            for (int mt = 0; mt < 2; mt++)
#pragma unroll
                for (int nt = 0; nt < 4; nt++) {
                    mma_f16(acc[mt][nt], a1[mt], b1[nt]);
                    mma_f16(acc[mt][nt], a2[mt], b1[nt]);
                }
        }
        __syncthreads();
    }

    const int g  = lane >> 2;
    const int tg = lane & 3;
#pragma unroll
    for (int mt = 0; mt < 2; mt++)
#pragma unroll
        for (int nt = 0; nt < 4; nt++)
#pragma unroll
            for (int half = 0; half < 2; half++) {
                int nrow = nblk * 128 + wm * 32 + mt * 16 + g + half * 8;
                int d    = wn * 32 + nt * 8 + tg * 2;
                float2 v = make_float2(acc[mt][nt][half * 2],
                                       acc[mt][nt][half * 2 + 1]);
                size_t adr = ((size_t)b * SEQ + nrow) * CH + h * HD + d;
                *(__half2*)&g_OC1[adr] =
                    __halves2half2(__float2half(v.x), __float2half(v.y));
            }
}

// ---------------- launch -----------------------------------------------------------
extern "C" void kernel_launch(void* const* d_in, const int* in_sizes, int n_in,
                              void* d_out, int out_size)
{
    const float *x = nullptr, *wqkv = nullptr, *wproj = nullptr,
                *bias = nullptr, *rm = nullptr;
    for (int i = 0; i < n_in; i++) {
        const float* p = (const float*)d_in[i];
        switch (in_sizes[i]) {
            case BATCH * SEQ * CH: x = p; break;
            case CH * 2 * CH:      wqkv = p; break;
            case CH * CH:          wproj = p; break;
            case CH:               bias = p; break;
            case NH * HD * RM:     rm = p; break;
        }
    }
    float* out = (float*)d_out;
    (void)out_size;

    cudaFuncSetAttribute(hmma_gemm<0>, cudaFuncAttributeMaxDynamicSharedMemorySize, DG_SMEM);
    cudaFuncSetAttribute(hmma_gemm<1>, cudaFuncAttributeMaxDynamicSharedMemorySize, DG_SMEM);
    cudaFuncSetAttribute(rf_hmma, cudaFuncAttributeMaxDynamicSharedMemorySize, RF_SMEM);
    cudaFuncSetAttribute(kkkv_hmma, cudaFuncAttributeMaxDynamicSharedMemorySize, KK_SMEM);
    cudaFuncSetAttribute(ista_fused, cudaFuncAttributeMaxDynamicSharedMemorySize, IST_SMEM);

    // conversions (all fp16)
    conv_x_kernel<<<BATCH * SEQ * CH / 1024, 256>>>(x);
    conv_small<<<(3 * CH * CH + NH * RM * HD) / 256, 256>>>(wqkv, wproj, rm);

    // 1. qkv = x @ Wqkv (q cols 2-term, v cols 1-term)
    hmma_gemm<0><<<dim3(12, 256), 256, DG_SMEM>>>(nullptr, nullptr, CH);
    // 2. rf (fp16 3-term, fast exp) -> rf fp16 pair
    rf_hmma<<<dim3(32, BH), 256, RF_SMEM>>>();
    // 3. kk/kv partials (fp16 2-term, 64-row chunks)
    kkkv_hmma<<<dim3(3, BH, SPLITS), 256, KK_SMEM>>>();
    // 4. fused reduce + d + L + ISTA (split over d-halves) -> sT fp16 single
    ista_fused<<<dim3(BH, 2), 256, IST_SMEM>>>();
    // 5. out_head = rf @ s (fp16 2-term) -> OC fp16 single
    outgemm_hmma<<<dim3(32, BH), 256>>>();
    // 6. final projection + bias (fp16 1-term)
    hmma_gemm<1><<<dim3(6, 256), 256, DG_SMEM>>>(bias, out, CH);
}

// round 16
// speedup vs baseline: 4.9910x; 1.0215x over previous
#include <cuda_runtime.h>
#include <cuda_fp16.h>
#include <math.h>
#include <cstdint>

// Problem constants
#define BATCH 8
#define SEQ   4096
#define CH    768
#define NH    12
#define HD    64
#define RM    128
#define BH    (BATCH*NH)
#define LAMBDA 0.3f
#define NSTEP 5
#define SPLITS 4
#define NCHUNK (SEQ/SPLITS)    // 1024

// ---------------- scratch ----------------------------------------------------
__device__ float g_PART[(size_t)SPLITS*BH*RM*(RM+HD)];
// fp16 split pairs / singles
__device__ __half g_XH1[(size_t)BATCH*SEQ*CH];       // x hi
__device__ __half g_XH2[(size_t)BATCH*SEQ*CH];       // x lo (q path only)
__device__ __half g_WQ1[(size_t)CH*CH];              // WqT single [n][k]
__device__ __half g_WV1[(size_t)CH*CH];              // WvT single
__device__ __half g_WP1[(size_t)CH*CH];              // WprojT single
__device__ __half g_QB1[(size_t)BH*SEQ*HD];          // qs pair [bh][n][d]
__device__ __half g_QB2[(size_t)BH*SEQ*HD];
__device__ __half g_RT1[(size_t)NH*RM*HD];           // R^T pair [h][m][d]
__device__ __half g_RT2[(size_t)NH*RM*HD];
__device__ __half g_RF1[(size_t)BH*SEQ*RM];          // rf pair [bh][n][m]
__device__ __half g_RF2[(size_t)BH*SEQ*RM];
__device__ __half g_VB1[(size_t)BH*SEQ*HD];          // v single [bh][n][d]
__device__ __half g_ST1[(size_t)BH*HD*RM];           // (d*s)^T single [bh][d][m]
__device__ __half g_OC1[(size_t)BATCH*SEQ*CH];       // out-head single

// ---------------- helpers ------------------------------------------------------
__device__ __forceinline__ uint32_t smem_u32(const void* p) {
    uint32_t a;
    asm("{ .reg .u64 t; cvta.to.shared.u64 t, %1; cvt.u32.u64 %0, t; }"
        : "=r"(a) : "l"(p));
    return a;
}
__device__ __forceinline__ void ldmx4(uint32_t& r0, uint32_t& r1,
                                      uint32_t& r2, uint32_t& r3, uint32_t addr)
{
    asm volatile("ldmatrix.sync.aligned.m8n8.x4.shared.b16 {%0,%1,%2,%3}, [%4];"
                 : "=r"(r0), "=r"(r1), "=r"(r2), "=r"(r3) : "r"(addr));
}
__device__ __forceinline__ void ldmx4t(uint32_t* r, uint32_t addr)
{
    asm volatile("ldmatrix.sync.aligned.m8n8.x4.trans.shared.b16 {%0,%1,%2,%3}, [%4];"
                 : "=r"(r[0]), "=r"(r[1]), "=r"(r[2]), "=r"(r[3]) : "r"(addr));
}
__device__ __forceinline__ void mma_f16(float* c, const uint32_t* a,
                                        const uint32_t* b)
{
    asm volatile(
        "mma.sync.aligned.m16n8k16.row.col.f32.f16.f16.f32 "
        "{%0,%1,%2,%3}, {%4,%5,%6,%7}, {%8,%9}, {%0,%1,%2,%3};"
        : "+f"(c[0]), "+f"(c[1]), "+f"(c[2]), "+f"(c[3])
        : "r"(a[0]), "r"(a[1]), "r"(a[2]), "r"(a[3]), "r"(b[0]), "r"(b[1]));
}
__device__ __forceinline__ void split2h(float v, __half& h, __half& l)
{
    h = __float2half(v);
    l = __float2half(v - __half2float(h));
}
__device__ __forceinline__ void cpa16(uint32_t saddr, const void* g)
{
    asm volatile("cp.async.cg.shared.global [%0], [%1], 16;"
                 :: "r"(saddr), "l"(g));
}
#define CP_COMMIT() asm volatile("cp.async.commit_group;")
#define CP_WAIT1()  asm volatile("cp.async.wait_group 1;")
#define CP_WAIT0()  asm volatile("cp.async.wait_group 0;")

#define PITCH 40
#define DG_TILE (128*PITCH)
#define DG_STAGE (3*DG_TILE)
#define DG_SMEM (2*DG_STAGE*2) // 61440 bytes

// ---------------- dense HMMA GEMM (fp16) -------------------------------------------
// EPI==0, q cols : 2-term (x pair x Wq single)         -> q fp16 pair (scaled)
// EPI==0, v cols : 1-term (x hi   x Wv single)         -> v fp16 single
// EPI==1         : 1-term (OC single x WP single)+bias -> fp32 out
template<int EPI>
__global__ __launch_bounds__(256, 2)
void hmma_gemm(const float* __restrict__ bias, float* __restrict__ Cout, int Kdim)
{
    extern __shared__ uint16_t dsm[];

    const int tid  = threadIdx.x;
    const int wid  = tid >> 5;
    const int lane = tid & 31;
    const int wm   = wid & 1;
    const int wn   = wid >> 1;
    const int brow = blockIdx.y * 128;
    const int bcol = blockIdx.x * 128;

    const bool qmode = (EPI == 0) && (bcol < CH);
    const uint16_t* A1 = (EPI == 0) ? (const uint16_t*)g_XH1 : (const uint16_t*)g_OC1;
    const uint16_t* A2 = qmode ? (const uint16_t*)g_XH2 : nullptr;
    const uint16_t* B1;
    int bb0;
    if (EPI == 1)      { B1 = (const uint16_t*)g_WP1; bb0 = bcol; }
    else if (qmode)    { B1 = (const uint16_t*)g_WQ1; bb0 = bcol; }
    else               { B1 = (const uint16_t*)g_WV1; bb0 = bcol - CH; }
    const int NT = qmode ? 3 : 2;

    float acc[4][4][4];
#pragma unroll
    for (int i = 0; i < 4; i++)
#pragma unroll
        for (int j = 0; j < 4; j++)
#pragma unroll
            for (int q = 0; q < 4; q++) acc[i][j][q] = 0.f;

    const uint32_t smbase = smem_u32(dsm);
    const int arow = wm * 64 + (lane & 15);
    const int acolL = (lane >> 4) * 8;
    const int bn   = wn * 32 + (lane & 7) + ((lane >> 4) & 1) * 8;
    const int bkL  = ((lane >> 3) & 1) * 8;

    const int l_row0 = tid >> 2,        l_ch0 = (tid & 3) * 8;
    const int l_row1 = (tid + 256) >> 2, l_ch1 = ((tid + 256) & 3) * 8;

    auto load_stage = [&](int stage, int k0) {
        uint32_t sb = smbase + stage * DG_STAGE * 2;
        for (int t = 0; t < NT; t++) {
            const uint16_t* src;
            int rbase;
            if (qmode) {
                src = (t == 0) ? A1 : (t == 1) ? A2 : B1;
                rbase = (t < 2) ? brow : bb0;
            } else {
                src = (t == 0) ? A1 : B1;
                rbase = (t == 0) ? brow : bb0;
            }
            uint32_t tb = sb + t * DG_TILE * 2;
            cpa16(tb + (l_row0 * PITCH + l_ch0) * 2,
                  src + (size_t)(rbase + l_row0) * Kdim + k0 + l_ch0);
            cpa16(tb + (l_row1 * PITCH + l_ch1) * 2,
                  src + (size_t)(rbase + l_row1) * Kdim + k0 + l_ch1);
        }
    };

    const int nchunk = Kdim >> 5;
    load_stage(0, 0);
    CP_COMMIT();

    for (int kc = 0; kc < nchunk; kc++) {
        if (kc + 1 < nchunk) load_stage((kc + 1) & 1, (kc + 1) << 5);
        CP_COMMIT();
        CP_WAIT1();
        __syncthreads();

        const uint32_t sb = smbase + (kc & 1) * DG_STAGE * 2;
        const uint32_t as1 = sb;
        const uint32_t as2 = sb + DG_TILE * 2;
        const uint32_t bs1 = qmode ? sb + 2 * DG_TILE * 2 : sb + DG_TILE * 2;
#pragma unroll
        for (int ks = 0; ks < 2; ks++) {
            const int acol = ks * 16 + acolL;
            const int bk   = ks * 16 + bkL;
            uint32_t a1[4][4], a2[4][4], b1[4][2];
#pragma unroll
            for (int mt = 0; mt < 4; mt++) {
                uint32_t off = ((arow + mt * 16) * PITCH + acol) * 2;
                ldmx4(a1[mt][0], a1[mt][1], a1[mt][2], a1[mt][3], as1 + off);
                if (qmode)
                    ldmx4(a2[mt][0], a2[mt][1], a2[mt][2], a2[mt][3], as2 + off);
            }
#pragma unroll
            for (int nt2 = 0; nt2 < 2; nt2++) {
                uint32_t off = ((bn + nt2 * 16) * PITCH + bk) * 2;
                ldmx4(b1[nt2 * 2][0], b1[nt2 * 2][1],
                      b1[nt2 * 2 + 1][0], b1[nt2 * 2 + 1][1], bs1 + off);
            }
#pragma unroll
            for (int mt = 0; mt < 4; mt++)
#pragma unroll
                for (int nt = 0; nt < 4; nt++) {
                    mma_f16(acc[mt][nt], a1[mt], b1[nt]);
                    if (qmode)
                        mma_f16(acc[mt][nt], a2[mt], b1[nt]);
                }
        }
        __syncthreads();
    }

    const int g  = lane >> 2;
    const int tg = lane & 3;
#pragma unroll
    for (int mt = 0; mt < 4; mt++)
#pragma unroll
        for (int nt = 0; nt < 4; nt++) {
#pragma unroll
            for (int half = 0; half < 2; half++) {
                int grow = brow + wm * 64 + mt * 16 + g + half * 8;
                int col  = bcol + wn * 32 + nt * 8 + tg * 2;
                float2 v = make_float2(acc[mt][nt][half * 2],
                                       acc[mt][nt][half * 2 + 1]);
                if (EPI == 0) {
                    int bb = grow >> 12, nn = grow & 4095;
                    if (col < CH) {
                        const float s = 0.35355339059327373f;  // hd^(-1/4)
                        v.x *= s; v.y *= s;
                        int h = col >> 6, dd = col & 63;
                        size_t adr = (((size_t)(bb * NH + h)) * SEQ + nn) * HD + dd;
                        __half h0, l0, h1, l1;
                        split2h(v.x, h0, l0); split2h(v.y, h1, l1);
                        *(__half2*)&g_QB1[adr] = __halves2half2(h0, h1);
                        *(__half2*)&g_QB2[adr] = __halves2half2(l0, l1);
                    } else {
                        int c2 = col - CH;
                        int h = c2 >> 6, dd = c2 & 63;
                        size_t adr = (((size_t)(bb * NH + h)) * SEQ + nn) * HD + dd;
                        *(__half2*)&g_VB1[adr] =
                            __halves2half2(__float2half(v.x), __float2half(v.y));
                    }
                } else {
                    v.x += bias[col];
                    v.y += bias[col + 1];
                    *(float2*)&Cout[(size_t)grow * CH + col] = v;
                }
            }
        }
}

// ---------------- conversion kernels -----------------------------------------
__global__ __launch_bounds__(256)
void conv_x_kernel(const float* __restrict__ x)
{
    size_t i = ((size_t)blockIdx.x * 256 + threadIdx.x) * 4;
    float4 v = *(const float4*)&x[i];
    __half h0, l0, h1, l1, h2, l2, h3, l3;
    split2h(v.x, h0, l0); split2h(v.y, h1, l1);
    split2h(v.z, h2, l2); split2h(v.w, h3, l3);
    *(__half2*)&g_XH1[i]     = __halves2half2(h0, h1);
    *(__half2*)&g_XH1[i + 2] = __halves2half2(h2, h3);
    *(__half2*)&g_XH2[i]     = __halves2half2(l0, l1);
    *(__half2*)&g_XH2[i + 2] = __halves2half2(l2, l3);
}

// merged Wq/Wv + Wp + R^T conversion (range-branched)
__global__ __launch_bounds__(256)
void conv_small(const float* __restrict__ wqkv, const float* __restrict__ wproj,
                const float* __restrict__ randm)
{
    int idx = blockIdx.x * 256 + threadIdx.x;
    if (idx < 2 * CH * CH) {
        int n = idx / CH, k = idx - n * CH;
        float v = wqkv[(size_t)k * (2 * CH) + n];
        if (n < CH) g_WQ1[(size_t)n * CH + k] = __float2half(v);
        else        g_WV1[(size_t)(n - CH) * CH + k] = __float2half(v);
    } else if (idx < 3 * CH * CH) {
        int i2 = idx - 2 * CH * CH;
        int n = i2 / CH, k = i2 - n * CH;
        g_WP1[i2] = __float2half(wproj[(size_t)k * CH + n]);
    } else {
        int i2 = idx - 3 * CH * CH;
        int h = i2 / (RM * HD);
        int r = i2 - h * (RM * HD);
        int m = r / HD, d = r - m * HD;
        float v = randm[((size_t)h * HD + d) * RM + m];
        __half hi, lo;
        split2h(v, hi, lo);
        g_RT1[i2] = hi;
        g_RT2[i2] = lo;
    }
}

// ---------------- rf via HMMA (fp16 3-term), staged coalesced stores -------------
#define RF_PITCH 72
#define RF_TILE (128*RF_PITCH)
#define RF_SMEM (4*RF_TILE*2)      // 73728 B; staging (2*128*136*2 = 69632) fits
#define RF_SPITCH 136

__global__ __launch_bounds__(256, 2)
void rf_hmma()
{
    extern __shared__ __half rsm[];
    __shared__ float rowq2[128];
    const int tid = threadIdx.x, wid = tid >> 5, lane = tid & 31;
    const int wm = wid & 1, wn = wid >> 1;
    const int bh = blockIdx.y, h = bh % NH;
    const int brow = blockIdx.x * 128;

    const __half* A1 = g_QB1 + ((size_t)bh * SEQ + brow) * HD;
    const __half* A2 = g_QB2 + ((size_t)bh * SEQ + brow) * HD;
    const __half* B1 = g_RT1 + (size_t)h * RM * HD;
    const __half* B2 = g_RT2 + (size_t)h * RM * HD;

    const uint32_t smbase = smem_u32(rsm);
#pragma unroll
    for (int t = 0; t < 4; t++) {
        const __half* src = (t == 0) ? A1 : (t == 1) ? A2 : (t == 2) ? B1 : B2;
        uint32_t dst = smbase + t * RF_TILE * 2;
#pragma unroll
        for (int u = 0; u < 4; u++) {
            int f = u * 256 + tid;
            int r = f >> 3, c = (f & 7) * 8;
            cpa16(dst + (r * RF_PITCH + c) * 2, src + (size_t)r * HD + c);
        }
    }
    CP_COMMIT();
    CP_WAIT0();
    __syncthreads();

    {
        int r = tid >> 1;
        int k0 = (tid & 1) * 32;
        const __half* q1 = rsm + r * RF_PITCH + k0;
        const __half* q2 = rsm + RF_TILE + r * RF_PITCH + k0;
        float s = 0.f;
#pragma unroll
        for (int k = 0; k < 32; k++) {
            float v = __half2float(q1[k]) + __half2float(q2[k]);
            s += v * v;
        }
        s += __shfl_xor_sync(0xffffffffu, s, 1);
        if (!(tid & 1)) rowq2[r] = s;
    }

    float acc[4][4][4];
#pragma unroll
    for (int i = 0; i < 4; i++)
#pragma unroll
        for (int j = 0; j < 4; j++)
#pragma unroll
            for (int q = 0; q < 4; q++) acc[i][j][q] = 0.f;

    const uint32_t as1 = smbase, as2 = smbase + RF_TILE * 2;
    const uint32_t bs1 = smbase + 2 * RF_TILE * 2, bs2 = smbase + 3 * RF_TILE * 2;
    const int arow = wm * 64 + (lane & 15);
    const int acolL = (lane >> 4) * 8;
    const int bn   = wn * 32 + (lane & 7) + ((lane >> 4) & 1) * 8;
    const int bkL  = ((lane >> 3) & 1) * 8;

#pragma unroll
    for (int ks = 0; ks < 4; ks++) {
        const int acol = ks * 16 + acolL;
        const int bk   = ks * 16 + bkL;
        uint32_t a1[4][4], a2[4][4], b1[4][2], b2[4][2];
#pragma unroll
        for (int mt = 0; mt < 4; mt++) {
            uint32_t off = ((arow + mt * 16) * RF_PITCH + acol) * 2;
            ldmx4(a1[mt][0], a1[mt][1], a1[mt][2], a1[mt][3], as1 + off);
            ldmx4(a2[mt][0], a2[mt][1], a2[mt][2], a2[mt][3], as2 + off);
        }
#pragma unroll
        for (int nt2 = 0; nt2 < 2; nt2++) {
            uint32_t off = ((bn + nt2 * 16) * RF_PITCH + bk) * 2;
            ldmx4(b1[nt2 * 2][0], b1[nt2 * 2][1],
                  b1[nt2 * 2 + 1][0], b1[nt2 * 2 + 1][1], bs1 + off);
            ldmx4(b2[nt2 * 2][0], b2[nt2 * 2][1],
                  b2[nt2 * 2 + 1][0], b2[nt2 * 2 + 1][1], bs2 + off);
        }
#pragma unroll
        for (int mt = 0; mt < 4; mt++)
#pragma unroll
            for (int nt = 0; nt < 4; nt++) {
                mma_f16(acc[mt][nt], a1[mt], b1[nt]);
                mma_f16(acc[mt][nt], a1[mt], b2[nt]);
                mma_f16(acc[mt][nt], a2[mt], b1[nt]);
            }
    }
    __syncthreads();   // all warps done with rsm tiles -> safe to re-use as staging

    // stage exp results in smem (conflict-free), then coalesced global stores
    __half* st1 = rsm;
    __half* st2 = rsm + 128 * RF_SPITCH;
    const int g  = lane >> 2;
    const int tg = lane & 3;
    const float sc = 0.08838834764831845f;  // 1/sqrt(128)
#pragma unroll
    for (int mt = 0; mt < 4; mt++)
#pragma unroll
        for (int nt = 0; nt < 4; nt++)
#pragma unroll
            for (int half = 0; half < 2; half++) {
                int row  = wm * 64 + mt * 16 + g + half * 8;
                int mcol = wn * 32 + nt * 8 + tg * 2;
                float base = -0.5f * rowq2[row];
                float v0 = __expf(acc[mt][nt][half * 2]     + base) * sc;
                float v1 = __expf(acc[mt][nt][half * 2 + 1] + base) * sc;
                __half h0, l0, h1, l1;
                split2h(v0, h0, l0); split2h(v1, h1, l1);
                *(__half2*)&st1[row * RF_SPITCH + mcol] = __halves2half2(h0, h1);
                *(__half2*)&st2[row * RF_SPITCH + mcol] = __halves2half2(l0, l1);
            }
    __syncthreads();

    size_t gbase = ((size_t)bh * SEQ + brow) * RM;
#pragma unroll
    for (int l = 0; l < 8; l++) {
        int f = tid + l * 256;          // 0..2047: 128 rows x 16 uint4
        int r = f >> 4, c = (f & 15) * 8;
        *(uint4*)(g_RF1 + gbase + (size_t)r * RM + c) =
            *(const uint4*)(st1 + r * RF_SPITCH + c);
        *(uint4*)(g_RF2 + gbase + (size_t)r * RM + c) =
            *(const uint4*)(st2 + r * RF_SPITCH + c);
    }
}

// ---------------- kk/kv via fp16 2-term HMMA (A=rf pair, B single) ---------------
// 64-row chunks; for ct<2 the B tile is a column slice of the resident A1 tile
#define KK_ROWS 64
#define KK_A_TILE (KK_ROWS*136)
#define KK_Y_TILE (KK_ROWS*72)
#define KK_STAGE (2*KK_A_TILE + KK_Y_TILE)
#define KK_SMEM (2*KK_STAGE*2)   // 88064 bytes

__global__ __launch_bounds__(256, 2)
void kkkv_hmma()
{
    extern __shared__ __half ksm[];
    const int tid = threadIdx.x, wid = tid >> 5, lane = tid & 31;
    const int ct = blockIdx.x, bh = blockIdx.y, split = blockIdx.z;
    const int wm = wid >> 1, wn = wid & 1;

    size_t abase = ((size_t)bh * SEQ + (size_t)split * NCHUNK) * RM;
    const __half *a1 = g_RF1 + abase, *a2 = g_RF2 + abase;
    const __half *b1 = nullptr;
    if (ct == 2)
        b1 = g_VB1 + ((size_t)bh * SEQ + (size_t)split * NCHUNK) * HD;
    const int ct_off  = (ct == 2) ? 0 : ct * 64;   // column offset into A1 tile
    const int ypitch  = (ct == 2) ? 72 : 136;

    float acc[2][4][4];
#pragma unroll
    for (int i = 0; i < 2; i++)
#pragma unroll
        for (int j = 0; j < 4; j++)
#pragma unroll
            for (int q = 0; q < 4; q++) acc[i][j][q] = 0.f;

    const uint32_t smbase = smem_u32(ksm);
    const int a_r = (lane & 7) + (lane >> 4) * 8;
    const int a_c = ((lane >> 3) & 1) * 8;
    const int b_r = (lane & 7) + ((lane >> 3) & 1) * 8;
    const int b_c = (lane >> 4) * 8;

    auto load_stage = [&](int stage, int n0) {
        uint32_t sb = smbase + stage * KK_STAGE * 2;
        uint32_t sA1 = sb, sA2 = sb + KK_A_TILE * 2;
        uint32_t sY1 = sb + 2 * KK_A_TILE * 2;
#pragma unroll
        for (int l = 0; l < 4; l++) {       // A: 64 rows x 16 uint4 = 1024 slots
            int f = tid + l * 256;
            int r = f >> 4, c = (f & 15) * 8;
            cpa16(sA1 + (r * 136 + c) * 2, a1 + (size_t)(n0 + r) * RM + c);
            cpa16(sA2 + (r * 136 + c) * 2, a2 + (size_t)(n0 + r) * RM + c);
        }
        if (ct == 2) {
#pragma unroll
            for (int l = 0; l < 2; l++) {   // Y: 64 rows x 8 uint4 = 512 slots
                int f = tid + l * 256;
                int r = f >> 3, c = (f & 7) * 8;
                cpa16(sY1 + (r * 72 + c) * 2, b1 + (size_t)(n0 + r) * HD + c);
            }
        }
    };

    load_stage(0, 0);
    CP_COMMIT();

    for (int chunk = 0; chunk < NCHUNK / KK_ROWS; chunk++) {
        if (chunk + 1 < NCHUNK / KK_ROWS) load_stage((chunk + 1) & 1, (chunk + 1) * KK_ROWS);
        CP_COMMIT();
        CP_WAIT1();
        __syncthreads();

        uint32_t sb = smbase + (chunk & 1) * KK_STAGE * 2;
        uint32_t as1 = sb, as2 = sb + KK_A_TILE * 2;
        uint32_t ybase = (ct == 2) ? sb + 2 * KK_A_TILE * 2 : as1;
#pragma unroll
        for (int ks = 0; ks < 4; ks++) {
            uint32_t A1f[2][4], A2f[2][4], B1f[4][2];
#pragma unroll
            for (int mt = 0; mt < 2; mt++) {
                uint32_t off = ((ks * 16 + a_r) * 136 + wm * 32 + mt * 16 + a_c) * 2;
                ldmx4t(A1f[mt], as1 + off);
                ldmx4t(A2f[mt], as2 + off);
            }
#pragma unroll
            for (int nb = 0; nb < 2; nb++) {
                uint32_t off = ((ks * 16 + b_r) * ypitch
                                + ct_off + wn * 32 + nb * 16 + b_c) * 2;
                uint32_t t1[4];
                ldmx4t(t1, ybase + off);
                B1f[nb * 2][0] = t1[0]; B1f[nb * 2][1] = t1[1];
                B1f[nb * 2 + 1][0] = t1[2]; B1f[nb * 2 + 1][1] = t1[3];
            }
#pragma unroll
            for (int mt = 0; mt < 2; mt++)
#pragma unroll
                for (int nt = 0; nt < 4; nt++) {
                    mma_f16(acc[mt][nt], A1f[mt], B1f[nt]);
                    mma_f16(acc[mt][nt], A2f[mt], B1f[nt]);
                }
        }
        __syncthreads();
    }

    float* dst = g_PART + ((size_t)split * BH + bh) * (RM * (RM + HD));
#pragma unroll
    for (int mt = 0; mt < 2; mt++)
#pragma unroll
        for (int nt = 0; nt < 4; nt++)
#pragma unroll
            for (int half = 0; half < 2; half++) {
                int m = wm * 32 + mt * 16 + (lane >> 2) + half * 8;
                int j = ct * 64 + wn * 32 + nt * 8 + (lane & 3) * 2;
                *(float2*)&dst[m * (RM + HD) + j] =
                    make_float2(acc[mt][nt][half * 2], acc[mt][nt][half * 2 + 1]);
            }
}

// ---------------- fused reduce + ISTA, split over d-halves -----------------------
__device__ __forceinline__ float softf(float z, float t)
{
    float a = fabsf(z) - t;
    return a > 0.f ? (z >= 0.f ? a : -a) : 0.f;
}

#define IST_SMEM ((RM*129 + RM*32 + RM*36) * 4)    // 100864 B

__global__ __launch_bounds__(256)
void ista_fused()
{
    extern __shared__ float sm[];
    float* kks = sm;                 // [128][129]
    float* kvs = sm + RM * 129;      // [128][32]
    float* ss  = kvs + RM * 32;      // [128][36]
    __shared__ float dsh[RM];
    __shared__ float rowsum[RM];
    __shared__ float Lsh;
    const int bh = blockIdx.x;
    const int dhalf = blockIdx.y;
    const float* part = g_PART;

    if (threadIdx.x < RM) {
        float s = 0.f;
#pragma unroll
        for (int sp = 0; sp < SPLITS; sp++)
            s += part[((size_t)sp * BH + bh) * (RM * (RM + HD))
                      + threadIdx.x * (RM + HD) + threadIdx.x];
        dsh[threadIdx.x] = 1.0f / fmaxf(sqrtf(s), 1e-12f);
    }
    __syncthreads();

    for (int idx = threadIdx.x; idx < RM * RM; idx += 256) {
        int m = idx >> 7, j = idx & 127;
        float s = 0.f;
#pragma unroll
        for (int sp = 0; sp < SPLITS; sp++)
            s += part[((size_t)sp * BH + bh) * (RM * (RM + HD)) + m * (RM + HD) + j];
        kks[m * 129 + j] = s * dsh[m] * dsh[j];
    }
    for (int idx = threadIdx.x; idx < RM * 32; idx += 256) {
        int m = idx >> 5, c = idx & 31;
        float s = 0.f;
#pragma unroll
        for (int sp = 0; sp < SPLITS; sp++)
            s += part[((size_t)sp * BH + bh) * (RM * (RM + HD))
                      + m * (RM + HD) + RM + dhalf * 32 + c];
        kvs[m * 32 + c] = s * dsh[m];
    }
    __syncthreads();

    if (threadIdx.x < RM) {
        float rs = 0.f;
        for (int j = 0; j < RM; j++) rs += fabsf(kks[threadIdx.x * 129 + j]);
        rowsum[threadIdx.x] = rs;
    }
    __syncthreads();
    if (threadIdx.x == 0) {
        float mx = 0.f;
        for (int i = 0; i < RM; i++) mx = fmaxf(mx, rowsum[i]);
        Lsh = mx + 1.0f;
    }
    __syncthreads();
    float invL = 1.0f / Lsh;
    float thr  = LAMBDA * invL;

    int m  = threadIdx.x >> 1;
    int cl = (threadIdx.x & 1) * 16;
#pragma unroll
    for (int i = 0; i < 16; i++)
        ss[m * 36 + cl + i] = softf(kvs[m * 32 + cl + i], LAMBDA);
    __syncthreads();

    for (int it = 0; it < NSTEP; it++) {
        float acc[16];
#pragma unroll
        for (int i = 0; i < 16; i++) acc[i] = 0.f;
        for (int p = 0; p < RM; p++) {
            float kv_ = kks[m * 129 + p];
            const float4* sp = (const float4*)&ss[p * 36 + cl];
#pragma unroll
            for (int q = 0; q < 4; q++) {
                float4 v = sp[q];
                acc[q * 4 + 0] += kv_ * v.x;
                acc[q * 4 + 1] += kv_ * v.y;
                acc[q * 4 + 2] += kv_ * v.z;
                acc[q * 4 + 3] += kv_ * v.w;
            }
        }
        float r[16];
#pragma unroll
        for (int i = 0; i < 16; i++) {
            float z = ss[m * 36 + cl + i] - (acc[i] - kvs[m * 32 + cl + i]) * invL;
            r[i] = softf(z, thr);
        }
        __syncthreads();
#pragma unroll
        for (int q = 0; q < 4; q++)
            *(float4*)&ss[m * 36 + cl + q * 4] =
                make_float4(r[q * 4], r[q * 4 + 1], r[q * 4 + 2], r[q * 4 + 3]);
        __syncthreads();
    }
    float dm = dsh[m];
#pragma unroll
    for (int q = 0; q < 4; q++) {
        float4 v = *(float4*)&ss[m * 36 + cl + q * 4];
        v.x *= dm; v.y *= dm; v.z *= dm; v.w *= dm;
        *(float4*)&ss[m * 36 + cl + q * 4] = v;
    }
    __syncthreads();
    int dl = threadIdx.x >> 3;
    int ms = (threadIdx.x & 7) * 16;
    size_t ob = ((size_t)bh * HD + dhalf * 32 + dl) * RM + ms;
#pragma unroll
    for (int i = 0; i < 16; i += 2) {
        float v0 = ss[(ms + i) * 36 + dl];
        float v1 = ss[(ms + i + 1) * 36 + dl];
        *(__half2*)&g_ST1[ob + i] =
            __halves2half2(__float2half(v0), __float2half(v1));
    }
}

// ---------------- out = rf(pair) @ sT(single) fp16 2-term, emits OC single --------
__global__ __launch_bounds__(256, 2)
void outgemm_hmma()
{
    __shared__ __half As1[128 * PITCH], As2[128 * PITCH];
    __shared__ __half Bs1[64 * PITCH];
    const int tid = threadIdx.x, wid = tid >> 5, lane = tid & 31;
    const int wm = wid & 3, wn = wid >> 2;
    const int bh = blockIdx.y, nblk = blockIdx.x;
    const int b = bh / NH, h = bh % NH;

    size_t rfbase = ((size_t)bh * SEQ + (size_t)nblk * 128) * RM;
    size_t stbase = (size_t)bh * HD * RM;

    float acc[2][4][4];
#pragma unroll
    for (int i = 0; i < 2; i++)
#pragma unroll
        for (int j = 0; j < 4; j++)
#pragma unroll
            for (int q = 0; q < 4; q++) acc[i][j][q] = 0.f;

    const uint32_t as1 = smem_u32(As1), as2 = smem_u32(As2);
    const uint32_t bs1 = smem_u32(Bs1);
    const int arow = wm * 32 + (lane & 15);
    const int acolL = (lane >> 4) * 8;
    const int bn   = wn * 32 + (lane & 7) + ((lane >> 4) & 1) * 8;
    const int bkL  = ((lane >> 3) & 1) * 8;

    for (int kc = 0; kc < 4; kc++) {
        const int k0 = kc * 32;
#pragma unroll
        for (int l = 0; l < 2; l++) {
            int f = tid + l * 256;
            int r = f >> 2, c = (f & 3) * 8;
            *(uint4*)(As1 + r * PITCH + c) =
                *(const uint4*)(g_RF1 + rfbase + (size_t)r * RM + k0 + c);
            *(uint4*)(As2 + r * PITCH + c) =
                *(const uint4*)(g_RF2 + rfbase + (size_t)r * RM + k0 + c);
        }
        {
            int r = tid >> 2, c = (tid & 3) * 8;
            if (r < 64)
                *(uint4*)(Bs1 + r * PITCH + c) =
                    *(const uint4*)(g_ST1 + stbase + (size_t)r * RM + k0 + c);
        }
        __syncthreads();
#pragma unroll
        for (int ks = 0; ks < 2; ks++) {
            const int acol = ks * 16 + acolL;
            const int bk   = ks * 16 + bkL;
            uint32_t a1[2][4], a2[2][4], b1[4][2];
#pragma unroll
            for (int mt = 0; mt < 2; mt++) {
                uint32_t off = ((arow + mt * 16) * PITCH + acol) * 2;
                ldmx4(a1[mt][0], a1[mt][1], a1[mt][2], a1[mt][3], as1 + off);
                ldmx4(a2[mt][0], a2[mt][1], a2[mt][2], a2[mt][3], as2 + off);
            }
#pragma unroll
            for (int nt2 = 0; nt2 < 2; nt2++) {
                uint32_t off = ((bn + nt2 * 16) * PITCH + bk) * 2;
                ldmx4(b1[nt2 * 2][0], b1[nt2 * 2][1],
                      b1[nt2 * 2 + 1][0], b1[nt2 * 2 + 1][1], bs1 + off);
            }
#pragma unroll
            for (int mt = 0; mt < 2; mt++)
#pragma unroll
                for (int nt = 0; nt < 4; nt++) {
                    mma_f16(acc[mt][nt], a1[mt], b1[nt]);
                    mma_f16(acc[mt][nt], a2[mt], b1[nt]);
                }
        }
        __syncthreads();
    }

    const int g  = lane >> 2;
    const int tg = lane & 3;
#pragma unroll
    for (int mt = 0; mt < 2; mt++)
#pragma unroll
        for (int nt = 0; nt < 4; nt++)
#pragma unroll
            for (int half = 0; half < 2; half++) {
                int nrow = nblk * 128 + wm * 32 + mt * 16 + g + half * 8;
                int d    = wn * 32 + nt * 8 + tg * 2;
                float2 v = make_float2(acc[mt][nt][half * 2],
                                       acc[mt][nt][half * 2 + 1]);
                size_t adr = ((size_t)b * SEQ + nrow) * CH + h * HD + d;
                *(__half2*)&g_OC1[adr] =
                    __halves2half2(__float2half(v.x), __float2half(v.y));
            }
}

// ---------------- launch -----------------------------------------------------------
extern "C" void kernel_launch(void* const* d_in, const int* in_sizes, int n_in,
                              void* d_out, int out_size)
{
    const float *x = nullptr, *wqkv = nullptr, *wproj = nullptr,
                *bias = nullptr, *rm = nullptr;
    for (int i = 0; i < n_in; i++) {
        const float* p = (const float*)d_in[i];
        switch (in_sizes[i]) {
            case BATCH * SEQ * CH: x = p; break;
            case CH * 2 * CH:      wqkv = p; break;
            case CH * CH:          wproj = p; break;
            case CH:               bias = p; break;
            case NH * HD * RM:     rm = p; break;
        }
    }
    float* out = (float*)d_out;
    (void)out_size;

    cudaFuncSetAttribute(hmma_gemm<0>, cudaFuncAttributeMaxDynamicSharedMemorySize, DG_SMEM);
    cudaFuncSetAttribute(hmma_gemm<1>, cudaFuncAttributeMaxDynamicSharedMemorySize, DG_SMEM);
    cudaFuncSetAttribute(rf_hmma, cudaFuncAttributeMaxDynamicSharedMemorySize, RF_SMEM);
    cudaFuncSetAttribute(kkkv_hmma, cudaFuncAttributeMaxDynamicSharedMemorySize, KK_SMEM);
    cudaFuncSetAttribute(ista_fused, cudaFuncAttributeMaxDynamicSharedMemorySize, IST_SMEM);

    // conversions (all fp16)
    conv_x_kernel<<<BATCH * SEQ * CH / 1024, 256>>>(x);
    conv_small<<<(3 * CH * CH + NH * RM * HD) / 256, 256>>>(wqkv, wproj, rm);

    // 1. qkv = x @ Wqkv (q cols 2-term, v cols 1-term)
    hmma_gemm<0><<<dim3(12, 256), 256, DG_SMEM>>>(nullptr, nullptr, CH);
    // 2. rf (fp16 3-term, staged coalesced stores) -> rf fp16 pair
    rf_hmma<<<dim3(32, BH), 256, RF_SMEM>>>();
    // 3. kk/kv partials (fp16 2-term; B from resident A tile for ct<2)
    kkkv_hmma<<<dim3(3, BH, SPLITS), 256, KK_SMEM>>>();
    // 4. fused reduce + d + L + ISTA (split over d-halves) -> sT fp16 single
    ista_fused<<<dim3(BH, 2), 256, IST_SMEM>>>();
    // 5. out_head = rf @ s (fp16 2-term) -> OC fp16 single
    outgemm_hmma<<<dim3(32, BH), 256>>>();
    // 6. final projection + bias (fp16 1-term)
    hmma_gemm<1><<<dim3(6, 256), 256, DG_SMEM>>>(bias, out, CH);
}